// round 4
// baseline (speedup 1.0000x reference)
#include <cuda_runtime.h>
#include <math.h>

#define BB 8
#define TT 8
#define HW 1024
#define CG 256
#define NSTATE (BB*64*HW)   // 524288

// ---- persistent state ----
__device__ float g_ih[NSTATE];
__device__ float g_ic[NSTATE];
__device__ float g_im[NSTATE];
// ---- scratch ----
__device__ float g_gates[BB*CG*HW];
__device__ float g_gsum [2][64];
__device__ float g_gsum2[2][64];
__device__ float g_oh[NSTATE];
__device__ float g_qkvh[BB*192*HW];
__device__ float g_kvm[BB*128*HW];
__device__ float g_S[2][(size_t)BB*HW*HW];   // raw scores, 64MB
__device__ float g_rmax[2][BB*HW];
__device__ float g_rinv[2][BB*HW];
__device__ float g_Zcat[BB*128*HW];
__device__ float g_Z[NSTATE];
__device__ float g_g2[BB*192*HW];
__device__ unsigned g_wT[1152*256];   // [(ci*9+pos)][co] tf32

__device__ __forceinline__ float sigm(float x){ return 1.f/(1.f+__expf(-x)); }
__device__ __forceinline__ unsigned f2t(float x){
  unsigned r; asm("cvt.rna.tf32.f32 %0,%1;" : "=r"(r) : "f"(x)); return r;
}
__device__ __forceinline__ void mma8(float* d, const unsigned* a, unsigned b0, unsigned b1){
  asm volatile("mma.sync.aligned.m16n8k8.row.col.f32.tf32.tf32.f32 "
    "{%0,%1,%2,%3},{%4,%5,%6,%7},{%8,%9},{%0,%1,%2,%3};"
    : "+f"(d[0]),"+f"(d[1]),"+f"(d[2]),"+f"(d[3])
    : "r"(a[0]),"r"(a[1]),"r"(a[2]),"r"(a[3]),"r"(b0),"r"(b1));
}

__global__ void zero_states(){
  int i = blockIdx.x*256 + threadIdx.x;
  if (i < NSTATE){ g_ih[i]=0.f; g_ic[i]=0.f; g_im[i]=0.f; }
  if (blockIdx.x==0 && threadIdx.x<64){
    g_gsum[0][threadIdx.x]=0.f; g_gsum2[0][threadIdx.x]=0.f;
    g_gsum[1][threadIdx.x]=0.f; g_gsum2[1][threadIdx.x]=0.f;
  }
}

__global__ void wtrans(const float* __restrict__ w){
  int co = blockIdx.x;
  for (int i = threadIdx.x; i < 1152; i += 256)
    g_wT[(size_t)i*256 + co] = f2t(w[(size_t)co*1152 + i]);
}

// ------------------- 3x3 conv (implicit GEMM, TC) + fused GN partial stats ----
__global__ __launch_bounds__(256) void conv_tc(const float* __restrict__ xin,
                                               const float* __restrict__ bias, int t)
{
  int pt = blockIdx.x, cot = blockIdx.y, b = blockIdx.z;
  int y0 = pt*4, co0 = cot*64, par = t & 1;
  __shared__ unsigned sIn[8][6][36];
  __shared__ unsigned sW[9][8][72];
  __shared__ float ws[8], ws2[8];
  int tid=threadIdx.x, warp=tid>>5, lane=tid&31, g=lane>>2, tq=lane&3;
  int wc = warp&3, wm = warp>>2;
  float acc[8][4];
  #pragma unroll
  for(int j=0;j<8;j++){acc[j][0]=0.f;acc[j][1]=0.f;acc[j][2]=0.f;acc[j][3]=0.f;}

  for (int chunk=0; chunk<16; chunk++){
    const float* src = (chunk<8) ? (xin + ((size_t)(b*TT+t)*64 + chunk*8)*HW)
                                 : (g_ih + ((size_t)b*64 + (chunk-8)*8)*HW);
    __syncthreads();
    for (int idx=tid; idx<8*6*34; idx+=256){
      int ci = idx/204; int r = idx-ci*204; int yy=r/34; int xx=r-yy*34;
      int gy = y0-1+yy, gx = xx-1;
      float v = 0.f;
      if ((unsigned)gy<32u && (unsigned)gx<32u) v = src[ci*HW + gy*32 + gx];
      sIn[ci][yy][xx] = f2t(v);
    }
    for (int idx=tid; idx<4608; idx+=256){
      int co = idx & 63; int r = idx >> 6;
      int ci = r/9, pos = r - ci*9;
      sW[pos][ci][co] = g_wT[(size_t)((chunk*8+ci)*9+pos)*256 + co0 + co];
    }
    __syncthreads();
    #pragma unroll
    for (int pos=0; pos<9; pos++){
      int ky = pos/3, kx = pos-3*ky;
      unsigned a[4];
      a[0] = sW[pos][tq  ][wc*16+g];
      a[1] = sW[pos][tq  ][wc*16+8+g];
      a[2] = sW[pos][tq+4][wc*16+g];
      a[3] = sW[pos][tq+4][wc*16+8+g];
      #pragma unroll
      for (int mf=0; mf<8; mf++){
        int p = wm*64 + mf*8 + g;
        int y = p>>5, x = p&31;
        unsigned b0 = sIn[tq  ][y+ky][x+kx];
        unsigned b1 = sIn[tq+4][y+ky][x+kx];
        mma8(acc[mf], a, b0, b1);
      }
    }
  }
  int r0 = co0 + wc*16 + g, r1 = r0 + 8;
  float bv0 = bias[r0], bv1 = bias[r1];
  float s=0.f, s2=0.f;
  #pragma unroll
  for (int mf=0; mf<8; mf++){
    int col = y0*32 + wm*64 + mf*8 + 2*tq;
    float v0=acc[mf][0]+bv0, v1=acc[mf][1]+bv0;
    float v2=acc[mf][2]+bv1, v3=acc[mf][3]+bv1;
    *(float2*)&g_gates[((size_t)b*CG + r0)*HW + col] = make_float2(v0,v1);
    *(float2*)&g_gates[((size_t)b*CG + r1)*HW + col] = make_float2(v2,v3);
    s  += v0+v1+v2+v3;
    s2 += v0*v0+v1*v1+v2*v2+v3*v3;
  }
  #pragma unroll
  for (int off=16; off; off>>=1){
    s  += __shfl_xor_sync(0xffffffffu, s , off);
    s2 += __shfl_xor_sync(0xffffffffu, s2, off);
  }
  if (lane==0){ ws[warp]=s; ws2[warp]=s2; }
  __syncthreads();
  if (tid<2){
    float S  = ws [tid*2]+ws [tid*2+1]+ws [tid*2+4]+ws [tid*2+5];
    float S2 = ws2[tid*2]+ws2[tid*2+1]+ws2[tid*2+4]+ws2[tid*2+5];
    int gidx = b*8 + (co0>>5) + tid;
    atomicAdd(&g_gsum [par][gidx], S );
    atomicAdd(&g_gsum2[par][gidx], S2);
  }
}

// ------------------- GN apply + LSTM gating -------------------
__global__ void gn_lstm(const float* __restrict__ gg, const float* __restrict__ gb, int t){
  int idx = blockIdx.x*256 + threadIdx.x;
  int b = idx >> 16; int c = (idx >> 10) & 63; int p = idx & 1023;
  int par = t & 1;
  __shared__ float smu[4], srs[4];
  if (threadIdx.x < 4){
    int grp = (c >> 5) + threadIdx.x*2;
    float s  = g_gsum [par][b*8+grp];
    float s2 = g_gsum2[par][b*8+grp];
    float m   = s*(1.f/32768.f);
    float var = s2*(1.f/32768.f) - m*m;
    smu[threadIdx.x] = m;
    srs[threadIdx.x] = rsqrtf(var + 1e-5f);
  }
  if (blockIdx.x==0 && threadIdx.x<64){
    g_gsum[par^1][threadIdx.x]=0.f; g_gsum2[par^1][threadIdx.x]=0.f;
  }
  __syncthreads();
  const float* gt = g_gates + (size_t)b*CG*HW + p;
  float vi = (gt[(size_t)(c      )*HW] - smu[0])*srs[0]*gg[c      ] + gb[c      ];
  float vf = (gt[(size_t)(c + 64 )*HW] - smu[1])*srs[1]*gg[c + 64 ] + gb[c + 64 ];
  float vc = (gt[(size_t)(c + 128)*HW] - smu[2])*srs[2]*gg[c + 128] + gb[c + 128];
  float vo = (gt[(size_t)(c + 192)*HW] - smu[3])*srs[3]*gg[c + 192] + gb[c + 192];
  float oc = g_ic[idx]*sigm(vf) + sigm(vi)*tanhf(vc);
  float oh = sigm(vo)*tanhf(oc);
  g_ic[idx] = oc;
  g_oh[idx] = oh;
}

// ------------------- 1x1 conv GEMM body (32co x 64px tile) -------------------
__device__ __forceinline__ void lin_body(const float* __restrict__ x1, int C1,
                                         const float* __restrict__ x2, int C2,
                                         const float* __restrict__ w,
                                         const float* __restrict__ bias,
                                         float* __restrict__ y, int Cout,
                                         int b, int o0, int p0,
                                         unsigned* uW, unsigned* uX)
{
  int Cin = C1 + C2;
  int pitch = Cin + 4;
  int tid=threadIdx.x, warp=tid>>5, lane=tid&31, g=lane>>2, tq=lane&3;
  int wc = warp&1, wm = warp>>1;
  for (int idx=tid; idx<32*Cin; idx+=256){
    int o = idx/Cin, c = idx - o*Cin;
    uW[o*pitch + c] = f2t(w[(size_t)(o0+o)*Cin + c]);
  }
  float acc[2][4];
  acc[0][0]=acc[0][1]=acc[0][2]=acc[0][3]=0.f;
  acc[1][0]=acc[1][1]=acc[1][2]=acc[1][3]=0.f;
  for (int cc=0; cc<Cin; cc+=8){
    __syncthreads();
    for (int idx=tid; idx<512; idx+=256){
      int ci = idx>>6, m = idx&63;
      int c = cc + ci;
      float v = (c<C1) ? x1[((size_t)b*C1 + c)*HW + p0 + m]
                       : x2[((size_t)b*C2 + (c-C1))*HW + p0 + m];
      uX[ci*72 + m] = f2t(v);
    }
    __syncthreads();
    unsigned a[4];
    a[0]=uW[(wc*16+g  )*pitch + cc+tq];   a[1]=uW[(wc*16+8+g)*pitch + cc+tq];
    a[2]=uW[(wc*16+g  )*pitch + cc+tq+4]; a[3]=uW[(wc*16+8+g)*pitch + cc+tq+4];
    #pragma unroll
    for (int mf=0; mf<2; mf++){
      unsigned b0 = uX[ tq   *72 + wm*16 + mf*8 + g];
      unsigned b1 = uX[(tq+4)*72 + wm*16 + mf*8 + g];
      mma8(acc[mf], a, b0, b1);
    }
  }
  #pragma unroll
  for (int mf=0; mf<2; mf++){
    int r0 = o0 + wc*16 + g, r1 = r0 + 8;
    int col = p0 + wm*16 + mf*8 + 2*tq;
    float bv0 = bias[r0], bv1 = bias[r1];
    *(float2*)&y[((size_t)b*Cout + r0)*HW + col] = make_float2(acc[mf][0]+bv0, acc[mf][1]+bv0);
    *(float2*)&y[((size_t)b*Cout + r1)*HW + col] = make_float2(acc[mf][2]+bv1, acc[mf][3]+bv1);
  }
}

__global__ __launch_bounds__(256) void lin_tc(const float* __restrict__ x1, int C1,
                                              const float* __restrict__ x2, int C2,
                                              const float* __restrict__ w,
                                              const float* __restrict__ bias,
                                              float* __restrict__ y, int Cout)
{
  __shared__ unsigned uW[32*132];
  __shared__ unsigned uX[8*72];
  lin_body(x1, C1, x2, C2, w, bias, y, Cout, blockIdx.x, blockIdx.y*32, blockIdx.z*64, uW, uX);
}

// merged QKV projections: y<6 -> h path (qkvh), else m path (kvm)
__global__ __launch_bounds__(256) void lin_hm(const float* __restrict__ h_w,
                                              const float* __restrict__ h_b,
                                              const float* __restrict__ m_w,
                                              const float* __restrict__ m_b)
{
  __shared__ unsigned uW[32*132];
  __shared__ unsigned uX[8*72];
  int b = blockIdx.x, p0 = blockIdx.z*64;
  if (blockIdx.y < 6)
    lin_body(g_oh, 64, (const float*)0, 0, h_w, h_b, g_qkvh, 192, b, blockIdx.y*32, p0, uW, uX);
  else
    lin_body(g_im, 64, (const float*)0, 0, m_w, m_b, g_kvm, 128, b, (blockIdx.y-6)*32, p0, uW, uX);
}

// ------------------- pass 1: scores GEMM -> write S + row softmax stats ----------
// grid (b=8, ntile=16 of 64 rows, which=2), block 256 (4 n-warps x 2 m-warps)
__global__ __launch_bounds__(256) void qk_stats(){
  extern __shared__ unsigned dsm[];
  unsigned* uQ = dsm;            // [64n][68c]
  unsigned* uK = dsm + 64*68;    // [64c][136m]
  __shared__ float sM[2][64], sL[2][64];
  int b = blockIdx.x, n0 = blockIdx.y*64, which = blockIdx.z;
  const float* q = g_qkvh + (size_t)b*192*HW;
  const float* k = which ? (g_kvm + (size_t)b*128*HW)
                         : (g_qkvh + (size_t)b*192*HW + (size_t)64*HW);
  float* Sb = g_S[which] + (size_t)b*HW*HW;
  int tid=threadIdx.x, warp=tid>>5, lane=tid&31, g=lane>>2, tq=lane&3;
  int wn = warp&3, wm = warp>>2;
  for (int idx=tid; idx<4096; idx+=256){
    int n = idx&63, c = idx>>6;
    uQ[n*68 + c] = f2t(q[(size_t)c*HW + n0 + n]);
  }
  float M0=-1e30f, M1=-1e30f, L0=0.f, L1=0.f;
  int r0 = n0 + wn*16 + g, r1 = r0 + 8;
  for (int m0=0; m0<HW; m0+=128){
    __syncthreads();
    for (int idx=tid; idx<8192; idx+=256){
      int m = idx&127, c = idx>>7;
      uK[c*136 + m] = f2t(k[(size_t)c*HW + m0 + m]);
    }
    __syncthreads();
    float cfr[8][4];
    #pragma unroll
    for(int mf=0;mf<8;mf++){cfr[mf][0]=0.f;cfr[mf][1]=0.f;cfr[mf][2]=0.f;cfr[mf][3]=0.f;}
    #pragma unroll
    for (int kk=0; kk<8; kk++){
      unsigned a[4];
      a[0]=uQ[(wn*16+g  )*68 + kk*8+tq];   a[1]=uQ[(wn*16+8+g)*68 + kk*8+tq];
      a[2]=uQ[(wn*16+g  )*68 + kk*8+tq+4]; a[3]=uQ[(wn*16+8+g)*68 + kk*8+tq+4];
      #pragma unroll
      for (int mf=0; mf<8; mf++){
        unsigned b0 = uK[(kk*8+tq  )*136 + wm*64 + mf*8 + g];
        unsigned b1 = uK[(kk*8+tq+4)*136 + wm*64 + mf*8 + g];
        mma8(cfr[mf], a, b0, b1);
      }
    }
    // write raw S tile
    #pragma unroll
    for (int mf=0; mf<8; mf++){
      int col = m0 + wm*64 + mf*8 + 2*tq;
      *(float2*)&Sb[(size_t)r0*HW + col] = make_float2(cfr[mf][0], cfr[mf][1]);
      *(float2*)&Sb[(size_t)r1*HW + col] = make_float2(cfr[mf][2], cfr[mf][3]);
    }
    float tm0=-1e30f, tm1=-1e30f;
    #pragma unroll
    for(int mf=0;mf<8;mf++){
      tm0 = fmaxf(tm0, fmaxf(cfr[mf][0], cfr[mf][1]));
      tm1 = fmaxf(tm1, fmaxf(cfr[mf][2], cfr[mf][3]));
    }
    tm0 = fmaxf(tm0, __shfl_xor_sync(0xffffffffu, tm0, 1));
    tm0 = fmaxf(tm0, __shfl_xor_sync(0xffffffffu, tm0, 2));
    tm1 = fmaxf(tm1, __shfl_xor_sync(0xffffffffu, tm1, 1));
    tm1 = fmaxf(tm1, __shfl_xor_sync(0xffffffffu, tm1, 2));
    float nM0 = fmaxf(M0, tm0), nM1 = fmaxf(M1, tm1);
    float s0=0.f, s1=0.f;
    #pragma unroll
    for(int mf=0;mf<8;mf++){
      s0 += __expf(cfr[mf][0]-nM0) + __expf(cfr[mf][1]-nM0);
      s1 += __expf(cfr[mf][2]-nM1) + __expf(cfr[mf][3]-nM1);
    }
    s0 += __shfl_xor_sync(0xffffffffu, s0, 1);
    s0 += __shfl_xor_sync(0xffffffffu, s0, 2);
    s1 += __shfl_xor_sync(0xffffffffu, s1, 1);
    s1 += __shfl_xor_sync(0xffffffffu, s1, 2);
    L0 = L0*__expf(M0-nM0) + s0; M0 = nM0;
    L1 = L1*__expf(M1-nM1) + s1; M1 = nM1;
  }
  if (tq==0){
    sM[wm][wn*16+g  ] = M0; sL[wm][wn*16+g  ] = L0;
    sM[wm][wn*16+8+g] = M1; sL[wm][wn*16+8+g] = L1;
  }
  __syncthreads();
  if (tid<64){
    float Ma = sM[0][tid], Mb = sM[1][tid];
    float M  = fmaxf(Ma, Mb);
    float L  = sL[0][tid]*__expf(Ma-M) + sL[1][tid]*__expf(Mb-M);
    g_rmax[which][b*HW + n0 + tid] = M;
    g_rinv[which][b*HW + n0 + tid] = 1.f/L;
  }
}

// ------------------- pass 2: P from stored S, AV GEMM ---------------------
// grid (b=8, mtile=16 of 64, which=2), block 256 (4 c-warps x 2 m-halves)
__global__ __launch_bounds__(256) void av_tc(){
  __shared__ unsigned uV[64*68];   // [c][n]
  __shared__ unsigned sP[64*72];   // [n][m]
  int b = blockIdx.x, m0 = blockIdx.y*64, which = blockIdx.z;
  const float* v = which ? (g_kvm + (size_t)b*128*HW + (size_t)64*HW)
                         : (g_qkvh + (size_t)b*192*HW + (size_t)128*HW);
  const float* Sb   = g_S[which] + (size_t)b*HW*HW;
  const float* rmax = g_rmax[which] + b*HW;
  const float* rinv = g_rinv[which] + b*HW;
  int zoff = which*64;
  int tid=threadIdx.x, warp=tid>>5, lane=tid&31, g=lane>>2, tq=lane&3;
  int wn = warp&3, wm = warp>>2;
  float accZ[4][4];
  #pragma unroll
  for(int mf=0;mf<4;mf++){accZ[mf][0]=0.f;accZ[mf][1]=0.f;accZ[mf][2]=0.f;accZ[mf][3]=0.f;}

  for (int nb=0; nb<HW; nb+=64){
    __syncthreads();
    for (int idx=tid; idx<4096; idx+=256){
      int n = idx&63, c = idx>>6;
      uV[c*68 + n] = f2t(v[(size_t)c*HW + nb + n]);
    }
    for (int idx=tid; idx<2048; idx+=256){
      int n = idx>>5, mp = idx&31;
      int row = nb + n;
      float2 s2 = *(const float2*)&Sb[(size_t)row*HW + m0 + 2*mp];
      float rm = rmax[row], ri = rinv[row];
      unsigned p0 = f2t(__expf(s2.x - rm)*ri);
      unsigned p1 = f2t(__expf(s2.y - rm)*ri);
      *(uint2*)&sP[n*72 + 2*mp] = make_uint2(p0, p1);
    }
    __syncthreads();
    #pragma unroll
    for (int kk=0; kk<8; kk++){
      unsigned a[4];
      a[0]=uV[(wn*16+g  )*68 + kk*8+tq];   a[1]=uV[(wn*16+8+g)*68 + kk*8+tq];
      a[2]=uV[(wn*16+g  )*68 + kk*8+tq+4]; a[3]=uV[(wn*16+8+g)*68 + kk*8+tq+4];
      #pragma unroll
      for (int mf=0; mf<4; mf++){
        unsigned b0 = sP[(kk*8+tq  )*72 + wm*32 + mf*8 + g];
        unsigned b1 = sP[(kk*8+tq+4)*72 + wm*32 + mf*8 + g];
        mma8(accZ[mf], a, b0, b1);
      }
    }
  }
  #pragma unroll
  for (int mf=0; mf<4; mf++){
    int r0 = wn*16 + g, r1 = r0 + 8;
    int col = m0 + wm*32 + mf*8 + 2*tq;
    *(float2*)&g_Zcat[((size_t)b*128 + zoff + r0)*HW + col] = make_float2(accZ[mf][0], accZ[mf][1]);
    *(float2*)&g_Zcat[((size_t)b*128 + zoff + r1)*HW + col] = make_float2(accZ[mf][2], accZ[mf][3]);
  }
}

// ------------------- final gating -------------------
__global__ void final_k(float* __restrict__ out, int t, int ws){
  int idx = blockIdx.x*256 + threadIdx.x;
  int b = idx >> 16; int c = (idx >> 10) & 63; int p = idx & 1023;
  const float* g2 = g_g2 + (size_t)b*192*HW + p;
  float vo = g2[(size_t)c*HW];
  float vg = g2[(size_t)(64+c)*HW];
  float vi = g2[(size_t)(128+c)*HW];
  float si = sigm(vi);
  float om  = tanhf(vg)*si + (1.f-si)*g_im[idx];
  float oh2 = sigm(vo)*om;
  g_im[idx] = om;
  g_ih[idx] = oh2;
  out[(((size_t)b*TT + t)*64 + c)*HW + p] = oh2;
  if (ws){
    float* st = out + (size_t)BB*TT*64*HW;
    st[idx]            = oh2;
    st[NSTATE + idx]   = g_ic[idx];
    st[2*NSTATE + idx] = om;
  }
}

extern "C" void kernel_launch(void* const* d_in, const int* in_sizes, int n_in,
                              void* d_out, int out_size)
{
  const float* inputs = (const float*)d_in[0];
  const float* conv_w = (const float*)d_in[1];
  const float* conv_b = (const float*)d_in[2];
  const float* gn_g   = (const float*)d_in[3];
  const float* gn_b   = (const float*)d_in[4];
  const float* h_w    = (const float*)d_in[5];
  const float* h_b    = (const float*)d_in[6];
  const float* m_w    = (const float*)d_in[7];
  const float* m_b    = (const float*)d_in[8];
  const float* z1_w   = (const float*)d_in[9];
  const float* z1_b   = (const float*)d_in[10];
  const float* z2_w   = (const float*)d_in[11];
  const float* z2_b   = (const float*)d_in[12];
  float* out = (float*)d_out;

  const int ST_SMEM = (64*68 + 64*136)*4;   // 52224
  cudaFuncSetAttribute(qk_stats, cudaFuncAttributeMaxDynamicSharedMemorySize, ST_SMEM);

  float *pZcat, *pZ, *pG2;
  cudaGetSymbolAddress((void**)&pZcat, g_Zcat);
  cudaGetSymbolAddress((void**)&pZ,    g_Z);
  cudaGetSymbolAddress((void**)&pG2,   g_g2);
  float *pOh;
  cudaGetSymbolAddress((void**)&pOh,   g_oh);

  zero_states<<<2048,256>>>();
  wtrans<<<256,256>>>(conv_w);
  int write_states = (out_size >= (int)(BB*TT*64*HW + 3*NSTATE)) ? 1 : 0;

  for (int t=0; t<TT; t++){
    conv_tc<<<dim3(8,4,8),256>>>(inputs, conv_b, t);
    gn_lstm<<<NSTATE/256,256>>>(gn_g, gn_b, t);

    lin_hm<<<dim3(8,10,16),256>>>(h_w, h_b, m_w, m_b);

    qk_stats<<<dim3(8,16,2),256,ST_SMEM>>>();
    av_tc  <<<dim3(8,16,2),256>>>();

    lin_tc<<<dim3(8,2,16),256>>>(pZcat, 128, (const float*)0, 0, z1_w, z1_b, pZ, 64);
    lin_tc<<<dim3(8,6,16),256>>>(pZ, 64, pOh, 64, z2_w, z2_b, pG2, 192);

    final_k<<<NSTATE/256,256>>>(out, t, (t==TT-1) ? write_states : 0);
  }
}

// round 5
// speedup vs baseline: 1.3332x; 1.3332x over previous
#include <cuda_runtime.h>
#include <math.h>

#define BB 8
#define TT 8
#define HW 1024
#define CG 256
#define NSTATE (BB*64*HW)   // 524288

// ---- persistent state ----
__device__ float g_ih[NSTATE];
__device__ float g_ic[NSTATE];
__device__ float g_im[NSTATE];
// ---- scratch ----
__device__ float g_gates[BB*CG*HW];
__device__ float g_gsum [2][64];
__device__ float g_gsum2[2][64];
__device__ float g_oh[NSTATE];
__device__ float g_qkvh[BB*192*HW];
__device__ float g_kvm[BB*128*HW];
__device__ float g_rmax[2][BB*HW];
__device__ float g_rinv[2][BB*HW];
__device__ float g_Zcat[BB*128*HW];
__device__ unsigned g_wT[1152*256];   // conv weights [(ci*9+pos)][co] tf32
__device__ unsigned g_z2T[128*192];   // z2 weights transposed [c][o] tf32

__device__ __forceinline__ float sigm(float x){ return 1.f/(1.f+__expf(-x)); }
__device__ __forceinline__ unsigned f2t(float x){
  unsigned r; asm("cvt.rna.tf32.f32 %0,%1;" : "=r"(r) : "f"(x)); return r;
}
__device__ __forceinline__ void mma8(float* d, const unsigned* a, unsigned b0, unsigned b1){
  asm volatile("mma.sync.aligned.m16n8k8.row.col.f32.tf32.tf32.f32 "
    "{%0,%1,%2,%3},{%4,%5,%6,%7},{%8,%9},{%0,%1,%2,%3};"
    : "+f"(d[0]),"+f"(d[1]),"+f"(d[2]),"+f"(d[3])
    : "r"(a[0]),"r"(a[1]),"r"(a[2]),"r"(a[3]),"r"(b0),"r"(b1));
}

__global__ void zero_states(){
  int i = blockIdx.x*256 + threadIdx.x;
  if (i < NSTATE){ g_ih[i]=0.f; g_ic[i]=0.f; g_im[i]=0.f; }
  if (blockIdx.x==0 && threadIdx.x<64){
    g_gsum[0][threadIdx.x]=0.f; g_gsum2[0][threadIdx.x]=0.f;
    g_gsum[1][threadIdx.x]=0.f; g_gsum2[1][threadIdx.x]=0.f;
  }
}

__global__ void wtrans(const float* __restrict__ w, const float* __restrict__ z2w){
  int co = blockIdx.x;
  for (int i = threadIdx.x; i < 1152; i += 256)
    g_wT[(size_t)i*256 + co] = f2t(w[(size_t)co*1152 + i]);
  if (co < 192){
    for (int c = threadIdx.x; c < 128; c += 256)
      g_z2T[c*192 + co] = f2t(z2w[co*128 + c]);
  }
}

// ------------------- 3x3 conv (implicit GEMM, TC) + fused GN partial stats ----
__global__ __launch_bounds__(256) void conv_tc(const float* __restrict__ xin,
                                               const float* __restrict__ bias, int t)
{
  int pt = blockIdx.x, cot = blockIdx.y, b = blockIdx.z;
  int y0 = pt*4, co0 = cot*64, par = t & 1;
  __shared__ unsigned sIn[8][6][36];
  __shared__ unsigned sW[9][8][72];
  __shared__ float ws[8], ws2[8];
  int tid=threadIdx.x, warp=tid>>5, lane=tid&31, g=lane>>2, tq=lane&3;
  int wc = warp&3, wm = warp>>2;
  float acc[8][4];
  #pragma unroll
  for(int j=0;j<8;j++){acc[j][0]=0.f;acc[j][1]=0.f;acc[j][2]=0.f;acc[j][3]=0.f;}

  for (int chunk=0; chunk<16; chunk++){
    const float* src = (chunk<8) ? (xin + ((size_t)(b*TT+t)*64 + chunk*8)*HW)
                                 : (g_ih + ((size_t)b*64 + (chunk-8)*8)*HW);
    __syncthreads();
    for (int idx=tid; idx<8*6*34; idx+=256){
      int ci = idx/204; int r = idx-ci*204; int yy=r/34; int xx=r-yy*34;
      int gy = y0-1+yy, gx = xx-1;
      float v = 0.f;
      if ((unsigned)gy<32u && (unsigned)gx<32u) v = src[ci*HW + gy*32 + gx];
      sIn[ci][yy][xx] = f2t(v);
    }
    for (int idx=tid; idx<4608; idx+=256){
      int co = idx & 63; int r = idx >> 6;
      int ci = r/9, pos = r - ci*9;
      sW[pos][ci][co] = g_wT[(size_t)((chunk*8+ci)*9+pos)*256 + co0 + co];
    }
    __syncthreads();
    #pragma unroll
    for (int pos=0; pos<9; pos++){
      int ky = pos/3, kx = pos-3*ky;
      unsigned a[4];
      a[0] = sW[pos][tq  ][wc*16+g];
      a[1] = sW[pos][tq  ][wc*16+8+g];
      a[2] = sW[pos][tq+4][wc*16+g];
      a[3] = sW[pos][tq+4][wc*16+8+g];
      #pragma unroll
      for (int mf=0; mf<8; mf++){
        int p = wm*64 + mf*8 + g;
        int y = p>>5, x = p&31;
        unsigned b0 = sIn[tq  ][y+ky][x+kx];
        unsigned b1 = sIn[tq+4][y+ky][x+kx];
        mma8(acc[mf], a, b0, b1);
      }
    }
  }
  int r0 = co0 + wc*16 + g, r1 = r0 + 8;
  float bv0 = bias[r0], bv1 = bias[r1];
  float s=0.f, s2=0.f;
  #pragma unroll
  for (int mf=0; mf<8; mf++){
    int col = y0*32 + wm*64 + mf*8 + 2*tq;
    float v0=acc[mf][0]+bv0, v1=acc[mf][1]+bv0;
    float v2=acc[mf][2]+bv1, v3=acc[mf][3]+bv1;
    *(float2*)&g_gates[((size_t)b*CG + r0)*HW + col] = make_float2(v0,v1);
    *(float2*)&g_gates[((size_t)b*CG + r1)*HW + col] = make_float2(v2,v3);
    s  += v0+v1+v2+v3;
    s2 += v0*v0+v1*v1+v2*v2+v3*v3;
  }
  #pragma unroll
  for (int off=16; off; off>>=1){
    s  += __shfl_xor_sync(0xffffffffu, s , off);
    s2 += __shfl_xor_sync(0xffffffffu, s2, off);
  }
  if (lane==0){ ws[warp]=s; ws2[warp]=s2; }
  __syncthreads();
  if (tid<2){
    float S  = ws [tid*2]+ws [tid*2+1]+ws [tid*2+4]+ws [tid*2+5];
    float S2 = ws2[tid*2]+ws2[tid*2+1]+ws2[tid*2+4]+ws2[tid*2+5];
    int gidx = b*8 + (co0>>5) + tid;
    atomicAdd(&g_gsum [par][gidx], S );
    atomicAdd(&g_gsum2[par][gidx], S2);
  }
}

// ------------------- GN apply + LSTM gating (float4) -------------------
// grid 512: block = one (b,c); 256 threads x 4 px
__global__ void gn_lstm4(const float* __restrict__ gg, const float* __restrict__ gb, int t){
  int b = blockIdx.x >> 6, c = blockIdx.x & 63;
  int p = threadIdx.x*4;
  int par = t & 1;
  __shared__ float smu[4], srs[4];
  if (threadIdx.x < 4){
    int grp = (c >> 5) + threadIdx.x*2;
    float s  = g_gsum [par][b*8+grp];
    float s2 = g_gsum2[par][b*8+grp];
    float m   = s*(1.f/32768.f);
    float var = s2*(1.f/32768.f) - m*m;
    smu[threadIdx.x] = m;
    srs[threadIdx.x] = rsqrtf(var + 1e-5f);
  }
  if (blockIdx.x==0 && threadIdx.x<64){
    g_gsum[par^1][threadIdx.x]=0.f; g_gsum2[par^1][threadIdx.x]=0.f;
  }
  __syncthreads();
  const float* gt = g_gates + (size_t)b*CG*HW + p;
  float4 vi = *(const float4*)&gt[(size_t)(c      )*HW];
  float4 vf = *(const float4*)&gt[(size_t)(c + 64 )*HW];
  float4 vc = *(const float4*)&gt[(size_t)(c + 128)*HW];
  float4 vo = *(const float4*)&gt[(size_t)(c + 192)*HW];
  int idx = (b*64 + c)*1024 + p;
  float4 ic4 = *(const float4*)&g_ic[idx];
  float4 oc4, oh4;
  {
    float a,f2,cc,o;
    a=(vi.x-smu[0])*srs[0]*gg[c]+gb[c]; f2=(vf.x-smu[1])*srs[1]*gg[c+64]+gb[c+64];
    cc=(vc.x-smu[2])*srs[2]*gg[c+128]+gb[c+128]; o=(vo.x-smu[3])*srs[3]*gg[c+192]+gb[c+192];
    oc4.x = ic4.x*sigm(f2)+sigm(a)*tanhf(cc); oh4.x = sigm(o)*tanhf(oc4.x);
    a=(vi.y-smu[0])*srs[0]*gg[c]+gb[c]; f2=(vf.y-smu[1])*srs[1]*gg[c+64]+gb[c+64];
    cc=(vc.y-smu[2])*srs[2]*gg[c+128]+gb[c+128]; o=(vo.y-smu[3])*srs[3]*gg[c+192]+gb[c+192];
    oc4.y = ic4.y*sigm(f2)+sigm(a)*tanhf(cc); oh4.y = sigm(o)*tanhf(oc4.y);
    a=(vi.z-smu[0])*srs[0]*gg[c]+gb[c]; f2=(vf.z-smu[1])*srs[1]*gg[c+64]+gb[c+64];
    cc=(vc.z-smu[2])*srs[2]*gg[c+128]+gb[c+128]; o=(vo.z-smu[3])*srs[3]*gg[c+192]+gb[c+192];
    oc4.z = ic4.z*sigm(f2)+sigm(a)*tanhf(cc); oh4.z = sigm(o)*tanhf(oc4.z);
    a=(vi.w-smu[0])*srs[0]*gg[c]+gb[c]; f2=(vf.w-smu[1])*srs[1]*gg[c+64]+gb[c+64];
    cc=(vc.w-smu[2])*srs[2]*gg[c+128]+gb[c+128]; o=(vo.w-smu[3])*srs[3]*gg[c+192]+gb[c+192];
    oc4.w = ic4.w*sigm(f2)+sigm(a)*tanhf(cc); oh4.w = sigm(o)*tanhf(oc4.w);
  }
  *(float4*)&g_ic[idx] = oc4;
  *(float4*)&g_oh[idx] = oh4;
}

// ------------------- 1x1 conv GEMM body (32co x 64px tile) -------------------
__device__ __forceinline__ void lin_body(const float* __restrict__ x1,
                                         const float* __restrict__ w,
                                         const float* __restrict__ bias,
                                         float* __restrict__ y, int Cout,
                                         int b, int o0, int p0,
                                         unsigned* uW, unsigned* uX)
{
  const int Cin = 64, pitch = 68;
  int tid=threadIdx.x, warp=tid>>5, lane=tid&31, g=lane>>2, tq=lane&3;
  int wc = warp&1, wm = warp>>1;
  for (int idx=tid; idx<32*Cin; idx+=256){
    int o = idx>>6, c = idx&63;
    uW[o*pitch + c] = f2t(w[(size_t)(o0+o)*Cin + c]);
  }
  float acc[2][4];
  acc[0][0]=acc[0][1]=acc[0][2]=acc[0][3]=0.f;
  acc[1][0]=acc[1][1]=acc[1][2]=acc[1][3]=0.f;
  for (int cc=0; cc<Cin; cc+=8){
    __syncthreads();
    for (int idx=tid; idx<256; idx+=256){
      int ci = idx>>5, m2 = idx&31;
      float2 v = *(const float2*)&x1[((size_t)b*Cin + cc+ci)*HW + p0 + 2*m2];
      *(uint2*)&uX[ci*72 + 2*m2] = make_uint2(f2t(v.x), f2t(v.y));
    }
    __syncthreads();
    unsigned a[4];
    a[0]=uW[(wc*16+g  )*pitch + cc+tq];   a[1]=uW[(wc*16+8+g)*pitch + cc+tq];
    a[2]=uW[(wc*16+g  )*pitch + cc+tq+4]; a[3]=uW[(wc*16+8+g)*pitch + cc+tq+4];
    #pragma unroll
    for (int mf=0; mf<2; mf++){
      unsigned b0 = uX[ tq   *72 + wm*16 + mf*8 + g];
      unsigned b1 = uX[(tq+4)*72 + wm*16 + mf*8 + g];
      mma8(acc[mf], a, b0, b1);
    }
  }
  #pragma unroll
  for (int mf=0; mf<2; mf++){
    int r0 = o0 + wc*16 + g, r1 = r0 + 8;
    int col = p0 + wm*16 + mf*8 + 2*tq;
    float bv0 = bias[r0], bv1 = bias[r1];
    *(float2*)&y[((size_t)b*Cout + r0)*HW + col] = make_float2(acc[mf][0]+bv0, acc[mf][1]+bv0);
    *(float2*)&y[((size_t)b*Cout + r1)*HW + col] = make_float2(acc[mf][2]+bv1, acc[mf][3]+bv1);
  }
}

// merged QKV projections: y<6 -> h path (qkvh), else m path (kvm)
__global__ __launch_bounds__(256) void lin_hm(const float* __restrict__ h_w,
                                              const float* __restrict__ h_b,
                                              const float* __restrict__ m_w,
                                              const float* __restrict__ m_b)
{
  __shared__ unsigned uW[32*68];
  __shared__ unsigned uX[8*72];
  int b = blockIdx.x, p0 = blockIdx.z*64;
  if (blockIdx.y < 6)
    lin_body(g_oh, h_w, h_b, g_qkvh, 192, b, blockIdx.y*32, p0, uW, uX);
  else
    lin_body(g_im, m_w, m_b, g_kvm, 128, b, (blockIdx.y-6)*32, p0, uW, uX);
}

// ------------------- pass 1: row softmax stats (no S materialization) ----------
__global__ __launch_bounds__(256) void qk_stats(){
  extern __shared__ unsigned dsm[];
  unsigned* uQ = dsm;            // [64n][68c]
  unsigned* uK = dsm + 64*68;    // [64c][136m]
  __shared__ float sM[2][64], sL[2][64];
  int b = blockIdx.x, n0 = blockIdx.y*64, which = blockIdx.z;
  const float* q = g_qkvh + (size_t)b*192*HW;
  const float* k = which ? (g_kvm + (size_t)b*128*HW)
                         : (g_qkvh + (size_t)b*192*HW + (size_t)64*HW);
  int tid=threadIdx.x, warp=tid>>5, lane=tid&31, g=lane>>2, tq=lane&3;
  int wn = warp&3, wm = warp>>2;
  for (int idx=tid; idx<2048; idx+=256){
    int n2 = idx&31, c = idx>>5;
    float2 v = *(const float2*)&q[(size_t)c*HW + n0 + 2*n2];
    uQ[(2*n2  )*68 + c] = f2t(v.x);
    uQ[(2*n2+1)*68 + c] = f2t(v.y);
  }
  float M0=-1e30f, M1=-1e30f, L0=0.f, L1=0.f;
  for (int m0=0; m0<HW; m0+=128){
    __syncthreads();
    for (int idx=tid; idx<4096; idx+=256){
      int m2 = idx&63, c = idx>>6;
      float2 v = *(const float2*)&k[(size_t)c*HW + m0 + 2*m2];
      *(uint2*)&uK[c*136 + 2*m2] = make_uint2(f2t(v.x), f2t(v.y));
    }
    __syncthreads();
    float cfr[8][4];
    #pragma unroll
    for(int mf=0;mf<8;mf++){cfr[mf][0]=0.f;cfr[mf][1]=0.f;cfr[mf][2]=0.f;cfr[mf][3]=0.f;}
    #pragma unroll
    for (int kk=0; kk<8; kk++){
      unsigned a[4];
      a[0]=uQ[(wn*16+g  )*68 + kk*8+tq];   a[1]=uQ[(wn*16+8+g)*68 + kk*8+tq];
      a[2]=uQ[(wn*16+g  )*68 + kk*8+tq+4]; a[3]=uQ[(wn*16+8+g)*68 + kk*8+tq+4];
      #pragma unroll
      for (int mf=0; mf<8; mf++){
        unsigned b0 = uK[(kk*8+tq  )*136 + wm*64 + mf*8 + g];
        unsigned b1 = uK[(kk*8+tq+4)*136 + wm*64 + mf*8 + g];
        mma8(cfr[mf], a, b0, b1);
      }
    }
    float tm0=-1e30f, tm1=-1e30f;
    #pragma unroll
    for(int mf=0;mf<8;mf++){
      tm0 = fmaxf(tm0, fmaxf(cfr[mf][0], cfr[mf][1]));
      tm1 = fmaxf(tm1, fmaxf(cfr[mf][2], cfr[mf][3]));
    }
    tm0 = fmaxf(tm0, __shfl_xor_sync(0xffffffffu, tm0, 1));
    tm0 = fmaxf(tm0, __shfl_xor_sync(0xffffffffu, tm0, 2));
    tm1 = fmaxf(tm1, __shfl_xor_sync(0xffffffffu, tm1, 1));
    tm1 = fmaxf(tm1, __shfl_xor_sync(0xffffffffu, tm1, 2));
    float nM0 = fmaxf(M0, tm0), nM1 = fmaxf(M1, tm1);
    float s0=0.f, s1=0.f;
    #pragma unroll
    for(int mf=0;mf<8;mf++){
      s0 += __expf(cfr[mf][0]-nM0) + __expf(cfr[mf][1]-nM0);
      s1 += __expf(cfr[mf][2]-nM1) + __expf(cfr[mf][3]-nM1);
    }
    s0 += __shfl_xor_sync(0xffffffffu, s0, 1);
    s0 += __shfl_xor_sync(0xffffffffu, s0, 2);
    s1 += __shfl_xor_sync(0xffffffffu, s1, 1);
    s1 += __shfl_xor_sync(0xffffffffu, s1, 2);
    L0 = L0*__expf(M0-nM0) + s0; M0 = nM0;
    L1 = L1*__expf(M1-nM1) + s1; M1 = nM1;
  }
  if (tq==0){
    sM[wm][wn*16+g  ] = M0; sL[wm][wn*16+g  ] = L0;
    sM[wm][wn*16+8+g] = M1; sL[wm][wn*16+8+g] = L1;
  }
  __syncthreads();
  if (tid<64){
    float Ma = sM[0][tid], Mb = sM[1][tid];
    float M  = fmaxf(Ma, Mb);
    float L  = sL[0][tid]*__expf(Ma-M) + sL[1][tid]*__expf(Mb-M);
    g_rmax[which][b*HW + n0 + tid] = M;
    g_rinv[which][b*HW + n0 + tid] = 1.f/L;
  }
}

// ------------------- pass 2: recompute S tile, exp, AV GEMM ---------------------
__global__ __launch_bounds__(256) void av_tc(){
  extern __shared__ unsigned dsm[];
  unsigned* uK = dsm;               // [64c][72m]
  unsigned* uQ = dsm + 64*72;       // [64n][68c]
  unsigned* uV = uQ + 64*68;        // [64c][68n]
  unsigned* sP = uV + 64*68;        // [64n][72m]
  int b = blockIdx.x, m0 = blockIdx.y*64, which = blockIdx.z;
  const float* q = g_qkvh + (size_t)b*192*HW;
  const float* k = which ? (g_kvm + (size_t)b*128*HW)
                         : (g_qkvh + (size_t)b*192*HW + (size_t)64*HW);
  const float* v = which ? (g_kvm + (size_t)b*128*HW + (size_t)64*HW)
                         : (g_qkvh + (size_t)b*192*HW + (size_t)128*HW);
  const float* rmax = g_rmax[which] + b*HW;
  const float* rinv = g_rinv[which] + b*HW;
  int zoff = which*64;
  int tid=threadIdx.x, warp=tid>>5, lane=tid&31, g=lane>>2, tq=lane&3;
  int wn = warp&3, wm = warp>>2;
  for (int idx=tid; idx<2048; idx+=256){
    int m2 = idx&31, c = idx>>5;
    float2 kv = *(const float2*)&k[(size_t)c*HW + m0 + 2*m2];
    *(uint2*)&uK[c*72 + 2*m2] = make_uint2(f2t(kv.x), f2t(kv.y));
  }
  float accZ[4][4];
  #pragma unroll
  for(int mf=0;mf<4;mf++){accZ[mf][0]=0.f;accZ[mf][1]=0.f;accZ[mf][2]=0.f;accZ[mf][3]=0.f;}

  for (int nb=0; nb<HW; nb+=64){
    __syncthreads();
    for (int idx=tid; idx<2048; idx+=256){
      int n2 = idx&31, c = idx>>5;
      float2 qv = *(const float2*)&q[(size_t)c*HW + nb + 2*n2];
      uQ[(2*n2  )*68 + c] = f2t(qv.x);
      uQ[(2*n2+1)*68 + c] = f2t(qv.y);
    }
    for (int idx=tid; idx<2048; idx+=256){
      int n2 = idx&31, c = idx>>5;
      float2 vv = *(const float2*)&v[(size_t)c*HW + nb + 2*n2];
      *(uint2*)&uV[c*68 + 2*n2] = make_uint2(f2t(vv.x), f2t(vv.y));
    }
    __syncthreads();
    float accS[4][4];
    #pragma unroll
    for(int mf=0;mf<4;mf++){accS[mf][0]=0.f;accS[mf][1]=0.f;accS[mf][2]=0.f;accS[mf][3]=0.f;}
    #pragma unroll
    for (int kk=0; kk<8; kk++){
      unsigned a[4];
      a[0]=uQ[(wn*16+g  )*68 + kk*8+tq];   a[1]=uQ[(wn*16+8+g)*68 + kk*8+tq];
      a[2]=uQ[(wn*16+g  )*68 + kk*8+tq+4]; a[3]=uQ[(wn*16+8+g)*68 + kk*8+tq+4];
      #pragma unroll
      for (int mf=0; mf<4; mf++){
        unsigned b0 = uK[(kk*8+tq  )*72 + wm*32 + mf*8 + g];
        unsigned b1 = uK[(kk*8+tq+4)*72 + wm*32 + mf*8 + g];
        mma8(accS[mf], a, b0, b1);
      }
    }
    int rb = nb + wn*16 + g;
    float rm0 = rmax[rb],   ri0 = rinv[rb];
    float rm1 = rmax[rb+8], ri1 = rinv[rb+8];
    #pragma unroll
    for (int mf=0; mf<4; mf++){
      int col = wm*32 + mf*8 + 2*tq;
      unsigned p0 = f2t(__expf(accS[mf][0]-rm0)*ri0);
      unsigned p1 = f2t(__expf(accS[mf][1]-rm0)*ri0);
      unsigned p2 = f2t(__expf(accS[mf][2]-rm1)*ri1);
      unsigned p3 = f2t(__expf(accS[mf][3]-rm1)*ri1);
      *(uint2*)&sP[(wn*16+g  )*72 + col] = make_uint2(p0,p1);
      *(uint2*)&sP[(wn*16+8+g)*72 + col] = make_uint2(p2,p3);
    }
    __syncthreads();
    #pragma unroll
    for (int kk=0; kk<8; kk++){
      unsigned a[4];
      a[0]=uV[(wn*16+g  )*68 + kk*8+tq];   a[1]=uV[(wn*16+8+g)*68 + kk*8+tq];
      a[2]=uV[(wn*16+g  )*68 + kk*8+tq+4]; a[3]=uV[(wn*16+8+g)*68 + kk*8+tq+4];
      #pragma unroll
      for (int mf=0; mf<4; mf++){
        unsigned b0 = sP[(kk*8+tq  )*72 + wm*32 + mf*8 + g];
        unsigned b1 = sP[(kk*8+tq+4)*72 + wm*32 + mf*8 + g];
        mma8(accZ[mf], a, b0, b1);
      }
    }
  }
  #pragma unroll
  for (int mf=0; mf<4; mf++){
    int r0 = wn*16 + g, r1 = r0 + 8;
    int col = m0 + wm*32 + mf*8 + 2*tq;
    *(float2*)&g_Zcat[((size_t)b*128 + zoff + r0)*HW + col] = make_float2(accZ[mf][0], accZ[mf][1]);
    *(float2*)&g_Zcat[((size_t)b*128 + zoff + r1)*HW + col] = make_float2(accZ[mf][2], accZ[mf][3]);
  }
}

// ------------------- tail: z1 GEMM + z2 GEMM + LSTM-style gating, fused -------
// grid (8 b, 32 ptiles of 32px), block 256
__global__ __launch_bounds__(256) void tail_k(const float* __restrict__ z1_w,
                                              const float* __restrict__ z1_b,
                                              const float* __restrict__ z2_b,
                                              float* __restrict__ out, int t, int ws)
{
  extern __shared__ unsigned sm[];
  unsigned* sZ  = sm;            // [64][40] tf32
  unsigned* sOh = sm + 2560;     // [64][40] tf32
  unsigned* wch = sm + 5120;     // [8][200] tf32 (z2T chunk)
  unsigned* sX  = sm + 6720;     // [8][40]  tf32
  unsigned* uz1 = sm + 7040;     // [64][132] tf32 (phase1)
  float*  gates = (float*)(sm + 7040); // [192][34] fp32 (phase2, overlays uz1)
  int b = blockIdx.x, p0 = blockIdx.y*32;
  int tid=threadIdx.x, warp=tid>>5, lane=tid&31, g=lane>>2, tq=lane&3;
  int wc = warp&1, wm = warp>>1;
  // stage z1 weights + oh tile
  for (int idx=tid; idx<64*128; idx+=256){
    int o = idx>>7, c = idx&127;
    uz1[o*132+c] = f2t(z1_w[o*128+c]);
  }
  for (int idx=tid; idx<1024; idx+=256){
    int c = idx>>4, p2 = idx&15;
    float2 v = *(const float2*)&g_oh[((size_t)b*64+c)*HW + p0 + 2*p2];
    *(uint2*)&sOh[c*40 + 2*p2] = make_uint2(f2t(v.x), f2t(v.y));
  }
  // ---- phase 1: Z = z1_w * Zcat ----
  float a1[2][4];
  #pragma unroll
  for(int ot=0;ot<2;ot++){a1[ot][0]=0.f;a1[ot][1]=0.f;a1[ot][2]=0.f;a1[ot][3]=0.f;}
  for (int cc=0; cc<128; cc+=8){
    __syncthreads();
    for (int idx=tid; idx<128; idx+=256){
      int c = idx>>4, p2 = idx&15;
      float2 v = *(const float2*)&g_Zcat[((size_t)b*128 + cc+c)*HW + p0 + 2*p2];
      *(uint2*)&sX[c*40 + 2*p2] = make_uint2(f2t(v.x), f2t(v.y));
    }
    __syncthreads();
    unsigned b0 = sX[ tq   *40 + wm*8 + g];
    unsigned b1 = sX[(tq+4)*40 + wm*8 + g];
    #pragma unroll
    for (int ot=0; ot<2; ot++){
      unsigned a[4];
      int r = ot*32 + wc*16 + g;
      a[0]=uz1[(r  )*132 + cc+tq];   a[1]=uz1[(r+8)*132 + cc+tq];
      a[2]=uz1[(r  )*132 + cc+tq+4]; a[3]=uz1[(r+8)*132 + cc+tq+4];
      mma8(a1[ot], a, b0, b1);
    }
  }
  __syncthreads();
  #pragma unroll
  for (int ot=0; ot<2; ot++){
    int r0 = ot*32 + wc*16 + g, r1 = r0 + 8;
    int col = wm*8 + 2*tq;
    float bv0 = z1_b[r0], bv1 = z1_b[r1];
    *(uint2*)&sZ[r0*40 + col] = make_uint2(f2t(a1[ot][0]+bv0), f2t(a1[ot][1]+bv0));
    *(uint2*)&sZ[r1*40 + col] = make_uint2(f2t(a1[ot][2]+bv1), f2t(a1[ot][3]+bv1));
  }
  // ---- phase 2: gates = z2_w * [Z; oh] ----
  float a2[6][4];
  #pragma unroll
  for(int ot=0;ot<6;ot++){a2[ot][0]=0.f;a2[ot][1]=0.f;a2[ot][2]=0.f;a2[ot][3]=0.f;}
  for (int cc=0; cc<128; cc+=8){
    __syncthreads();
    for (int idx=tid; idx<1536; idx+=256){
      int r = idx/192, o = idx - r*192;
      wch[r*200 + o] = g_z2T[(cc+r)*192 + o];
    }
    __syncthreads();
    const unsigned* src = (cc<64) ? (sZ + cc*40) : (sOh + (cc-64)*40);
    unsigned b0 = src[ tq   *40 + wm*8 + g];
    unsigned b1 = src[(tq+4)*40 + wm*8 + g];
    #pragma unroll
    for (int ot=0; ot<6; ot++){
      unsigned a[4];
      int o = ot*32 + wc*16 + g;
      a[0]=wch[ tq   *200 + o];   a[1]=wch[ tq   *200 + o+8];
      a[2]=wch[(tq+4)*200 + o];   a[3]=wch[(tq+4)*200 + o+8];
      mma8(a2[ot], a, b0, b1);
    }
  }
  __syncthreads();
  #pragma unroll
  for (int ot=0; ot<6; ot++){
    int r0 = ot*32 + wc*16 + g, r1 = r0 + 8;
    int col = wm*8 + 2*tq;
    float bv0 = z2_b[r0], bv1 = z2_b[r1];
    *(float2*)&gates[r0*34 + col] = make_float2(a2[ot][0]+bv0, a2[ot][1]+bv0);
    *(float2*)&gates[r1*34 + col] = make_float2(a2[ot][2]+bv1, a2[ot][3]+bv1);
  }
  __syncthreads();
  // ---- gating epilogue ----
  for (int i=tid; i<2048; i+=256){
    int c = i>>5, p = i&31;
    float vo = gates[(c     )*34 + p];
    float vg = gates[(64 +c )*34 + p];
    float vi = gates[(128+c )*34 + p];
    int idx = (b*64 + c)*1024 + p0 + p;
    float si = sigm(vi);
    float om  = tanhf(vg)*si + (1.f-si)*g_im[idx];
    float oh2 = sigm(vo)*om;
    g_im[idx] = om;
    g_ih[idx] = oh2;
    out[(((size_t)b*TT + t)*64 + c)*HW + p0 + p] = oh2;
    if (ws){
      float* st = out + (size_t)BB*TT*64*HW;
      st[idx]            = oh2;
      st[NSTATE + idx]   = g_ic[idx];
      st[2*NSTATE + idx] = om;
    }
  }
}

extern "C" void kernel_launch(void* const* d_in, const int* in_sizes, int n_in,
                              void* d_out, int out_size)
{
  const float* inputs = (const float*)d_in[0];
  const float* conv_w = (const float*)d_in[1];
  const float* conv_b = (const float*)d_in[2];
  const float* gn_g   = (const float*)d_in[3];
  const float* gn_b   = (const float*)d_in[4];
  const float* h_w    = (const float*)d_in[5];
  const float* h_b    = (const float*)d_in[6];
  const float* m_w    = (const float*)d_in[7];
  const float* m_b    = (const float*)d_in[8];
  const float* z1_w   = (const float*)d_in[9];
  const float* z1_b   = (const float*)d_in[10];
  const float* z2_w   = (const float*)d_in[11];
  const float* z2_b   = (const float*)d_in[12];
  float* out = (float*)d_out;

  const int ST_SMEM = (64*68 + 64*136)*4;           // 52224
  const int AV_SMEM = (64*72 + 64*68*2 + 64*72)*4;  // 71680
  const int TL_SMEM = 15488*4;                      // 61952
  cudaFuncSetAttribute(qk_stats, cudaFuncAttributeMaxDynamicSharedMemorySize, ST_SMEM);
  cudaFuncSetAttribute(av_tc,    cudaFuncAttributeMaxDynamicSharedMemorySize, AV_SMEM);
  cudaFuncSetAttribute(tail_k,   cudaFuncAttributeMaxDynamicSharedMemorySize, TL_SMEM);

  zero_states<<<2048,256>>>();
  wtrans<<<256,256>>>(conv_w, z2_w);
  int write_states = (out_size >= (int)(BB*TT*64*HW + 3*NSTATE)) ? 1 : 0;

  for (int t=0; t<TT; t++){
    conv_tc<<<dim3(8,4,8),256>>>(inputs, conv_b, t);
    gn_lstm4<<<512,256>>>(gn_g, gn_b, t);
    lin_hm<<<dim3(8,10,16),256>>>(h_w, h_b, m_w, m_b);
    qk_stats<<<dim3(8,16,2),256,ST_SMEM>>>();
    av_tc  <<<dim3(8,16,2),256,AV_SMEM>>>();
    tail_k<<<dim3(8,32),256,TL_SMEM>>>(z1_w, z1_b, z2_b, out, t, (t==TT-1) ? write_states : 0);
  }
}

// round 6
// speedup vs baseline: 1.5109x; 1.1333x over previous
#include <cuda_runtime.h>
#include <cuda_fp16.h>
#include <math.h>

#define BB 8
#define TT 8
#define HW 1024
#define CG 256
#define NSTATE (BB*64*HW)   // 524288

// ---- persistent state ----
__device__ float g_ih[NSTATE];
__device__ float g_ic[NSTATE];
__device__ float g_im[NSTATE];
// ---- scratch ----
__device__ float g_gates[BB*CG*HW];
__device__ float g_gsum [2][64];
__device__ float g_gsum2[2][64];
__device__ float g_oh[NSTATE];
__device__ float g_qkvh[BB*192*HW];
__device__ float g_kvm[BB*128*HW];
__device__ float g_rmax[2][BB*HW];
__device__ float g_rinv[2][BB*HW];
__device__ float g_Zcat[BB*128*HW];
__device__ unsigned g_wT[1152*256];   // conv weights [(ci*9+pos)][co] tf32
__device__ unsigned g_z2T[128*192];   // z2 weights transposed [c][o] tf32

__device__ __forceinline__ float sigm(float x){ return 1.f/(1.f+__expf(-x)); }
__device__ __forceinline__ unsigned f2t(float x){
  unsigned r; asm("cvt.rna.tf32.f32 %0,%1;" : "=r"(r) : "f"(x)); return r;
}
__device__ __forceinline__ void mma8(float* d, const unsigned* a, unsigned b0, unsigned b1){
  asm volatile("mma.sync.aligned.m16n8k8.row.col.f32.tf32.tf32.f32 "
    "{%0,%1,%2,%3},{%4,%5,%6,%7},{%8,%9},{%0,%1,%2,%3};"
    : "+f"(d[0]),"+f"(d[1]),"+f"(d[2]),"+f"(d[3])
    : "r"(a[0]),"r"(a[1]),"r"(a[2]),"r"(a[3]),"r"(b0),"r"(b1));
}
__device__ __forceinline__ void mma16(float* d, const unsigned* a, unsigned b0, unsigned b1){
  asm volatile("mma.sync.aligned.m16n8k16.row.col.f32.f16.f16.f32 "
    "{%0,%1,%2,%3},{%4,%5,%6,%7},{%8,%9},{%0,%1,%2,%3};"
    : "+f"(d[0]),"+f"(d[1]),"+f"(d[2]),"+f"(d[3])
    : "r"(a[0]),"r"(a[1]),"r"(a[2]),"r"(a[3]),"r"(b0),"r"(b1));
}
__device__ __forceinline__ unsigned pack2h(float x, float y){
  __half2 h = __floats2half2_rn(x, y);
  return *(unsigned*)&h;
}

// --- swizzled 64x64 half tile: word index for (row, half-pair j) ---
__device__ __forceinline__ int tw(int row, int j){ return row*32 + (j ^ ((row&7)<<2)); }

// transposed stage: src [c][spatial] (stride HW) -> tile [spatial row][c halves]
__device__ __forceinline__ void load_tT(unsigned* dst, const float* __restrict__ src, int s0){
  int tid = threadIdx.x;
  #pragma unroll
  for (int it=0; it<8; it++){
    int idx = it*256 + tid;
    int m = (idx & 7) | (((idx >> 8) & 7) << 3);
    int j = (idx >> 3) & 31;
    float f0 = src[(size_t)(2*j  )*HW + s0 + m];
    float f1 = src[(size_t)(2*j+1)*HW + s0 + m];
    dst[tw(m, j)] = pack2h(f0, f1);
  }
}
// direct stage: src [c][spatial] -> tile [c row][spatial halves]
__device__ __forceinline__ void load_tN(unsigned* dst, const float* __restrict__ src, int s0){
  int tid = threadIdx.x;
  #pragma unroll
  for (int it=0; it<8; it++){
    int idx = it*256 + tid;
    int j = idx & 31, c = idx >> 5;
    float2 v = *(const float2*)&src[(size_t)c*HW + s0 + 2*j];
    dst[tw(c, j)] = pack2h(v.x, v.y);
  }
}
__device__ __forceinline__ void ldA(unsigned* a, const unsigned* t, int r, int kk, int g, int tq){
  int j = kk*8 + tq;
  a[0] = t[tw(r+g,   j)];
  a[1] = t[tw(r+g+8, j)];
  a[2] = t[tw(r+g,   j+4)];
  a[3] = t[tw(r+g+8, j+4)];
}
__device__ __forceinline__ void ldB(unsigned* b, const unsigned* t, int r, int kk, int g, int tq){
  int j = kk*8 + tq;
  b[0] = t[tw(r+g, j)];
  b[1] = t[tw(r+g, j+4)];
}

__global__ void zero_states(){
  int i = blockIdx.x*256 + threadIdx.x;
  if (i < NSTATE){ g_ih[i]=0.f; g_ic[i]=0.f; g_im[i]=0.f; }
  if (blockIdx.x==0 && threadIdx.x<64){
    g_gsum[0][threadIdx.x]=0.f; g_gsum2[0][threadIdx.x]=0.f;
    g_gsum[1][threadIdx.x]=0.f; g_gsum2[1][threadIdx.x]=0.f;
  }
}

__global__ void wtrans(const float* __restrict__ w, const float* __restrict__ z2w){
  int co = blockIdx.x;
  for (int i = threadIdx.x; i < 1152; i += 256)
    g_wT[(size_t)i*256 + co] = f2t(w[(size_t)co*1152 + i]);
  if (co < 192){
    for (int c = threadIdx.x; c < 128; c += 256)
      g_z2T[c*192 + co] = f2t(z2w[co*128 + c]);
  }
}

// ------------------- 3x3 conv (implicit GEMM, TC tf32) + fused GN stats ----
__global__ __launch_bounds__(256) void conv_tc(const float* __restrict__ xin,
                                               const float* __restrict__ bias, int t)
{
  int pt = blockIdx.x, cot = blockIdx.y, b = blockIdx.z;
  int y0 = pt*4, co0 = cot*64, par = t & 1;
  __shared__ unsigned sIn[8][6][36];
  __shared__ unsigned sW[9][8][72];
  __shared__ float ws[8], ws2[8];
  int tid=threadIdx.x, warp=tid>>5, lane=tid&31, g=lane>>2, tq=lane&3;
  int wc = warp&3, wm = warp>>2;
  float acc[8][4];
  #pragma unroll
  for(int j=0;j<8;j++){acc[j][0]=0.f;acc[j][1]=0.f;acc[j][2]=0.f;acc[j][3]=0.f;}

  for (int chunk=0; chunk<16; chunk++){
    const float* src = (chunk<8) ? (xin + ((size_t)(b*TT+t)*64 + chunk*8)*HW)
                                 : (g_ih + ((size_t)b*64 + (chunk-8)*8)*HW);
    __syncthreads();
    for (int idx=tid; idx<8*6*34; idx+=256){
      int ci = idx/204; int r = idx-ci*204; int yy=r/34; int xx=r-yy*34;
      int gy = y0-1+yy, gx = xx-1;
      float v = 0.f;
      if ((unsigned)gy<32u && (unsigned)gx<32u) v = src[ci*HW + gy*32 + gx];
      sIn[ci][yy][xx] = f2t(v);
    }
    for (int idx=tid; idx<4608; idx+=256){
      int co = idx & 63; int r = idx >> 6;
      int ci = r/9, pos = r - ci*9;
      sW[pos][ci][co] = g_wT[(size_t)((chunk*8+ci)*9+pos)*256 + co0 + co];
    }
    __syncthreads();
    #pragma unroll
    for (int pos=0; pos<9; pos++){
      int ky = pos/3, kx = pos-3*ky;
      unsigned a[4];
      a[0] = sW[pos][tq  ][wc*16+g];
      a[1] = sW[pos][tq  ][wc*16+8+g];
      a[2] = sW[pos][tq+4][wc*16+g];
      a[3] = sW[pos][tq+4][wc*16+8+g];
      #pragma unroll
      for (int mf=0; mf<8; mf++){
        int p = wm*64 + mf*8 + g;
        int y = p>>5, x = p&31;
        unsigned b0 = sIn[tq  ][y+ky][x+kx];
        unsigned b1 = sIn[tq+4][y+ky][x+kx];
        mma8(acc[mf], a, b0, b1);
      }
    }
  }
  int r0 = co0 + wc*16 + g, r1 = r0 + 8;
  float bv0 = bias[r0], bv1 = bias[r1];
  float s=0.f, s2=0.f;
  #pragma unroll
  for (int mf=0; mf<8; mf++){
    int col = y0*32 + wm*64 + mf*8 + 2*tq;
    float v0=acc[mf][0]+bv0, v1=acc[mf][1]+bv0;
    float v2=acc[mf][2]+bv1, v3=acc[mf][3]+bv1;
    *(float2*)&g_gates[((size_t)b*CG + r0)*HW + col] = make_float2(v0,v1);
    *(float2*)&g_gates[((size_t)b*CG + r1)*HW + col] = make_float2(v2,v3);
    s  += v0+v1+v2+v3;
    s2 += v0*v0+v1*v1+v2*v2+v3*v3;
  }
  #pragma unroll
  for (int off=16; off; off>>=1){
    s  += __shfl_xor_sync(0xffffffffu, s , off);
    s2 += __shfl_xor_sync(0xffffffffu, s2, off);
  }
  if (lane==0){ ws[warp]=s; ws2[warp]=s2; }
  __syncthreads();
  if (tid<2){
    float S  = ws [tid*2]+ws [tid*2+1]+ws [tid*2+4]+ws [tid*2+5];
    float S2 = ws2[tid*2]+ws2[tid*2+1]+ws2[tid*2+4]+ws2[tid*2+5];
    int gidx = b*8 + (co0>>5) + tid;
    atomicAdd(&g_gsum [par][gidx], S );
    atomicAdd(&g_gsum2[par][gidx], S2);
  }
}

// ------------------- GN apply + LSTM gating (float4) -------------------
__global__ void gn_lstm4(const float* __restrict__ gg, const float* __restrict__ gb, int t){
  int b = blockIdx.x >> 6, c = blockIdx.x & 63;
  int p = threadIdx.x*4;
  int par = t & 1;
  __shared__ float smu[4], srs[4];
  if (threadIdx.x < 4){
    int grp = (c >> 5) + threadIdx.x*2;
    float s  = g_gsum [par][b*8+grp];
    float s2 = g_gsum2[par][b*8+grp];
    float m   = s*(1.f/32768.f);
    float var = s2*(1.f/32768.f) - m*m;
    smu[threadIdx.x] = m;
    srs[threadIdx.x] = rsqrtf(var + 1e-5f);
  }
  if (blockIdx.x==0 && threadIdx.x<64){
    g_gsum[par^1][threadIdx.x]=0.f; g_gsum2[par^1][threadIdx.x]=0.f;
  }
  __syncthreads();
  const float* gt = g_gates + (size_t)b*CG*HW + p;
  float4 vi = *(const float4*)&gt[(size_t)(c      )*HW];
  float4 vf = *(const float4*)&gt[(size_t)(c + 64 )*HW];
  float4 vc = *(const float4*)&gt[(size_t)(c + 128)*HW];
  float4 vo = *(const float4*)&gt[(size_t)(c + 192)*HW];
  int idx = (b*64 + c)*1024 + p;
  float4 ic4 = *(const float4*)&g_ic[idx];
  float4 oc4, oh4;
  {
    float a,f2,cc,o;
    a=(vi.x-smu[0])*srs[0]*gg[c]+gb[c]; f2=(vf.x-smu[1])*srs[1]*gg[c+64]+gb[c+64];
    cc=(vc.x-smu[2])*srs[2]*gg[c+128]+gb[c+128]; o=(vo.x-smu[3])*srs[3]*gg[c+192]+gb[c+192];
    oc4.x = ic4.x*sigm(f2)+sigm(a)*tanhf(cc); oh4.x = sigm(o)*tanhf(oc4.x);
    a=(vi.y-smu[0])*srs[0]*gg[c]+gb[c]; f2=(vf.y-smu[1])*srs[1]*gg[c+64]+gb[c+64];
    cc=(vc.y-smu[2])*srs[2]*gg[c+128]+gb[c+128]; o=(vo.y-smu[3])*srs[3]*gg[c+192]+gb[c+192];
    oc4.y = ic4.y*sigm(f2)+sigm(a)*tanhf(cc); oh4.y = sigm(o)*tanhf(oc4.y);
    a=(vi.z-smu[0])*srs[0]*gg[c]+gb[c]; f2=(vf.z-smu[1])*srs[1]*gg[c+64]+gb[c+64];
    cc=(vc.z-smu[2])*srs[2]*gg[c+128]+gb[c+128]; o=(vo.z-smu[3])*srs[3]*gg[c+192]+gb[c+192];
    oc4.z = ic4.z*sigm(f2)+sigm(a)*tanhf(cc); oh4.z = sigm(o)*tanhf(oc4.z);
    a=(vi.w-smu[0])*srs[0]*gg[c]+gb[c]; f2=(vf.w-smu[1])*srs[1]*gg[c+64]+gb[c+64];
    cc=(vc.w-smu[2])*srs[2]*gg[c+128]+gb[c+128]; o=(vo.w-smu[3])*srs[3]*gg[c+192]+gb[c+192];
    oc4.w = ic4.w*sigm(f2)+sigm(a)*tanhf(cc); oh4.w = sigm(o)*tanhf(oc4.w);
  }
  *(float4*)&g_ic[idx] = oc4;
  *(float4*)&g_oh[idx] = oh4;
}

// ------------------- 1x1 conv GEMM body (tf32, 32co x 64px tile) -------------------
__device__ __forceinline__ void lin_body(const float* __restrict__ x1,
                                         const float* __restrict__ w,
                                         const float* __restrict__ bias,
                                         float* __restrict__ y, int Cout,
                                         int b, int o0, int p0,
                                         unsigned* uW, unsigned* uX)
{
  const int Cin = 64, pitch = 68;
  int tid=threadIdx.x, warp=tid>>5, lane=tid&31, g=lane>>2, tq=lane&3;
  int wc = warp&1, wm = warp>>1;
  for (int idx=tid; idx<32*Cin; idx+=256){
    int o = idx>>6, c = idx&63;
    uW[o*pitch + c] = f2t(w[(size_t)(o0+o)*Cin + c]);
  }
  float acc[2][4];
  acc[0][0]=acc[0][1]=acc[0][2]=acc[0][3]=0.f;
  acc[1][0]=acc[1][1]=acc[1][2]=acc[1][3]=0.f;
  for (int cc=0; cc<Cin; cc+=8){
    __syncthreads();
    for (int idx=tid; idx<256; idx+=256){
      int ci = idx>>5, m2 = idx&31;
      float2 v = *(const float2*)&x1[((size_t)b*Cin + cc+ci)*HW + p0 + 2*m2];
      *(uint2*)&uX[ci*72 + 2*m2] = make_uint2(f2t(v.x), f2t(v.y));
    }
    __syncthreads();
    unsigned a[4];
    a[0]=uW[(wc*16+g  )*pitch + cc+tq];   a[1]=uW[(wc*16+8+g)*pitch + cc+tq];
    a[2]=uW[(wc*16+g  )*pitch + cc+tq+4]; a[3]=uW[(wc*16+8+g)*pitch + cc+tq+4];
    #pragma unroll
    for (int mf=0; mf<2; mf++){
      unsigned b0 = uX[ tq   *72 + wm*16 + mf*8 + g];
      unsigned b1 = uX[(tq+4)*72 + wm*16 + mf*8 + g];
      mma8(acc[mf], a, b0, b1);
    }
  }
  #pragma unroll
  for (int mf=0; mf<2; mf++){
    int r0 = o0 + wc*16 + g, r1 = r0 + 8;
    int col = p0 + wm*16 + mf*8 + 2*tq;
    float bv0 = bias[r0], bv1 = bias[r1];
    *(float2*)&y[((size_t)b*Cout + r0)*HW + col] = make_float2(acc[mf][0]+bv0, acc[mf][1]+bv0);
    *(float2*)&y[((size_t)b*Cout + r1)*HW + col] = make_float2(acc[mf][2]+bv1, acc[mf][3]+bv1);
  }
}

__global__ __launch_bounds__(256) void lin_hm(const float* __restrict__ h_w,
                                              const float* __restrict__ h_b,
                                              const float* __restrict__ m_w,
                                              const float* __restrict__ m_b)
{
  __shared__ unsigned uW[32*68];
  __shared__ unsigned uX[8*72];
  int b = blockIdx.x, p0 = blockIdx.z*64;
  if (blockIdx.y < 6)
    lin_body(g_oh, h_w, h_b, g_qkvh, 192, b, blockIdx.y*32, p0, uW, uX);
  else
    lin_body(g_im, m_w, m_b, g_kvm, 128, b, (blockIdx.y-6)*32, p0, uW, uX);
}

// ------------------- pass 1 (fp16 TC): row softmax stats -------------------
// grid (b=8, ntile=16 of 64 rows, which=2), block 256 (4 n-warps x 2 m-warps)
__global__ __launch_bounds__(256) void qk_stats(){
  __shared__ unsigned uQ[2048];      // Q^T [n][c]
  __shared__ unsigned uK[2][2048];   // K^T [m][c], two 64-m tiles
  __shared__ float sM[2][64], sL[2][64];
  int b = blockIdx.x, n0 = blockIdx.y*64, which = blockIdx.z;
  const float* q = g_qkvh + (size_t)b*192*HW;
  const float* k = which ? (g_kvm + (size_t)b*128*HW)
                         : (g_qkvh + (size_t)b*192*HW + (size_t)64*HW);
  int tid=threadIdx.x, warp=tid>>5, lane=tid&31, g=lane>>2, tq=lane&3;
  int wn = warp&3, wm = warp>>2;
  load_tT(uQ, q, n0);
  float M0=-1e30f, M1=-1e30f, L0=0.f, L1=0.f;
  for (int m0=0; m0<HW; m0+=128){
    __syncthreads();
    load_tT(uK[0], k, m0);
    load_tT(uK[1], k, m0+64);
    __syncthreads();
    const unsigned* kt = uK[wm];
    float cfr[8][4];
    #pragma unroll
    for(int mf=0;mf<8;mf++){cfr[mf][0]=0.f;cfr[mf][1]=0.f;cfr[mf][2]=0.f;cfr[mf][3]=0.f;}
    #pragma unroll
    for (int kk=0; kk<4; kk++){
      unsigned a[4]; ldA(a, uQ, wn*16, kk, g, tq);
      #pragma unroll
      for (int mf=0; mf<8; mf++){
        unsigned bb[2]; ldB(bb, kt, mf*8, kk, g, tq);
        mma16(cfr[mf], a, bb[0], bb[1]);
      }
    }
    float tm0=-1e30f, tm1=-1e30f;
    #pragma unroll
    for(int mf=0;mf<8;mf++){
      tm0 = fmaxf(tm0, fmaxf(cfr[mf][0], cfr[mf][1]));
      tm1 = fmaxf(tm1, fmaxf(cfr[mf][2], cfr[mf][3]));
    }
    tm0 = fmaxf(tm0, __shfl_xor_sync(0xffffffffu, tm0, 1));
    tm0 = fmaxf(tm0, __shfl_xor_sync(0xffffffffu, tm0, 2));
    tm1 = fmaxf(tm1, __shfl_xor_sync(0xffffffffu, tm1, 1));
    tm1 = fmaxf(tm1, __shfl_xor_sync(0xffffffffu, tm1, 2));
    float nM0 = fmaxf(M0, tm0), nM1 = fmaxf(M1, tm1);
    float s0=0.f, s1=0.f;
    #pragma unroll
    for(int mf=0;mf<8;mf++){
      s0 += __expf(cfr[mf][0]-nM0) + __expf(cfr[mf][1]-nM0);
      s1 += __expf(cfr[mf][2]-nM1) + __expf(cfr[mf][3]-nM1);
    }
    s0 += __shfl_xor_sync(0xffffffffu, s0, 1);
    s0 += __shfl_xor_sync(0xffffffffu, s0, 2);
    s1 += __shfl_xor_sync(0xffffffffu, s1, 1);
    s1 += __shfl_xor_sync(0xffffffffu, s1, 2);
    L0 = L0*__expf(M0-nM0) + s0; M0 = nM0;
    L1 = L1*__expf(M1-nM1) + s1; M1 = nM1;
  }
  if (tq==0){
    sM[wm][wn*16+g  ] = M0; sL[wm][wn*16+g  ] = L0;
    sM[wm][wn*16+8+g] = M1; sL[wm][wn*16+8+g] = L1;
  }
  __syncthreads();
  if (tid<64){
    float Ma = sM[0][tid], Mb = sM[1][tid];
    float M  = fmaxf(Ma, Mb);
    float L  = sL[0][tid]*__expf(Ma-M) + sL[1][tid]*__expf(Mb-M);
    g_rmax[which][b*HW + n0 + tid] = M;
    g_rinv[which][b*HW + n0 + tid] = 1.f/L;
  }
}

// ------------------- pass 2 (fp16 TC): S^T recompute -> P^T -> AV GEMM ----------
// grid (b=8, mtile=16 of 64, which=2), block 256 (4 row-warps x 2 col-warps)
__global__ __launch_bounds__(256) void av_tc(){
  __shared__ unsigned uK[2048];   // K^T [m][c]   (A of GEMM1)
  __shared__ unsigned uQ[2048];   // Q^T [n][c]   (B of GEMM1)
  __shared__ unsigned uV[2048];   // V   [c][n]   (A of GEMM2)
  __shared__ unsigned uP[2048];   // P^T [m][n]   (B of GEMM2)
  __shared__ float srm[64], sri[64];
  int b = blockIdx.x, m0 = blockIdx.y*64, which = blockIdx.z;
  const float* q = g_qkvh + (size_t)b*192*HW;
  const float* k = which ? (g_kvm + (size_t)b*128*HW)
                         : (g_qkvh + (size_t)b*192*HW + (size_t)64*HW);
  const float* v = which ? (g_kvm + (size_t)b*128*HW + (size_t)64*HW)
                         : (g_qkvh + (size_t)b*192*HW + (size_t)128*HW);
  const float* rmax = g_rmax[which] + b*HW;
  const float* rinv = g_rinv[which] + b*HW;
  int zoff = which*64;
  int tid=threadIdx.x, warp=tid>>5, lane=tid&31, g=lane>>2, tq=lane&3;
  int wr = warp&3, wm = warp>>2;
  load_tT(uK, k, m0);
  float accZ[4][4];
  #pragma unroll
  for(int mf=0;mf<4;mf++){accZ[mf][0]=0.f;accZ[mf][1]=0.f;accZ[mf][2]=0.f;accZ[mf][3]=0.f;}

  for (int nb=0; nb<HW; nb+=64){
    __syncthreads();
    load_tT(uQ, q, nb);
    load_tN(uV, v, nb);
    if (tid < 64){ srm[tid] = rmax[nb+tid]; sri[tid] = rinv[nb+tid]; }
    __syncthreads();
    // GEMM1: S^T[m][n] = K[m,:]·Q[n,:]
    float accS[4][4];
    #pragma unroll
    for(int mf=0;mf<4;mf++){accS[mf][0]=0.f;accS[mf][1]=0.f;accS[mf][2]=0.f;accS[mf][3]=0.f;}
    #pragma unroll
    for (int kk=0; kk<4; kk++){
      unsigned a[4]; ldA(a, uK, wr*16, kk, g, tq);
      #pragma unroll
      for (int mf=0; mf<4; mf++){
        unsigned bb[2]; ldB(bb, uQ, wm*32 + mf*8, kk, g, tq);
        mma16(accS[mf], a, bb[0], bb[1]);
      }
    }
    // exp -> P^T packed (n-pairs contiguous, perfect B-operand layout)
    #pragma unroll
    for (int mf=0; mf<4; mf++){
      int n = wm*32 + mf*8 + 2*tq;
      float rm0 = srm[n],   ri0 = sri[n];
      float rm1 = srm[n+1], ri1 = sri[n+1];
      int jn = n >> 1;
      int r0 = wr*16 + g;
      uP[tw(r0,   jn)] = pack2h(__expf(accS[mf][0]-rm0)*ri0, __expf(accS[mf][1]-rm1)*ri1);
      uP[tw(r0+8, jn)] = pack2h(__expf(accS[mf][2]-rm0)*ri0, __expf(accS[mf][3]-rm1)*ri1);
    }
    __syncthreads();
    // GEMM2: Z[c][m] += V[c][n] * P[n][m]
    #pragma unroll
    for (int kk=0; kk<4; kk++){
      unsigned a[4]; ldA(a, uV, wr*16, kk, g, tq);
      #pragma unroll
      for (int mf=0; mf<4; mf++){
        unsigned bb[2]; ldB(bb, uP, wm*32 + mf*8, kk, g, tq);
        mma16(accZ[mf], a, bb[0], bb[1]);
      }
    }
  }
  #pragma unroll
  for (int mf=0; mf<4; mf++){
    int r0 = wr*16 + g, r1 = r0 + 8;
    int col = m0 + wm*32 + mf*8 + 2*tq;
    *(float2*)&g_Zcat[((size_t)b*128 + zoff + r0)*HW + col] = make_float2(accZ[mf][0], accZ[mf][1]);
    *(float2*)&g_Zcat[((size_t)b*128 + zoff + r1)*HW + col] = make_float2(accZ[mf][2], accZ[mf][3]);
  }
}

// ------------------- tail: z1 GEMM + z2 GEMM + gating, fused (tf32) -------
__global__ __launch_bounds__(256) void tail_k(const float* __restrict__ z1_w,
                                              const float* __restrict__ z1_b,
                                              const float* __restrict__ z2_b,
                                              float* __restrict__ out, int t, int ws)
{
  extern __shared__ unsigned sm[];
  unsigned* sZ  = sm;            // [64][40] tf32
  unsigned* sOh = sm + 2560;     // [64][40] tf32
  unsigned* wch = sm + 5120;     // [8][200] tf32 (z2T chunk)
  unsigned* sX  = sm + 6720;     // [8][40]  tf32
  unsigned* uz1 = sm + 7040;     // [64][132] tf32 (phase1)
  float*  gates = (float*)(sm + 7040); // [192][34] fp32 (phase2, overlays uz1)
  int b = blockIdx.x, p0 = blockIdx.y*32;
  int tid=threadIdx.x, warp=tid>>5, lane=tid&31, g=lane>>2, tq=lane&3;
  int wc = warp&1, wm = warp>>1;
  for (int idx=tid; idx<64*128; idx+=256){
    int o = idx>>7, c = idx&127;
    uz1[o*132+c] = f2t(z1_w[o*128+c]);
  }
  for (int idx=tid; idx<1024; idx+=256){
    int c = idx>>4, p2 = idx&15;
    float2 v = *(const float2*)&g_oh[((size_t)b*64+c)*HW + p0 + 2*p2];
    *(uint2*)&sOh[c*40 + 2*p2] = make_uint2(f2t(v.x), f2t(v.y));
  }
  float a1[2][4];
  #pragma unroll
  for(int ot=0;ot<2;ot++){a1[ot][0]=0.f;a1[ot][1]=0.f;a1[ot][2]=0.f;a1[ot][3]=0.f;}
  for (int cc=0; cc<128; cc+=8){
    __syncthreads();
    for (int idx=tid; idx<128; idx+=256){
      int c = idx>>4, p2 = idx&15;
      float2 v = *(const float2*)&g_Zcat[((size_t)b*128 + cc+c)*HW + p0 + 2*p2];
      *(uint2*)&sX[c*40 + 2*p2] = make_uint2(f2t(v.x), f2t(v.y));
    }
    __syncthreads();
    unsigned b0 = sX[ tq   *40 + wm*8 + g];
    unsigned b1 = sX[(tq+4)*40 + wm*8 + g];
    #pragma unroll
    for (int ot=0; ot<2; ot++){
      unsigned a[4];
      int r = ot*32 + wc*16 + g;
      a[0]=uz1[(r  )*132 + cc+tq];   a[1]=uz1[(r+8)*132 + cc+tq];
      a[2]=uz1[(r  )*132 + cc+tq+4]; a[3]=uz1[(r+8)*132 + cc+tq+4];
      mma8(a1[ot], a, b0, b1);
    }
  }
  __syncthreads();
  #pragma unroll
  for (int ot=0; ot<2; ot++){
    int r0 = ot*32 + wc*16 + g, r1 = r0 + 8;
    int col = wm*8 + 2*tq;
    float bv0 = z1_b[r0], bv1 = z1_b[r1];
    *(uint2*)&sZ[r0*40 + col] = make_uint2(f2t(a1[ot][0]+bv0), f2t(a1[ot][1]+bv0));
    *(uint2*)&sZ[r1*40 + col] = make_uint2(f2t(a1[ot][2]+bv1), f2t(a1[ot][3]+bv1));
  }
  float a2[6][4];
  #pragma unroll
  for(int ot=0;ot<6;ot++){a2[ot][0]=0.f;a2[ot][1]=0.f;a2[ot][2]=0.f;a2[ot][3]=0.f;}
  for (int cc=0; cc<128; cc+=8){
    __syncthreads();
    for (int idx=tid; idx<1536; idx+=256){
      int r = idx/192, o = idx - r*192;
      wch[r*200 + o] = g_z2T[(cc+r)*192 + o];
    }
    __syncthreads();
    const unsigned* src = (cc<64) ? (sZ + cc*40) : (sOh + (cc-64)*40);
    unsigned b0 = src[ tq   *40 + wm*8 + g];
    unsigned b1 = src[(tq+4)*40 + wm*8 + g];
    #pragma unroll
    for (int ot=0; ot<6; ot++){
      unsigned a[4];
      int o = ot*32 + wc*16 + g;
      a[0]=wch[ tq   *200 + o];   a[1]=wch[ tq   *200 + o+8];
      a[2]=wch[(tq+4)*200 + o];   a[3]=wch[(tq+4)*200 + o+8];
      mma8(a2[ot], a, b0, b1);
    }
  }
  __syncthreads();
  #pragma unroll
  for (int ot=0; ot<6; ot++){
    int r0 = ot*32 + wc*16 + g, r1 = r0 + 8;
    int col = wm*8 + 2*tq;
    float bv0 = z2_b[r0], bv1 = z2_b[r1];
    *(float2*)&gates[r0*34 + col] = make_float2(a2[ot][0]+bv0, a2[ot][1]+bv0);
    *(float2*)&gates[r1*34 + col] = make_float2(a2[ot][2]+bv1, a2[ot][3]+bv1);
  }
  __syncthreads();
  for (int i=tid; i<2048; i+=256){
    int c = i>>5, p = i&31;
    float vo = gates[(c     )*34 + p];
    float vg = gates[(64 +c )*34 + p];
    float vi = gates[(128+c )*34 + p];
    int idx = (b*64 + c)*1024 + p0 + p;
    float si = sigm(vi);
    float om  = tanhf(vg)*si + (1.f-si)*g_im[idx];
    float oh2 = sigm(vo)*om;
    g_im[idx] = om;
    g_ih[idx] = oh2;
    out[(((size_t)b*TT + t)*64 + c)*HW + p0 + p] = oh2;
    if (ws){
      float* st = out + (size_t)BB*TT*64*HW;
      st[idx]            = oh2;
      st[NSTATE + idx]   = g_ic[idx];
      st[2*NSTATE + idx] = om;
    }
  }
}

extern "C" void kernel_launch(void* const* d_in, const int* in_sizes, int n_in,
                              void* d_out, int out_size)
{
  const float* inputs = (const float*)d_in[0];
  const float* conv_w = (const float*)d_in[1];
  const float* conv_b = (const float*)d_in[2];
  const float* gn_g   = (const float*)d_in[3];
  const float* gn_b   = (const float*)d_in[4];
  const float* h_w    = (const float*)d_in[5];
  const float* h_b    = (const float*)d_in[6];
  const float* m_w    = (const float*)d_in[7];
  const float* m_b    = (const float*)d_in[8];
  const float* z1_w   = (const float*)d_in[9];
  const float* z1_b   = (const float*)d_in[10];
  const float* z2_w   = (const float*)d_in[11];
  const float* z2_b   = (const float*)d_in[12];
  float* out = (float*)d_out;

  const int TL_SMEM = 15488*4;   // 61952
  cudaFuncSetAttribute(tail_k, cudaFuncAttributeMaxDynamicSharedMemorySize, TL_SMEM);

  zero_states<<<2048,256>>>();
  wtrans<<<256,256>>>(conv_w, z2_w);
  int write_states = (out_size >= (int)(BB*TT*64*HW + 3*NSTATE)) ? 1 : 0;

  for (int t=0; t<TT; t++){
    conv_tc<<<dim3(8,4,8),256>>>(inputs, conv_b, t);
    gn_lstm4<<<512,256>>>(gn_g, gn_b, t);
    lin_hm<<<dim3(8,10,16),256>>>(h_w, h_b, m_w, m_b);
    qk_stats<<<dim3(8,16,2),256>>>();
    av_tc  <<<dim3(8,16,2),256>>>();
    tail_k<<<dim3(8,32),256,TL_SMEM>>>(z1_w, z1_b, z2_b, out, t, (t==TT-1) ? write_states : 0);
  }
}

// round 7
// speedup vs baseline: 2.2962x; 1.5197x over previous
#include <cuda_runtime.h>
#include <cuda_fp16.h>
#include <math.h>

#define BB 8
#define TT 8
#define HW 1024
#define CG 256
#define NSTATE (BB*64*HW)   // 524288

// ---- persistent state ----
__device__ float g_ih[NSTATE];
__device__ float g_ic[NSTATE];
__device__ float g_im[NSTATE];
// ---- scratch ----
__device__ float g_gates[BB*CG*HW];
__device__ float g_gsum [2][64];
__device__ float g_gsum2[2][64];
__device__ float g_oh[NSTATE];
__device__ float g_rmax[2][BB*HW];
__device__ float g_rinv[2][BB*HW];
__device__ float g_Zcat[BB*128*HW];
__device__ unsigned g_wTh[8*9*256*8];   // conv weights half2: [chunk16ci*9+pos][co][jpair]
__device__ unsigned g_z2T[128*192];     // z2 weights transposed [c][o] tf32
// attention operands, half-packed
__device__ unsigned g_qT[8*1024*32];       // Q^T  [b][n][c-pairs]
__device__ unsigned g_kT[2][8*1024*32];    // K^T  [which][b][m][c-pairs]
__device__ unsigned g_vv[2][8*64*512];     // V    [which][b][c][n-pairs]

__device__ __forceinline__ float sigm(float x){ return 1.f/(1.f+__expf(-x)); }
__device__ __forceinline__ unsigned f2t(float x){
  unsigned r; asm("cvt.rna.tf32.f32 %0,%1;" : "=r"(r) : "f"(x)); return r;
}
__device__ __forceinline__ void mma8(float* d, const unsigned* a, unsigned b0, unsigned b1){
  asm volatile("mma.sync.aligned.m16n8k8.row.col.f32.tf32.tf32.f32 "
    "{%0,%1,%2,%3},{%4,%5,%6,%7},{%8,%9},{%0,%1,%2,%3};"
    : "+f"(d[0]),"+f"(d[1]),"+f"(d[2]),"+f"(d[3])
    : "r"(a[0]),"r"(a[1]),"r"(a[2]),"r"(a[3]),"r"(b0),"r"(b1));
}
__device__ __forceinline__ void mma16(float* d, const unsigned* a, unsigned b0, unsigned b1){
  asm volatile("mma.sync.aligned.m16n8k16.row.col.f32.f16.f16.f32 "
    "{%0,%1,%2,%3},{%4,%5,%6,%7},{%8,%9},{%0,%1,%2,%3};"
    : "+f"(d[0]),"+f"(d[1]),"+f"(d[2]),"+f"(d[3])
    : "r"(a[0]),"r"(a[1]),"r"(a[2]),"r"(a[3]),"r"(b0),"r"(b1));
}
__device__ __forceinline__ unsigned pack2h(float x, float y){
  __half2 h = __floats2half2_rn(x, y);
  return *(unsigned*)&h;
}

// --- swizzled 64x64 half tile: word index for (row, half-pair j) ---
__device__ __forceinline__ int tw(int row, int j){ return row*32 + (j ^ ((row&7)<<2)); }

// coalesced tile stage from pre-packed half buffers (512 words = 64 rows x 32)
__device__ __forceinline__ void loadTile(unsigned* dst, const unsigned* __restrict__ src,
                                         int rowstride){
  int tid = threadIdx.x;
  #pragma unroll
  for (int it=0; it<2; it++){
    int idx = it*256 + tid;
    int row = idx>>3, j4 = (idx&7)*4;
    uint4 v = *(const uint4*)(src + (size_t)row*rowstride + j4);
    *(uint4*)&dst[tw(row, j4)] = v;
  }
}
__device__ __forceinline__ void ldA(unsigned* a, const unsigned* t, int r, int kk, int g, int tq){
  int j = kk*8 + tq;
  a[0] = t[tw(r+g,   j)];
  a[1] = t[tw(r+g+8, j)];
  a[2] = t[tw(r+g,   j+4)];
  a[3] = t[tw(r+g+8, j+4)];
}
__device__ __forceinline__ void ldB(unsigned* b, const unsigned* t, int r, int kk, int g, int tq){
  int j = kk*8 + tq;
  b[0] = t[tw(r+g, j)];
  b[1] = t[tw(r+g, j+4)];
}

__global__ void zero_states(){
  int i = blockIdx.x*256 + threadIdx.x;
  if (i < NSTATE){ g_ih[i]=0.f; g_ic[i]=0.f; g_im[i]=0.f; }
  if (blockIdx.x==0 && threadIdx.x<64){
    g_gsum[0][threadIdx.x]=0.f; g_gsum2[0][threadIdx.x]=0.f;
    g_gsum[1][threadIdx.x]=0.f; g_gsum2[1][threadIdx.x]=0.f;
  }
}

__global__ void wtrans(const float* __restrict__ w, const float* __restrict__ z2w){
  int co = blockIdx.x;
  for (int idx = threadIdx.x; idx < 576; idx += 256){
    int chunk = idx/72, r = idx - chunk*72, pos = r>>3, j = r&7;
    int ci = chunk*16 + 2*j;
    float v0 = w[((size_t)co*128 + ci  )*9 + pos];
    float v1 = w[((size_t)co*128 + ci+1)*9 + pos];
    g_wTh[((size_t)(chunk*9+pos)*256 + co)*8 + j] = pack2h(v0, v1);
  }
  if (co < 192){
    for (int c = threadIdx.x; c < 128; c += 256)
      g_z2T[c*192 + co] = f2t(z2w[co*128 + c]);
  }
}

// ------------------- 3x3 conv (implicit GEMM, fp16 TC) + fused GN stats ----
// grid (8 ptiles of 4 rows, 4 co-tiles of 64, 8 b), block 256
__global__ __launch_bounds__(256) void conv_tc(const float* __restrict__ xin,
                                               const float* __restrict__ bias, int t)
{
  int pt = blockIdx.x, cot = blockIdx.y, b = blockIdx.z;
  int y0 = pt*4, co0 = cot*64, par = t & 1;
  __shared__ unsigned sIn[8*232];    // [jpair][pixel], pitch 232 (==8 mod 32)
  __shared__ unsigned sW[9*64*8];    // [pos][co][jpair]
  __shared__ float ws[8], ws2[8];
  int tid=threadIdx.x, warp=tid>>5, lane=tid&31, g=lane>>2, tq=lane&3;
  int wc = warp&3, wm = warp>>2;
  float acc[8][4];
  #pragma unroll
  for(int j=0;j<8;j++){acc[j][0]=0.f;acc[j][1]=0.f;acc[j][2]=0.f;acc[j][3]=0.f;}

  int pix = tid;
  int yy = pix/34, xx = pix - yy*34;
  int gy = y0-1+yy, gx = xx-1;
  bool pv = (pix<204) && ((unsigned)gy<32u) && ((unsigned)gx<32u);
  int gidx = gy*32 + gx;

  for (int chunk=0; chunk<8; chunk++){
    const float* src = (chunk<4) ? (xin + ((size_t)(b*TT+t)*64 + chunk*16)*HW)
                                 : (g_ih + ((size_t)b*64 + (chunk-4)*16)*HW);
    __syncthreads();
    if (pix < 204){
      #pragma unroll
      for (int j=0;j<8;j++){
        float f0=0.f, f1=0.f;
        if (pv){ f0 = src[(size_t)(2*j)*HW + gidx]; f1 = src[(size_t)(2*j+1)*HW + gidx]; }
        sIn[j*232 + pix] = pack2h(f0, f1);
      }
    }
    for (int idx=tid; idx<4608; idx+=256){
      int pos = idx>>9, r2 = idx&511;
      sW[idx] = g_wTh[(size_t)(chunk*9+pos)*2048 + co0*8 + r2];
    }
    __syncthreads();
    #pragma unroll
    for (int pos=0; pos<9; pos++){
      int ky = pos/3, kx = pos - 3*ky;
      unsigned a[4];
      int rb = (pos*64 + wc*16 + g)*8;
      a[0] = sW[rb + tq];       a[1] = sW[rb + 64 + tq];
      a[2] = sW[rb + tq + 4];   a[3] = sW[rb + 64 + tq + 4];
      #pragma unroll
      for (int mf=0; mf<8; mf++){
        int p = wm*64 + mf*8 + g;
        int pixb = ((p>>5)+ky)*34 + (p&31) + kx;
        mma16(acc[mf], a, sIn[tq*232 + pixb], sIn[(tq+4)*232 + pixb]);
      }
    }
  }
  int r0 = co0 + wc*16 + g, r1 = r0 + 8;
  float bv0 = bias[r0], bv1 = bias[r1];
  float s=0.f, s2=0.f;
  #pragma unroll
  for (int mf=0; mf<8; mf++){
    int col = y0*32 + wm*64 + mf*8 + 2*tq;
    float v0=acc[mf][0]+bv0, v1=acc[mf][1]+bv0;
    float v2=acc[mf][2]+bv1, v3=acc[mf][3]+bv1;
    *(float2*)&g_gates[((size_t)b*CG + r0)*HW + col] = make_float2(v0,v1);
    *(float2*)&g_gates[((size_t)b*CG + r1)*HW + col] = make_float2(v2,v3);
    s  += v0+v1+v2+v3;
    s2 += v0*v0+v1*v1+v2*v2+v3*v3;
  }
  #pragma unroll
  for (int off=16; off; off>>=1){
    s  += __shfl_xor_sync(0xffffffffu, s , off);
    s2 += __shfl_xor_sync(0xffffffffu, s2, off);
  }
  if (lane==0){ ws[warp]=s; ws2[warp]=s2; }
  __syncthreads();
  if (tid<2){
    float S  = ws [tid*2]+ws [tid*2+1]+ws [tid*2+4]+ws [tid*2+5];
    float S2 = ws2[tid*2]+ws2[tid*2+1]+ws2[tid*2+4]+ws2[tid*2+5];
    int gidx2 = b*8 + (co0>>5) + tid;
    atomicAdd(&g_gsum [par][gidx2], S );
    atomicAdd(&g_gsum2[par][gidx2], S2);
  }
}

// ------------------- GN apply + LSTM gating (float4) -------------------
__global__ void gn_lstm4(const float* __restrict__ gg, const float* __restrict__ gb, int t){
  int b = blockIdx.x >> 6, c = blockIdx.x & 63;
  int p = threadIdx.x*4;
  int par = t & 1;
  __shared__ float smu[4], srs[4];
  if (threadIdx.x < 4){
    int grp = (c >> 5) + threadIdx.x*2;
    float s  = g_gsum [par][b*8+grp];
    float s2 = g_gsum2[par][b*8+grp];
    float m   = s*(1.f/32768.f);
    float var = s2*(1.f/32768.f) - m*m;
    smu[threadIdx.x] = m;
    srs[threadIdx.x] = rsqrtf(var + 1e-5f);
  }
  if (blockIdx.x==0 && threadIdx.x<64){
    g_gsum[par^1][threadIdx.x]=0.f; g_gsum2[par^1][threadIdx.x]=0.f;
  }
  __syncthreads();
  const float* gt = g_gates + (size_t)b*CG*HW + p;
  float4 vi = *(const float4*)&gt[(size_t)(c      )*HW];
  float4 vf = *(const float4*)&gt[(size_t)(c + 64 )*HW];
  float4 vc = *(const float4*)&gt[(size_t)(c + 128)*HW];
  float4 vo = *(const float4*)&gt[(size_t)(c + 192)*HW];
  int idx = (b*64 + c)*1024 + p;
  float4 ic4 = *(const float4*)&g_ic[idx];
  float4 oc4, oh4;
  {
    float a,f2,cc,o;
    a=(vi.x-smu[0])*srs[0]*gg[c]+gb[c]; f2=(vf.x-smu[1])*srs[1]*gg[c+64]+gb[c+64];
    cc=(vc.x-smu[2])*srs[2]*gg[c+128]+gb[c+128]; o=(vo.x-smu[3])*srs[3]*gg[c+192]+gb[c+192];
    oc4.x = ic4.x*sigm(f2)+sigm(a)*tanhf(cc); oh4.x = sigm(o)*tanhf(oc4.x);
    a=(vi.y-smu[0])*srs[0]*gg[c]+gb[c]; f2=(vf.y-smu[1])*srs[1]*gg[c+64]+gb[c+64];
    cc=(vc.y-smu[2])*srs[2]*gg[c+128]+gb[c+128]; o=(vo.y-smu[3])*srs[3]*gg[c+192]+gb[c+192];
    oc4.y = ic4.y*sigm(f2)+sigm(a)*tanhf(cc); oh4.y = sigm(o)*tanhf(oc4.y);
    a=(vi.z-smu[0])*srs[0]*gg[c]+gb[c]; f2=(vf.z-smu[1])*srs[1]*gg[c+64]+gb[c+64];
    cc=(vc.z-smu[2])*srs[2]*gg[c+128]+gb[c+128]; o=(vo.z-smu[3])*srs[3]*gg[c+192]+gb[c+192];
    oc4.z = ic4.z*sigm(f2)+sigm(a)*tanhf(cc); oh4.z = sigm(o)*tanhf(oc4.z);
    a=(vi.w-smu[0])*srs[0]*gg[c]+gb[c]; f2=(vf.w-smu[1])*srs[1]*gg[c+64]+gb[c+64];
    cc=(vc.w-smu[2])*srs[2]*gg[c+128]+gb[c+128]; o=(vo.w-smu[3])*srs[3]*gg[c+192]+gb[c+192];
    oc4.w = ic4.w*sigm(f2)+sigm(a)*tanhf(cc); oh4.w = sigm(o)*tanhf(oc4.w);
  }
  *(float4*)&g_ic[idx] = oc4;
  *(float4*)&g_oh[idx] = oh4;
}

// ------------------- QKV projections (tf32 GEMM) -> half operand buffers -----
// grid (b=8, y=10 co-tiles, 16 px-tiles of 64), block 256 (2 co-warps x 4 px-warps)
__global__ __launch_bounds__(256) void lin_hm(const float* __restrict__ h_w,
                                              const float* __restrict__ h_b,
                                              const float* __restrict__ m_w,
                                              const float* __restrict__ m_b)
{
  __shared__ unsigned uW[32*68];
  __shared__ unsigned uX[8*72];
  __shared__ __half sT[64*34];
  int b = blockIdx.x, p0 = blockIdx.z*64, yb = blockIdx.y;
  const float *x1, *w, *bias;
  int o0;
  if (yb < 6){ x1 = g_oh; w = h_w; bias = h_b; o0 = yb*32; }
  else       { x1 = g_im; w = m_w; bias = m_b; o0 = (yb-6)*32; }
  // route output
  unsigned* dstT = 0; unsigned* dstV = 0; int crel = 0;
  if (yb < 6){
    if      (o0 <  64){ dstT = g_qT;    crel = o0;       }
    else if (o0 < 128){ dstT = g_kT[0]; crel = o0 - 64;  }
    else              { dstV = g_vv[0]; crel = o0 - 128; }
  } else {
    if (o0 < 64){ dstT = g_kT[1]; crel = o0; }
    else        { dstV = g_vv[1]; crel = o0 - 64; }
  }

  const int Cin = 64, pitch = 68;
  int tid=threadIdx.x, warp=tid>>5, lane=tid&31, g=lane>>2, tq=lane&3;
  int wc = warp&1, wm = warp>>1;
  for (int idx=tid; idx<32*Cin; idx+=256){
    int o = idx>>6, c = idx&63;
    uW[o*pitch + c] = f2t(w[(size_t)(o0+o)*Cin + c]);
  }
  float acc[2][4];
  acc[0][0]=acc[0][1]=acc[0][2]=acc[0][3]=0.f;
  acc[1][0]=acc[1][1]=acc[1][2]=acc[1][3]=0.f;
  for (int cc=0; cc<Cin; cc+=8){
    __syncthreads();
    {
      int ci = tid>>5, m2 = tid&31;
      float2 v = *(const float2*)&x1[((size_t)b*Cin + cc+ci)*HW + p0 + 2*m2];
      *(uint2*)&uX[ci*72 + 2*m2] = make_uint2(f2t(v.x), f2t(v.y));
    }
    __syncthreads();
    unsigned a[4];
    a[0]=uW[(wc*16+g  )*pitch + cc+tq];   a[1]=uW[(wc*16+8+g)*pitch + cc+tq];
    a[2]=uW[(wc*16+g  )*pitch + cc+tq+4]; a[3]=uW[(wc*16+8+g)*pitch + cc+tq+4];
    #pragma unroll
    for (int mf=0; mf<2; mf++){
      unsigned b0 = uX[ tq   *72 + wm*16 + mf*8 + g];
      unsigned b1 = uX[(tq+4)*72 + wm*16 + mf*8 + g];
      mma8(acc[mf], a, b0, b1);
    }
  }
  int cc0 = wc*16 + g;          // row within 32-co tile
  float bv0 = bias[o0+cc0], bv1 = bias[o0+cc0+8];
  if (dstV){
    #pragma unroll
    for (int mf=0; mf<2; mf++){
      int col = p0 + wm*16 + mf*8 + 2*tq;
      dstV[((size_t)(b*64 + crel + cc0  ))*512 + (col>>1)] = pack2h(acc[mf][0]+bv0, acc[mf][1]+bv0);
      dstV[((size_t)(b*64 + crel + cc0+8))*512 + (col>>1)] = pack2h(acc[mf][2]+bv1, acc[mf][3]+bv1);
    }
  } else {
    __syncthreads();
    #pragma unroll
    for (int mf=0; mf<2; mf++){
      int col = wm*16 + mf*8 + 2*tq;   // 0..63 relative
      sT[(col  )*34 + cc0  ] = __float2half(acc[mf][0]+bv0);
      sT[(col+1)*34 + cc0  ] = __float2half(acc[mf][1]+bv0);
      sT[(col  )*34 + cc0+8] = __float2half(acc[mf][2]+bv1);
      sT[(col+1)*34 + cc0+8] = __float2half(acc[mf][3]+bv1);
    }
    __syncthreads();
    for (int idx=tid; idx<1024; idx+=256){
      int px = idx>>4, wj = idx&15;
      __half2 hv;
      hv.x = sT[px*34 + 2*wj];
      hv.y = sT[px*34 + 2*wj + 1];
      dstT[((size_t)(b*1024 + p0 + px))*32 + (crel>>1) + wj] = *(unsigned*)&hv;
    }
  }
}

// ------------------- pass 1 (fp16 TC): row softmax stats -------------------
__global__ __launch_bounds__(256) void qk_stats(){
  __shared__ unsigned uQ[2048];      // Q^T [n][c]
  __shared__ unsigned uK[2][2048];   // K^T [m][c], two 64-m tiles
  __shared__ float sM[2][64], sL[2][64];
  int b = blockIdx.x, n0 = blockIdx.y*64, which = blockIdx.z;
  const unsigned* qsrc = g_qT + (size_t)(b*1024 + n0)*32;
  const unsigned* ksrc = g_kT[which] + (size_t)b*1024*32;
  int tid=threadIdx.x, warp=tid>>5, lane=tid&31, g=lane>>2, tq=lane&3;
  int wn = warp&3, wm = warp>>2;
  loadTile(uQ, qsrc, 32);
  float M0=-1e30f, M1=-1e30f, L0=0.f, L1=0.f;
  for (int m0=0; m0<HW; m0+=128){
    __syncthreads();
    loadTile(uK[0], ksrc + (size_t)m0*32, 32);
    loadTile(uK[1], ksrc + (size_t)(m0+64)*32, 32);
    __syncthreads();
    const unsigned* kt = uK[wm];
    float cfr[8][4];
    #pragma unroll
    for(int mf=0;mf<8;mf++){cfr[mf][0]=0.f;cfr[mf][1]=0.f;cfr[mf][2]=0.f;cfr[mf][3]=0.f;}
    #pragma unroll
    for (int kk=0; kk<4; kk++){
      unsigned a[4]; ldA(a, uQ, wn*16, kk, g, tq);
      #pragma unroll
      for (int mf=0; mf<8; mf++){
        unsigned bb[2]; ldB(bb, kt, mf*8, kk, g, tq);
        mma16(cfr[mf], a, bb[0], bb[1]);
      }
    }
    float tm0=-1e30f, tm1=-1e30f;
    #pragma unroll
    for(int mf=0;mf<8;mf++){
      tm0 = fmaxf(tm0, fmaxf(cfr[mf][0], cfr[mf][1]));
      tm1 = fmaxf(tm1, fmaxf(cfr[mf][2], cfr[mf][3]));
    }
    tm0 = fmaxf(tm0, __shfl_xor_sync(0xffffffffu, tm0, 1));
    tm0 = fmaxf(tm0, __shfl_xor_sync(0xffffffffu, tm0, 2));
    tm1 = fmaxf(tm1, __shfl_xor_sync(0xffffffffu, tm1, 1));
    tm1 = fmaxf(tm1, __shfl_xor_sync(0xffffffffu, tm1, 2));
    float nM0 = fmaxf(M0, tm0), nM1 = fmaxf(M1, tm1);
    float s0=0.f, s1=0.f;
    #pragma unroll
    for(int mf=0;mf<8;mf++){
      s0 += __expf(cfr[mf][0]-nM0) + __expf(cfr[mf][1]-nM0);
      s1 += __expf(cfr[mf][2]-nM1) + __expf(cfr[mf][3]-nM1);
    }
    s0 += __shfl_xor_sync(0xffffffffu, s0, 1);
    s0 += __shfl_xor_sync(0xffffffffu, s0, 2);
    s1 += __shfl_xor_sync(0xffffffffu, s1, 1);
    s1 += __shfl_xor_sync(0xffffffffu, s1, 2);
    L0 = L0*__expf(M0-nM0) + s0; M0 = nM0;
    L1 = L1*__expf(M1-nM1) + s1; M1 = nM1;
  }
  if (tq==0){
    sM[wm][wn*16+g  ] = M0; sL[wm][wn*16+g  ] = L0;
    sM[wm][wn*16+8+g] = M1; sL[wm][wn*16+8+g] = L1;
  }
  __syncthreads();
  if (tid<64){
    float Ma = sM[0][tid], Mb = sM[1][tid];
    float M  = fmaxf(Ma, Mb);
    float L  = sL[0][tid]*__expf(Ma-M) + sL[1][tid]*__expf(Mb-M);
    g_rmax[which][b*HW + n0 + tid] = M;
    g_rinv[which][b*HW + n0 + tid] = 1.f/L;
  }
}

// ------------------- pass 2 (fp16 TC): S^T recompute -> P^T -> AV GEMM ----------
__global__ __launch_bounds__(256) void av_tc(){
  __shared__ unsigned uK[2048];   // K^T [m][c]   (A of GEMM1)
  __shared__ unsigned uQ[2048];   // Q^T [n][c]   (B of GEMM1)
  __shared__ unsigned uV[2048];   // V   [c][n]   (A of GEMM2)
  __shared__ unsigned uP[2048];   // P^T [m][n]   (B of GEMM2)
  __shared__ float srm[64], sri[64];
  int b = blockIdx.x, m0 = blockIdx.y*64, which = blockIdx.z;
  const unsigned* qsrc = g_qT + (size_t)b*1024*32;
  const unsigned* ksrc = g_kT[which] + (size_t)(b*1024 + m0)*32;
  const unsigned* vsrc = g_vv[which] + (size_t)b*64*512;
  const float* rmax = g_rmax[which] + b*HW;
  const float* rinv = g_rinv[which] + b*HW;
  int zoff = which*64;
  int tid=threadIdx.x, warp=tid>>5, lane=tid&31, g=lane>>2, tq=lane&3;
  int wr = warp&3, wm = warp>>2;
  loadTile(uK, ksrc, 32);
  float accZ[4][4];
  #pragma unroll
  for(int mf=0;mf<4;mf++){accZ[mf][0]=0.f;accZ[mf][1]=0.f;accZ[mf][2]=0.f;accZ[mf][3]=0.f;}

  for (int nb=0; nb<HW; nb+=64){
    __syncthreads();
    loadTile(uQ, qsrc + (size_t)nb*32, 32);
    loadTile(uV, vsrc + (nb>>1), 512);
    if (tid < 64){ srm[tid] = rmax[nb+tid]; sri[tid] = rinv[nb+tid]; }
    __syncthreads();
    // GEMM1: S^T[m][n] = K[m,:]·Q[n,:]
    float accS[4][4];
    #pragma unroll
    for(int mf=0;mf<4;mf++){accS[mf][0]=0.f;accS[mf][1]=0.f;accS[mf][2]=0.f;accS[mf][3]=0.f;}
    #pragma unroll
    for (int kk=0; kk<4; kk++){
      unsigned a[4]; ldA(a, uK, wr*16, kk, g, tq);
      #pragma unroll
      for (int mf=0; mf<4; mf++){
        unsigned bb[2]; ldB(bb, uQ, wm*32 + mf*8, kk, g, tq);
        mma16(accS[mf], a, bb[0], bb[1]);
      }
    }
    // exp -> P^T packed (n-pairs contiguous)
    #pragma unroll
    for (int mf=0; mf<4; mf++){
      int n = wm*32 + mf*8 + 2*tq;
      float rm0 = srm[n],   ri0 = sri[n];
      float rm1 = srm[n+1], ri1 = sri[n+1];
      int jn = n >> 1;
      int r0 = wr*16 + g;
      uP[tw(r0,   jn)] = pack2h(__expf(accS[mf][0]-rm0)*ri0, __expf(accS[mf][1]-rm1)*ri1);
      uP[tw(r0+8, jn)] = pack2h(__expf(accS[mf][2]-rm0)*ri0, __expf(accS[mf][3]-rm1)*ri1);
    }
    __syncthreads();
    // GEMM2: Z[c][m] += V[c][n] * P[n][m]
    #pragma unroll
    for (int kk=0; kk<4; kk++){
      unsigned a[4]; ldA(a, uV, wr*16, kk, g, tq);
      #pragma unroll
      for (int mf=0; mf<4; mf++){
        unsigned bb[2]; ldB(bb, uP, wm*32 + mf*8, kk, g, tq);
        mma16(accZ[mf], a, bb[0], bb[1]);
      }
    }
  }
  #pragma unroll
  for (int mf=0; mf<4; mf++){
    int r0 = wr*16 + g, r1 = r0 + 8;
    int col = m0 + wm*32 + mf*8 + 2*tq;
    *(float2*)&g_Zcat[((size_t)b*128 + zoff + r0)*HW + col] = make_float2(accZ[mf][0], accZ[mf][1]);
    *(float2*)&g_Zcat[((size_t)b*128 + zoff + r1)*HW + col] = make_float2(accZ[mf][2], accZ[mf][3]);
  }
}

// ------------------- tail: z1 GEMM + z2 GEMM + gating, fused (tf32) -------
__global__ __launch_bounds__(256) void tail_k(const float* __restrict__ z1_w,
                                              const float* __restrict__ z1_b,
                                              const float* __restrict__ z2_b,
                                              float* __restrict__ out, int t, int ws)
{
  extern __shared__ unsigned sm[];
  unsigned* sZ  = sm;            // [64][40] tf32
  unsigned* sOh = sm + 2560;     // [64][40] tf32
  unsigned* wch = sm + 5120;     // [8][200] tf32 (z2T chunk)
  unsigned* sX  = sm + 6720;     // [8][40]  tf32
  unsigned* uz1 = sm + 7040;     // [64][132] tf32 (phase1)
  float*  gates = (float*)(sm + 7040); // [192][34] fp32 (phase2, overlays uz1)
  int b = blockIdx.x, p0 = blockIdx.y*32;
  int tid=threadIdx.x, warp=tid>>5, lane=tid&31, g=lane>>2, tq=lane&3;
  int wc = warp&1, wm = warp>>1;
  for (int idx=tid; idx<64*128; idx+=256){
    int o = idx>>7, c = idx&127;
    uz1[o*132+c] = f2t(z1_w[o*128+c]);
  }
  for (int idx=tid; idx<1024; idx+=256){
    int c = idx>>4, p2 = idx&15;
    float2 v = *(const float2*)&g_oh[((size_t)b*64+c)*HW + p0 + 2*p2];
    *(uint2*)&sOh[c*40 + 2*p2] = make_uint2(f2t(v.x), f2t(v.y));
  }
  float a1[2][4];
  #pragma unroll
  for(int ot=0;ot<2;ot++){a1[ot][0]=0.f;a1[ot][1]=0.f;a1[ot][2]=0.f;a1[ot][3]=0.f;}
  for (int cc=0; cc<128; cc+=8){
    __syncthreads();
    for (int idx=tid; idx<128; idx+=256){
      int c = idx>>4, p2 = idx&15;
      float2 v = *(const float2*)&g_Zcat[((size_t)b*128 + cc+c)*HW + p0 + 2*p2];
      *(uint2*)&sX[c*40 + 2*p2] = make_uint2(f2t(v.x), f2t(v.y));
    }
    __syncthreads();
    unsigned b0 = sX[ tq   *40 + wm*8 + g];
    unsigned b1 = sX[(tq+4)*40 + wm*8 + g];
    #pragma unroll
    for (int ot=0; ot<2; ot++){
      unsigned a[4];
      int r = ot*32 + wc*16 + g;
      a[0]=uz1[(r  )*132 + cc+tq];   a[1]=uz1[(r+8)*132 + cc+tq];
      a[2]=uz1[(r  )*132 + cc+tq+4]; a[3]=uz1[(r+8)*132 + cc+tq+4];
      mma8(a1[ot], a, b0, b1);
    }
  }
  __syncthreads();
  #pragma unroll
  for (int ot=0; ot<2; ot++){
    int r0 = ot*32 + wc*16 + g, r1 = r0 + 8;
    int col = wm*8 + 2*tq;
    float bv0 = z1_b[r0], bv1 = z1_b[r1];
    *(uint2*)&sZ[r0*40 + col] = make_uint2(f2t(a1[ot][0]+bv0), f2t(a1[ot][1]+bv0));
    *(uint2*)&sZ[r1*40 + col] = make_uint2(f2t(a1[ot][2]+bv1), f2t(a1[ot][3]+bv1));
  }
  float a2[6][4];
  #pragma unroll
  for(int ot=0;ot<6;ot++){a2[ot][0]=0.f;a2[ot][1]=0.f;a2[ot][2]=0.f;a2[ot][3]=0.f;}
  for (int cc=0; cc<128; cc+=8){
    __syncthreads();
    for (int idx=tid; idx<1536; idx+=256){
      int r = idx/192, o = idx - r*192;
      wch[r*200 + o] = g_z2T[(cc+r)*192 + o];
    }
    __syncthreads();
    const unsigned* src = (cc<64) ? (sZ + cc*40) : (sOh + (cc-64)*40);
    unsigned b0 = src[ tq   *40 + wm*8 + g];
    unsigned b1 = src[(tq+4)*40 + wm*8 + g];
    #pragma unroll
    for (int ot=0; ot<6; ot++){
      unsigned a[4];
      int o = ot*32 + wc*16 + g;
      a[0]=wch[ tq   *200 + o];   a[1]=wch[ tq   *200 + o+8];
      a[2]=wch[(tq+4)*200 + o];   a[3]=wch[(tq+4)*200 + o+8];
      mma8(a2[ot], a, b0, b1);
    }
  }
  __syncthreads();
  #pragma unroll
  for (int ot=0; ot<6; ot++){
    int r0 = ot*32 + wc*16 + g, r1 = r0 + 8;
    int col = wm*8 + 2*tq;
    float bv0 = z2_b[r0], bv1 = z2_b[r1];
    *(float2*)&gates[r0*34 + col] = make_float2(a2[ot][0]+bv0, a2[ot][1]+bv0);
    *(float2*)&gates[r1*34 + col] = make_float2(a2[ot][2]+bv1, a2[ot][3]+bv1);
  }
  __syncthreads();
  for (int i=tid; i<2048; i+=256){
    int c = i>>5, p = i&31;
    float vo = gates[(c     )*34 + p];
    float vg = gates[(64 +c )*34 + p];
    float vi = gates[(128+c )*34 + p];
    int idx = (b*64 + c)*1024 + p0 + p;
    float si = sigm(vi);
    float om  = tanhf(vg)*si + (1.f-si)*g_im[idx];
    float oh2 = sigm(vo)*om;
    g_im[idx] = om;
    g_ih[idx] = oh2;
    out[(((size_t)b*TT + t)*64 + c)*HW + p0 + p] = oh2;
    if (ws){
      float* st = out + (size_t)BB*TT*64*HW;
      st[idx]            = oh2;
      st[NSTATE + idx]   = g_ic[idx];
      st[2*NSTATE + idx] = om;
    }
  }
}

extern "C" void kernel_launch(void* const* d_in, const int* in_sizes, int n_in,
                              void* d_out, int out_size)
{
  const float* inputs = (const float*)d_in[0];
  const float* conv_w = (const float*)d_in[1];
  const float* conv_b = (const float*)d_in[2];
  const float* gn_g   = (const float*)d_in[3];
  const float* gn_b   = (const float*)d_in[4];
  const float* h_w    = (const float*)d_in[5];
  const float* h_b    = (const float*)d_in[6];
  const float* m_w    = (const float*)d_in[7];
  const float* m_b    = (const float*)d_in[8];
  const float* z1_w   = (const float*)d_in[9];
  const float* z1_b   = (const float*)d_in[10];
  const float* z2_w   = (const float*)d_in[11];
  const float* z2_b   = (const float*)d_in[12];
  float* out = (float*)d_out;

  const int TL_SMEM = 15488*4;   // 61952
  cudaFuncSetAttribute(tail_k, cudaFuncAttributeMaxDynamicSharedMemorySize, TL_SMEM);

  zero_states<<<2048,256>>>();
  wtrans<<<256,256>>>(conv_w, z2_w);
  int write_states = (out_size >= (int)(BB*TT*64*HW + 3*NSTATE)) ? 1 : 0;

  for (int t=0; t<TT; t++){
    conv_tc<<<dim3(8,4,8),256>>>(inputs, conv_b, t);
    gn_lstm4<<<512,256>>>(gn_g, gn_b, t);
    lin_hm<<<dim3(8,10,16),256>>>(h_w, h_b, m_w, m_b);
    qk_stats<<<dim3(8,16,2),256>>>();
    av_tc  <<<dim3(8,16,2),256>>>();
    tail_k<<<dim3(8,32),256,TL_SMEM>>>(z1_w, z1_b, z2_b, out, t, (t==TT-1) ? write_states : 0);
  }
}

// round 8
// speedup vs baseline: 2.6089x; 1.1362x over previous
#include <cuda_runtime.h>
#include <cuda_fp16.h>
#include <math.h>

#define BB 8
#define TT 8
#define HW 1024
#define CG 256
#define NSTATE (BB*64*HW)   // 524288

// ---- persistent state ----
__device__ float g_ih[NSTATE];
__device__ float g_ic[NSTATE];
__device__ float g_im[NSTATE];
// ---- scratch ----
__device__ float g_gates[BB*CG*HW];
__device__ float g_gsum [2][64];
__device__ float g_gsum2[2][64];
__device__ float g_oh[NSTATE];
__device__ float g_rmax[2][BB*HW];
__device__ float g_rinv[2][BB*HW];
__device__ float g_Zcat[BB*128*HW];
__device__ unsigned g_wTh[8*9*256*8];   // conv weights half2: [chunk16ci*9+pos][co][jpair]
__device__ unsigned g_z2T[128*192];     // z2 weights transposed [c][o] tf32
// attention operands, half-packed
__device__ unsigned g_qT[8*1024*32];       // Q^T  [b][n][c-pairs]
__device__ unsigned g_kT[2][8*1024*32];    // K^T  [which][b][m][c-pairs]
__device__ unsigned g_vv[2][8*64*512];     // V    [which][b][c][n-pairs]

__device__ __forceinline__ float sigm(float x){ return 1.f/(1.f+__expf(-x)); }
__device__ __forceinline__ unsigned f2t(float x){
  unsigned r; asm("cvt.rna.tf32.f32 %0,%1;" : "=r"(r) : "f"(x)); return r;
}
__device__ __forceinline__ void mma8(float* d, const unsigned* a, unsigned b0, unsigned b1){
  asm volatile("mma.sync.aligned.m16n8k8.row.col.f32.tf32.tf32.f32 "
    "{%0,%1,%2,%3},{%4,%5,%6,%7},{%8,%9},{%0,%1,%2,%3};"
    : "+f"(d[0]),"+f"(d[1]),"+f"(d[2]),"+f"(d[3])
    : "r"(a[0]),"r"(a[1]),"r"(a[2]),"r"(a[3]),"r"(b0),"r"(b1));
}
__device__ __forceinline__ void mma16(float* d, const unsigned* a, unsigned b0, unsigned b1){
  asm volatile("mma.sync.aligned.m16n8k16.row.col.f32.f16.f16.f32 "
    "{%0,%1,%2,%3},{%4,%5,%6,%7},{%8,%9},{%0,%1,%2,%3};"
    : "+f"(d[0]),"+f"(d[1]),"+f"(d[2]),"+f"(d[3])
    : "r"(a[0]),"r"(a[1]),"r"(a[2]),"r"(a[3]),"r"(b0),"r"(b1));
}
__device__ __forceinline__ unsigned pack2h(float x, float y){
  __half2 h = __floats2half2_rn(x, y);
  return *(unsigned*)&h;
}

// --- swizzled 64x64 half tile: word index for (row, half-pair j) ---
__device__ __forceinline__ int tw(int row, int j){ return row*32 + (j ^ ((row&7)<<2)); }

// coalesced tile stage from pre-packed half buffers (512 words = 64 rows x 32)
__device__ __forceinline__ void loadTile(unsigned* dst, const unsigned* __restrict__ src,
                                         int rowstride){
  int tid = threadIdx.x;
  #pragma unroll
  for (int it=0; it<2; it++){
    int idx = it*256 + tid;
    int row = idx>>3, j4 = (idx&7)*4;
    uint4 v = *(const uint4*)(src + (size_t)row*rowstride + j4);
    *(uint4*)&dst[tw(row, j4)] = v;
  }
}

// ---- ldmatrix fragment loads (b16, no trans; layout [row][k-pairs] swizzled) ----
__device__ __forceinline__ unsigned saddr(const unsigned* p){
  return (unsigned)__cvta_generic_to_shared((const void*)p);
}
// A fragment m16k16 at rows r..r+15, k-words kk*8..+7 -> a[0..3]
__device__ __forceinline__ void ldsmA(unsigned* a, const unsigned* t, int r, int kk){
  int lane = threadIdx.x & 31;
  int row = r + (lane&7) + (lane&8);
  int j   = kk*8 + ((lane>>4)<<2);
  unsigned ad = saddr(t + tw(row, j));
  asm volatile("ldmatrix.sync.aligned.m8n8.x4.shared.b16 {%0,%1,%2,%3}, [%4];"
    : "=r"(a[0]),"=r"(a[1]),"=r"(a[2]),"=r"(a[3]) : "r"(ad));
}
// two B fragments (n-octets nb, nb+8), k-words kk*8..+7 -> b[0..1], b[2..3]
__device__ __forceinline__ void ldsmB2(unsigned* b, const unsigned* t, int nb, int kk){
  int lane = threadIdx.x & 31;
  int row = nb + (lane&7) + ((lane>>4)<<3);
  int j   = kk*8 + (((lane>>3)&1)<<2);
  unsigned ad = saddr(t + tw(row, j));
  asm volatile("ldmatrix.sync.aligned.m8n8.x4.shared.b16 {%0,%1,%2,%3}, [%4];"
    : "=r"(b[0]),"=r"(b[1]),"=r"(b[2]),"=r"(b[3]) : "r"(ad));
}

__global__ void zero_states(){
  int i = blockIdx.x*256 + threadIdx.x;
  if (i < NSTATE){ g_ih[i]=0.f; g_ic[i]=0.f; g_im[i]=0.f; }
  if (blockIdx.x==0 && threadIdx.x<64){
    g_gsum[0][threadIdx.x]=0.f; g_gsum2[0][threadIdx.x]=0.f;
    g_gsum[1][threadIdx.x]=0.f; g_gsum2[1][threadIdx.x]=0.f;
  }
}

__global__ void wtrans(const float* __restrict__ w, const float* __restrict__ z2w){
  int co = blockIdx.x;
  for (int idx = threadIdx.x; idx < 576; idx += 256){
    int chunk = idx/72, r = idx - chunk*72, pos = r>>3, j = r&7;
    int ci = chunk*16 + 2*j;
    float v0 = w[((size_t)co*128 + ci  )*9 + pos];
    float v1 = w[((size_t)co*128 + ci+1)*9 + pos];
    g_wTh[((size_t)(chunk*9+pos)*256 + co)*8 + j] = pack2h(v0, v1);
  }
  if (co < 192){
    for (int c = threadIdx.x; c < 128; c += 256)
      g_z2T[c*192 + co] = f2t(z2w[co*128 + c]);
  }
}

// ------------------- 3x3 conv (implicit GEMM, fp16 TC) + fused GN stats ----
__global__ __launch_bounds__(256) void conv_tc(const float* __restrict__ xin,
                                               const float* __restrict__ bias, int t)
{
  int pt = blockIdx.x, cot = blockIdx.y, b = blockIdx.z;
  int y0 = pt*4, co0 = cot*64, par = t & 1;
  __shared__ unsigned sIn[8*232];    // [jpair][pixel], pitch 232
  __shared__ unsigned sW[9*64*8];    // [pos][co][jpair]
  __shared__ float ws[8], ws2[8];
  int tid=threadIdx.x, warp=tid>>5, lane=tid&31, g=lane>>2, tq=lane&3;
  int wc = warp&3, wm = warp>>2;
  float acc[8][4];
  #pragma unroll
  for(int j=0;j<8;j++){acc[j][0]=0.f;acc[j][1]=0.f;acc[j][2]=0.f;acc[j][3]=0.f;}

  int pix = tid;
  int yy = pix/34, xx = pix - yy*34;
  int gy = y0-1+yy, gx = xx-1;
  bool pv = (pix<204) && ((unsigned)gy<32u) && ((unsigned)gx<32u);
  int gidx = gy*32 + gx;

  for (int chunk=0; chunk<8; chunk++){
    const float* src = (chunk<4) ? (xin + ((size_t)(b*TT+t)*64 + chunk*16)*HW)
                                 : (g_ih + ((size_t)b*64 + (chunk-4)*16)*HW);
    __syncthreads();
    if (pix < 204){
      #pragma unroll
      for (int j=0;j<8;j++){
        float f0=0.f, f1=0.f;
        if (pv){ f0 = src[(size_t)(2*j)*HW + gidx]; f1 = src[(size_t)(2*j+1)*HW + gidx]; }
        sIn[j*232 + pix] = pack2h(f0, f1);
      }
    }
    for (int idx=tid; idx<4608; idx+=256){
      int pos = idx>>9, r2 = idx&511;
      sW[idx] = g_wTh[(size_t)(chunk*9+pos)*2048 + co0*8 + r2];
    }
    __syncthreads();
    #pragma unroll
    for (int pos=0; pos<9; pos++){
      int ky = pos/3, kx = pos - 3*ky;
      unsigned a[4];
      int rb = (pos*64 + wc*16 + g)*8;
      a[0] = sW[rb + tq];       a[1] = sW[rb + 64 + tq];
      a[2] = sW[rb + tq + 4];   a[3] = sW[rb + 64 + tq + 4];
      #pragma unroll
      for (int mf=0; mf<8; mf++){
        int p = wm*64 + mf*8 + g;
        int pixb = ((p>>5)+ky)*34 + (p&31) + kx;
        mma16(acc[mf], a, sIn[tq*232 + pixb], sIn[(tq+4)*232 + pixb]);
      }
    }
  }
  int r0 = co0 + wc*16 + g, r1 = r0 + 8;
  float bv0 = bias[r0], bv1 = bias[r1];
  float s=0.f, s2=0.f;
  #pragma unroll
  for (int mf=0; mf<8; mf++){
    int col = y0*32 + wm*64 + mf*8 + 2*tq;
    float v0=acc[mf][0]+bv0, v1=acc[mf][1]+bv0;
    float v2=acc[mf][2]+bv1, v3=acc[mf][3]+bv1;
    *(float2*)&g_gates[((size_t)b*CG + r0)*HW + col] = make_float2(v0,v1);
    *(float2*)&g_gates[((size_t)b*CG + r1)*HW + col] = make_float2(v2,v3);
    s  += v0+v1+v2+v3;
    s2 += v0*v0+v1*v1+v2*v2+v3*v3;
  }
  #pragma unroll
  for (int off=16; off; off>>=1){
    s  += __shfl_xor_sync(0xffffffffu, s , off);
    s2 += __shfl_xor_sync(0xffffffffu, s2, off);
  }
  if (lane==0){ ws[warp]=s; ws2[warp]=s2; }
  __syncthreads();
  if (tid<2){
    float S  = ws [tid*2]+ws [tid*2+1]+ws [tid*2+4]+ws [tid*2+5];
    float S2 = ws2[tid*2]+ws2[tid*2+1]+ws2[tid*2+4]+ws2[tid*2+5];
    int gidx2 = b*8 + (co0>>5) + tid;
    atomicAdd(&g_gsum [par][gidx2], S );
    atomicAdd(&g_gsum2[par][gidx2], S2);
  }
}

// ------------------- GN apply + LSTM gating (float4) -------------------
__global__ void gn_lstm4(const float* __restrict__ gg, const float* __restrict__ gb, int t){
  int b = blockIdx.x >> 6, c = blockIdx.x & 63;
  int p = threadIdx.x*4;
  int par = t & 1;
  __shared__ float smu[4], srs[4];
  if (threadIdx.x < 4){
    int grp = (c >> 5) + threadIdx.x*2;
    float s  = g_gsum [par][b*8+grp];
    float s2 = g_gsum2[par][b*8+grp];
    float m   = s*(1.f/32768.f);
    float var = s2*(1.f/32768.f) - m*m;
    smu[threadIdx.x] = m;
    srs[threadIdx.x] = rsqrtf(var + 1e-5f);
  }
  if (blockIdx.x==0 && threadIdx.x<64){
    g_gsum[par^1][threadIdx.x]=0.f; g_gsum2[par^1][threadIdx.x]=0.f;
  }
  __syncthreads();
  const float* gt = g_gates + (size_t)b*CG*HW + p;
  float4 vi = *(const float4*)&gt[(size_t)(c      )*HW];
  float4 vf = *(const float4*)&gt[(size_t)(c + 64 )*HW];
  float4 vc = *(const float4*)&gt[(size_t)(c + 128)*HW];
  float4 vo = *(const float4*)&gt[(size_t)(c + 192)*HW];
  int idx = (b*64 + c)*1024 + p;
  float4 ic4 = *(const float4*)&g_ic[idx];
  float4 oc4, oh4;
  {
    float a,f2,cc,o;
    a=(vi.x-smu[0])*srs[0]*gg[c]+gb[c]; f2=(vf.x-smu[1])*srs[1]*gg[c+64]+gb[c+64];
    cc=(vc.x-smu[2])*srs[2]*gg[c+128]+gb[c+128]; o=(vo.x-smu[3])*srs[3]*gg[c+192]+gb[c+192];
    oc4.x = ic4.x*sigm(f2)+sigm(a)*tanhf(cc); oh4.x = sigm(o)*tanhf(oc4.x);
    a=(vi.y-smu[0])*srs[0]*gg[c]+gb[c]; f2=(vf.y-smu[1])*srs[1]*gg[c+64]+gb[c+64];
    cc=(vc.y-smu[2])*srs[2]*gg[c+128]+gb[c+128]; o=(vo.y-smu[3])*srs[3]*gg[c+192]+gb[c+192];
    oc4.y = ic4.y*sigm(f2)+sigm(a)*tanhf(cc); oh4.y = sigm(o)*tanhf(oc4.y);
    a=(vi.z-smu[0])*srs[0]*gg[c]+gb[c]; f2=(vf.z-smu[1])*srs[1]*gg[c+64]+gb[c+64];
    cc=(vc.z-smu[2])*srs[2]*gg[c+128]+gb[c+128]; o=(vo.z-smu[3])*srs[3]*gg[c+192]+gb[c+192];
    oc4.z = ic4.z*sigm(f2)+sigm(a)*tanhf(cc); oh4.z = sigm(o)*tanhf(oc4.z);
    a=(vi.w-smu[0])*srs[0]*gg[c]+gb[c]; f2=(vf.w-smu[1])*srs[1]*gg[c+64]+gb[c+64];
    cc=(vc.w-smu[2])*srs[2]*gg[c+128]+gb[c+128]; o=(vo.w-smu[3])*srs[3]*gg[c+192]+gb[c+192];
    oc4.w = ic4.w*sigm(f2)+sigm(a)*tanhf(cc); oh4.w = sigm(o)*tanhf(oc4.w);
  }
  *(float4*)&g_ic[idx] = oc4;
  *(float4*)&g_oh[idx] = oh4;
}

// ------------------- QKV projections (tf32 GEMM) -> half operand buffers -----
__global__ __launch_bounds__(256) void lin_hm(const float* __restrict__ h_w,
                                              const float* __restrict__ h_b,
                                              const float* __restrict__ m_w,
                                              const float* __restrict__ m_b)
{
  __shared__ unsigned uW[32*68];
  __shared__ unsigned uX[8*72];
  __shared__ __half sT[64*34];
  int b = blockIdx.x, p0 = blockIdx.z*64, yb = blockIdx.y;
  const float *x1, *w, *bias;
  int o0;
  if (yb < 6){ x1 = g_oh; w = h_w; bias = h_b; o0 = yb*32; }
  else       { x1 = g_im; w = m_w; bias = m_b; o0 = (yb-6)*32; }
  unsigned* dstT = 0; unsigned* dstV = 0; int crel = 0;
  if (yb < 6){
    if      (o0 <  64){ dstT = g_qT;    crel = o0;       }
    else if (o0 < 128){ dstT = g_kT[0]; crel = o0 - 64;  }
    else              { dstV = g_vv[0]; crel = o0 - 128; }
  } else {
    if (o0 < 64){ dstT = g_kT[1]; crel = o0; }
    else        { dstV = g_vv[1]; crel = o0 - 64; }
  }

  const int Cin = 64, pitch = 68;
  int tid=threadIdx.x, warp=tid>>5, lane=tid&31, g=lane>>2, tq=lane&3;
  int wc = warp&1, wm = warp>>1;
  for (int idx=tid; idx<32*Cin; idx+=256){
    int o = idx>>6, c = idx&63;
    uW[o*pitch + c] = f2t(w[(size_t)(o0+o)*Cin + c]);
  }
  float acc[2][4];
  acc[0][0]=acc[0][1]=acc[0][2]=acc[0][3]=0.f;
  acc[1][0]=acc[1][1]=acc[1][2]=acc[1][3]=0.f;
  for (int cc=0; cc<Cin; cc+=8){
    __syncthreads();
    {
      int ci = tid>>5, m2 = tid&31;
      float2 v = *(const float2*)&x1[((size_t)b*Cin + cc+ci)*HW + p0 + 2*m2];
      *(uint2*)&uX[ci*72 + 2*m2] = make_uint2(f2t(v.x), f2t(v.y));
    }
    __syncthreads();
    unsigned a[4];
    a[0]=uW[(wc*16+g  )*pitch + cc+tq];   a[1]=uW[(wc*16+8+g)*pitch + cc+tq];
    a[2]=uW[(wc*16+g  )*pitch + cc+tq+4]; a[3]=uW[(wc*16+8+g)*pitch + cc+tq+4];
    #pragma unroll
    for (int mf=0; mf<2; mf++){
      unsigned b0 = uX[ tq   *72 + wm*16 + mf*8 + g];
      unsigned b1 = uX[(tq+4)*72 + wm*16 + mf*8 + g];
      mma8(acc[mf], a, b0, b1);
    }
  }
  int cc0 = wc*16 + g;
  float bv0 = bias[o0+cc0], bv1 = bias[o0+cc0+8];
  if (dstV){
    #pragma unroll
    for (int mf=0; mf<2; mf++){
      int col = p0 + wm*16 + mf*8 + 2*tq;
      dstV[((size_t)(b*64 + crel + cc0  ))*512 + (col>>1)] = pack2h(acc[mf][0]+bv0, acc[mf][1]+bv0);
      dstV[((size_t)(b*64 + crel + cc0+8))*512 + (col>>1)] = pack2h(acc[mf][2]+bv1, acc[mf][3]+bv1);
    }
  } else {
    __syncthreads();
    #pragma unroll
    for (int mf=0; mf<2; mf++){
      int col = wm*16 + mf*8 + 2*tq;
      sT[(col  )*34 + cc0  ] = __float2half(acc[mf][0]+bv0);
      sT[(col+1)*34 + cc0  ] = __float2half(acc[mf][1]+bv0);
      sT[(col  )*34 + cc0+8] = __float2half(acc[mf][2]+bv1);
      sT[(col+1)*34 + cc0+8] = __float2half(acc[mf][3]+bv1);
    }
    __syncthreads();
    for (int idx=tid; idx<1024; idx+=256){
      int px = idx>>4, wj = idx&15;
      __half2 hv;
      hv.x = sT[px*34 + 2*wj];
      hv.y = sT[px*34 + 2*wj + 1];
      dstT[((size_t)(b*1024 + p0 + px))*32 + (crel>>1) + wj] = *(unsigned*)&hv;
    }
  }
}

// ------------------- pass 1 (fp16 TC + ldmatrix): row softmax stats ----------
__global__ __launch_bounds__(256) void qk_stats(){
  __shared__ unsigned uQ[2048];      // Q^T [n][c]
  __shared__ unsigned uK[2][2048];   // K^T [m][c], two 64-m tiles
  __shared__ float sM[2][64], sL[2][64];
  int b = blockIdx.x, n0 = blockIdx.y*64, which = blockIdx.z;
  const unsigned* qsrc = g_qT + (size_t)(b*1024 + n0)*32;
  const unsigned* ksrc = g_kT[which] + (size_t)b*1024*32;
  int tid=threadIdx.x, warp=tid>>5, tq=(tid&31)&3;
  int g = (tid&31)>>2;
  int wn = warp&3, wm = warp>>2;
  loadTile(uQ, qsrc, 32);
  float M0=-1e30f, M1=-1e30f, L0=0.f, L1=0.f;
  for (int m0=0; m0<HW; m0+=128){
    __syncthreads();
    loadTile(uK[0], ksrc + (size_t)m0*32, 32);
    loadTile(uK[1], ksrc + (size_t)(m0+64)*32, 32);
    __syncthreads();
    const unsigned* kt = uK[wm];
    float cfr[8][4];
    #pragma unroll
    for(int mf=0;mf<8;mf++){cfr[mf][0]=0.f;cfr[mf][1]=0.f;cfr[mf][2]=0.f;cfr[mf][3]=0.f;}
    #pragma unroll
    for (int kk=0; kk<4; kk++){
      unsigned a[4]; ldsmA(a, uQ, wn*16, kk);
      #pragma unroll
      for (int mp=0; mp<4; mp++){
        unsigned bb[4]; ldsmB2(bb, kt, mp*16, kk);
        mma16(cfr[2*mp  ], a, bb[0], bb[1]);
        mma16(cfr[2*mp+1], a, bb[2], bb[3]);
      }
    }
    float tm0=-1e30f, tm1=-1e30f;
    #pragma unroll
    for(int mf=0;mf<8;mf++){
      tm0 = fmaxf(tm0, fmaxf(cfr[mf][0], cfr[mf][1]));
      tm1 = fmaxf(tm1, fmaxf(cfr[mf][2], cfr[mf][3]));
    }
    tm0 = fmaxf(tm0, __shfl_xor_sync(0xffffffffu, tm0, 1));
    tm0 = fmaxf(tm0, __shfl_xor_sync(0xffffffffu, tm0, 2));
    tm1 = fmaxf(tm1, __shfl_xor_sync(0xffffffffu, tm1, 1));
    tm1 = fmaxf(tm1, __shfl_xor_sync(0xffffffffu, tm1, 2));
    float nM0 = fmaxf(M0, tm0), nM1 = fmaxf(M1, tm1);
    float s0=0.f, s1=0.f;
    #pragma unroll
    for(int mf=0;mf<8;mf++){
      s0 += __expf(cfr[mf][0]-nM0) + __expf(cfr[mf][1]-nM0);
      s1 += __expf(cfr[mf][2]-nM1) + __expf(cfr[mf][3]-nM1);
    }
    s0 += __shfl_xor_sync(0xffffffffu, s0, 1);
    s0 += __shfl_xor_sync(0xffffffffu, s0, 2);
    s1 += __shfl_xor_sync(0xffffffffu, s1, 1);
    s1 += __shfl_xor_sync(0xffffffffu, s1, 2);
    L0 = L0*__expf(M0-nM0) + s0; M0 = nM0;
    L1 = L1*__expf(M1-nM1) + s1; M1 = nM1;
  }
  if (tq==0){
    sM[wm][wn*16+g  ] = M0; sL[wm][wn*16+g  ] = L0;
    sM[wm][wn*16+8+g] = M1; sL[wm][wn*16+8+g] = L1;
  }
  __syncthreads();
  if (tid<64){
    float Ma = sM[0][tid], Mb = sM[1][tid];
    float M  = fmaxf(Ma, Mb);
    float L  = sL[0][tid]*__expf(Ma-M) + sL[1][tid]*__expf(Mb-M);
    g_rmax[which][b*HW + n0 + tid] = M;
    g_rinv[which][b*HW + n0 + tid] = 1.f/L;
  }
}

// ------------------- pass 2 (fp16 TC + ldmatrix): S^T recompute -> P^T -> AV ----
__global__ __launch_bounds__(256) void av_tc(){
  __shared__ unsigned uK[2048];   // K^T [m][c]   (A of GEMM1)
  __shared__ unsigned uQ[2048];   // Q^T [n][c]   (B of GEMM1)
  __shared__ unsigned uV[2048];   // V   [c][n]   (A of GEMM2)
  __shared__ unsigned uP[2048];   // P^T [m][n]   (B of GEMM2)
  __shared__ float srm[64], sri[64];
  int b = blockIdx.x, m0 = blockIdx.y*64, which = blockIdx.z;
  const unsigned* qsrc = g_qT + (size_t)b*1024*32;
  const unsigned* ksrc = g_kT[which] + (size_t)(b*1024 + m0)*32;
  const unsigned* vsrc = g_vv[which] + (size_t)b*64*512;
  const float* rmax = g_rmax[which] + b*HW;
  const float* rinv = g_rinv[which] + b*HW;
  int zoff = which*64;
  int tid=threadIdx.x, warp=tid>>5, lane=tid&31, g=lane>>2, tq=lane&3;
  int wr = warp&3, wm = warp>>2;
  loadTile(uK, ksrc, 32);
  float accZ[4][4];
  #pragma unroll
  for(int mf=0;mf<4;mf++){accZ[mf][0]=0.f;accZ[mf][1]=0.f;accZ[mf][2]=0.f;accZ[mf][3]=0.f;}

  for (int nb=0; nb<HW; nb+=64){
    __syncthreads();
    loadTile(uQ, qsrc + (size_t)nb*32, 32);
    loadTile(uV, vsrc + (nb>>1), 512);
    if (tid < 64){ srm[tid] = rmax[nb+tid]; sri[tid] = rinv[nb+tid]; }
    __syncthreads();
    // GEMM1: S^T[m][n] = K[m,:]·Q[n,:]
    float accS[4][4];
    #pragma unroll
    for(int mf=0;mf<4;mf++){accS[mf][0]=0.f;accS[mf][1]=0.f;accS[mf][2]=0.f;accS[mf][3]=0.f;}
    #pragma unroll
    for (int kk=0; kk<4; kk++){
      unsigned a[4]; ldsmA(a, uK, wr*16, kk);
      #pragma unroll
      for (int mp=0; mp<2; mp++){
        unsigned bb[4]; ldsmB2(bb, uQ, wm*32 + mp*16, kk);
        mma16(accS[2*mp  ], a, bb[0], bb[1]);
        mma16(accS[2*mp+1], a, bb[2], bb[3]);
      }
    }
    // exp -> P^T packed (n-pairs contiguous)
    #pragma unroll
    for (int mf=0; mf<4; mf++){
      int n = wm*32 + mf*8 + 2*tq;
      float rm0 = srm[n],   ri0 = sri[n];
      float rm1 = srm[n+1], ri1 = sri[n+1];
      int jn = n >> 1;
      int r0 = wr*16 + g;
      uP[tw(r0,   jn)] = pack2h(__expf(accS[mf][0]-rm0)*ri0, __expf(accS[mf][1]-rm1)*ri1);
      uP[tw(r0+8, jn)] = pack2h(__expf(accS[mf][2]-rm0)*ri0, __expf(accS[mf][3]-rm1)*ri1);
    }
    __syncthreads();
    // GEMM2: Z[c][m] += V[c][n] * P[n][m]
    #pragma unroll
    for (int kk=0; kk<4; kk++){
      unsigned a[4]; ldsmA(a, uV, wr*16, kk);
      #pragma unroll
      for (int mp=0; mp<2; mp++){
        unsigned bb[4]; ldsmB2(bb, uP, wm*32 + mp*16, kk);
        mma16(accZ[2*mp  ], a, bb[0], bb[1]);
        mma16(accZ[2*mp+1], a, bb[2], bb[3]);
      }
    }
  }
  #pragma unroll
  for (int mf=0; mf<4; mf++){
    int r0 = wr*16 + g, r1 = r0 + 8;
    int col = m0 + wm*32 + mf*8 + 2*tq;
    *(float2*)&g_Zcat[((size_t)b*128 + zoff + r0)*HW + col] = make_float2(accZ[mf][0], accZ[mf][1]);
    *(float2*)&g_Zcat[((size_t)b*128 + zoff + r1)*HW + col] = make_float2(accZ[mf][2], accZ[mf][3]);
  }
}

// ------------------- tail: z1 GEMM + z2 GEMM + gating, fused (tf32) -------
__global__ __launch_bounds__(256) void tail_k(const float* __restrict__ z1_w,
                                              const float* __restrict__ z1_b,
                                              const float* __restrict__ z2_b,
                                              float* __restrict__ out, int t, int ws)
{
  extern __shared__ unsigned sm[];
  unsigned* sZ  = sm;            // [64][40] tf32
  unsigned* sOh = sm + 2560;     // [64][40] tf32
  unsigned* wch = sm + 5120;     // [8][200] tf32 (z2T chunk)
  unsigned* sX  = sm + 6720;     // [8][40]  tf32
  unsigned* uz1 = sm + 7040;     // [64][132] tf32 (phase1)
  float*  gates = (float*)(sm + 7040); // [192][34] fp32 (phase2, overlays uz1)
  int b = blockIdx.x, p0 = blockIdx.y*32;
  int tid=threadIdx.x, warp=tid>>5, lane=tid&31, g=lane>>2, tq=lane&3;
  int wc = warp&1, wm = warp>>1;
  for (int idx=tid; idx<64*128; idx+=256){
    int o = idx>>7, c = idx&127;
    uz1[o*132+c] = f2t(z1_w[o*128+c]);
  }
  for (int idx=tid; idx<1024; idx+=256){
    int c = idx>>4, p2 = idx&15;
    float2 v = *(const float2*)&g_oh[((size_t)b*64+c)*HW + p0 + 2*p2];
    *(uint2*)&sOh[c*40 + 2*p2] = make_uint2(f2t(v.x), f2t(v.y));
  }
  float a1[2][4];
  #pragma unroll
  for(int ot=0;ot<2;ot++){a1[ot][0]=0.f;a1[ot][1]=0.f;a1[ot][2]=0.f;a1[ot][3]=0.f;}
  for (int cc=0; cc<128; cc+=8){
    __syncthreads();
    for (int idx=tid; idx<128; idx+=256){
      int c = idx>>4, p2 = idx&15;
      float2 v = *(const float2*)&g_Zcat[((size_t)b*128 + cc+c)*HW + p0 + 2*p2];
      *(uint2*)&sX[c*40 + 2*p2] = make_uint2(f2t(v.x), f2t(v.y));
    }
    __syncthreads();
    unsigned b0 = sX[ tq   *40 + wm*8 + g];
    unsigned b1 = sX[(tq+4)*40 + wm*8 + g];
    #pragma unroll
    for (int ot=0; ot<2; ot++){
      unsigned a[4];
      int r = ot*32 + wc*16 + g;
      a[0]=uz1[(r  )*132 + cc+tq];   a[1]=uz1[(r+8)*132 + cc+tq];
      a[2]=uz1[(r  )*132 + cc+tq+4]; a[3]=uz1[(r+8)*132 + cc+tq+4];
      mma8(a1[ot], a, b0, b1);
    }
  }
  __syncthreads();
  #pragma unroll
  for (int ot=0; ot<2; ot++){
    int r0 = ot*32 + wc*16 + g, r1 = r0 + 8;
    int col = wm*8 + 2*tq;
    float bv0 = z1_b[r0], bv1 = z1_b[r1];
    *(uint2*)&sZ[r0*40 + col] = make_uint2(f2t(a1[ot][0]+bv0), f2t(a1[ot][1]+bv0));
    *(uint2*)&sZ[r1*40 + col] = make_uint2(f2t(a1[ot][2]+bv1), f2t(a1[ot][3]+bv1));
  }
  float a2[6][4];
  #pragma unroll
  for(int ot=0;ot<6;ot++){a2[ot][0]=0.f;a2[ot][1]=0.f;a2[ot][2]=0.f;a2[ot][3]=0.f;}
  for (int cc=0; cc<128; cc+=8){
    __syncthreads();
    for (int idx=tid; idx<1536; idx+=256){
      int r = idx/192, o = idx - r*192;
      wch[r*200 + o] = g_z2T[(cc+r)*192 + o];
    }
    __syncthreads();
    const unsigned* src = (cc<64) ? (sZ + cc*40) : (sOh + (cc-64)*40);
    unsigned b0 = src[ tq   *40 + wm*8 + g];
    unsigned b1 = src[(tq+4)*40 + wm*8 + g];
    #pragma unroll
    for (int ot=0; ot<6; ot++){
      unsigned a[4];
      int o = ot*32 + wc*16 + g;
      a[0]=wch[ tq   *200 + o];   a[1]=wch[ tq   *200 + o+8];
      a[2]=wch[(tq+4)*200 + o];   a[3]=wch[(tq+4)*200 + o+8];
      mma8(a2[ot], a, b0, b1);
    }
  }
  __syncthreads();
  #pragma unroll
  for (int ot=0; ot<6; ot++){
    int r0 = ot*32 + wc*16 + g, r1 = r0 + 8;
    int col = wm*8 + 2*tq;
    float bv0 = z2_b[r0], bv1 = z2_b[r1];
    *(float2*)&gates[r0*34 + col] = make_float2(a2[ot][0]+bv0, a2[ot][1]+bv0);
    *(float2*)&gates[r1*34 + col] = make_float2(a2[ot][2]+bv1, a2[ot][3]+bv1);
  }
  __syncthreads();
  for (int i=tid; i<2048; i+=256){
    int c = i>>5, p = i&31;
    float vo = gates[(c     )*34 + p];
    float vg = gates[(64 +c )*34 + p];
    float vi = gates[(128+c )*34 + p];
    int idx = (b*64 + c)*1024 + p0 + p;
    float si = sigm(vi);
    float om  = tanhf(vg)*si + (1.f-si)*g_im[idx];
    float oh2 = sigm(vo)*om;
    g_im[idx] = om;
    g_ih[idx] = oh2;
    out[(((size_t)b*TT + t)*64 + c)*HW + p0 + p] = oh2;
    if (ws){
      float* st = out + (size_t)BB*TT*64*HW;
      st[idx]            = oh2;
      st[NSTATE + idx]   = g_ic[idx];
      st[2*NSTATE + idx] = om;
    }
  }
}

extern "C" void kernel_launch(void* const* d_in, const int* in_sizes, int n_in,
                              void* d_out, int out_size)
{
  const float* inputs = (const float*)d_in[0];
  const float* conv_w = (const float*)d_in[1];
  const float* conv_b = (const float*)d_in[2];
  const float* gn_g   = (const float*)d_in[3];
  const float* gn_b   = (const float*)d_in[4];
  const float* h_w    = (const float*)d_in[5];
  const float* h_b    = (const float*)d_in[6];
  const float* m_w    = (const float*)d_in[7];
  const float* m_b    = (const float*)d_in[8];
  const float* z1_w   = (const float*)d_in[9];
  const float* z1_b   = (const float*)d_in[10];
  const float* z2_w   = (const float*)d_in[11];
  const float* z2_b   = (const float*)d_in[12];
  float* out = (float*)d_out;

  const int TL_SMEM = 15488*4;   // 61952
  cudaFuncSetAttribute(tail_k, cudaFuncAttributeMaxDynamicSharedMemorySize, TL_SMEM);

  zero_states<<<2048,256>>>();
  wtrans<<<256,256>>>(conv_w, z2_w);
  int write_states = (out_size >= (int)(BB*TT*64*HW + 3*NSTATE)) ? 1 : 0;

  for (int t=0; t<TT; t++){
    conv_tc<<<dim3(8,4,8),256>>>(inputs, conv_b, t);
    gn_lstm4<<<512,256>>>(gn_g, gn_b, t);
    lin_hm<<<dim3(8,10,16),256>>>(h_w, h_b, m_w, m_b);
    qk_stats<<<dim3(8,16,2),256>>>();
    av_tc  <<<dim3(8,16,2),256>>>();
    tail_k<<<dim3(8,32),256,TL_SMEM>>>(z1_w, z1_b, z2_b, out, t, (t==TT-1) ? write_states : 0);
  }
}

// round 9
// speedup vs baseline: 2.6224x; 1.0051x over previous
#include <cuda_runtime.h>
#include <cuda_fp16.h>
#include <math.h>

#define BB 8
#define TT 8
#define HW 1024
#define CG 256
#define NSTATE (BB*64*HW)   // 524288
#define LOG2E 1.4426950408889634f

// ---- persistent state ----
__device__ float g_ih[NSTATE];
__device__ float g_ic[NSTATE];
__device__ float g_im[NSTATE];
// ---- scratch ----
__device__ float g_gates[BB*CG*HW];
__device__ float g_gsum [2][64];
__device__ float g_gsum2[2][64];
__device__ float g_oh[NSTATE];
__device__ float g_roff[2][BB*HW];      // M*log2e + log2(L) per row
__device__ float g_Zcat[BB*128*HW];
__device__ unsigned g_wTh[8*9*256*8];   // conv weights half2: [chunk16ci*9+pos][co][jpair]
__device__ unsigned g_z2T[128*192];     // z2 weights transposed [c][o] tf32
// attention operands, half-packed
__device__ unsigned g_qT[8*1024*32];       // Q^T  [b][n][c-pairs]
__device__ unsigned g_kT[2][8*1024*32];    // K^T  [which][b][m][c-pairs]
__device__ unsigned g_vv[2][8*64*512];     // V    [which][b][c][n-pairs]

__device__ __forceinline__ float sigm(float x){ return 1.f/(1.f+__expf(-x)); }
__device__ __forceinline__ unsigned f2t(float x){
  unsigned r; asm("cvt.rna.tf32.f32 %0,%1;" : "=r"(r) : "f"(x)); return r;
}
__device__ __forceinline__ void mma8(float* d, const unsigned* a, unsigned b0, unsigned b1){
  asm volatile("mma.sync.aligned.m16n8k8.row.col.f32.tf32.tf32.f32 "
    "{%0,%1,%2,%3},{%4,%5,%6,%7},{%8,%9},{%0,%1,%2,%3};"
    : "+f"(d[0]),"+f"(d[1]),"+f"(d[2]),"+f"(d[3])
    : "r"(a[0]),"r"(a[1]),"r"(a[2]),"r"(a[3]),"r"(b0),"r"(b1));
}
__device__ __forceinline__ void mma16(float* d, const unsigned* a, unsigned b0, unsigned b1){
  asm volatile("mma.sync.aligned.m16n8k16.row.col.f32.f16.f16.f32 "
    "{%0,%1,%2,%3},{%4,%5,%6,%7},{%8,%9},{%0,%1,%2,%3};"
    : "+f"(d[0]),"+f"(d[1]),"+f"(d[2]),"+f"(d[3])
    : "r"(a[0]),"r"(a[1]),"r"(a[2]),"r"(a[3]),"r"(b0),"r"(b1));
}
__device__ __forceinline__ unsigned pack2h(float x, float y){
  __half2 h = __floats2half2_rn(x, y);
  return *(unsigned*)&h;
}
// exp2 of a float pair via one MUFU (ex2.approx.f16x2); returns packed half2 word
__device__ __forceinline__ unsigned exp2_pair_h(float x0, float x1){
  __half2 h = h2exp2(__floats2half2_rn(x0, x1));
  return *(unsigned*)&h;
}
__device__ __forceinline__ float2 exp2_pair_f(float x0, float x1){
  __half2 h = h2exp2(__floats2half2_rn(x0, x1));
  return __half22float2(h);
}

// --- swizzled 64x64 half tile: word index for (row, half-pair j) ---
__device__ __forceinline__ int tw(int row, int j){ return row*32 + (j ^ ((row&7)<<2)); }

// coalesced tile stage from pre-packed half buffers (512 words = 64 rows x 32)
__device__ __forceinline__ void loadTile(unsigned* dst, const unsigned* __restrict__ src,
                                         int rowstride){
  int tid = threadIdx.x;
  #pragma unroll
  for (int it=0; it<2; it++){
    int idx = it*256 + tid;
    int row = idx>>3, j4 = (idx&7)*4;
    uint4 v = *(const uint4*)(src + (size_t)row*rowstride + j4);
    *(uint4*)&dst[tw(row, j4)] = v;
  }
}

// ---- ldmatrix fragment loads (b16, no trans; layout [row][k-pairs] swizzled) ----
__device__ __forceinline__ unsigned saddr(const unsigned* p){
  return (unsigned)__cvta_generic_to_shared((const void*)p);
}
__device__ __forceinline__ void ldsmA(unsigned* a, const unsigned* t, int r, int kk){
  int lane = threadIdx.x & 31;
  int row = r + (lane&7) + (lane&8);
  int j   = kk*8 + ((lane>>4)<<2);
  unsigned ad = saddr(t + tw(row, j));
  asm volatile("ldmatrix.sync.aligned.m8n8.x4.shared.b16 {%0,%1,%2,%3}, [%4];"
    : "=r"(a[0]),"=r"(a[1]),"=r"(a[2]),"=r"(a[3]) : "r"(ad));
}
__device__ __forceinline__ void ldsmB2(unsigned* b, const unsigned* t, int nb, int kk){
  int lane = threadIdx.x & 31;
  int row = nb + (lane&7) + ((lane>>4)<<3);
  int j   = kk*8 + (((lane>>3)&1)<<2);
  unsigned ad = saddr(t + tw(row, j));
  asm volatile("ldmatrix.sync.aligned.m8n8.x4.shared.b16 {%0,%1,%2,%3}, [%4];"
    : "=r"(b[0]),"=r"(b[1]),"=r"(b[2]),"=r"(b[3]) : "r"(ad));
}

__global__ void zero_states(){
  int i = blockIdx.x*256 + threadIdx.x;
  if (i < NSTATE){ g_ih[i]=0.f; g_ic[i]=0.f; g_im[i]=0.f; }
  if (blockIdx.x==0 && threadIdx.x<64){
    g_gsum[0][threadIdx.x]=0.f; g_gsum2[0][threadIdx.x]=0.f;
    g_gsum[1][threadIdx.x]=0.f; g_gsum2[1][threadIdx.x]=0.f;
  }
}

__global__ void wtrans(const float* __restrict__ w, const float* __restrict__ z2w){
  int co = blockIdx.x;
  for (int idx = threadIdx.x; idx < 576; idx += 256){
    int chunk = idx/72, r = idx - chunk*72, pos = r>>3, j = r&7;
    int ci = chunk*16 + 2*j;
    float v0 = w[((size_t)co*128 + ci  )*9 + pos];
    float v1 = w[((size_t)co*128 + ci+1)*9 + pos];
    g_wTh[((size_t)(chunk*9+pos)*256 + co)*8 + j] = pack2h(v0, v1);
  }
  if (co < 192){
    for (int c = threadIdx.x; c < 128; c += 256)
      g_z2T[c*192 + co] = f2t(z2w[co*128 + c]);
  }
}

// ------------------- 3x3 conv (implicit GEMM, fp16 TC) + fused GN stats ----
__global__ __launch_bounds__(256) void conv_tc(const float* __restrict__ xin,
                                               const float* __restrict__ bias, int t)
{
  int pt = blockIdx.x, cot = blockIdx.y, b = blockIdx.z;
  int y0 = pt*4, co0 = cot*64, par = t & 1;
  __shared__ unsigned sIn[8*232];
  __shared__ unsigned sW[9*64*8];
  __shared__ float ws[8], ws2[8];
  int tid=threadIdx.x, warp=tid>>5, lane=tid&31, g=lane>>2, tq=lane&3;
  int wc = warp&3, wm = warp>>2;
  float acc[8][4];
  #pragma unroll
  for(int j=0;j<8;j++){acc[j][0]=0.f;acc[j][1]=0.f;acc[j][2]=0.f;acc[j][3]=0.f;}

  int pix = tid;
  int yy = pix/34, xx = pix - yy*34;
  int gy = y0-1+yy, gx = xx-1;
  bool pv = (pix<204) && ((unsigned)gy<32u) && ((unsigned)gx<32u);
  int gidx = gy*32 + gx;

  for (int chunk=0; chunk<8; chunk++){
    const float* src = (chunk<4) ? (xin + ((size_t)(b*TT+t)*64 + chunk*16)*HW)
                                 : (g_ih + ((size_t)b*64 + (chunk-4)*16)*HW);
    __syncthreads();
    if (pix < 204){
      #pragma unroll
      for (int j=0;j<8;j++){
        float f0=0.f, f1=0.f;
        if (pv){ f0 = src[(size_t)(2*j)*HW + gidx]; f1 = src[(size_t)(2*j+1)*HW + gidx]; }
        sIn[j*232 + pix] = pack2h(f0, f1);
      }
    }
    for (int idx=tid; idx<4608; idx+=256){
      int pos = idx>>9, r2 = idx&511;
      sW[idx] = g_wTh[(size_t)(chunk*9+pos)*2048 + co0*8 + r2];
    }
    __syncthreads();
    #pragma unroll
    for (int pos=0; pos<9; pos++){
      int ky = pos/3, kx = pos - 3*ky;
      unsigned a[4];
      int rb = (pos*64 + wc*16 + g)*8;
      a[0] = sW[rb + tq];       a[1] = sW[rb + 64 + tq];
      a[2] = sW[rb + tq + 4];   a[3] = sW[rb + 64 + tq + 4];
      #pragma unroll
      for (int mf=0; mf<8; mf++){
        int p = wm*64 + mf*8 + g;
        int pixb = ((p>>5)+ky)*34 + (p&31) + kx;
        mma16(acc[mf], a, sIn[tq*232 + pixb], sIn[(tq+4)*232 + pixb]);
      }
    }
  }
  int r0 = co0 + wc*16 + g, r1 = r0 + 8;
  float bv0 = bias[r0], bv1 = bias[r1];
  float s=0.f, s2=0.f;
  #pragma unroll
  for (int mf=0; mf<8; mf++){
    int col = y0*32 + wm*64 + mf*8 + 2*tq;
    float v0=acc[mf][0]+bv0, v1=acc[mf][1]+bv0;
    float v2=acc[mf][2]+bv1, v3=acc[mf][3]+bv1;
    *(float2*)&g_gates[((size_t)b*CG + r0)*HW + col] = make_float2(v0,v1);
    *(float2*)&g_gates[((size_t)b*CG + r1)*HW + col] = make_float2(v2,v3);
    s  += v0+v1+v2+v3;
    s2 += v0*v0+v1*v1+v2*v2+v3*v3;
  }
  #pragma unroll
  for (int off=16; off; off>>=1){
    s  += __shfl_xor_sync(0xffffffffu, s , off);
    s2 += __shfl_xor_sync(0xffffffffu, s2, off);
  }
  if (lane==0){ ws[warp]=s; ws2[warp]=s2; }
  __syncthreads();
  if (tid<2){
    float S  = ws [tid*2]+ws [tid*2+1]+ws [tid*2+4]+ws [tid*2+5];
    float S2 = ws2[tid*2]+ws2[tid*2+1]+ws2[tid*2+4]+ws2[tid*2+5];
    int gidx2 = b*8 + (co0>>5) + tid;
    atomicAdd(&g_gsum [par][gidx2], S );
    atomicAdd(&g_gsum2[par][gidx2], S2);
  }
}

// ------------------- GN apply + LSTM gating (float4) -------------------
__global__ void gn_lstm4(const float* __restrict__ gg, const float* __restrict__ gb, int t){
  int b = blockIdx.x >> 6, c = blockIdx.x & 63;
  int p = threadIdx.x*4;
  int par = t & 1;
  __shared__ float smu[4], srs[4];
  if (threadIdx.x < 4){
    int grp = (c >> 5) + threadIdx.x*2;
    float s  = g_gsum [par][b*8+grp];
    float s2 = g_gsum2[par][b*8+grp];
    float m   = s*(1.f/32768.f);
    float var = s2*(1.f/32768.f) - m*m;
    smu[threadIdx.x] = m;
    srs[threadIdx.x] = rsqrtf(var + 1e-5f);
  }
  if (blockIdx.x==0 && threadIdx.x<64){
    g_gsum[par^1][threadIdx.x]=0.f; g_gsum2[par^1][threadIdx.x]=0.f;
  }
  __syncthreads();
  const float* gt = g_gates + (size_t)b*CG*HW + p;
  float4 vi = *(const float4*)&gt[(size_t)(c      )*HW];
  float4 vf = *(const float4*)&gt[(size_t)(c + 64 )*HW];
  float4 vc = *(const float4*)&gt[(size_t)(c + 128)*HW];
  float4 vo = *(const float4*)&gt[(size_t)(c + 192)*HW];
  int idx = (b*64 + c)*1024 + p;
  float4 ic4 = *(const float4*)&g_ic[idx];
  float4 oc4, oh4;
  {
    float a,f2,cc,o;
    a=(vi.x-smu[0])*srs[0]*gg[c]+gb[c]; f2=(vf.x-smu[1])*srs[1]*gg[c+64]+gb[c+64];
    cc=(vc.x-smu[2])*srs[2]*gg[c+128]+gb[c+128]; o=(vo.x-smu[3])*srs[3]*gg[c+192]+gb[c+192];
    oc4.x = ic4.x*sigm(f2)+sigm(a)*tanhf(cc); oh4.x = sigm(o)*tanhf(oc4.x);
    a=(vi.y-smu[0])*srs[0]*gg[c]+gb[c]; f2=(vf.y-smu[1])*srs[1]*gg[c+64]+gb[c+64];
    cc=(vc.y-smu[2])*srs[2]*gg[c+128]+gb[c+128]; o=(vo.y-smu[3])*srs[3]*gg[c+192]+gb[c+192];
    oc4.y = ic4.y*sigm(f2)+sigm(a)*tanhf(cc); oh4.y = sigm(o)*tanhf(oc4.y);
    a=(vi.z-smu[0])*srs[0]*gg[c]+gb[c]; f2=(vf.z-smu[1])*srs[1]*gg[c+64]+gb[c+64];
    cc=(vc.z-smu[2])*srs[2]*gg[c+128]+gb[c+128]; o=(vo.z-smu[3])*srs[3]*gg[c+192]+gb[c+192];
    oc4.z = ic4.z*sigm(f2)+sigm(a)*tanhf(cc); oh4.z = sigm(o)*tanhf(oc4.z);
    a=(vi.w-smu[0])*srs[0]*gg[c]+gb[c]; f2=(vf.w-smu[1])*srs[1]*gg[c+64]+gb[c+64];
    cc=(vc.w-smu[2])*srs[2]*gg[c+128]+gb[c+128]; o=(vo.w-smu[3])*srs[3]*gg[c+192]+gb[c+192];
    oc4.w = ic4.w*sigm(f2)+sigm(a)*tanhf(cc); oh4.w = sigm(o)*tanhf(oc4.w);
  }
  *(float4*)&g_ic[idx] = oc4;
  *(float4*)&g_oh[idx] = oh4;
}

// ------------------- QKV projections (tf32 GEMM) -> half operand buffers -----
__global__ __launch_bounds__(256) void lin_hm(const float* __restrict__ h_w,
                                              const float* __restrict__ h_b,
                                              const float* __restrict__ m_w,
                                              const float* __restrict__ m_b)
{
  __shared__ unsigned uW[32*68];
  __shared__ unsigned uX[8*72];
  __shared__ __half sT[64*34];
  int b = blockIdx.x, p0 = blockIdx.z*64, yb = blockIdx.y;
  const float *x1, *w, *bias;
  int o0;
  if (yb < 6){ x1 = g_oh; w = h_w; bias = h_b; o0 = yb*32; }
  else       { x1 = g_im; w = m_w; bias = m_b; o0 = (yb-6)*32; }
  unsigned* dstT = 0; unsigned* dstV = 0; int crel = 0;
  if (yb < 6){
    if      (o0 <  64){ dstT = g_qT;    crel = o0;       }
    else if (o0 < 128){ dstT = g_kT[0]; crel = o0 - 64;  }
    else              { dstV = g_vv[0]; crel = o0 - 128; }
  } else {
    if (o0 < 64){ dstT = g_kT[1]; crel = o0; }
    else        { dstV = g_vv[1]; crel = o0 - 64; }
  }

  const int Cin = 64, pitch = 68;
  int tid=threadIdx.x, warp=tid>>5, lane=tid&31, g=lane>>2, tq=lane&3;
  int wc = warp&1, wm = warp>>1;
  for (int idx=tid; idx<32*Cin; idx+=256){
    int o = idx>>6, c = idx&63;
    uW[o*pitch + c] = f2t(w[(size_t)(o0+o)*Cin + c]);
  }
  float acc[2][4];
  acc[0][0]=acc[0][1]=acc[0][2]=acc[0][3]=0.f;
  acc[1][0]=acc[1][1]=acc[1][2]=acc[1][3]=0.f;
  for (int cc=0; cc<Cin; cc+=8){
    __syncthreads();
    {
      int ci = tid>>5, m2 = tid&31;
      float2 v = *(const float2*)&x1[((size_t)b*Cin + cc+ci)*HW + p0 + 2*m2];
      *(uint2*)&uX[ci*72 + 2*m2] = make_uint2(f2t(v.x), f2t(v.y));
    }
    __syncthreads();
    unsigned a[4];
    a[0]=uW[(wc*16+g  )*pitch + cc+tq];   a[1]=uW[(wc*16+8+g)*pitch + cc+tq];
    a[2]=uW[(wc*16+g  )*pitch + cc+tq+4]; a[3]=uW[(wc*16+8+g)*pitch + cc+tq+4];
    #pragma unroll
    for (int mf=0; mf<2; mf++){
      unsigned b0 = uX[ tq   *72 + wm*16 + mf*8 + g];
      unsigned b1 = uX[(tq+4)*72 + wm*16 + mf*8 + g];
      mma8(acc[mf], a, b0, b1);
    }
  }
  int cc0 = wc*16 + g;
  float bv0 = bias[o0+cc0], bv1 = bias[o0+cc0+8];
  if (dstV){
    #pragma unroll
    for (int mf=0; mf<2; mf++){
      int col = p0 + wm*16 + mf*8 + 2*tq;
      dstV[((size_t)(b*64 + crel + cc0  ))*512 + (col>>1)] = pack2h(acc[mf][0]+bv0, acc[mf][1]+bv0);
      dstV[((size_t)(b*64 + crel + cc0+8))*512 + (col>>1)] = pack2h(acc[mf][2]+bv1, acc[mf][3]+bv1);
    }
  } else {
    __syncthreads();
    #pragma unroll
    for (int mf=0; mf<2; mf++){
      int col = wm*16 + mf*8 + 2*tq;
      sT[(col  )*34 + cc0  ] = __float2half(acc[mf][0]+bv0);
      sT[(col+1)*34 + cc0  ] = __float2half(acc[mf][1]+bv0);
      sT[(col  )*34 + cc0+8] = __float2half(acc[mf][2]+bv1);
      sT[(col+1)*34 + cc0+8] = __float2half(acc[mf][3]+bv1);
    }
    __syncthreads();
    for (int idx=tid; idx<1024; idx+=256){
      int px = idx>>4, wj = idx&15;
      __half2 hv;
      hv.x = sT[px*34 + 2*wj];
      hv.y = sT[px*34 + 2*wj + 1];
      dstT[((size_t)(b*1024 + p0 + px))*32 + (crel>>1) + wj] = *(unsigned*)&hv;
    }
  }
}

// ------------------- pass 1 (fp16 TC + ldmatrix + f16x2 exp): row stats --------
__global__ __launch_bounds__(256) void qk_stats(){
  __shared__ unsigned uQ[2048];
  __shared__ unsigned uK[2][2048];
  __shared__ float sM[2][64], sL[2][64];
  int b = blockIdx.x, n0 = blockIdx.y*64, which = blockIdx.z;
  const unsigned* qsrc = g_qT + (size_t)(b*1024 + n0)*32;
  const unsigned* ksrc = g_kT[which] + (size_t)b*1024*32;
  int tid=threadIdx.x, warp=tid>>5, tq=(tid&31)&3;
  int g = (tid&31)>>2;
  int wn = warp&3, wm = warp>>2;
  loadTile(uQ, qsrc, 32);
  float M0=-1e30f, M1=-1e30f, L0=0.f, L1=0.f;
  for (int m0=0; m0<HW; m0+=128){
    __syncthreads();
    loadTile(uK[0], ksrc + (size_t)m0*32, 32);
    loadTile(uK[1], ksrc + (size_t)(m0+64)*32, 32);
    __syncthreads();
    const unsigned* kt = uK[wm];
    float cfr[8][4];
    #pragma unroll
    for(int mf=0;mf<8;mf++){cfr[mf][0]=0.f;cfr[mf][1]=0.f;cfr[mf][2]=0.f;cfr[mf][3]=0.f;}
    #pragma unroll
    for (int kk=0; kk<4; kk++){
      unsigned a[4]; ldsmA(a, uQ, wn*16, kk);
      #pragma unroll
      for (int mp=0; mp<4; mp++){
        unsigned bb[4]; ldsmB2(bb, kt, mp*16, kk);
        mma16(cfr[2*mp  ], a, bb[0], bb[1]);
        mma16(cfr[2*mp+1], a, bb[2], bb[3]);
      }
    }
    float tm0=-1e30f, tm1=-1e30f;
    #pragma unroll
    for(int mf=0;mf<8;mf++){
      tm0 = fmaxf(tm0, fmaxf(cfr[mf][0], cfr[mf][1]));
      tm1 = fmaxf(tm1, fmaxf(cfr[mf][2], cfr[mf][3]));
    }
    tm0 = fmaxf(tm0, __shfl_xor_sync(0xffffffffu, tm0, 1));
    tm0 = fmaxf(tm0, __shfl_xor_sync(0xffffffffu, tm0, 2));
    tm1 = fmaxf(tm1, __shfl_xor_sync(0xffffffffu, tm1, 1));
    tm1 = fmaxf(tm1, __shfl_xor_sync(0xffffffffu, tm1, 2));
    float nM0 = fmaxf(M0, tm0), nM1 = fmaxf(M1, tm1);
    float c0 = nM0*LOG2E, c1 = nM1*LOG2E;
    float s0=0.f, s1=0.f;
    #pragma unroll
    for(int mf=0;mf<8;mf++){
      float2 e0 = exp2_pair_f(__fmaf_rn(cfr[mf][0], LOG2E, -c0),
                              __fmaf_rn(cfr[mf][1], LOG2E, -c0));
      float2 e1 = exp2_pair_f(__fmaf_rn(cfr[mf][2], LOG2E, -c1),
                              __fmaf_rn(cfr[mf][3], LOG2E, -c1));
      s0 += e0.x + e0.y;
      s1 += e1.x + e1.y;
    }
    s0 += __shfl_xor_sync(0xffffffffu, s0, 1);
    s0 += __shfl_xor_sync(0xffffffffu, s0, 2);
    s1 += __shfl_xor_sync(0xffffffffu, s1, 1);
    s1 += __shfl_xor_sync(0xffffffffu, s1, 2);
    L0 = L0*__expf(M0-nM0) + s0; M0 = nM0;
    L1 = L1*__expf(M1-nM1) + s1; M1 = nM1;
  }
  if (tq==0){
    sM[wm][wn*16+g  ] = M0; sL[wm][wn*16+g  ] = L0;
    sM[wm][wn*16+8+g] = M1; sL[wm][wn*16+8+g] = L1;
  }
  __syncthreads();
  if (tid<64){
    float Ma = sM[0][tid], Mb = sM[1][tid];
    float M  = fmaxf(Ma, Mb);
    float L  = sL[0][tid]*__expf(Ma-M) + sL[1][tid]*__expf(Mb-M);
    g_roff[which][b*HW + n0 + tid] = __fmaf_rn(M, LOG2E, __log2f(L));
  }
}

// ------------------- pass 2 (fp16 TC + ldmatrix + f16x2 exp): S^T -> P^T -> AV ----
__global__ __launch_bounds__(256) void av_tc(){
  __shared__ unsigned uK[2048];   // K^T [m][c]
  __shared__ unsigned uQ[2048];   // Q^T [n][c]
  __shared__ unsigned uV[2048];   // V   [c][n]
  __shared__ unsigned uP[2048];   // P^T [m][n]
  __shared__ float sro[64];
  int b = blockIdx.x, m0 = blockIdx.y*64, which = blockIdx.z;
  const unsigned* qsrc = g_qT + (size_t)b*1024*32;
  const unsigned* ksrc = g_kT[which] + (size_t)(b*1024 + m0)*32;
  const unsigned* vsrc = g_vv[which] + (size_t)b*64*512;
  const float* roff = g_roff[which] + b*HW;
  int zoff = which*64;
  int tid=threadIdx.x, warp=tid>>5, lane=tid&31, g=lane>>2, tq=lane&3;
  int wr = warp&3, wm = warp>>2;
  loadTile(uK, ksrc, 32);
  float accZ[4][4];
  #pragma unroll
  for(int mf=0;mf<4;mf++){accZ[mf][0]=0.f;accZ[mf][1]=0.f;accZ[mf][2]=0.f;accZ[mf][3]=0.f;}

  for (int nb=0; nb<HW; nb+=64){
    __syncthreads();
    loadTile(uQ, qsrc + (size_t)nb*32, 32);
    loadTile(uV, vsrc + (nb>>1), 512);
    if (tid < 64){ sro[tid] = roff[nb+tid]; }
    __syncthreads();
    // GEMM1: S^T[m][n] = K[m,:]·Q[n,:]
    float accS[4][4];
    #pragma unroll
    for(int mf=0;mf<4;mf++){accS[mf][0]=0.f;accS[mf][1]=0.f;accS[mf][2]=0.f;accS[mf][3]=0.f;}
    #pragma unroll
    for (int kk=0; kk<4; kk++){
      unsigned a[4]; ldsmA(a, uK, wr*16, kk);
      #pragma unroll
      for (int mp=0; mp<2; mp++){
        unsigned bb[4]; ldsmB2(bb, uQ, wm*32 + mp*16, kk);
        mma16(accS[2*mp  ], a, bb[0], bb[1]);
        mma16(accS[2*mp+1], a, bb[2], bb[3]);
      }
    }
    // P = exp2(S*log2e - roff) in f16x2 (one MUFU per pair; result is the packed word)
    #pragma unroll
    for (int mf=0; mf<4; mf++){
      int n = wm*32 + mf*8 + 2*tq;
      float ro0 = sro[n], ro1 = sro[n+1];
      int jn = n >> 1;
      int r0 = wr*16 + g;
      uP[tw(r0,   jn)] = exp2_pair_h(__fmaf_rn(accS[mf][0], LOG2E, -ro0),
                                     __fmaf_rn(accS[mf][1], LOG2E, -ro1));
      uP[tw(r0+8, jn)] = exp2_pair_h(__fmaf_rn(accS[mf][2], LOG2E, -ro0),
                                     __fmaf_rn(accS[mf][3], LOG2E, -ro1));
    }
    __syncthreads();
    // GEMM2: Z[c][m] += V[c][n] * P[n][m]
    #pragma unroll
    for (int kk=0; kk<4; kk++){
      unsigned a[4]; ldsmA(a, uV, wr*16, kk);
      #pragma unroll
      for (int mp=0; mp<2; mp++){
        unsigned bb[4]; ldsmB2(bb, uP, wm*32 + mp*16, kk);
        mma16(accZ[2*mp  ], a, bb[0], bb[1]);
        mma16(accZ[2*mp+1], a, bb[2], bb[3]);
      }
    }
  }
  #pragma unroll
  for (int mf=0; mf<4; mf++){
    int r0 = wr*16 + g, r1 = r0 + 8;
    int col = m0 + wm*32 + mf*8 + 2*tq;
    *(float2*)&g_Zcat[((size_t)b*128 + zoff + r0)*HW + col] = make_float2(accZ[mf][0], accZ[mf][1]);
    *(float2*)&g_Zcat[((size_t)b*128 + zoff + r1)*HW + col] = make_float2(accZ[mf][2], accZ[mf][3]);
  }
}

// ------------------- tail: z1 GEMM + z2 GEMM + gating, fused (tf32) -------
__global__ __launch_bounds__(256) void tail_k(const float* __restrict__ z1_w,
                                              const float* __restrict__ z1_b,
                                              const float* __restrict__ z2_b,
                                              float* __restrict__ out, int t, int ws)
{
  extern __shared__ unsigned sm[];
  unsigned* sZ  = sm;
  unsigned* sOh = sm + 2560;
  unsigned* wch = sm + 5120;
  unsigned* sX  = sm + 6720;
  unsigned* uz1 = sm + 7040;
  float*  gates = (float*)(sm + 7040);
  int b = blockIdx.x, p0 = blockIdx.y*32;
  int tid=threadIdx.x, warp=tid>>5, lane=tid&31, g=lane>>2, tq=lane&3;
  int wc = warp&1, wm = warp>>1;
  for (int idx=tid; idx<64*128; idx+=256){
    int o = idx>>7, c = idx&127;
    uz1[o*132+c] = f2t(z1_w[o*128+c]);
  }
  for (int idx=tid; idx<1024; idx+=256){
    int c = idx>>4, p2 = idx&15;
    float2 v = *(const float2*)&g_oh[((size_t)b*64+c)*HW + p0 + 2*p2];
    *(uint2*)&sOh[c*40 + 2*p2] = make_uint2(f2t(v.x), f2t(v.y));
  }
  float a1[2][4];
  #pragma unroll
  for(int ot=0;ot<2;ot++){a1[ot][0]=0.f;a1[ot][1]=0.f;a1[ot][2]=0.f;a1[ot][3]=0.f;}
  for (int cc=0; cc<128; cc+=8){
    __syncthreads();
    for (int idx=tid; idx<128; idx+=256){
      int c = idx>>4, p2 = idx&15;
      float2 v = *(const float2*)&g_Zcat[((size_t)b*128 + cc+c)*HW + p0 + 2*p2];
      *(uint2*)&sX[c*40 + 2*p2] = make_uint2(f2t(v.x), f2t(v.y));
    }
    __syncthreads();
    unsigned b0 = sX[ tq   *40 + wm*8 + g];
    unsigned b1 = sX[(tq+4)*40 + wm*8 + g];
    #pragma unroll
    for (int ot=0; ot<2; ot++){
      unsigned a[4];
      int r = ot*32 + wc*16 + g;
      a[0]=uz1[(r  )*132 + cc+tq];   a[1]=uz1[(r+8)*132 + cc+tq];
      a[2]=uz1[(r  )*132 + cc+tq+4]; a[3]=uz1[(r+8)*132 + cc+tq+4];
      mma8(a1[ot], a, b0, b1);
    }
  }
  __syncthreads();
  #pragma unroll
  for (int ot=0; ot<2; ot++){
    int r0 = ot*32 + wc*16 + g, r1 = r0 + 8;
    int col = wm*8 + 2*tq;
    float bv0 = z1_b[r0], bv1 = z1_b[r1];
    *(uint2*)&sZ[r0*40 + col] = make_uint2(f2t(a1[ot][0]+bv0), f2t(a1[ot][1]+bv0));
    *(uint2*)&sZ[r1*40 + col] = make_uint2(f2t(a1[ot][2]+bv1), f2t(a1[ot][3]+bv1));
  }
  float a2[6][4];
  #pragma unroll
  for(int ot=0;ot<6;ot++){a2[ot][0]=0.f;a2[ot][1]=0.f;a2[ot][2]=0.f;a2[ot][3]=0.f;}
  for (int cc=0; cc<128; cc+=8){
    __syncthreads();
    for (int idx=tid; idx<1536; idx+=256){
      int r = idx/192, o = idx - r*192;
      wch[r*200 + o] = g_z2T[(cc+r)*192 + o];
    }
    __syncthreads();
    const unsigned* src = (cc<64) ? (sZ + cc*40) : (sOh + (cc-64)*40);
    unsigned b0 = src[ tq   *40 + wm*8 + g];
    unsigned b1 = src[(tq+4)*40 + wm*8 + g];
    #pragma unroll
    for (int ot=0; ot<6; ot++){
      unsigned a[4];
      int o = ot*32 + wc*16 + g;
      a[0]=wch[ tq   *200 + o];   a[1]=wch[ tq   *200 + o+8];
      a[2]=wch[(tq+4)*200 + o];   a[3]=wch[(tq+4)*200 + o+8];
      mma8(a2[ot], a, b0, b1);
    }
  }
  __syncthreads();
  #pragma unroll
  for (int ot=0; ot<6; ot++){
    int r0 = ot*32 + wc*16 + g, r1 = r0 + 8;
    int col = wm*8 + 2*tq;
    float bv0 = z2_b[r0], bv1 = z2_b[r1];
    *(float2*)&gates[r0*34 + col] = make_float2(a2[ot][0]+bv0, a2[ot][1]+bv0);
    *(float2*)&gates[r1*34 + col] = make_float2(a2[ot][2]+bv1, a2[ot][3]+bv1);
  }
  __syncthreads();
  for (int i=tid; i<2048; i+=256){
    int c = i>>5, p = i&31;
    float vo = gates[(c     )*34 + p];
    float vg = gates[(64 +c )*34 + p];
    float vi = gates[(128+c )*34 + p];
    int idx = (b*64 + c)*1024 + p0 + p;
    float si = sigm(vi);
    float om  = tanhf(vg)*si + (1.f-si)*g_im[idx];
    float oh2 = sigm(vo)*om;
    g_im[idx] = om;
    g_ih[idx] = oh2;
    out[(((size_t)b*TT + t)*64 + c)*HW + p0 + p] = oh2;
    if (ws){
      float* st = out + (size_t)BB*TT*64*HW;
      st[idx]            = oh2;
      st[NSTATE + idx]   = g_ic[idx];
      st[2*NSTATE + idx] = om;
    }
  }
}

extern "C" void kernel_launch(void* const* d_in, const int* in_sizes, int n_in,
                              void* d_out, int out_size)
{
  const float* inputs = (const float*)d_in[0];
  const float* conv_w = (const float*)d_in[1];
  const float* conv_b = (const float*)d_in[2];
  const float* gn_g   = (const float*)d_in[3];
  const float* gn_b   = (const float*)d_in[4];
  const float* h_w    = (const float*)d_in[5];
  const float* h_b    = (const float*)d_in[6];
  const float* m_w    = (const float*)d_in[7];
  const float* m_b    = (const float*)d_in[8];
  const float* z1_w   = (const float*)d_in[9];
  const float* z1_b   = (const float*)d_in[10];
  const float* z2_w   = (const float*)d_in[11];
  const float* z2_b   = (const float*)d_in[12];
  float* out = (float*)d_out;

  const int TL_SMEM = 15488*4;   // 61952
  cudaFuncSetAttribute(tail_k, cudaFuncAttributeMaxDynamicSharedMemorySize, TL_SMEM);

  zero_states<<<2048,256>>>();
  wtrans<<<256,256>>>(conv_w, z2_w);
  int write_states = (out_size >= (int)(BB*TT*64*HW + 3*NSTATE)) ? 1 : 0;

  for (int t=0; t<TT; t++){
    conv_tc<<<dim3(8,4,8),256>>>(inputs, conv_b, t);
    gn_lstm4<<<512,256>>>(gn_g, gn_b, t);
    lin_hm<<<dim3(8,10,16),256>>>(h_w, h_b, m_w, m_b);
    qk_stats<<<dim3(8,16,2),256>>>();
    av_tc  <<<dim3(8,16,2),256>>>();
    tail_k<<<dim3(8,32),256,TL_SMEM>>>(z1_w, z1_b, z2_b, out, t, (t==TT-1) ? write_states : 0);
  }
}

// round 10
// speedup vs baseline: 2.8576x; 1.0897x over previous
#include <cuda_runtime.h>
#include <cuda_fp16.h>
#include <math.h>

#define BB 8
#define TT 8
#define HW 1024
#define CG 256
#define NSTATE (BB*64*HW)   // 524288
#define LOG2E 1.4426950408889634f

// ---- persistent state ----
__device__ float g_ih[NSTATE];
__device__ float g_ic[NSTATE];
__device__ float g_im[NSTATE];
// ---- scratch ----
__device__ float g_gates[BB*CG*HW];
__device__ float g_gsum [2][64];
__device__ float g_gsum2[2][64];
__device__ float g_oh[NSTATE];
__device__ float g_roff[2][BB*HW];      // M*log2e + log2(L) per row
__device__ unsigned g_wTh[8*9*256*8];   // conv weights half2
__device__ unsigned g_z2T[128*192];     // z2 weights transposed [c][o] tf32
// attention operands, half-packed
__device__ unsigned g_qT[8*1024*32];       // Q^T  [b][n][c-pairs]
__device__ unsigned g_kT[2][8*1024*32];    // K^T  [which][b][m][c-pairs]
__device__ unsigned g_vv[2][8*64*512];     // V    [which][b][c][n-pairs]

__device__ __forceinline__ float sigm(float x){ return 1.f/(1.f+__expf(-x)); }
__device__ __forceinline__ unsigned f2t(float x){
  unsigned r; asm("cvt.rna.tf32.f32 %0,%1;" : "=r"(r) : "f"(x)); return r;
}
__device__ __forceinline__ void mma8(float* d, const unsigned* a, unsigned b0, unsigned b1){
  asm volatile("mma.sync.aligned.m16n8k8.row.col.f32.tf32.tf32.f32 "
    "{%0,%1,%2,%3},{%4,%5,%6,%7},{%8,%9},{%0,%1,%2,%3};"
    : "+f"(d[0]),"+f"(d[1]),"+f"(d[2]),"+f"(d[3])
    : "r"(a[0]),"r"(a[1]),"r"(a[2]),"r"(a[3]),"r"(b0),"r"(b1));
}
__device__ __forceinline__ void mma16(float* d, const unsigned* a, unsigned b0, unsigned b1){
  asm volatile("mma.sync.aligned.m16n8k16.row.col.f32.f16.f16.f32 "
    "{%0,%1,%2,%3},{%4,%5,%6,%7},{%8,%9},{%0,%1,%2,%3};"
    : "+f"(d[0]),"+f"(d[1]),"+f"(d[2]),"+f"(d[3])
    : "r"(a[0]),"r"(a[1]),"r"(a[2]),"r"(a[3]),"r"(b0),"r"(b1));
}
__device__ __forceinline__ unsigned pack2h(float x, float y){
  __half2 h = __floats2half2_rn(x, y);
  return *(unsigned*)&h;
}
__device__ __forceinline__ unsigned exp2_pair_h(float x0, float x1){
  __half2 h = h2exp2(__floats2half2_rn(x0, x1));
  return *(unsigned*)&h;
}
__device__ __forceinline__ float2 exp2_pair_f(float x0, float x1){
  __half2 h = h2exp2(__floats2half2_rn(x0, x1));
  return __half22float2(h);
}

// --- swizzled 64x64 half tile ---
__device__ __forceinline__ int tw(int row, int j){ return row*32 + (j ^ ((row&7)<<2)); }

__device__ __forceinline__ void loadTile(unsigned* dst, const unsigned* __restrict__ src,
                                         int rowstride, int ltid){
  #pragma unroll
  for (int it=0; it<2; it++){
    int idx = it*256 + ltid;
    int row = idx>>3, j4 = (idx&7)*4;
    uint4 v = *(const uint4*)(src + (size_t)row*rowstride + j4);
    *(uint4*)&dst[tw(row, j4)] = v;
  }
}
__device__ __forceinline__ unsigned saddr(const unsigned* p){
  return (unsigned)__cvta_generic_to_shared((const void*)p);
}
__device__ __forceinline__ void ldsmA(unsigned* a, const unsigned* t, int r, int kk){
  int lane = threadIdx.x & 31;
  int row = r + (lane&7) + (lane&8);
  int j   = kk*8 + ((lane>>4)<<2);
  unsigned ad = saddr(t + tw(row, j));
  asm volatile("ldmatrix.sync.aligned.m8n8.x4.shared.b16 {%0,%1,%2,%3}, [%4];"
    : "=r"(a[0]),"=r"(a[1]),"=r"(a[2]),"=r"(a[3]) : "r"(ad));
}
__device__ __forceinline__ void ldsmB2(unsigned* b, const unsigned* t, int nb, int kk){
  int lane = threadIdx.x & 31;
  int row = nb + (lane&7) + ((lane>>4)<<3);
  int j   = kk*8 + (((lane>>3)&1)<<2);
  unsigned ad = saddr(t + tw(row, j));
  asm volatile("ldmatrix.sync.aligned.m8n8.x4.shared.b16 {%0,%1,%2,%3}, [%4];"
    : "=r"(b[0]),"=r"(b[1]),"=r"(b[2]),"=r"(b[3]) : "r"(ad));
}

__global__ void zero_states(){
  int i = blockIdx.x*256 + threadIdx.x;
  if (i < NSTATE){ g_ih[i]=0.f; g_ic[i]=0.f; g_im[i]=0.f; }
  if (blockIdx.x==0 && threadIdx.x<64){
    g_gsum[0][threadIdx.x]=0.f; g_gsum2[0][threadIdx.x]=0.f;
    g_gsum[1][threadIdx.x]=0.f; g_gsum2[1][threadIdx.x]=0.f;
  }
}

__global__ void wtrans(const float* __restrict__ w, const float* __restrict__ z2w){
  int co = blockIdx.x;
  for (int idx = threadIdx.x; idx < 576; idx += 256){
    int chunk = idx/72, r = idx - chunk*72, pos = r>>3, j = r&7;
    int ci = chunk*16 + 2*j;
    float v0 = w[((size_t)co*128 + ci  )*9 + pos];
    float v1 = w[((size_t)co*128 + ci+1)*9 + pos];
    g_wTh[((size_t)(chunk*9+pos)*256 + co)*8 + j] = pack2h(v0, v1);
  }
  if (co < 192){
    for (int c = threadIdx.x; c < 128; c += 256)
      g_z2T[c*192 + co] = f2t(z2w[co*128 + c]);
  }
}

// ------------------- 3x3 conv (implicit GEMM, fp16 TC) + fused GN stats ----
__global__ __launch_bounds__(256) void conv_tc(const float* __restrict__ xin,
                                               const float* __restrict__ bias, int t)
{
  int pt = blockIdx.x, cot = blockIdx.y, b = blockIdx.z;
  int y0 = pt*4, co0 = cot*64, par = t & 1;
  __shared__ unsigned sIn[8*232];
  __shared__ unsigned sW[9*64*8];
  __shared__ float ws[8], ws2[8];
  int tid=threadIdx.x, warp=tid>>5, lane=tid&31, g=lane>>2, tq=lane&3;
  int wc = warp&3, wm = warp>>2;
  float acc[8][4];
  #pragma unroll
  for(int j=0;j<8;j++){acc[j][0]=0.f;acc[j][1]=0.f;acc[j][2]=0.f;acc[j][3]=0.f;}

  int pix = tid;
  int yy = pix/34, xx = pix - yy*34;
  int gy = y0-1+yy, gx = xx-1;
  bool pv = (pix<204) && ((unsigned)gy<32u) && ((unsigned)gx<32u);
  int gidx = gy*32 + gx;

  for (int chunk=0; chunk<8; chunk++){
    const float* src = (chunk<4) ? (xin + ((size_t)(b*TT+t)*64 + chunk*16)*HW)
                                 : (g_ih + ((size_t)b*64 + (chunk-4)*16)*HW);
    __syncthreads();
    if (pix < 204){
      #pragma unroll
      for (int j=0;j<8;j++){
        float f0=0.f, f1=0.f;
        if (pv){ f0 = src[(size_t)(2*j)*HW + gidx]; f1 = src[(size_t)(2*j+1)*HW + gidx]; }
        sIn[j*232 + pix] = pack2h(f0, f1);
      }
    }
    for (int idx=tid; idx<4608; idx+=256){
      int pos = idx>>9, r2 = idx&511;
      sW[idx] = g_wTh[(size_t)(chunk*9+pos)*2048 + co0*8 + r2];
    }
    __syncthreads();
    #pragma unroll
    for (int pos=0; pos<9; pos++){
      int ky = pos/3, kx = pos - 3*ky;
      unsigned a[4];
      int rb = (pos*64 + wc*16 + g)*8;
      a[0] = sW[rb + tq];       a[1] = sW[rb + 64 + tq];
      a[2] = sW[rb + tq + 4];   a[3] = sW[rb + 64 + tq + 4];
      #pragma unroll
      for (int mf=0; mf<8; mf++){
        int p = wm*64 + mf*8 + g;
        int pixb = ((p>>5)+ky)*34 + (p&31) + kx;
        mma16(acc[mf], a, sIn[tq*232 + pixb], sIn[(tq+4)*232 + pixb]);
      }
    }
  }
  int r0 = co0 + wc*16 + g, r1 = r0 + 8;
  float bv0 = bias[r0], bv1 = bias[r1];
  float s=0.f, s2=0.f;
  #pragma unroll
  for (int mf=0; mf<8; mf++){
    int col = y0*32 + wm*64 + mf*8 + 2*tq;
    float v0=acc[mf][0]+bv0, v1=acc[mf][1]+bv0;
    float v2=acc[mf][2]+bv1, v3=acc[mf][3]+bv1;
    *(float2*)&g_gates[((size_t)b*CG + r0)*HW + col] = make_float2(v0,v1);
    *(float2*)&g_gates[((size_t)b*CG + r1)*HW + col] = make_float2(v2,v3);
    s  += v0+v1+v2+v3;
    s2 += v0*v0+v1*v1+v2*v2+v3*v3;
  }
  #pragma unroll
  for (int off=16; off; off>>=1){
    s  += __shfl_xor_sync(0xffffffffu, s , off);
    s2 += __shfl_xor_sync(0xffffffffu, s2, off);
  }
  if (lane==0){ ws[warp]=s; ws2[warp]=s2; }
  __syncthreads();
  if (tid<2){
    float S  = ws [tid*2]+ws [tid*2+1]+ws [tid*2+4]+ws [tid*2+5];
    float S2 = ws2[tid*2]+ws2[tid*2+1]+ws2[tid*2+4]+ws2[tid*2+5];
    int gidx2 = b*8 + (co0>>5) + tid;
    atomicAdd(&g_gsum [par][gidx2], S );
    atomicAdd(&g_gsum2[par][gidx2], S2);
  }
}

// ------------------- GN apply + LSTM gating (float4) -------------------
__global__ void gn_lstm4(const float* __restrict__ gg, const float* __restrict__ gb, int t){
  int b = blockIdx.x >> 6, c = blockIdx.x & 63;
  int p = threadIdx.x*4;
  int par = t & 1;
  __shared__ float smu[4], srs[4];
  if (threadIdx.x < 4){
    int grp = (c >> 5) + threadIdx.x*2;
    float s  = g_gsum [par][b*8+grp];
    float s2 = g_gsum2[par][b*8+grp];
    float m   = s*(1.f/32768.f);
    float var = s2*(1.f/32768.f) - m*m;
    smu[threadIdx.x] = m;
    srs[threadIdx.x] = rsqrtf(var + 1e-5f);
  }
  if (blockIdx.x==0 && threadIdx.x<64){
    g_gsum[par^1][threadIdx.x]=0.f; g_gsum2[par^1][threadIdx.x]=0.f;
  }
  __syncthreads();
  const float* gt = g_gates + (size_t)b*CG*HW + p;
  float4 vi = *(const float4*)&gt[(size_t)(c      )*HW];
  float4 vf = *(const float4*)&gt[(size_t)(c + 64 )*HW];
  float4 vc = *(const float4*)&gt[(size_t)(c + 128)*HW];
  float4 vo = *(const float4*)&gt[(size_t)(c + 192)*HW];
  int idx = (b*64 + c)*1024 + p;
  float4 ic4 = *(const float4*)&g_ic[idx];
  float4 oc4, oh4;
  {
    float a,f2,cc,o;
    a=(vi.x-smu[0])*srs[0]*gg[c]+gb[c]; f2=(vf.x-smu[1])*srs[1]*gg[c+64]+gb[c+64];
    cc=(vc.x-smu[2])*srs[2]*gg[c+128]+gb[c+128]; o=(vo.x-smu[3])*srs[3]*gg[c+192]+gb[c+192];
    oc4.x = ic4.x*sigm(f2)+sigm(a)*tanhf(cc); oh4.x = sigm(o)*tanhf(oc4.x);
    a=(vi.y-smu[0])*srs[0]*gg[c]+gb[c]; f2=(vf.y-smu[1])*srs[1]*gg[c+64]+gb[c+64];
    cc=(vc.y-smu[2])*srs[2]*gg[c+128]+gb[c+128]; o=(vo.y-smu[3])*srs[3]*gg[c+192]+gb[c+192];
    oc4.y = ic4.y*sigm(f2)+sigm(a)*tanhf(cc); oh4.y = sigm(o)*tanhf(oc4.y);
    a=(vi.z-smu[0])*srs[0]*gg[c]+gb[c]; f2=(vf.z-smu[1])*srs[1]*gg[c+64]+gb[c+64];
    cc=(vc.z-smu[2])*srs[2]*gg[c+128]+gb[c+128]; o=(vo.z-smu[3])*srs[3]*gg[c+192]+gb[c+192];
    oc4.z = ic4.z*sigm(f2)+sigm(a)*tanhf(cc); oh4.z = sigm(o)*tanhf(oc4.z);
    a=(vi.w-smu[0])*srs[0]*gg[c]+gb[c]; f2=(vf.w-smu[1])*srs[1]*gg[c+64]+gb[c+64];
    cc=(vc.w-smu[2])*srs[2]*gg[c+128]+gb[c+128]; o=(vo.w-smu[3])*srs[3]*gg[c+192]+gb[c+192];
    oc4.w = ic4.w*sigm(f2)+sigm(a)*tanhf(cc); oh4.w = sigm(o)*tanhf(oc4.w);
  }
  *(float4*)&g_ic[idx] = oc4;
  *(float4*)&g_oh[idx] = oh4;
}

// ------------------- QKV projections (tf32 GEMM) -> half operand buffers -----
__global__ __launch_bounds__(256) void lin_hm(const float* __restrict__ h_w,
                                              const float* __restrict__ h_b,
                                              const float* __restrict__ m_w,
                                              const float* __restrict__ m_b)
{
  __shared__ unsigned uW[32*68];
  __shared__ unsigned uX[8*72];
  __shared__ __half sT[64*34];
  int b = blockIdx.x, p0 = blockIdx.z*64, yb = blockIdx.y;
  const float *x1, *w, *bias;
  int o0;
  if (yb < 6){ x1 = g_oh; w = h_w; bias = h_b; o0 = yb*32; }
  else       { x1 = g_im; w = m_w; bias = m_b; o0 = (yb-6)*32; }
  unsigned* dstT = 0; unsigned* dstV = 0; int crel = 0;
  if (yb < 6){
    if      (o0 <  64){ dstT = g_qT;    crel = o0;       }
    else if (o0 < 128){ dstT = g_kT[0]; crel = o0 - 64;  }
    else              { dstV = g_vv[0]; crel = o0 - 128; }
  } else {
    if (o0 < 64){ dstT = g_kT[1]; crel = o0; }
    else        { dstV = g_vv[1]; crel = o0 - 64; }
  }

  const int Cin = 64, pitch = 68;
  int tid=threadIdx.x, warp=tid>>5, lane=tid&31, g=lane>>2, tq=lane&3;
  int wc = warp&1, wm = warp>>1;
  for (int idx=tid; idx<32*Cin; idx+=256){
    int o = idx>>6, c = idx&63;
    uW[o*pitch + c] = f2t(w[(size_t)(o0+o)*Cin + c]);
  }
  float acc[2][4];
  acc[0][0]=acc[0][1]=acc[0][2]=acc[0][3]=0.f;
  acc[1][0]=acc[1][1]=acc[1][2]=acc[1][3]=0.f;
  for (int cc=0; cc<Cin; cc+=8){
    __syncthreads();
    {
      int ci = tid>>5, m2 = tid&31;
      float2 v = *(const float2*)&x1[((size_t)b*Cin + cc+ci)*HW + p0 + 2*m2];
      *(uint2*)&uX[ci*72 + 2*m2] = make_uint2(f2t(v.x), f2t(v.y));
    }
    __syncthreads();
    unsigned a[4];
    a[0]=uW[(wc*16+g  )*pitch + cc+tq];   a[1]=uW[(wc*16+8+g)*pitch + cc+tq];
    a[2]=uW[(wc*16+g  )*pitch + cc+tq+4]; a[3]=uW[(wc*16+8+g)*pitch + cc+tq+4];
    #pragma unroll
    for (int mf=0; mf<2; mf++){
      unsigned b0 = uX[ tq   *72 + wm*16 + mf*8 + g];
      unsigned b1 = uX[(tq+4)*72 + wm*16 + mf*8 + g];
      mma8(acc[mf], a, b0, b1);
    }
  }
  int cc0 = wc*16 + g;
  float bv0 = bias[o0+cc0], bv1 = bias[o0+cc0+8];
  if (dstV){
    #pragma unroll
    for (int mf=0; mf<2; mf++){
      int col = p0 + wm*16 + mf*8 + 2*tq;
      dstV[((size_t)(b*64 + crel + cc0  ))*512 + (col>>1)] = pack2h(acc[mf][0]+bv0, acc[mf][1]+bv0);
      dstV[((size_t)(b*64 + crel + cc0+8))*512 + (col>>1)] = pack2h(acc[mf][2]+bv1, acc[mf][3]+bv1);
    }
  } else {
    __syncthreads();
    #pragma unroll
    for (int mf=0; mf<2; mf++){
      int col = wm*16 + mf*8 + 2*tq;
      sT[(col  )*34 + cc0  ] = __float2half(acc[mf][0]+bv0);
      sT[(col+1)*34 + cc0  ] = __float2half(acc[mf][1]+bv0);
      sT[(col  )*34 + cc0+8] = __float2half(acc[mf][2]+bv1);
      sT[(col+1)*34 + cc0+8] = __float2half(acc[mf][3]+bv1);
    }
    __syncthreads();
    for (int idx=tid; idx<1024; idx+=256){
      int px = idx>>4, wj = idx&15;
      __half2 hv;
      hv.x = sT[px*34 + 2*wj];
      hv.y = sT[px*34 + 2*wj + 1];
      dstT[((size_t)(b*1024 + p0 + px))*32 + (crel>>1) + wj] = *(unsigned*)&hv;
    }
  }
}

// ------------------- pass 1 (fp16 TC + ldmatrix): row softmax stats ----------
__global__ __launch_bounds__(256) void qk_stats(){
  __shared__ unsigned uQ[2048];
  __shared__ unsigned uK[2][2048];
  __shared__ float sM[2][64], sL[2][64];
  int b = blockIdx.x, n0 = blockIdx.y*64, which = blockIdx.z;
  const unsigned* qsrc = g_qT + (size_t)(b*1024 + n0)*32;
  const unsigned* ksrc = g_kT[which] + (size_t)b*1024*32;
  int tid=threadIdx.x, warp=tid>>5, tq=(tid&31)&3;
  int g = (tid&31)>>2;
  int wn = warp&3, wm = warp>>2;
  loadTile(uQ, qsrc, 32, tid);
  float M0=-1e30f, M1=-1e30f, L0=0.f, L1=0.f;
  for (int m0=0; m0<HW; m0+=128){
    __syncthreads();
    loadTile(uK[0], ksrc + (size_t)m0*32, 32, tid);
    loadTile(uK[1], ksrc + (size_t)(m0+64)*32, 32, tid);
    __syncthreads();
    const unsigned* kt = uK[wm];
    float cfr[8][4];
    #pragma unroll
    for(int mf=0;mf<8;mf++){cfr[mf][0]=0.f;cfr[mf][1]=0.f;cfr[mf][2]=0.f;cfr[mf][3]=0.f;}
    #pragma unroll
    for (int kk=0; kk<4; kk++){
      unsigned a[4]; ldsmA(a, uQ, wn*16, kk);
      #pragma unroll
      for (int mp=0; mp<4; mp++){
        unsigned bb[4]; ldsmB2(bb, kt, mp*16, kk);
        mma16(cfr[2*mp  ], a, bb[0], bb[1]);
        mma16(cfr[2*mp+1], a, bb[2], bb[3]);
      }
    }
    float tm0=-1e30f, tm1=-1e30f;
    #pragma unroll
    for(int mf=0;mf<8;mf++){
      tm0 = fmaxf(tm0, fmaxf(cfr[mf][0], cfr[mf][1]));
      tm1 = fmaxf(tm1, fmaxf(cfr[mf][2], cfr[mf][3]));
    }
    tm0 = fmaxf(tm0, __shfl_xor_sync(0xffffffffu, tm0, 1));
    tm0 = fmaxf(tm0, __shfl_xor_sync(0xffffffffu, tm0, 2));
    tm1 = fmaxf(tm1, __shfl_xor_sync(0xffffffffu, tm1, 1));
    tm1 = fmaxf(tm1, __shfl_xor_sync(0xffffffffu, tm1, 2));
    float nM0 = fmaxf(M0, tm0), nM1 = fmaxf(M1, tm1);
    float c0 = nM0*LOG2E, c1 = nM1*LOG2E;
    float s0=0.f, s1=0.f;
    #pragma unroll
    for(int mf=0;mf<8;mf++){
      float2 e0 = exp2_pair_f(__fmaf_rn(cfr[mf][0], LOG2E, -c0),
                              __fmaf_rn(cfr[mf][1], LOG2E, -c0));
      float2 e1 = exp2_pair_f(__fmaf_rn(cfr[mf][2], LOG2E, -c1),
                              __fmaf_rn(cfr[mf][3], LOG2E, -c1));
      s0 += e0.x + e0.y;
      s1 += e1.x + e1.y;
    }
    s0 += __shfl_xor_sync(0xffffffffu, s0, 1);
    s0 += __shfl_xor_sync(0xffffffffu, s0, 2);
    s1 += __shfl_xor_sync(0xffffffffu, s1, 1);
    s1 += __shfl_xor_sync(0xffffffffu, s1, 2);
    L0 = L0*__expf(M0-nM0) + s0; M0 = nM0;
    L1 = L1*__expf(M1-nM1) + s1; M1 = nM1;
  }
  if (tq==0){
    sM[wm][wn*16+g  ] = M0; sL[wm][wn*16+g  ] = L0;
    sM[wm][wn*16+8+g] = M1; sL[wm][wn*16+8+g] = L1;
  }
  __syncthreads();
  if (tid<64){
    float Ma = sM[0][tid], Mb = sM[1][tid];
    float M  = fmaxf(Ma, Mb);
    float L  = sL[0][tid]*__expf(Ma-M) + sL[1][tid]*__expf(Mb-M);
    g_roff[which][b*HW + n0 + tid] = __fmaf_rn(M, LOG2E, __log2f(L));
  }
}

// ------------------- merged pass 2 + tail --------------------------------------
// grid (8 b, 16 mtiles of 64px), block 512.
// Warps 0-7: attention which=0; warps 8-15: which=1. Then z1+z2+gating in-block.
// smem arena (unsigned words):
//   AV phase:   which w at [w*8256): uK 2048 | uQ 2048 | uV 2048 | uP 2048 | sro 64
//   tail phase: sZc [0..9216) [128][72] tf32 ; uz1 [9216..17664) [64][132] ;
//               sOh [17664..22272) [64][72] ; sZ [22272..26880) [64][72] ;
//               wch [26880..28480) [8][200] ; gates fp32 [0..12672) (overlays sZc+uz1 head)
__global__ __launch_bounds__(512,1) void av_tail(const float* __restrict__ z1_w,
                                                 const float* __restrict__ z1_b,
                                                 const float* __restrict__ z2_b,
                                                 float* __restrict__ out, int t, int ws)
{
  extern __shared__ unsigned arena[];
  int b = blockIdx.x, m0 = blockIdx.y*64;
  int p0 = m0;
  int tid = threadIdx.x;
  int lane = tid & 31, g = lane>>2, tq = lane&3;

  // ================= AV phase =================
  {
    int which = tid >> 8;
    int ltid  = tid & 255;
    int warp8 = ltid >> 5;          // 0..7 within half
    int wr = warp8 & 3, wm = warp8 >> 2;
    unsigned* base = arena + which*8256;
    unsigned* uK = base;
    unsigned* uQ = base + 2048;
    unsigned* uV = base + 4096;
    unsigned* uP = base + 6144;
    float*   sro = (float*)(base + 8192);
    const unsigned* qsrc = g_qT + (size_t)b*1024*32;
    const unsigned* ksrc = g_kT[which] + (size_t)(b*1024 + m0)*32;
    const unsigned* vsrc = g_vv[which] + (size_t)b*64*512;
    const float*    roff = g_roff[which] + b*HW;

    loadTile(uK, ksrc, 32, ltid);
    float accZ[4][4];
    #pragma unroll
    for(int mf=0;mf<4;mf++){accZ[mf][0]=0.f;accZ[mf][1]=0.f;accZ[mf][2]=0.f;accZ[mf][3]=0.f;}

    for (int nb=0; nb<HW; nb+=64){
      __syncthreads();
      loadTile(uQ, qsrc + (size_t)nb*32, 32, ltid);
      loadTile(uV, vsrc + (nb>>1), 512, ltid);
      if (ltid < 64){ sro[ltid] = roff[nb+ltid]; }
      __syncthreads();
      float accS[4][4];
      #pragma unroll
      for(int mf=0;mf<4;mf++){accS[mf][0]=0.f;accS[mf][1]=0.f;accS[mf][2]=0.f;accS[mf][3]=0.f;}
      #pragma unroll
      for (int kk=0; kk<4; kk++){
        unsigned a[4]; ldsmA(a, uK, wr*16, kk);
        #pragma unroll
        for (int mp=0; mp<2; mp++){
          unsigned bb[4]; ldsmB2(bb, uQ, wm*32 + mp*16, kk);
          mma16(accS[2*mp  ], a, bb[0], bb[1]);
          mma16(accS[2*mp+1], a, bb[2], bb[3]);
        }
      }
      #pragma unroll
      for (int mf=0; mf<4; mf++){
        int n = wm*32 + mf*8 + 2*tq;
        float ro0 = sro[n], ro1 = sro[n+1];
        int jn = n >> 1;
        int r0 = wr*16 + g;
        uP[tw(r0,   jn)] = exp2_pair_h(__fmaf_rn(accS[mf][0], LOG2E, -ro0),
                                       __fmaf_rn(accS[mf][1], LOG2E, -ro1));
        uP[tw(r0+8, jn)] = exp2_pair_h(__fmaf_rn(accS[mf][2], LOG2E, -ro0),
                                       __fmaf_rn(accS[mf][3], LOG2E, -ro1));
      }
      __syncthreads();
      #pragma unroll
      for (int kk=0; kk<4; kk++){
        unsigned a[4]; ldsmA(a, uV, wr*16, kk);
        #pragma unroll
        for (int mp=0; mp<2; mp++){
          unsigned bb[4]; ldsmB2(bb, uP, wm*32 + mp*16, kk);
          mma16(accZ[2*mp  ], a, bb[0], bb[1]);
          mma16(accZ[2*mp+1], a, bb[2], bb[3]);
        }
      }
    }
    __syncthreads();   // AV arrays dead; safe to overlay with sZc/uz1
    // write Zcat tile to smem (tf32)
    unsigned* sZc = arena;
    int zoff = which*64;
    #pragma unroll
    for (int mf=0; mf<4; mf++){
      int r0 = zoff + wr*16 + g, r1 = r0 + 8;
      int col = wm*32 + mf*8 + 2*tq;
      *(uint2*)&sZc[r0*72 + col] = make_uint2(f2t(accZ[mf][0]), f2t(accZ[mf][1]));
      *(uint2*)&sZc[r1*72 + col] = make_uint2(f2t(accZ[mf][2]), f2t(accZ[mf][3]));
    }
  }
  // ================= tail phase =================
  unsigned* sZc = arena;                 // [128][72] tf32
  unsigned* uz1 = arena + 9216;          // [64][132]
  unsigned* sOh = arena + 17664;         // [64][72]
  unsigned* sZ  = arena + 22272;         // [64][72]
  unsigned* wch = arena + 26880;         // [8][200]
  float*  gates = (float*)arena;         // [192][66] (overlays sZc+uz1 head)

  // stage z1 weights + oh tile (concurrent with sZc writes; disjoint regions? uz1/sOh
  // regions overlap old AV arrays only, which are dead after the barrier above)
  for (int idx=tid; idx<8192; idx+=512){
    int o = idx>>7, c = idx&127;
    uz1[o*132+c] = f2t(z1_w[o*128+c]);
  }
  for (int idx=tid; idx<2048; idx+=512){
    int c = idx>>5, p2 = idx&31;
    float2 v = *(const float2*)&g_oh[((size_t)b*64+c)*HW + p0 + 2*p2];
    *(uint2*)&sOh[c*72 + 2*p2] = make_uint2(f2t(v.x), f2t(v.y));
  }
  __syncthreads();

  int warp16 = tid>>5;
  int wc = warp16 & 1, wm8 = warp16 >> 1;   // wc: co half, wm8: px octet (0..7)

  // ---- z1: Z[64][64px] = z1_w[64][128] x Zcat[128][64px] ----
  float a1[2][4];
  #pragma unroll
  for(int ot=0;ot<2;ot++){a1[ot][0]=0.f;a1[ot][1]=0.f;a1[ot][2]=0.f;a1[ot][3]=0.f;}
  for (int cc=0; cc<128; cc+=8){
    unsigned b0 = sZc[(cc+tq  )*72 + wm8*8 + g];
    unsigned b1 = sZc[(cc+tq+4)*72 + wm8*8 + g];
    #pragma unroll
    for (int ot=0; ot<2; ot++){
      unsigned a[4];
      int r = ot*32 + wc*16 + g;
      a[0]=uz1[(r  )*132 + cc+tq];   a[1]=uz1[(r+8)*132 + cc+tq];
      a[2]=uz1[(r  )*132 + cc+tq+4]; a[3]=uz1[(r+8)*132 + cc+tq+4];
      mma8(a1[ot], a, b0, b1);
    }
  }
  __syncthreads();
  #pragma unroll
  for (int ot=0; ot<2; ot++){
    int r0 = ot*32 + wc*16 + g, r1 = r0 + 8;
    int col = wm8*8 + 2*tq;
    float bv0 = z1_b[r0], bv1 = z1_b[r1];
    *(uint2*)&sZ[r0*72 + col] = make_uint2(f2t(a1[ot][0]+bv0), f2t(a1[ot][1]+bv0));
    *(uint2*)&sZ[r1*72 + col] = make_uint2(f2t(a1[ot][2]+bv1), f2t(a1[ot][3]+bv1));
  }
  // ---- z2: gates[192][64px] = z2_w x [Z; oh] ----
  float a2[6][4];
  #pragma unroll
  for(int ot=0;ot<6;ot++){a2[ot][0]=0.f;a2[ot][1]=0.f;a2[ot][2]=0.f;a2[ot][3]=0.f;}
  for (int cc=0; cc<128; cc+=8){
    __syncthreads();
    for (int idx=tid; idx<1536; idx+=512){
      int r = idx/192, o = idx - r*192;
      wch[r*200 + o] = g_z2T[(cc+r)*192 + o];
    }
    __syncthreads();
    const unsigned* src = (cc<64) ? (sZ + cc*72) : (sOh + (cc-64)*72);
    unsigned b0 = src[ tq   *72 + wm8*8 + g];
    unsigned b1 = src[(tq+4)*72 + wm8*8 + g];
    #pragma unroll
    for (int ot=0; ot<6; ot++){
      unsigned a[4];
      int o = ot*32 + wc*16 + g;
      a[0]=wch[ tq   *200 + o];   a[1]=wch[ tq   *200 + o+8];
      a[2]=wch[(tq+4)*200 + o];   a[3]=wch[(tq+4)*200 + o+8];
      mma8(a2[ot], a, b0, b1);
    }
  }
  __syncthreads();
  #pragma unroll
  for (int ot=0; ot<6; ot++){
    int r0 = ot*32 + wc*16 + g, r1 = r0 + 8;
    int col = wm8*8 + 2*tq;
    float bv0 = z2_b[r0], bv1 = z2_b[r1];
    *(float2*)&gates[r0*66 + col] = make_float2(a2[ot][0]+bv0, a2[ot][1]+bv0);
    *(float2*)&gates[r1*66 + col] = make_float2(a2[ot][2]+bv1, a2[ot][3]+bv1);
  }
  __syncthreads();
  // ---- gating epilogue ----
  for (int i=tid; i<4096; i+=512){
    int c = i>>6, p = i&63;
    float vo = gates[(c     )*66 + p];
    float vg = gates[(64 +c )*66 + p];
    float vi = gates[(128+c )*66 + p];
    int idx = (b*64 + c)*1024 + p0 + p;
    float si = sigm(vi);
    float om  = tanhf(vg)*si + (1.f-si)*g_im[idx];
    float oh2 = sigm(vo)*om;
    g_im[idx] = om;
    g_ih[idx] = oh2;
    out[(((size_t)b*TT + t)*64 + c)*HW + p0 + p] = oh2;
    if (ws){
      float* st = out + (size_t)BB*TT*64*HW;
      st[idx]            = oh2;
      st[NSTATE + idx]   = g_ic[idx];
      st[2*NSTATE + idx] = om;
    }
  }
}

extern "C" void kernel_launch(void* const* d_in, const int* in_sizes, int n_in,
                              void* d_out, int out_size)
{
  const float* inputs = (const float*)d_in[0];
  const float* conv_w = (const float*)d_in[1];
  const float* conv_b = (const float*)d_in[2];
  const float* gn_g   = (const float*)d_in[3];
  const float* gn_b   = (const float*)d_in[4];
  const float* h_w    = (const float*)d_in[5];
  const float* h_b    = (const float*)d_in[6];
  const float* m_w    = (const float*)d_in[7];
  const float* m_b    = (const float*)d_in[8];
  const float* z1_w   = (const float*)d_in[9];
  const float* z1_b   = (const float*)d_in[10];
  const float* z2_w   = (const float*)d_in[11];
  const float* z2_b   = (const float*)d_in[12];
  float* out = (float*)d_out;

  const int AT_SMEM = 28480*4;   // 113920
  cudaFuncSetAttribute(av_tail, cudaFuncAttributeMaxDynamicSharedMemorySize, AT_SMEM);

  zero_states<<<2048,256>>>();
  wtrans<<<256,256>>>(conv_w, z2_w);
  int write_states = (out_size >= (int)(BB*TT*64*HW + 3*NSTATE)) ? 1 : 0;

  for (int t=0; t<TT; t++){
    conv_tc<<<dim3(8,4,8),256>>>(inputs, conv_b, t);
    gn_lstm4<<<512,256>>>(gn_g, gn_b, t);
    lin_hm<<<dim3(8,10,16),256>>>(h_w, h_b, m_w, m_b);
    qk_stats<<<dim3(8,16,2),256>>>();
    av_tail<<<dim3(8,16),512,AT_SMEM>>>(z1_w, z1_b, z2_b, out, t, (t==TT-1) ? write_states : 0);
  }
}

// round 11
// speedup vs baseline: 3.0263x; 1.0590x over previous
#include <cuda_runtime.h>
#include <cuda_fp16.h>
#include <math.h>

#define BB 8
#define TT 8
#define HW 1024
#define CG 256
#define NSTATE (BB*64*HW)   // 524288
#define LOG2E 1.4426950408889634f

// ---- persistent state ----
__device__ float g_ih[NSTATE];
__device__ float g_ic[NSTATE];
__device__ float g_im[NSTATE];
// ---- scratch ----
__device__ float g_gates[BB*CG*HW];
__device__ float g_gsum [2][64];
__device__ float g_gsum2[2][64];
__device__ float g_oh[NSTATE];
__device__ float g_roff[2][BB*HW];      // M*log2e + log2(L) per row
__device__ unsigned g_wTh[8*9*256*8];   // conv weights half2
__device__ unsigned g_z2T[128*192];     // z2 weights transposed [c][o] tf32
__device__ unsigned g_hmw[10*1024];     // h_w/m_w half tiles, tw-swizzled per 32-o tile
// attention operands, half-packed
__device__ unsigned g_qT[8*1024*32];       // Q^T  [b][n][c-pairs]
__device__ unsigned g_kT[2][8*1024*32];    // K^T  [which][b][m][c-pairs]
__device__ unsigned g_vv[2][8*64*512];     // V    [which][b][c][n-pairs]

// fast sigmoid: MUFU exp + MUFU rcp (err ~1e-7)
__device__ __forceinline__ float sigm(float x){
  float e = __expf(-x);
  float r; asm("rcp.approx.f32 %0,%1;" : "=f"(r) : "f"(1.f+e));
  return r;
}
// fast tanh via sigmoid identity (abs err ~1e-7)
__device__ __forceinline__ float tfast(float x){
  return __fmaf_rn(2.f, sigm(2.f*x), -1.f);
}
__device__ __forceinline__ unsigned f2t(float x){
  unsigned r; asm("cvt.rna.tf32.f32 %0,%1;" : "=r"(r) : "f"(x)); return r;
}
__device__ __forceinline__ void mma8(float* d, const unsigned* a, unsigned b0, unsigned b1){
  asm volatile("mma.sync.aligned.m16n8k8.row.col.f32.tf32.tf32.f32 "
    "{%0,%1,%2,%3},{%4,%5,%6,%7},{%8,%9},{%0,%1,%2,%3};"
    : "+f"(d[0]),"+f"(d[1]),"+f"(d[2]),"+f"(d[3])
    : "r"(a[0]),"r"(a[1]),"r"(a[2]),"r"(a[3]),"r"(b0),"r"(b1));
}
__device__ __forceinline__ void mma16(float* d, const unsigned* a, unsigned b0, unsigned b1){
  asm volatile("mma.sync.aligned.m16n8k16.row.col.f32.f16.f16.f32 "
    "{%0,%1,%2,%3},{%4,%5,%6,%7},{%8,%9},{%0,%1,%2,%3};"
    : "+f"(d[0]),"+f"(d[1]),"+f"(d[2]),"+f"(d[3])
    : "r"(a[0]),"r"(a[1]),"r"(a[2]),"r"(a[3]),"r"(b0),"r"(b1));
}
__device__ __forceinline__ unsigned pack2h(float x, float y){
  __half2 h = __floats2half2_rn(x, y);
  return *(unsigned*)&h;
}
__device__ __forceinline__ unsigned exp2_pair_h(float x0, float x1){
  __half2 h = h2exp2(__floats2half2_rn(x0, x1));
  return *(unsigned*)&h;
}
__device__ __forceinline__ float2 exp2_pair_f(float x0, float x1){
  __half2 h = h2exp2(__floats2half2_rn(x0, x1));
  return __half22float2(h);
}

// --- swizzled 64x64 half tile ---
__device__ __forceinline__ int tw(int row, int j){ return row*32 + (j ^ ((row&7)<<2)); }

__device__ __forceinline__ void loadTile(unsigned* dst, const unsigned* __restrict__ src,
                                         int rowstride, int ltid){
  #pragma unroll
  for (int it=0; it<2; it++){
    int idx = it*256 + ltid;
    int row = idx>>3, j4 = (idx&7)*4;
    uint4 v = *(const uint4*)(src + (size_t)row*rowstride + j4);
    *(uint4*)&dst[tw(row, j4)] = v;
  }
}
__device__ __forceinline__ unsigned saddr(const unsigned* p){
  return (unsigned)__cvta_generic_to_shared((const void*)p);
}
__device__ __forceinline__ void ldsmA(unsigned* a, const unsigned* t, int r, int kk){
  int lane = threadIdx.x & 31;
  int row = r + (lane&7) + (lane&8);
  int j   = kk*8 + ((lane>>4)<<2);
  unsigned ad = saddr(t + tw(row, j));
  asm volatile("ldmatrix.sync.aligned.m8n8.x4.shared.b16 {%0,%1,%2,%3}, [%4];"
    : "=r"(a[0]),"=r"(a[1]),"=r"(a[2]),"=r"(a[3]) : "r"(ad));
}
__device__ __forceinline__ void ldsmB2(unsigned* b, const unsigned* t, int nb, int kk){
  int lane = threadIdx.x & 31;
  int row = nb + (lane&7) + ((lane>>4)<<3);
  int j   = kk*8 + (((lane>>3)&1)<<2);
  unsigned ad = saddr(t + tw(row, j));
  asm volatile("ldmatrix.sync.aligned.m8n8.x4.shared.b16 {%0,%1,%2,%3}, [%4];"
    : "=r"(b[0]),"=r"(b[1]),"=r"(b[2]),"=r"(b[3]) : "r"(ad));
}

__global__ void zero_states(){
  int i = blockIdx.x*256 + threadIdx.x;
  if (i < NSTATE){ g_ih[i]=0.f; g_ic[i]=0.f; g_im[i]=0.f; }
  if (blockIdx.x==0 && threadIdx.x<64){
    g_gsum[0][threadIdx.x]=0.f; g_gsum2[0][threadIdx.x]=0.f;
    g_gsum[1][threadIdx.x]=0.f; g_gsum2[1][threadIdx.x]=0.f;
  }
}

__global__ void wtrans(const float* __restrict__ w, const float* __restrict__ z2w,
                       const float* __restrict__ hw, const float* __restrict__ mw){
  int co = blockIdx.x;
  for (int idx = threadIdx.x; idx < 576; idx += 256){
    int chunk = idx/72, r = idx - chunk*72, pos = r>>3, j = r&7;
    int ci = chunk*16 + 2*j;
    float v0 = w[((size_t)co*128 + ci  )*9 + pos];
    float v1 = w[((size_t)co*128 + ci+1)*9 + pos];
    g_wTh[((size_t)(chunk*9+pos)*256 + co)*8 + j] = pack2h(v0, v1);
  }
  if (co < 192){
    for (int c = threadIdx.x; c < 128; c += 256)
      g_z2T[c*192 + co] = f2t(z2w[co*128 + c]);
    // h_w tiles 0..5
    if (threadIdx.x < 32){
      int j = threadIdx.x;
      int y = co>>5, row = co&31;
      g_hmw[y*1024 + tw(row, j)] = pack2h(hw[co*64 + 2*j], hw[co*64 + 2*j + 1]);
    }
  }
  if (co < 128 && threadIdx.x >= 32 && threadIdx.x < 64){
    int j = threadIdx.x - 32;
    int y = 6 + (co>>5), row = co&31;
    g_hmw[y*1024 + tw(row, j)] = pack2h(mw[co*64 + 2*j], mw[co*64 + 2*j + 1]);
  }
}

// ------------------- 3x3 conv (implicit GEMM, fp16 TC) + fused GN stats ----
__global__ __launch_bounds__(256) void conv_tc(const float* __restrict__ xin,
                                               const float* __restrict__ bias, int t)
{
  int pt = blockIdx.x, cot = blockIdx.y, b = blockIdx.z;
  int y0 = pt*4, co0 = cot*64, par = t & 1;
  __shared__ unsigned sIn[8*232];
  __shared__ unsigned sW[9*64*8];
  __shared__ float ws[8], ws2[8];
  int tid=threadIdx.x, warp=tid>>5, lane=tid&31, g=lane>>2, tq=lane&3;
  int wc = warp&3, wm = warp>>2;
  float acc[8][4];
  #pragma unroll
  for(int j=0;j<8;j++){acc[j][0]=0.f;acc[j][1]=0.f;acc[j][2]=0.f;acc[j][3]=0.f;}

  int pix = tid;
  int yy = pix/34, xx = pix - yy*34;
  int gy = y0-1+yy, gx = xx-1;
  bool pv = (pix<204) && ((unsigned)gy<32u) && ((unsigned)gx<32u);
  int gidx = gy*32 + gx;

  for (int chunk=0; chunk<8; chunk++){
    const float* src = (chunk<4) ? (xin + ((size_t)(b*TT+t)*64 + chunk*16)*HW)
                                 : (g_ih + ((size_t)b*64 + (chunk-4)*16)*HW);
    __syncthreads();
    if (pix < 204){
      #pragma unroll
      for (int j=0;j<8;j++){
        float f0=0.f, f1=0.f;
        if (pv){ f0 = src[(size_t)(2*j)*HW + gidx]; f1 = src[(size_t)(2*j+1)*HW + gidx]; }
        sIn[j*232 + pix] = pack2h(f0, f1);
      }
    }
    for (int idx=tid; idx<4608; idx+=256){
      int pos = idx>>9, r2 = idx&511;
      sW[idx] = g_wTh[(size_t)(chunk*9+pos)*2048 + co0*8 + r2];
    }
    __syncthreads();
    #pragma unroll
    for (int pos=0; pos<9; pos++){
      int ky = pos/3, kx = pos - 3*ky;
      unsigned a[4];
      int rb = (pos*64 + wc*16 + g)*8;
      a[0] = sW[rb + tq];       a[1] = sW[rb + 64 + tq];
      a[2] = sW[rb + tq + 4];   a[3] = sW[rb + 64 + tq + 4];
      #pragma unroll
      for (int mf=0; mf<8; mf++){
        int p = wm*64 + mf*8 + g;
        int pixb = ((p>>5)+ky)*34 + (p&31) + kx;
        mma16(acc[mf], a, sIn[tq*232 + pixb], sIn[(tq+4)*232 + pixb]);
      }
    }
  }
  int r0 = co0 + wc*16 + g, r1 = r0 + 8;
  float bv0 = bias[r0], bv1 = bias[r1];
  float s=0.f, s2=0.f;
  #pragma unroll
  for (int mf=0; mf<8; mf++){
    int col = y0*32 + wm*64 + mf*8 + 2*tq;
    float v0=acc[mf][0]+bv0, v1=acc[mf][1]+bv0;
    float v2=acc[mf][2]+bv1, v3=acc[mf][3]+bv1;
    *(float2*)&g_gates[((size_t)b*CG + r0)*HW + col] = make_float2(v0,v1);
    *(float2*)&g_gates[((size_t)b*CG + r1)*HW + col] = make_float2(v2,v3);
    s  += v0+v1+v2+v3;
    s2 += v0*v0+v1*v1+v2*v2+v3*v3;
  }
  #pragma unroll
  for (int off=16; off; off>>=1){
    s  += __shfl_xor_sync(0xffffffffu, s , off);
    s2 += __shfl_xor_sync(0xffffffffu, s2, off);
  }
  if (lane==0){ ws[warp]=s; ws2[warp]=s2; }
  __syncthreads();
  if (tid<2){
    float S  = ws [tid*2]+ws [tid*2+1]+ws [tid*2+4]+ws [tid*2+5];
    float S2 = ws2[tid*2]+ws2[tid*2+1]+ws2[tid*2+4]+ws2[tid*2+5];
    int gidx2 = b*8 + (co0>>5) + tid;
    atomicAdd(&g_gsum [par][gidx2], S );
    atomicAdd(&g_gsum2[par][gidx2], S2);
  }
}

// ------------------- GN apply + LSTM gating (float4, fast transcendentals) -----
__global__ void gn_lstm4(const float* __restrict__ gg, const float* __restrict__ gb, int t){
  int b = blockIdx.x >> 6, c = blockIdx.x & 63;
  int p = threadIdx.x*4;
  int par = t & 1;
  __shared__ float smu[4], srs[4];
  if (threadIdx.x < 4){
    int grp = (c >> 5) + threadIdx.x*2;
    float s  = g_gsum [par][b*8+grp];
    float s2 = g_gsum2[par][b*8+grp];
    float m   = s*(1.f/32768.f);
    float var = s2*(1.f/32768.f) - m*m;
    smu[threadIdx.x] = m;
    srs[threadIdx.x] = rsqrtf(var + 1e-5f);
  }
  if (blockIdx.x==0 && threadIdx.x<64){
    g_gsum[par^1][threadIdx.x]=0.f; g_gsum2[par^1][threadIdx.x]=0.f;
  }
  __syncthreads();
  const float* gt = g_gates + (size_t)b*CG*HW + p;
  float4 vi = *(const float4*)&gt[(size_t)(c      )*HW];
  float4 vf = *(const float4*)&gt[(size_t)(c + 64 )*HW];
  float4 vc = *(const float4*)&gt[(size_t)(c + 128)*HW];
  float4 vo = *(const float4*)&gt[(size_t)(c + 192)*HW];
  int idx = (b*64 + c)*1024 + p;
  float4 ic4 = *(const float4*)&g_ic[idx];
  float4 oc4, oh4;
  {
    float a,f2,cc,o;
    a=(vi.x-smu[0])*srs[0]*gg[c]+gb[c]; f2=(vf.x-smu[1])*srs[1]*gg[c+64]+gb[c+64];
    cc=(vc.x-smu[2])*srs[2]*gg[c+128]+gb[c+128]; o=(vo.x-smu[3])*srs[3]*gg[c+192]+gb[c+192];
    oc4.x = ic4.x*sigm(f2)+sigm(a)*tfast(cc); oh4.x = sigm(o)*tfast(oc4.x);
    a=(vi.y-smu[0])*srs[0]*gg[c]+gb[c]; f2=(vf.y-smu[1])*srs[1]*gg[c+64]+gb[c+64];
    cc=(vc.y-smu[2])*srs[2]*gg[c+128]+gb[c+128]; o=(vo.y-smu[3])*srs[3]*gg[c+192]+gb[c+192];
    oc4.y = ic4.y*sigm(f2)+sigm(a)*tfast(cc); oh4.y = sigm(o)*tfast(oc4.y);
    a=(vi.z-smu[0])*srs[0]*gg[c]+gb[c]; f2=(vf.z-smu[1])*srs[1]*gg[c+64]+gb[c+64];
    cc=(vc.z-smu[2])*srs[2]*gg[c+128]+gb[c+128]; o=(vo.z-smu[3])*srs[3]*gg[c+192]+gb[c+192];
    oc4.z = ic4.z*sigm(f2)+sigm(a)*tfast(cc); oh4.z = sigm(o)*tfast(oc4.z);
    a=(vi.w-smu[0])*srs[0]*gg[c]+gb[c]; f2=(vf.w-smu[1])*srs[1]*gg[c+64]+gb[c+64];
    cc=(vc.w-smu[2])*srs[2]*gg[c+128]+gb[c+128]; o=(vo.w-smu[3])*srs[3]*gg[c+192]+gb[c+192];
    oc4.w = ic4.w*sigm(f2)+sigm(a)*tfast(cc); oh4.w = sigm(o)*tfast(oc4.w);
  }
  *(float4*)&g_ic[idx] = oc4;
  *(float4*)&g_oh[idx] = oh4;
}

// ------------------- QKV projections (fp16 TC, single-shot K=64) -------------
// grid (b=8, y=10 co-tiles of 32, 16 px-tiles of 64), block 256
__global__ __launch_bounds__(256) void lin_hm(const float* __restrict__ h_b,
                                              const float* __restrict__ m_b)
{
  __shared__ unsigned uW[1024];   // A: 32o x 32 c-pairs, tw
  __shared__ unsigned uX[2048];   // B: 64px x 32 c-pairs, tw
  __shared__ __half sT[64*34];
  int b = blockIdx.x, p0 = blockIdx.z*64, yb = blockIdx.y;
  const float* x1  = (yb < 6) ? g_oh : g_im;
  const float* bias= (yb < 6) ? h_b  : m_b;
  int o0 = (yb < 6) ? yb*32 : (yb-6)*32;
  unsigned* dstT = 0; unsigned* dstV = 0; int crel = 0;
  if (yb < 6){
    if      (o0 <  64){ dstT = g_qT;    crel = o0;       }
    else if (o0 < 128){ dstT = g_kT[0]; crel = o0 - 64;  }
    else              { dstV = g_vv[0]; crel = o0 - 128; }
  } else {
    if (o0 < 64){ dstT = g_kT[1]; crel = o0; }
    else        { dstV = g_vv[1]; crel = o0 - 64; }
  }

  int tid=threadIdx.x, warp=tid>>5, lane=tid&31, g=lane>>2, tq=lane&3;
  int wc = warp&1, wm = warp>>1;   // wc: o half(16), wm: px quarter(16)
  // stage weights (already tw-swizzled in global) + x tile
  for (int idx=tid; idx<1024; idx+=256) uW[idx] = g_hmw[yb*1024 + idx];
  const float* xb = x1 + (size_t)b*64*HW + p0;
  #pragma unroll
  for (int it=0; it<8; it++){
    int idx = it*256 + tid;
    int px = idx & 63, j = idx >> 6;
    float v0 = xb[(size_t)(2*j  )*HW + px];
    float v1 = xb[(size_t)(2*j+1)*HW + px];
    uX[tw(px, j)] = pack2h(v0, v1);
  }
  __syncthreads();
  float acc[2][4];
  acc[0][0]=acc[0][1]=acc[0][2]=acc[0][3]=0.f;
  acc[1][0]=acc[1][1]=acc[1][2]=acc[1][3]=0.f;
  #pragma unroll
  for (int kk=0; kk<4; kk++){
    unsigned a[4]; ldsmA(a, uW, wc*16, kk);
    unsigned bb[4]; ldsmB2(bb, uX, wm*16, kk);
    mma16(acc[0], a, bb[0], bb[1]);
    mma16(acc[1], a, bb[2], bb[3]);
  }
  int cc0 = wc*16 + g;
  float bv0 = bias[o0+cc0], bv1 = bias[o0+cc0+8];
  if (dstV){
    #pragma unroll
    for (int oct=0; oct<2; oct++){
      int col = p0 + wm*16 + oct*8 + 2*tq;
      dstV[((size_t)(b*64 + crel + cc0  ))*512 + (col>>1)] = pack2h(acc[oct][0]+bv0, acc[oct][1]+bv0);
      dstV[((size_t)(b*64 + crel + cc0+8))*512 + (col>>1)] = pack2h(acc[oct][2]+bv1, acc[oct][3]+bv1);
    }
  } else {
    __syncthreads();
    #pragma unroll
    for (int oct=0; oct<2; oct++){
      int col = wm*16 + oct*8 + 2*tq;
      sT[(col  )*34 + cc0  ] = __float2half(acc[oct][0]+bv0);
      sT[(col+1)*34 + cc0  ] = __float2half(acc[oct][1]+bv0);
      sT[(col  )*34 + cc0+8] = __float2half(acc[oct][2]+bv1);
      sT[(col+1)*34 + cc0+8] = __float2half(acc[oct][3]+bv1);
    }
    __syncthreads();
    for (int idx=tid; idx<1024; idx+=256){
      int px = idx>>4, wj = idx&15;
      __half2 hv;
      hv.x = sT[px*34 + 2*wj];
      hv.y = sT[px*34 + 2*wj + 1];
      dstT[((size_t)(b*1024 + p0 + px))*32 + (crel>>1) + wj] = *(unsigned*)&hv;
    }
  }
}

// ------------------- pass 1 (fp16 TC + ldmatrix): row softmax stats ----------
__global__ __launch_bounds__(256) void qk_stats(){
  __shared__ unsigned uQ[2048];
  __shared__ unsigned uK[2][2048];
  __shared__ float sM[2][64], sL[2][64];
  int b = blockIdx.x, n0 = blockIdx.y*64, which = blockIdx.z;
  const unsigned* qsrc = g_qT + (size_t)(b*1024 + n0)*32;
  const unsigned* ksrc = g_kT[which] + (size_t)b*1024*32;
  int tid=threadIdx.x, warp=tid>>5, tq=(tid&31)&3;
  int g = (tid&31)>>2;
  int wn = warp&3, wm = warp>>2;
  loadTile(uQ, qsrc, 32, tid);
  float M0=-1e30f, M1=-1e30f, L0=0.f, L1=0.f;
  for (int m0=0; m0<HW; m0+=128){
    __syncthreads();
    loadTile(uK[0], ksrc + (size_t)m0*32, 32, tid);
    loadTile(uK[1], ksrc + (size_t)(m0+64)*32, 32, tid);
    __syncthreads();
    const unsigned* kt = uK[wm];
    float cfr[8][4];
    #pragma unroll
    for(int mf=0;mf<8;mf++){cfr[mf][0]=0.f;cfr[mf][1]=0.f;cfr[mf][2]=0.f;cfr[mf][3]=0.f;}
    #pragma unroll
    for (int kk=0; kk<4; kk++){
      unsigned a[4]; ldsmA(a, uQ, wn*16, kk);
      #pragma unroll
      for (int mp=0; mp<4; mp++){
        unsigned bb[4]; ldsmB2(bb, kt, mp*16, kk);
        mma16(cfr[2*mp  ], a, bb[0], bb[1]);
        mma16(cfr[2*mp+1], a, bb[2], bb[3]);
      }
    }
    float tm0=-1e30f, tm1=-1e30f;
    #pragma unroll
    for(int mf=0;mf<8;mf++){
      tm0 = fmaxf(tm0, fmaxf(cfr[mf][0], cfr[mf][1]));
      tm1 = fmaxf(tm1, fmaxf(cfr[mf][2], cfr[mf][3]));
    }
    tm0 = fmaxf(tm0, __shfl_xor_sync(0xffffffffu, tm0, 1));
    tm0 = fmaxf(tm0, __shfl_xor_sync(0xffffffffu, tm0, 2));
    tm1 = fmaxf(tm1, __shfl_xor_sync(0xffffffffu, tm1, 1));
    tm1 = fmaxf(tm1, __shfl_xor_sync(0xffffffffu, tm1, 2));
    float nM0 = fmaxf(M0, tm0), nM1 = fmaxf(M1, tm1);
    float c0 = nM0*LOG2E, c1 = nM1*LOG2E;
    float s0=0.f, s1=0.f;
    #pragma unroll
    for(int mf=0;mf<8;mf++){
      float2 e0 = exp2_pair_f(__fmaf_rn(cfr[mf][0], LOG2E, -c0),
                              __fmaf_rn(cfr[mf][1], LOG2E, -c0));
      float2 e1 = exp2_pair_f(__fmaf_rn(cfr[mf][2], LOG2E, -c1),
                              __fmaf_rn(cfr[mf][3], LOG2E, -c1));
      s0 += e0.x + e0.y;
      s1 += e1.x + e1.y;
    }
    s0 += __shfl_xor_sync(0xffffffffu, s0, 1);
    s0 += __shfl_xor_sync(0xffffffffu, s0, 2);
    s1 += __shfl_xor_sync(0xffffffffu, s1, 1);
    s1 += __shfl_xor_sync(0xffffffffu, s1, 2);
    L0 = L0*__expf(M0-nM0) + s0; M0 = nM0;
    L1 = L1*__expf(M1-nM1) + s1; M1 = nM1;
  }
  if (tq==0){
    sM[wm][wn*16+g  ] = M0; sL[wm][wn*16+g  ] = L0;
    sM[wm][wn*16+8+g] = M1; sL[wm][wn*16+8+g] = L1;
  }
  __syncthreads();
  if (tid<64){
    float Ma = sM[0][tid], Mb = sM[1][tid];
    float M  = fmaxf(Ma, Mb);
    float L  = sL[0][tid]*__expf(Ma-M) + sL[1][tid]*__expf(Mb-M);
    g_roff[which][b*HW + n0 + tid] = __fmaf_rn(M, LOG2E, __log2f(L));
  }
}

// ------------------- merged pass 2 + tail --------------------------------------
__global__ __launch_bounds__(512,1) void av_tail(const float* __restrict__ z1_w,
                                                 const float* __restrict__ z1_b,
                                                 const float* __restrict__ z2_b,
                                                 float* __restrict__ out, int t, int ws)
{
  extern __shared__ unsigned arena[];
  int b = blockIdx.x, m0 = blockIdx.y*64;
  int p0 = m0;
  int tid = threadIdx.x;
  int lane = tid & 31, g = lane>>2, tq = lane&3;

  // ================= AV phase =================
  {
    int which = tid >> 8;
    int ltid  = tid & 255;
    int warp8 = ltid >> 5;
    int wr = warp8 & 3, wm = warp8 >> 2;
    unsigned* base = arena + which*8256;
    unsigned* uK = base;
    unsigned* uQ = base + 2048;
    unsigned* uV = base + 4096;
    unsigned* uP = base + 6144;
    float*   sro = (float*)(base + 8192);
    const unsigned* qsrc = g_qT + (size_t)b*1024*32;
    const unsigned* ksrc = g_kT[which] + (size_t)(b*1024 + m0)*32;
    const unsigned* vsrc = g_vv[which] + (size_t)b*64*512;
    const float*    roff = g_roff[which] + b*HW;

    loadTile(uK, ksrc, 32, ltid);
    float accZ[4][4];
    #pragma unroll
    for(int mf=0;mf<4;mf++){accZ[mf][0]=0.f;accZ[mf][1]=0.f;accZ[mf][2]=0.f;accZ[mf][3]=0.f;}

    for (int nb=0; nb<HW; nb+=64){
      __syncthreads();
      loadTile(uQ, qsrc + (size_t)nb*32, 32, ltid);
      loadTile(uV, vsrc + (nb>>1), 512, ltid);
      if (ltid < 64){ sro[ltid] = roff[nb+ltid]; }
      __syncthreads();
      float accS[4][4];
      #pragma unroll
      for(int mf=0;mf<4;mf++){accS[mf][0]=0.f;accS[mf][1]=0.f;accS[mf][2]=0.f;accS[mf][3]=0.f;}
      #pragma unroll
      for (int kk=0; kk<4; kk++){
        unsigned a[4]; ldsmA(a, uK, wr*16, kk);
        #pragma unroll
        for (int mp=0; mp<2; mp++){
          unsigned bb[4]; ldsmB2(bb, uQ, wm*32 + mp*16, kk);
          mma16(accS[2*mp  ], a, bb[0], bb[1]);
          mma16(accS[2*mp+1], a, bb[2], bb[3]);
        }
      }
      #pragma unroll
      for (int mf=0; mf<4; mf++){
        int n = wm*32 + mf*8 + 2*tq;
        float ro0 = sro[n], ro1 = sro[n+1];
        int jn = n >> 1;
        int r0 = wr*16 + g;
        uP[tw(r0,   jn)] = exp2_pair_h(__fmaf_rn(accS[mf][0], LOG2E, -ro0),
                                       __fmaf_rn(accS[mf][1], LOG2E, -ro1));
        uP[tw(r0+8, jn)] = exp2_pair_h(__fmaf_rn(accS[mf][2], LOG2E, -ro0),
                                       __fmaf_rn(accS[mf][3], LOG2E, -ro1));
      }
      __syncthreads();
      #pragma unroll
      for (int kk=0; kk<4; kk++){
        unsigned a[4]; ldsmA(a, uV, wr*16, kk);
        #pragma unroll
        for (int mp=0; mp<2; mp++){
          unsigned bb[4]; ldsmB2(bb, uP, wm*32 + mp*16, kk);
          mma16(accZ[2*mp  ], a, bb[0], bb[1]);
          mma16(accZ[2*mp+1], a, bb[2], bb[3]);
        }
      }
    }
    __syncthreads();
    unsigned* sZc = arena;
    int zoff = which*64;
    #pragma unroll
    for (int mf=0; mf<4; mf++){
      int r0 = zoff + wr*16 + g, r1 = r0 + 8;
      int col = wm*32 + mf*8 + 2*tq;
      *(uint2*)&sZc[r0*72 + col] = make_uint2(f2t(accZ[mf][0]), f2t(accZ[mf][1]));
      *(uint2*)&sZc[r1*72 + col] = make_uint2(f2t(accZ[mf][2]), f2t(accZ[mf][3]));
    }
  }
  // ================= tail phase =================
  unsigned* sZc = arena;                 // [128][72] tf32
  unsigned* uz1 = arena + 9216;          // [64][132]
  unsigned* sOh = arena + 17664;         // [64][72]
  unsigned* sZ  = arena + 22272;         // [64][72]
  unsigned* wch = arena + 26880;         // [8][200]
  float*  gates = (float*)arena;         // [192][66]

  for (int idx=tid; idx<8192; idx+=512){
    int o = idx>>7, c = idx&127;
    uz1[o*132+c] = f2t(z1_w[o*128+c]);
  }
  for (int idx=tid; idx<2048; idx+=512){
    int c = idx>>5, p2 = idx&31;
    float2 v = *(const float2*)&g_oh[((size_t)b*64+c)*HW + p0 + 2*p2];
    *(uint2*)&sOh[c*72 + 2*p2] = make_uint2(f2t(v.x), f2t(v.y));
  }
  __syncthreads();

  int warp16 = tid>>5;
  int wc = warp16 & 1, wm8 = warp16 >> 1;

  // ---- z1 ----
  float a1[2][4];
  #pragma unroll
  for(int ot=0;ot<2;ot++){a1[ot][0]=0.f;a1[ot][1]=0.f;a1[ot][2]=0.f;a1[ot][3]=0.f;}
  for (int cc=0; cc<128; cc+=8){
    unsigned b0 = sZc[(cc+tq  )*72 + wm8*8 + g];
    unsigned b1 = sZc[(cc+tq+4)*72 + wm8*8 + g];
    #pragma unroll
    for (int ot=0; ot<2; ot++){
      unsigned a[4];
      int r = ot*32 + wc*16 + g;
      a[0]=uz1[(r  )*132 + cc+tq];   a[1]=uz1[(r+8)*132 + cc+tq];
      a[2]=uz1[(r  )*132 + cc+tq+4]; a[3]=uz1[(r+8)*132 + cc+tq+4];
      mma8(a1[ot], a, b0, b1);
    }
  }
  __syncthreads();
  #pragma unroll
  for (int ot=0; ot<2; ot++){
    int r0 = ot*32 + wc*16 + g, r1 = r0 + 8;
    int col = wm8*8 + 2*tq;
    float bv0 = z1_b[r0], bv1 = z1_b[r1];
    *(uint2*)&sZ[r0*72 + col] = make_uint2(f2t(a1[ot][0]+bv0), f2t(a1[ot][1]+bv0));
    *(uint2*)&sZ[r1*72 + col] = make_uint2(f2t(a1[ot][2]+bv1), f2t(a1[ot][3]+bv1));
  }
  // ---- z2 ----
  float a2[6][4];
  #pragma unroll
  for(int ot=0;ot<6;ot++){a2[ot][0]=0.f;a2[ot][1]=0.f;a2[ot][2]=0.f;a2[ot][3]=0.f;}
  for (int cc=0; cc<128; cc+=8){
    __syncthreads();
    for (int idx=tid; idx<1536; idx+=512){
      int r = idx/192, o = idx - r*192;
      wch[r*200 + o] = g_z2T[(cc+r)*192 + o];
    }
    __syncthreads();
    const unsigned* src = (cc<64) ? (sZ + cc*72) : (sOh + (cc-64)*72);
    unsigned b0 = src[ tq   *72 + wm8*8 + g];
    unsigned b1 = src[(tq+4)*72 + wm8*8 + g];
    #pragma unroll
    for (int ot=0; ot<6; ot++){
      unsigned a[4];
      int o = ot*32 + wc*16 + g;
      a[0]=wch[ tq   *200 + o];   a[1]=wch[ tq   *200 + o+8];
      a[2]=wch[(tq+4)*200 + o];   a[3]=wch[(tq+4)*200 + o+8];
      mma8(a2[ot], a, b0, b1);
    }
  }
  __syncthreads();
  #pragma unroll
  for (int ot=0; ot<6; ot++){
    int r0 = ot*32 + wc*16 + g, r1 = r0 + 8;
    int col = wm8*8 + 2*tq;
    float bv0 = z2_b[r0], bv1 = z2_b[r1];
    *(float2*)&gates[r0*66 + col] = make_float2(a2[ot][0]+bv0, a2[ot][1]+bv0);
    *(float2*)&gates[r1*66 + col] = make_float2(a2[ot][2]+bv1, a2[ot][3]+bv1);
  }
  __syncthreads();
  // ---- gating epilogue (fast transcendentals) ----
  for (int i=tid; i<4096; i+=512){
    int c = i>>6, p = i&63;
    float vo = gates[(c     )*66 + p];
    float vg = gates[(64 +c )*66 + p];
    float vi = gates[(128+c )*66 + p];
    int idx = (b*64 + c)*1024 + p0 + p;
    float si = sigm(vi);
    float om  = tfast(vg)*si + (1.f-si)*g_im[idx];
    float oh2 = sigm(vo)*om;
    g_im[idx] = om;
    g_ih[idx] = oh2;
    out[(((size_t)b*TT + t)*64 + c)*HW + p0 + p] = oh2;
    if (ws){
      float* st = out + (size_t)BB*TT*64*HW;
      st[idx]            = oh2;
      st[NSTATE + idx]   = g_ic[idx];
      st[2*NSTATE + idx] = om;
    }
  }
}

extern "C" void kernel_launch(void* const* d_in, const int* in_sizes, int n_in,
                              void* d_out, int out_size)
{
  const float* inputs = (const float*)d_in[0];
  const float* conv_w = (const float*)d_in[1];
  const float* conv_b = (const float*)d_in[2];
  const float* gn_g   = (const float*)d_in[3];
  const float* gn_b   = (const float*)d_in[4];
  const float* h_w    = (const float*)d_in[5];
  const float* h_b    = (const float*)d_in[6];
  const float* m_w    = (const float*)d_in[7];
  const float* m_b    = (const float*)d_in[8];
  const float* z1_w   = (const float*)d_in[9];
  const float* z1_b   = (const float*)d_in[10];
  const float* z2_w   = (const float*)d_in[11];
  const float* z2_b   = (const float*)d_in[12];
  float* out = (float*)d_out;

  const int AT_SMEM = 28480*4;   // 113920
  cudaFuncSetAttribute(av_tail, cudaFuncAttributeMaxDynamicSharedMemorySize, AT_SMEM);

  zero_states<<<2048,256>>>();
  wtrans<<<256,256>>>(conv_w, z2_w, h_w, m_w);
  int write_states = (out_size >= (int)(BB*TT*64*HW + 3*NSTATE)) ? 1 : 0;

  for (int t=0; t<TT; t++){
    conv_tc<<<dim3(8,4,8),256>>>(inputs, conv_b, t);
    gn_lstm4<<<512,256>>>(gn_g, gn_b, t);
    lin_hm<<<dim3(8,10,16),256>>>(h_b, m_b);
    qk_stats<<<dim3(8,16,2),256>>>();
    av_tail<<<dim3(8,16),512,AT_SMEM>>>(z1_w, z1_b, z2_b, out, t, (t==TT-1) ? write_states : 0);
  }
}

// round 12
// speedup vs baseline: 3.4412x; 1.1371x over previous
#include <cuda_runtime.h>
#include <cuda_fp16.h>
#include <math.h>

#define BB 8
#define TT 8
#define HW 1024
#define CG 256
#define NSTATE (BB*64*HW)   // 524288
#define LOG2E 1.4426950408889634f

// ---- persistent state ----
__device__ float g_ih[NSTATE];
__device__ float g_ic[NSTATE];
__device__ float g_im[NSTATE];
// ---- scratch ----
__device__ float g_gates[BB*CG*HW];
__device__ float g_gsum [2][64];
__device__ float g_gsum2[2][64];
__device__ float g_oh[NSTATE];
__device__ float g_roff[2][BB*HW];
__device__ unsigned g_wTh[8*9*256*8];
__device__ unsigned g_z2T[128*192];
__device__ unsigned g_hmw[10*1024];
__device__ unsigned g_qT[8*1024*32];
__device__ unsigned g_kT[2][8*1024*32];
__device__ unsigned g_vv[2][8*64*512];

__device__ __forceinline__ float sigm(float x){
  float e = __expf(-x);
  float r; asm("rcp.approx.f32 %0,%1;" : "=f"(r) : "f"(1.f+e));
  return r;
}
__device__ __forceinline__ float tfast(float x){
  return __fmaf_rn(2.f, sigm(2.f*x), -1.f);
}
__device__ __forceinline__ unsigned f2t(float x){
  unsigned r; asm("cvt.rna.tf32.f32 %0,%1;" : "=r"(r) : "f"(x)); return r;
}
__device__ __forceinline__ void mma8(float* d, const unsigned* a, unsigned b0, unsigned b1){
  asm volatile("mma.sync.aligned.m16n8k8.row.col.f32.tf32.tf32.f32 "
    "{%0,%1,%2,%3},{%4,%5,%6,%7},{%8,%9},{%0,%1,%2,%3};"
    : "+f"(d[0]),"+f"(d[1]),"+f"(d[2]),"+f"(d[3])
    : "r"(a[0]),"r"(a[1]),"r"(a[2]),"r"(a[3]),"r"(b0),"r"(b1));
}
__device__ __forceinline__ void mma16(float* d, const unsigned* a, unsigned b0, unsigned b1){
  asm volatile("mma.sync.aligned.m16n8k16.row.col.f32.f16.f16.f32 "
    "{%0,%1,%2,%3},{%4,%5,%6,%7},{%8,%9},{%0,%1,%2,%3};"
    : "+f"(d[0]),"+f"(d[1]),"+f"(d[2]),"+f"(d[3])
    : "r"(a[0]),"r"(a[1]),"r"(a[2]),"r"(a[3]),"r"(b0),"r"(b1));
}
__device__ __forceinline__ unsigned pack2h(float x, float y){
  __half2 h = __floats2half2_rn(x, y);
  return *(unsigned*)&h;
}
__device__ __forceinline__ unsigned exp2_pair_h(float x0, float x1){
  __half2 h = h2exp2(__floats2half2_rn(x0, x1));
  return *(unsigned*)&h;
}
__device__ __forceinline__ float2 exp2_pair_f(float x0, float x1){
  __half2 h = h2exp2(__floats2half2_rn(x0, x1));
  return __half22float2(h);
}

__device__ __forceinline__ int tw(int row, int j){ return row*32 + (j ^ ((row&7)<<2)); }

__device__ __forceinline__ unsigned saddr(const unsigned* p){
  return (unsigned)__cvta_generic_to_shared((const void*)p);
}
__device__ __forceinline__ void cpa16(unsigned* sdst, const void* gsrc){
  unsigned ad = saddr(sdst);
  asm volatile("cp.async.cg.shared.global [%0], [%1], 16;" :: "r"(ad), "l"(gsrc));
}
#define CP_COMMIT asm volatile("cp.async.commit_group;")
#define CP_WAIT0  asm volatile("cp.async.wait_group 0;")

__device__ __forceinline__ void loadTile(unsigned* dst, const unsigned* __restrict__ src,
                                         int rowstride, int ltid){
  #pragma unroll
  for (int it=0; it<2; it++){
    int idx = it*256 + ltid;
    int row = idx>>3, j4 = (idx&7)*4;
    uint4 v = *(const uint4*)(src + (size_t)row*rowstride + j4);
    *(uint4*)&dst[tw(row, j4)] = v;
  }
}
__device__ __forceinline__ void loadTileAsync(unsigned* dst, const unsigned* __restrict__ src,
                                              int rowstride, int ltid){
  #pragma unroll
  for (int it=0; it<2; it++){
    int idx = it*256 + ltid;
    int row = idx>>3, j4 = (idx&7)*4;
    cpa16(dst + tw(row, j4), src + (size_t)row*rowstride + j4);
  }
}
__device__ __forceinline__ void ldsmA(unsigned* a, const unsigned* t, int r, int kk){
  int lane = threadIdx.x & 31;
  int row = r + (lane&7) + (lane&8);
  int j   = kk*8 + ((lane>>4)<<2);
  unsigned ad = saddr(t + tw(row, j));
  asm volatile("ldmatrix.sync.aligned.m8n8.x4.shared.b16 {%0,%1,%2,%3}, [%4];"
    : "=r"(a[0]),"=r"(a[1]),"=r"(a[2]),"=r"(a[3]) : "r"(ad));
}
__device__ __forceinline__ void ldsmB2(unsigned* b, const unsigned* t, int nb, int kk){
  int lane = threadIdx.x & 31;
  int row = nb + (lane&7) + ((lane>>4)<<3);
  int j   = kk*8 + (((lane>>3)&1)<<2);
  unsigned ad = saddr(t + tw(row, j));
  asm volatile("ldmatrix.sync.aligned.m8n8.x4.shared.b16 {%0,%1,%2,%3}, [%4];"
    : "=r"(b[0]),"=r"(b[1]),"=r"(b[2]),"=r"(b[3]) : "r"(ad));
}

__global__ void zero_states(){
  int i = blockIdx.x*256 + threadIdx.x;
  if (i < NSTATE){ g_ih[i]=0.f; g_ic[i]=0.f; g_im[i]=0.f; }
  if (blockIdx.x==0 && threadIdx.x<64){
    g_gsum[0][threadIdx.x]=0.f; g_gsum2[0][threadIdx.x]=0.f;
    g_gsum[1][threadIdx.x]=0.f; g_gsum2[1][threadIdx.x]=0.f;
  }
}

__global__ void wtrans(const float* __restrict__ w, const float* __restrict__ z2w,
                       const float* __restrict__ hw, const float* __restrict__ mw){
  int co = blockIdx.x;
  for (int idx = threadIdx.x; idx < 576; idx += 256){
    int chunk = idx/72, r = idx - chunk*72, pos = r>>3, j = r&7;
    int ci = chunk*16 + 2*j;
    float v0 = w[((size_t)co*128 + ci  )*9 + pos];
    float v1 = w[((size_t)co*128 + ci+1)*9 + pos];
    g_wTh[((size_t)(chunk*9+pos)*256 + co)*8 + j] = pack2h(v0, v1);
  }
  if (co < 192){
    for (int c = threadIdx.x; c < 128; c += 256)
      g_z2T[c*192 + co] = f2t(z2w[co*128 + c]);
    if (threadIdx.x < 32){
      int j = threadIdx.x;
      int y = co>>5, row = co&31;
      g_hmw[y*1024 + tw(row, j)] = pack2h(hw[co*64 + 2*j], hw[co*64 + 2*j + 1]);
    }
  }
  if (co < 128 && threadIdx.x >= 32 && threadIdx.x < 64){
    int j = threadIdx.x - 32;
    int y = 6 + (co>>5), row = co&31;
    g_hmw[y*1024 + tw(row, j)] = pack2h(mw[co*64 + 2*j], mw[co*64 + 2*j + 1]);
  }
}

// ------------- 3x3 conv (fp16 TC, pipelined staging) + fused GN stats -------
__global__ __launch_bounds__(256) void conv_tc(const float* __restrict__ xin,
                                               const float* __restrict__ bias, int t)
{
  int pt = blockIdx.x, cot = blockIdx.y, b = blockIdx.z;
  int y0 = pt*4, co0 = cot*64, par = t & 1;
  __shared__ unsigned sIn[8*232];
  __shared__ unsigned sW[2][4608];
  __shared__ float ws[8], ws2[8];
  int tid=threadIdx.x, warp=tid>>5, lane=tid&31, g=lane>>2, tq=lane&3;
  int wc = warp&3, wm = warp>>2;
  float acc[8][4];
  #pragma unroll
  for(int j=0;j<8;j++){acc[j][0]=0.f;acc[j][1]=0.f;acc[j][2]=0.f;acc[j][3]=0.f;}

  int pix = tid;
  int yy = pix/34, xx = pix - yy*34;
  int gy = y0-1+yy, gx = xx-1;
  bool pv = (pix<204) && ((unsigned)gy<32u) && ((unsigned)gx<32u);
  int gidx = gy*32 + gx;

  const float* xbase = xin + (size_t)(b*TT+t)*64*HW;
  const float* hbase = g_ih + (size_t)b*64*HW;

  float rin[16];
  // prefetch chunk 0 input into regs
  {
    const float* src = xbase;
    #pragma unroll
    for (int j=0;j<8;j++){
      rin[2*j]=0.f; rin[2*j+1]=0.f;
      if (pv){ rin[2*j] = src[(size_t)(2*j)*HW + gidx]; rin[2*j+1] = src[(size_t)(2*j+1)*HW + gidx]; }
    }
  }
  // async weights chunk 0
  for (int i4=tid; i4<1152; i4+=256)
    cpa16(&sW[0][i4*4], g_wTh + (size_t)0*9*2048 + co0*8 + (i4>>7)*2048 + (i4&127)*4);
  CP_COMMIT;

  for (int chunk=0; chunk<8; chunk++){
    int cb = chunk&1;
    __syncthreads();                    // sIn free
    if (pix < 204){
      #pragma unroll
      for (int j=0;j<8;j++) sIn[j*232 + pix] = pack2h(rin[2*j], rin[2*j+1]);
    }
    CP_WAIT0;                           // weights for this chunk landed
    __syncthreads();
    if (chunk < 7){
      // prefetch next input into regs + next weights async
      const float* src = (chunk+1<4) ? (xbase + (size_t)(chunk+1)*16*HW)
                                     : (hbase + (size_t)(chunk+1-4)*16*HW);
      #pragma unroll
      for (int j=0;j<8;j++){
        rin[2*j]=0.f; rin[2*j+1]=0.f;
        if (pv){ rin[2*j] = src[(size_t)(2*j)*HW + gidx]; rin[2*j+1] = src[(size_t)(2*j+1)*HW + gidx]; }
      }
      for (int i4=tid; i4<1152; i4+=256)
        cpa16(&sW[cb^1][i4*4], g_wTh + (size_t)(chunk+1)*9*2048 + co0*8 + (i4>>7)*2048 + (i4&127)*4);
      CP_COMMIT;
    }
    #pragma unroll
    for (int pos=0; pos<9; pos++){
      int ky = pos/3, kx = pos - 3*ky;
      unsigned a[4];
      int rb = pos*512 + (wc*16+g)*8;
      a[0] = sW[cb][rb + tq];       a[1] = sW[cb][rb + 64 + tq];
      a[2] = sW[cb][rb + tq + 4];   a[3] = sW[cb][rb + 64 + tq + 4];
      #pragma unroll
      for (int mf=0; mf<8; mf++){
        int p = wm*64 + mf*8 + g;
        int pixb = ((p>>5)+ky)*34 + (p&31) + kx;
        mma16(acc[mf], a, sIn[tq*232 + pixb], sIn[(tq+4)*232 + pixb]);
      }
    }
  }
  int r0 = co0 + wc*16 + g, r1 = r0 + 8;
  float bv0 = bias[r0], bv1 = bias[r1];
  float s=0.f, s2=0.f;
  #pragma unroll
  for (int mf=0; mf<8; mf++){
    int col = y0*32 + wm*64 + mf*8 + 2*tq;
    float v0=acc[mf][0]+bv0, v1=acc[mf][1]+bv0;
    float v2=acc[mf][2]+bv1, v3=acc[mf][3]+bv1;
    *(float2*)&g_gates[((size_t)b*CG + r0)*HW + col] = make_float2(v0,v1);
    *(float2*)&g_gates[((size_t)b*CG + r1)*HW + col] = make_float2(v2,v3);
    s  += v0+v1+v2+v3;
    s2 += v0*v0+v1*v1+v2*v2+v3*v3;
  }
  #pragma unroll
  for (int off=16; off; off>>=1){
    s  += __shfl_xor_sync(0xffffffffu, s , off);
    s2 += __shfl_xor_sync(0xffffffffu, s2, off);
  }
  if (lane==0){ ws[warp]=s; ws2[warp]=s2; }
  __syncthreads();
  if (tid<2){
    float S  = ws [tid*2]+ws [tid*2+1]+ws [tid*2+4]+ws [tid*2+5];
    float S2 = ws2[tid*2]+ws2[tid*2+1]+ws2[tid*2+4]+ws2[tid*2+5];
    int gidx2 = b*8 + (co0>>5) + tid;
    atomicAdd(&g_gsum [par][gidx2], S );
    atomicAdd(&g_gsum2[par][gidx2], S2);
  }
}

// ------------------- GN apply + LSTM gating -------------------
__global__ void gn_lstm4(const float* __restrict__ gg, const float* __restrict__ gb, int t){
  int b = blockIdx.x >> 6, c = blockIdx.x & 63;
  int p = threadIdx.x*4;
  int par = t & 1;
  __shared__ float smu[4], srs[4];
  if (threadIdx.x < 4){
    int grp = (c >> 5) + threadIdx.x*2;
    float s  = g_gsum [par][b*8+grp];
    float s2 = g_gsum2[par][b*8+grp];
    float m   = s*(1.f/32768.f);
    float var = s2*(1.f/32768.f) - m*m;
    smu[threadIdx.x] = m;
    srs[threadIdx.x] = rsqrtf(var + 1e-5f);
  }
  if (blockIdx.x==0 && threadIdx.x<64){
    g_gsum[par^1][threadIdx.x]=0.f; g_gsum2[par^1][threadIdx.x]=0.f;
  }
  __syncthreads();
  const float* gt = g_gates + (size_t)b*CG*HW + p;
  float4 vi = *(const float4*)&gt[(size_t)(c      )*HW];
  float4 vf = *(const float4*)&gt[(size_t)(c + 64 )*HW];
  float4 vc = *(const float4*)&gt[(size_t)(c + 128)*HW];
  float4 vo = *(const float4*)&gt[(size_t)(c + 192)*HW];
  int idx = (b*64 + c)*1024 + p;
  float4 ic4 = *(const float4*)&g_ic[idx];
  float4 oc4, oh4;
  {
    float a,f2,cc,o;
    a=(vi.x-smu[0])*srs[0]*gg[c]+gb[c]; f2=(vf.x-smu[1])*srs[1]*gg[c+64]+gb[c+64];
    cc=(vc.x-smu[2])*srs[2]*gg[c+128]+gb[c+128]; o=(vo.x-smu[3])*srs[3]*gg[c+192]+gb[c+192];
    oc4.x = ic4.x*sigm(f2)+sigm(a)*tfast(cc); oh4.x = sigm(o)*tfast(oc4.x);
    a=(vi.y-smu[0])*srs[0]*gg[c]+gb[c]; f2=(vf.y-smu[1])*srs[1]*gg[c+64]+gb[c+64];
    cc=(vc.y-smu[2])*srs[2]*gg[c+128]+gb[c+128]; o=(vo.y-smu[3])*srs[3]*gg[c+192]+gb[c+192];
    oc4.y = ic4.y*sigm(f2)+sigm(a)*tfast(cc); oh4.y = sigm(o)*tfast(oc4.y);
    a=(vi.z-smu[0])*srs[0]*gg[c]+gb[c]; f2=(vf.z-smu[1])*srs[1]*gg[c+64]+gb[c+64];
    cc=(vc.z-smu[2])*srs[2]*gg[c+128]+gb[c+128]; o=(vo.z-smu[3])*srs[3]*gg[c+192]+gb[c+192];
    oc4.z = ic4.z*sigm(f2)+sigm(a)*tfast(cc); oh4.z = sigm(o)*tfast(oc4.z);
    a=(vi.w-smu[0])*srs[0]*gg[c]+gb[c]; f2=(vf.w-smu[1])*srs[1]*gg[c+64]+gb[c+64];
    cc=(vc.w-smu[2])*srs[2]*gg[c+128]+gb[c+128]; o=(vo.w-smu[3])*srs[3]*gg[c+192]+gb[c+192];
    oc4.w = ic4.w*sigm(f2)+sigm(a)*tfast(cc); oh4.w = sigm(o)*tfast(oc4.w);
  }
  *(float4*)&g_ic[idx] = oc4;
  *(float4*)&g_oh[idx] = oh4;
}

// ------------------- QKV projections (fp16 TC, single-shot K=64) -------------
__global__ __launch_bounds__(256) void lin_hm(const float* __restrict__ h_b,
                                              const float* __restrict__ m_b)
{
  __shared__ unsigned uW[1024];
  __shared__ unsigned uX[2048];
  __shared__ __half sT[64*34];
  int b = blockIdx.x, p0 = blockIdx.z*64, yb = blockIdx.y;
  const float* x1  = (yb < 6) ? g_oh : g_im;
  const float* bias= (yb < 6) ? h_b  : m_b;
  int o0 = (yb < 6) ? yb*32 : (yb-6)*32;
  unsigned* dstT = 0; unsigned* dstV = 0; int crel = 0;
  if (yb < 6){
    if      (o0 <  64){ dstT = g_qT;    crel = o0;       }
    else if (o0 < 128){ dstT = g_kT[0]; crel = o0 - 64;  }
    else              { dstV = g_vv[0]; crel = o0 - 128; }
  } else {
    if (o0 < 64){ dstT = g_kT[1]; crel = o0; }
    else        { dstV = g_vv[1]; crel = o0 - 64; }
  }

  int tid=threadIdx.x, warp=tid>>5, lane=tid&31, g=lane>>2, tq=lane&3;
  int wc = warp&1, wm = warp>>1;
  for (int idx=tid; idx<1024; idx+=256) uW[idx] = g_hmw[yb*1024 + idx];
  const float* xb = x1 + (size_t)b*64*HW + p0;
  #pragma unroll
  for (int it=0; it<8; it++){
    int idx = it*256 + tid;
    int px = idx & 63, j = idx >> 6;
    float v0 = xb[(size_t)(2*j  )*HW + px];
    float v1 = xb[(size_t)(2*j+1)*HW + px];
    uX[tw(px, j)] = pack2h(v0, v1);
  }
  __syncthreads();
  float acc[2][4];
  acc[0][0]=acc[0][1]=acc[0][2]=acc[0][3]=0.f;
  acc[1][0]=acc[1][1]=acc[1][2]=acc[1][3]=0.f;
  #pragma unroll
  for (int kk=0; kk<4; kk++){
    unsigned a[4]; ldsmA(a, uW, wc*16, kk);
    unsigned bb[4]; ldsmB2(bb, uX, wm*16, kk);
    mma16(acc[0], a, bb[0], bb[1]);
    mma16(acc[1], a, bb[2], bb[3]);
  }
  int cc0 = wc*16 + g;
  float bv0 = bias[o0+cc0], bv1 = bias[o0+cc0+8];
  if (dstV){
    #pragma unroll
    for (int oct=0; oct<2; oct++){
      int col = p0 + wm*16 + oct*8 + 2*tq;
      dstV[((size_t)(b*64 + crel + cc0  ))*512 + (col>>1)] = pack2h(acc[oct][0]+bv0, acc[oct][1]+bv0);
      dstV[((size_t)(b*64 + crel + cc0+8))*512 + (col>>1)] = pack2h(acc[oct][2]+bv1, acc[oct][3]+bv1);
    }
  } else {
    __syncthreads();
    #pragma unroll
    for (int oct=0; oct<2; oct++){
      int col = wm*16 + oct*8 + 2*tq;
      sT[(col  )*34 + cc0  ] = __float2half(acc[oct][0]+bv0);
      sT[(col+1)*34 + cc0  ] = __float2half(acc[oct][1]+bv0);
      sT[(col  )*34 + cc0+8] = __float2half(acc[oct][2]+bv1);
      sT[(col+1)*34 + cc0+8] = __float2half(acc[oct][3]+bv1);
    }
    __syncthreads();
    for (int idx=tid; idx<1024; idx+=256){
      int px = idx>>4, wj = idx&15;
      __half2 hv;
      hv.x = sT[px*34 + 2*wj];
      hv.y = sT[px*34 + 2*wj + 1];
      dstT[((size_t)(b*1024 + p0 + px))*32 + (crel>>1) + wj] = *(unsigned*)&hv;
    }
  }
}

// ------------------- pass 1 (pipelined K): row softmax stats ----------
__global__ __launch_bounds__(256) void qk_stats(){
  __shared__ unsigned uQ[2048];
  __shared__ unsigned uK[2][2][2048];
  __shared__ float sM[2][64], sL[2][64];
  int b = blockIdx.x, n0 = blockIdx.y*64, which = blockIdx.z;
  const unsigned* qsrc = g_qT + (size_t)(b*1024 + n0)*32;
  const unsigned* ksrc = g_kT[which] + (size_t)b*1024*32;
  int tid=threadIdx.x, warp=tid>>5, tq=(tid&31)&3;
  int g = (tid&31)>>2;
  int wn = warp&3, wm = warp>>2;
  loadTile(uQ, qsrc, 32, tid);
  loadTileAsync(uK[0][0], ksrc, 32, tid);
  loadTileAsync(uK[0][1], ksrc + 64*32, 32, tid);
  CP_COMMIT;
  CP_WAIT0;
  __syncthreads();
  float M0=-1e30f, M1=-1e30f, L0=0.f, L1=0.f;
  for (int it=0; it<8; it++){
    int cur = it&1;
    if (it < 7){
      const unsigned* kn = ksrc + (size_t)(it+1)*128*32;
      loadTileAsync(uK[cur^1][0], kn, 32, tid);
      loadTileAsync(uK[cur^1][1], kn + 64*32, 32, tid);
      CP_COMMIT;
    }
    const unsigned* kt = uK[cur][wm];
    float cfr[8][4];
    #pragma unroll
    for(int mf=0;mf<8;mf++){cfr[mf][0]=0.f;cfr[mf][1]=0.f;cfr[mf][2]=0.f;cfr[mf][3]=0.f;}
    #pragma unroll
    for (int kk=0; kk<4; kk++){
      unsigned a[4]; ldsmA(a, uQ, wn*16, kk);
      #pragma unroll
      for (int mp=0; mp<4; mp++){
        unsigned bb[4]; ldsmB2(bb, kt, mp*16, kk);
        mma16(cfr[2*mp  ], a, bb[0], bb[1]);
        mma16(cfr[2*mp+1], a, bb[2], bb[3]);
      }
    }
    float tm0=-1e30f, tm1=-1e30f;
    #pragma unroll
    for(int mf=0;mf<8;mf++){
      tm0 = fmaxf(tm0, fmaxf(cfr[mf][0], cfr[mf][1]));
      tm1 = fmaxf(tm1, fmaxf(cfr[mf][2], cfr[mf][3]));
    }
    tm0 = fmaxf(tm0, __shfl_xor_sync(0xffffffffu, tm0, 1));
    tm0 = fmaxf(tm0, __shfl_xor_sync(0xffffffffu, tm0, 2));
    tm1 = fmaxf(tm1, __shfl_xor_sync(0xffffffffu, tm1, 1));
    tm1 = fmaxf(tm1, __shfl_xor_sync(0xffffffffu, tm1, 2));
    float nM0 = fmaxf(M0, tm0), nM1 = fmaxf(M1, tm1);
    float c0 = nM0*LOG2E, c1 = nM1*LOG2E;
    float s0=0.f, s1=0.f;
    #pragma unroll
    for(int mf=0;mf<8;mf++){
      float2 e0 = exp2_pair_f(__fmaf_rn(cfr[mf][0], LOG2E, -c0),
                              __fmaf_rn(cfr[mf][1], LOG2E, -c0));
      float2 e1 = exp2_pair_f(__fmaf_rn(cfr[mf][2], LOG2E, -c1),
                              __fmaf_rn(cfr[mf][3], LOG2E, -c1));
      s0 += e0.x + e0.y;
      s1 += e1.x + e1.y;
    }
    s0 += __shfl_xor_sync(0xffffffffu, s0, 1);
    s0 += __shfl_xor_sync(0xffffffffu, s0, 2);
    s1 += __shfl_xor_sync(0xffffffffu, s1, 1);
    s1 += __shfl_xor_sync(0xffffffffu, s1, 2);
    L0 = L0*__expf(M0-nM0) + s0; M0 = nM0;
    L1 = L1*__expf(M1-nM1) + s1; M1 = nM1;
    if (it < 7){ CP_WAIT0; }
    __syncthreads();
  }
  if (tq==0){
    sM[wm][wn*16+g  ] = M0; sL[wm][wn*16+g  ] = L0;
    sM[wm][wn*16+8+g] = M1; sL[wm][wn*16+8+g] = L1;
  }
  __syncthreads();
  if (tid<64){
    float Ma = sM[0][tid], Mb = sM[1][tid];
    float M  = fmaxf(Ma, Mb);
    float L  = sL[0][tid]*__expf(Ma-M) + sL[1][tid]*__expf(Mb-M);
    g_roff[which][b*HW + n0 + tid] = __fmaf_rn(M, LOG2E, __log2f(L));
  }
}

// ------------------- merged pass 2 + tail (pipelined Q/V) ----------------------
__global__ __launch_bounds__(512,1) void av_tail(const float* __restrict__ z1_w,
                                                 const float* __restrict__ z1_b,
                                                 const float* __restrict__ z2_b,
                                                 float* __restrict__ out, int t, int ws)
{
  extern __shared__ unsigned arena[];
  int b = blockIdx.x, m0 = blockIdx.y*64;
  int p0 = m0;
  int tid = threadIdx.x;
  int lane = tid & 31, g = lane>>2, tq = lane&3;

  // ================= AV phase =================
  {
    int which = tid >> 8;
    int ltid  = tid & 255;
    int warp8 = ltid >> 5;
    int wr = warp8 & 3, wm = warp8 >> 2;
    unsigned* base = arena + which*12416;
    unsigned* uK  = base;
    unsigned* uQb = base + 2048;   // [2][2048]
    unsigned* uVb = base + 6144;   // [2][2048]
    unsigned* uP  = base + 10240;
    float*   sro  = (float*)(base + 12288);  // [2][64]
    const unsigned* qsrc = g_qT + (size_t)b*1024*32;
    const unsigned* ksrc = g_kT[which] + (size_t)(b*1024 + m0)*32;
    const unsigned* vsrc = g_vv[which] + (size_t)b*64*512;
    const float*    roff = g_roff[which] + b*HW;

    loadTile(uK, ksrc, 32, ltid);
    loadTileAsync(uQb, qsrc, 32, ltid);
    loadTileAsync(uVb, vsrc, 512, ltid);
    CP_COMMIT;
    if (ltid < 64) sro[ltid] = roff[ltid];
    float accZ[4][4];
    #pragma unroll
    for(int mf=0;mf<4;mf++){accZ[mf][0]=0.f;accZ[mf][1]=0.f;accZ[mf][2]=0.f;accZ[mf][3]=0.f;}
    CP_WAIT0;
    __syncthreads();

    for (int itn=0; itn<16; itn++){
      int nb = itn*64;
      int cur = itn&1;
      unsigned* uQ = uQb + cur*2048;
      unsigned* uV = uVb + cur*2048;
      float*   sr  = sro + cur*64;
      if (itn < 15){
        loadTileAsync(uQb + (cur^1)*2048, qsrc + (size_t)(nb+64)*32, 32, ltid);
        loadTileAsync(uVb + (cur^1)*2048, vsrc + ((nb+64)>>1), 512, ltid);
        CP_COMMIT;
        if (ltid < 64) sro[(cur^1)*64 + ltid] = roff[nb+64+ltid];
      }
      float accS[4][4];
      #pragma unroll
      for(int mf=0;mf<4;mf++){accS[mf][0]=0.f;accS[mf][1]=0.f;accS[mf][2]=0.f;accS[mf][3]=0.f;}
      #pragma unroll
      for (int kk=0; kk<4; kk++){
        unsigned a[4]; ldsmA(a, uK, wr*16, kk);
        #pragma unroll
        for (int mp=0; mp<2; mp++){
          unsigned bb[4]; ldsmB2(bb, uQ, wm*32 + mp*16, kk);
          mma16(accS[2*mp  ], a, bb[0], bb[1]);
          mma16(accS[2*mp+1], a, bb[2], bb[3]);
        }
      }
      #pragma unroll
      for (int mf=0; mf<4; mf++){
        int n = wm*32 + mf*8 + 2*tq;
        float ro0 = sr[n], ro1 = sr[n+1];
        int jn = n >> 1;
        int r0 = wr*16 + g;
        uP[tw(r0,   jn)] = exp2_pair_h(__fmaf_rn(accS[mf][0], LOG2E, -ro0),
                                       __fmaf_rn(accS[mf][1], LOG2E, -ro1));
        uP[tw(r0+8, jn)] = exp2_pair_h(__fmaf_rn(accS[mf][2], LOG2E, -ro0),
                                       __fmaf_rn(accS[mf][3], LOG2E, -ro1));
      }
      __syncthreads();
      #pragma unroll
      for (int kk=0; kk<4; kk++){
        unsigned a[4]; ldsmA(a, uV, wr*16, kk);
        #pragma unroll
        for (int mp=0; mp<2; mp++){
          unsigned bb[4]; ldsmB2(bb, uP, wm*32 + mp*16, kk);
          mma16(accZ[2*mp  ], a, bb[0], bb[1]);
          mma16(accZ[2*mp+1], a, bb[2], bb[3]);
        }
      }
      if (itn < 15){ CP_WAIT0; }
      __syncthreads();
    }
    // write Zcat tile to smem (tf32)
    unsigned* sZc = arena;
    int zoff = which*64;
    #pragma unroll
    for (int mf=0; mf<4; mf++){
      int r0 = zoff + wr*16 + g, r1 = r0 + 8;
      int col = wm*32 + mf*8 + 2*tq;
      *(uint2*)&sZc[r0*72 + col] = make_uint2(f2t(accZ[mf][0]), f2t(accZ[mf][1]));
      *(uint2*)&sZc[r1*72 + col] = make_uint2(f2t(accZ[mf][2]), f2t(accZ[mf][3]));
    }
  }
  // ================= tail phase =================
  unsigned* sZc = arena;                 // [128][72] tf32
  unsigned* uz1 = arena + 9216;          // [64][132]
  unsigned* sOh = arena + 17664;         // [64][72]
  unsigned* sZ  = arena + 22272;         // [64][72]
  unsigned* wch = arena + 26880;         // [8][200]
  float*  gates = (float*)arena;         // [192][66]

  for (int idx=tid; idx<8192; idx+=512){
    int o = idx>>7, c = idx&127;
    uz1[o*132+c] = f2t(z1_w[o*128+c]);
  }
  for (int idx=tid; idx<2048; idx+=512){
    int c = idx>>5, p2 = idx&31;
    float2 v = *(const float2*)&g_oh[((size_t)b*64+c)*HW + p0 + 2*p2];
    *(uint2*)&sOh[c*72 + 2*p2] = make_uint2(f2t(v.x), f2t(v.y));
  }
  __syncthreads();

  int warp16 = tid>>5;
  int wc = warp16 & 1, wm8 = warp16 >> 1;

  // ---- z1 ----
  float a1[2][4];
  #pragma unroll
  for(int ot=0;ot<2;ot++){a1[ot][0]=0.f;a1[ot][1]=0.f;a1[ot][2]=0.f;a1[ot][3]=0.f;}
  for (int cc=0; cc<128; cc+=8){
    unsigned b0 = sZc[(cc+tq  )*72 + wm8*8 + g];
    unsigned b1 = sZc[(cc+tq+4)*72 + wm8*8 + g];
    #pragma unroll
    for (int ot=0; ot<2; ot++){
      unsigned a[4];
      int r = ot*32 + wc*16 + g;
      a[0]=uz1[(r  )*132 + cc+tq];   a[1]=uz1[(r+8)*132 + cc+tq];
      a[2]=uz1[(r  )*132 + cc+tq+4]; a[3]=uz1[(r+8)*132 + cc+tq+4];
      mma8(a1[ot], a, b0, b1);
    }
  }
  __syncthreads();
  #pragma unroll
  for (int ot=0; ot<2; ot++){
    int r0 = ot*32 + wc*16 + g, r1 = r0 + 8;
    int col = wm8*8 + 2*tq;
    float bv0 = z1_b[r0], bv1 = z1_b[r1];
    *(uint2*)&sZ[r0*72 + col] = make_uint2(f2t(a1[ot][0]+bv0), f2t(a1[ot][1]+bv0));
    *(uint2*)&sZ[r1*72 + col] = make_uint2(f2t(a1[ot][2]+bv1), f2t(a1[ot][3]+bv1));
  }
  // ---- z2 ----
  float a2[6][4];
  #pragma unroll
  for(int ot=0;ot<6;ot++){a2[ot][0]=0.f;a2[ot][1]=0.f;a2[ot][2]=0.f;a2[ot][3]=0.f;}
  for (int cc=0; cc<128; cc+=8){
    __syncthreads();
    for (int idx=tid; idx<1536; idx+=512){
      int r = idx/192, o = idx - r*192;
      wch[r*200 + o] = g_z2T[(cc+r)*192 + o];
    }
    __syncthreads();
    const unsigned* src = (cc<64) ? (sZ + cc*72) : (sOh + (cc-64)*72);
    unsigned b0 = src[ tq   *72 + wm8*8 + g];
    unsigned b1 = src[(tq+4)*72 + wm8*8 + g];
    #pragma unroll
    for (int ot=0; ot<6; ot++){
      unsigned a[4];
      int o = ot*32 + wc*16 + g;
      a[0]=wch[ tq   *200 + o];   a[1]=wch[ tq   *200 + o+8];
      a[2]=wch[(tq+4)*200 + o];   a[3]=wch[(tq+4)*200 + o+8];
      mma8(a2[ot], a, b0, b1);
    }
  }
  __syncthreads();
  #pragma unroll
  for (int ot=0; ot<6; ot++){
    int r0 = ot*32 + wc*16 + g, r1 = r0 + 8;
    int col = wm8*8 + 2*tq;
    float bv0 = z2_b[r0], bv1 = z2_b[r1];
    *(float2*)&gates[r0*66 + col] = make_float2(a2[ot][0]+bv0, a2[ot][1]+bv0);
    *(float2*)&gates[r1*66 + col] = make_float2(a2[ot][2]+bv1, a2[ot][3]+bv1);
  }
  __syncthreads();
  // ---- gating epilogue ----
  for (int i=tid; i<4096; i+=512){
    int c = i>>6, p = i&63;
    float vo = gates[(c     )*66 + p];
    float vg = gates[(64 +c )*66 + p];
    float vi = gates[(128+c )*66 + p];
    int idx = (b*64 + c)*1024 + p0 + p;
    float si = sigm(vi);
    float om  = tfast(vg)*si + (1.f-si)*g_im[idx];
    float oh2 = sigm(vo)*om;
    g_im[idx] = om;
    g_ih[idx] = oh2;
    out[(((size_t)b*TT + t)*64 + c)*HW + p0 + p] = oh2;
    if (ws){
      float* st = out + (size_t)BB*TT*64*HW;
      st[idx]            = oh2;
      st[NSTATE + idx]   = g_ic[idx];
      st[2*NSTATE + idx] = om;
    }
  }
}

extern "C" void kernel_launch(void* const* d_in, const int* in_sizes, int n_in,
                              void* d_out, int out_size)
{
  const float* inputs = (const float*)d_in[0];
  const float* conv_w = (const float*)d_in[1];
  const float* conv_b = (const float*)d_in[2];
  const float* gn_g   = (const float*)d_in[3];
  const float* gn_b   = (const float*)d_in[4];
  const float* h_w    = (const float*)d_in[5];
  const float* h_b    = (const float*)d_in[6];
  const float* m_w    = (const float*)d_in[7];
  const float* m_b    = (const float*)d_in[8];
  const float* z1_w   = (const float*)d_in[9];
  const float* z1_b   = (const float*)d_in[10];
  const float* z2_w   = (const float*)d_in[11];
  const float* z2_b   = (const float*)d_in[12];
  float* out = (float*)d_out;

  const int AT_SMEM = 28480*4;   // 113920
  cudaFuncSetAttribute(av_tail, cudaFuncAttributeMaxDynamicSharedMemorySize, AT_SMEM);

  zero_states<<<2048,256>>>();
  wtrans<<<256,256>>>(conv_w, z2_w, h_w, m_w);
  int write_states = (out_size >= (int)(BB*TT*64*HW + 3*NSTATE)) ? 1 : 0;

  for (int t=0; t<TT; t++){
    conv_tc<<<dim3(8,4,8),256>>>(inputs, conv_b, t);
    gn_lstm4<<<512,256>>>(gn_g, gn_b, t);
    lin_hm<<<dim3(8,10,16),256>>>(h_b, m_b);
    qk_stats<<<dim3(8,16,2),256>>>();
    av_tail<<<dim3(8,16),512,AT_SMEM>>>(z1_w, z1_b, z2_b, out, t, (t==TT-1) ? write_states : 0);
  }
}

// round 13
// speedup vs baseline: 3.4726x; 1.0091x over previous
#include <cuda_runtime.h>
#include <cuda_fp16.h>
#include <math.h>

#define BB 8
#define TT 8
#define HW 1024
#define CG 256
#define NSTATE (BB*64*HW)   // 524288
#define LOG2E 1.4426950408889634f

// ---- persistent state ----
__device__ float g_ih[NSTATE];
__device__ float g_ic[NSTATE];
__device__ float g_im[NSTATE];
// ---- scratch ----
__device__ float g_gates[BB*CG*HW];
__device__ float g_gsum [2][64];
__device__ float g_gsum2[2][64];
__device__ float g_oh[NSTATE];
__device__ float g_roff[2][BB*HW];
__device__ unsigned g_wTh[8*9*256*8];
__device__ unsigned g_z2T[128*192];
__device__ unsigned g_hmw[10*1024];
__device__ unsigned g_qT[8*1024*32];
__device__ unsigned g_kT[2][8*1024*32];
__device__ unsigned g_vv[2][8*64*512];

__device__ __forceinline__ float sigm(float x){
  float e = __expf(-x);
  float r; asm("rcp.approx.f32 %0,%1;" : "=f"(r) : "f"(1.f+e));
  return r;
}
__device__ __forceinline__ float tfast(float x){
  return __fmaf_rn(2.f, sigm(2.f*x), -1.f);
}
__device__ __forceinline__ unsigned f2t(float x){
  unsigned r; asm("cvt.rna.tf32.f32 %0,%1;" : "=r"(r) : "f"(x)); return r;
}
__device__ __forceinline__ void mma8(float* d, const unsigned* a, unsigned b0, unsigned b1){
  asm volatile("mma.sync.aligned.m16n8k8.row.col.f32.tf32.tf32.f32 "
    "{%0,%1,%2,%3},{%4,%5,%6,%7},{%8,%9},{%0,%1,%2,%3};"
    : "+f"(d[0]),"+f"(d[1]),"+f"(d[2]),"+f"(d[3])
    : "r"(a[0]),"r"(a[1]),"r"(a[2]),"r"(a[3]),"r"(b0),"r"(b1));
}
__device__ __forceinline__ void mma16(float* d, const unsigned* a, unsigned b0, unsigned b1){
  asm volatile("mma.sync.aligned.m16n8k16.row.col.f32.f16.f16.f32 "
    "{%0,%1,%2,%3},{%4,%5,%6,%7},{%8,%9},{%0,%1,%2,%3};"
    : "+f"(d[0]),"+f"(d[1]),"+f"(d[2]),"+f"(d[3])
    : "r"(a[0]),"r"(a[1]),"r"(a[2]),"r"(a[3]),"r"(b0),"r"(b1));
}
__device__ __forceinline__ unsigned pack2h(float x, float y){
  __half2 h = __floats2half2_rn(x, y);
  return *(unsigned*)&h;
}
__device__ __forceinline__ unsigned exp2_pair_h(float x0, float x1){
  __half2 h = h2exp2(__floats2half2_rn(x0, x1));
  return *(unsigned*)&h;
}
__device__ __forceinline__ float2 exp2_pair_f(float x0, float x1){
  __half2 h = h2exp2(__floats2half2_rn(x0, x1));
  return __half22float2(h);
}

__device__ __forceinline__ int tw(int row, int j){ return row*32 + (j ^ ((row&7)<<2)); }

__device__ __forceinline__ unsigned saddr(const unsigned* p){
  return (unsigned)__cvta_generic_to_shared((const void*)p);
}
__device__ __forceinline__ void cpa16(unsigned* sdst, const void* gsrc){
  unsigned ad = saddr(sdst);
  asm volatile("cp.async.cg.shared.global [%0], [%1], 16;" :: "r"(ad), "l"(gsrc));
}
#define CP_COMMIT asm volatile("cp.async.commit_group;")
#define CP_WAIT0  asm volatile("cp.async.wait_group 0;")

__device__ __forceinline__ void loadTile(unsigned* dst, const unsigned* __restrict__ src,
                                         int rowstride, int ltid){
  #pragma unroll
  for (int it=0; it<2; it++){
    int idx = it*256 + ltid;
    int row = idx>>3, j4 = (idx&7)*4;
    uint4 v = *(const uint4*)(src + (size_t)row*rowstride + j4);
    *(uint4*)&dst[tw(row, j4)] = v;
  }
}
__device__ __forceinline__ void loadTileAsync(unsigned* dst, const unsigned* __restrict__ src,
                                              int rowstride, int ltid){
  #pragma unroll
  for (int it=0; it<2; it++){
    int idx = it*256 + ltid;
    int row = idx>>3, j4 = (idx&7)*4;
    cpa16(dst + tw(row, j4), src + (size_t)row*rowstride + j4);
  }
}
__device__ __forceinline__ void ldsmA(unsigned* a, const unsigned* t, int r, int kk){
  int lane = threadIdx.x & 31;
  int row = r + (lane&7) + (lane&8);
  int j   = kk*8 + ((lane>>4)<<2);
  unsigned ad = saddr(t + tw(row, j));
  asm volatile("ldmatrix.sync.aligned.m8n8.x4.shared.b16 {%0,%1,%2,%3}, [%4];"
    : "=r"(a[0]),"=r"(a[1]),"=r"(a[2]),"=r"(a[3]) : "r"(ad));
}
__device__ __forceinline__ void ldsmB2(unsigned* b, const unsigned* t, int nb, int kk){
  int lane = threadIdx.x & 31;
  int row = nb + (lane&7) + ((lane>>4)<<3);
  int j   = kk*8 + (((lane>>3)&1)<<2);
  unsigned ad = saddr(t + tw(row, j));
  asm volatile("ldmatrix.sync.aligned.m8n8.x4.shared.b16 {%0,%1,%2,%3}, [%4];"
    : "=r"(b[0]),"=r"(b[1]),"=r"(b[2]),"=r"(b[3]) : "r"(ad));
}

__global__ void zero_states(){
  int i = blockIdx.x*256 + threadIdx.x;
  if (i < NSTATE){ g_ih[i]=0.f; g_ic[i]=0.f; g_im[i]=0.f; }
  if (blockIdx.x==0 && threadIdx.x<64){
    g_gsum[0][threadIdx.x]=0.f; g_gsum2[0][threadIdx.x]=0.f;
    g_gsum[1][threadIdx.x]=0.f; g_gsum2[1][threadIdx.x]=0.f;
  }
}

__global__ void wtrans(const float* __restrict__ w, const float* __restrict__ z2w,
                       const float* __restrict__ hw, const float* __restrict__ mw){
  int co = blockIdx.x;
  for (int idx = threadIdx.x; idx < 576; idx += 256){
    int chunk = idx/72, r = idx - chunk*72, pos = r>>3, j = r&7;
    int ci = chunk*16 + 2*j;
    float v0 = w[((size_t)co*128 + ci  )*9 + pos];
    float v1 = w[((size_t)co*128 + ci+1)*9 + pos];
    g_wTh[((size_t)(chunk*9+pos)*256 + co)*8 + j] = pack2h(v0, v1);
  }
  if (co < 192){
    for (int c = threadIdx.x; c < 128; c += 256)
      g_z2T[c*192 + co] = f2t(z2w[co*128 + c]);
    if (threadIdx.x < 32){
      int j = threadIdx.x;
      int y = co>>5, row = co&31;
      g_hmw[y*1024 + tw(row, j)] = pack2h(hw[co*64 + 2*j], hw[co*64 + 2*j + 1]);
    }
  }
  if (co < 128 && threadIdx.x >= 32 && threadIdx.x < 64){
    int j = threadIdx.x - 32;
    int y = 6 + (co>>5), row = co&31;
    g_hmw[y*1024 + tw(row, j)] = pack2h(mw[co*64 + 2*j], mw[co*64 + 2*j + 1]);
  }
}

// ------------- 3x3 conv (fp16 TC, pipelined staging) + fused GN stats -------
__global__ __launch_bounds__(256) void conv_tc(const float* __restrict__ xin,
                                               const float* __restrict__ bias, int t)
{
  int pt = blockIdx.x, cot = blockIdx.y, b = blockIdx.z;
  int y0 = pt*4, co0 = cot*64, par = t & 1;
  __shared__ unsigned sIn[8*232];
  __shared__ unsigned sW[2][4608];
  __shared__ float ws[8], ws2[8];
  int tid=threadIdx.x, warp=tid>>5, lane=tid&31, g=lane>>2, tq=lane&3;
  int wc = warp&3, wm = warp>>2;
  float acc[8][4];
  #pragma unroll
  for(int j=0;j<8;j++){acc[j][0]=0.f;acc[j][1]=0.f;acc[j][2]=0.f;acc[j][3]=0.f;}

  int pix = tid;
  int yy = pix/34, xx = pix - yy*34;
  int gy = y0-1+yy, gx = xx-1;
  bool pv = (pix<204) && ((unsigned)gy<32u) && ((unsigned)gx<32u);
  int gidx = gy*32 + gx;

  const float* xbase = xin + (size_t)(b*TT+t)*64*HW;
  const float* hbase = g_ih + (size_t)b*64*HW;

  float rin[16];
  {
    const float* src = xbase;
    #pragma unroll
    for (int j=0;j<8;j++){
      rin[2*j]=0.f; rin[2*j+1]=0.f;
      if (pv){ rin[2*j] = src[(size_t)(2*j)*HW + gidx]; rin[2*j+1] = src[(size_t)(2*j+1)*HW + gidx]; }
    }
  }
  for (int i4=tid; i4<1152; i4+=256)
    cpa16(&sW[0][i4*4], g_wTh + (size_t)0*9*2048 + co0*8 + (i4>>7)*2048 + (i4&127)*4);
  CP_COMMIT;

  for (int chunk=0; chunk<8; chunk++){
    int cb = chunk&1;
    __syncthreads();
    if (pix < 204){
      #pragma unroll
      for (int j=0;j<8;j++) sIn[j*232 + pix] = pack2h(rin[2*j], rin[2*j+1]);
    }
    CP_WAIT0;
    __syncthreads();
    if (chunk < 7){
      const float* src = (chunk+1<4) ? (xbase + (size_t)(chunk+1)*16*HW)
                                     : (hbase + (size_t)(chunk+1-4)*16*HW);
      #pragma unroll
      for (int j=0;j<8;j++){
        rin[2*j]=0.f; rin[2*j+1]=0.f;
        if (pv){ rin[2*j] = src[(size_t)(2*j)*HW + gidx]; rin[2*j+1] = src[(size_t)(2*j+1)*HW + gidx]; }
      }
      for (int i4=tid; i4<1152; i4+=256)
        cpa16(&sW[cb^1][i4*4], g_wTh + (size_t)(chunk+1)*9*2048 + co0*8 + (i4>>7)*2048 + (i4&127)*4);
      CP_COMMIT;
    }
    #pragma unroll
    for (int pos=0; pos<9; pos++){
      int ky = pos/3, kx = pos - 3*ky;
      unsigned a[4];
      int rb = pos*512 + (wc*16+g)*8;
      a[0] = sW[cb][rb + tq];       a[1] = sW[cb][rb + 64 + tq];
      a[2] = sW[cb][rb + tq + 4];   a[3] = sW[cb][rb + 64 + tq + 4];
      #pragma unroll
      for (int mf=0; mf<8; mf++){
        int p = wm*64 + mf*8 + g;
        int pixb = ((p>>5)+ky)*34 + (p&31) + kx;
        mma16(acc[mf], a, sIn[tq*232 + pixb], sIn[(tq+4)*232 + pixb]);
      }
    }
  }
  int r0 = co0 + wc*16 + g, r1 = r0 + 8;
  float bv0 = bias[r0], bv1 = bias[r1];
  float s=0.f, s2=0.f;
  #pragma unroll
  for (int mf=0; mf<8; mf++){
    int col = y0*32 + wm*64 + mf*8 + 2*tq;
    float v0=acc[mf][0]+bv0, v1=acc[mf][1]+bv0;
    float v2=acc[mf][2]+bv1, v3=acc[mf][3]+bv1;
    *(float2*)&g_gates[((size_t)b*CG + r0)*HW + col] = make_float2(v0,v1);
    *(float2*)&g_gates[((size_t)b*CG + r1)*HW + col] = make_float2(v2,v3);
    s  += v0+v1+v2+v3;
    s2 += v0*v0+v1*v1+v2*v2+v3*v3;
  }
  #pragma unroll
  for (int off=16; off; off>>=1){
    s  += __shfl_xor_sync(0xffffffffu, s , off);
    s2 += __shfl_xor_sync(0xffffffffu, s2, off);
  }
  if (lane==0){ ws[warp]=s; ws2[warp]=s2; }
  __syncthreads();
  if (tid<2){
    float S  = ws [tid*2]+ws [tid*2+1]+ws [tid*2+4]+ws [tid*2+5];
    float S2 = ws2[tid*2]+ws2[tid*2+1]+ws2[tid*2+4]+ws2[tid*2+5];
    int gidx2 = b*8 + (co0>>5) + tid;
    atomicAdd(&g_gsum [par][gidx2], S );
    atomicAdd(&g_gsum2[par][gidx2], S2);
  }
}

// ------------------- GN apply + LSTM gating (8 px/thread) -------------------
__global__ void gn_lstm8(const float* __restrict__ gg, const float* __restrict__ gb, int t){
  int bci = blockIdx.x;            // 256 blocks
  int b = bci >> 5;
  int c0 = (bci & 31)*2;
  int ch = threadIdx.x >> 7;
  int c  = c0 + ch;
  int p  = (threadIdx.x & 127)*8;
  int par = t & 1;
  __shared__ float smu[4], srs[4];
  if (threadIdx.x < 4){
    int grp = (c0 >> 5) + threadIdx.x*2;
    float s  = g_gsum [par][b*8+grp];
    float s2 = g_gsum2[par][b*8+grp];
    float m   = s*(1.f/32768.f);
    float var = s2*(1.f/32768.f) - m*m;
    smu[threadIdx.x] = m;
    srs[threadIdx.x] = rsqrtf(var + 1e-5f);
  }
  if (bci==0 && threadIdx.x<64){
    g_gsum[par^1][threadIdx.x]=0.f; g_gsum2[par^1][threadIdx.x]=0.f;
  }
  __syncthreads();
  const float* gt = g_gates + (size_t)b*CG*HW + p;
  float vi[8], vf[8], vcg[8], vo[8], ic[8];
  *(float4*)&vi[0]  = *(const float4*)&gt[(size_t)(c      )*HW];
  *(float4*)&vi[4]  = *(const float4*)&gt[(size_t)(c      )*HW + 4];
  *(float4*)&vf[0]  = *(const float4*)&gt[(size_t)(c + 64 )*HW];
  *(float4*)&vf[4]  = *(const float4*)&gt[(size_t)(c + 64 )*HW + 4];
  *(float4*)&vcg[0] = *(const float4*)&gt[(size_t)(c + 128)*HW];
  *(float4*)&vcg[4] = *(const float4*)&gt[(size_t)(c + 128)*HW + 4];
  *(float4*)&vo[0]  = *(const float4*)&gt[(size_t)(c + 192)*HW];
  *(float4*)&vo[4]  = *(const float4*)&gt[(size_t)(c + 192)*HW + 4];
  int idx = (b*64 + c)*1024 + p;
  *(float4*)&ic[0] = *(const float4*)&g_ic[idx];
  *(float4*)&ic[4] = *(const float4*)&g_ic[idx + 4];
  float gi=gg[c], gf=gg[c+64], gc=gg[c+128], go=gg[c+192];
  float bi=gb[c], bf=gb[c+64], bc=gb[c+128], bo=gb[c+192];
  float oc[8], oh[8];
  #pragma unroll
  for (int e=0; e<8; e++){
    float a  = (vi[e] -smu[0])*srs[0]*gi + bi;
    float f2 = (vf[e] -smu[1])*srs[1]*gf + bf;
    float cc = (vcg[e]-smu[2])*srs[2]*gc + bc;
    float o  = (vo[e] -smu[3])*srs[3]*go + bo;
    oc[e] = ic[e]*sigm(f2) + sigm(a)*tfast(cc);
    oh[e] = sigm(o)*tfast(oc[e]);
  }
  *(float4*)&g_ic[idx]     = *(float4*)&oc[0];
  *(float4*)&g_ic[idx + 4] = *(float4*)&oc[4];
  *(float4*)&g_oh[idx]     = *(float4*)&oh[0];
  *(float4*)&g_oh[idx + 4] = *(float4*)&oh[4];
}

// ------------------- QKV projections (fp16 TC) -------------------------------
// Q/K tiles computed TRANSPOSED (A=x rows=px, B=w rows=o) for direct [n][c-pair] stores
__global__ __launch_bounds__(256) void lin_hm(const float* __restrict__ h_b,
                                              const float* __restrict__ m_b)
{
  __shared__ unsigned uW[1024];
  __shared__ unsigned uX[2048];
  int b = blockIdx.x, p0 = blockIdx.z*64, yb = blockIdx.y;
  const float* x1  = (yb < 6) ? g_oh : g_im;
  const float* bias= (yb < 6) ? h_b  : m_b;
  int o0 = (yb < 6) ? yb*32 : (yb-6)*32;
  unsigned* dstT = 0; unsigned* dstV = 0; int crel = 0;
  if (yb < 6){
    if      (o0 <  64){ dstT = g_qT;    crel = o0;       }
    else if (o0 < 128){ dstT = g_kT[0]; crel = o0 - 64;  }
    else              { dstV = g_vv[0]; crel = o0 - 128; }
  } else {
    if (o0 < 64){ dstT = g_kT[1]; crel = o0; }
    else        { dstV = g_vv[1]; crel = o0 - 64; }
  }

  int tid=threadIdx.x, warp=tid>>5, lane=tid&31, g=lane>>2, tq=lane&3;
  for (int idx=tid; idx<1024; idx+=256) uW[idx] = g_hmw[yb*1024 + idx];
  const float* xb = x1 + (size_t)b*64*HW + p0;
  #pragma unroll
  for (int it=0; it<8; it++){
    int idx = it*256 + tid;
    int px = idx & 63, j = idx >> 6;
    float v0 = xb[(size_t)(2*j  )*HW + px];
    float v1 = xb[(size_t)(2*j+1)*HW + px];
    uX[tw(px, j)] = pack2h(v0, v1);
  }
  __syncthreads();
  if (dstV){
    int wc = warp&1, wm = warp>>1;
    float acc[2][4];
    acc[0][0]=acc[0][1]=acc[0][2]=acc[0][3]=0.f;
    acc[1][0]=acc[1][1]=acc[1][2]=acc[1][3]=0.f;
    #pragma unroll
    for (int kk=0; kk<4; kk++){
      unsigned a[4]; ldsmA(a, uW, wc*16, kk);
      unsigned bb[4]; ldsmB2(bb, uX, wm*16, kk);
      mma16(acc[0], a, bb[0], bb[1]);
      mma16(acc[1], a, bb[2], bb[3]);
    }
    int cc0 = wc*16 + g;
    float bv0 = bias[o0+cc0], bv1 = bias[o0+cc0+8];
    #pragma unroll
    for (int oct=0; oct<2; oct++){
      int col = p0 + wm*16 + oct*8 + 2*tq;
      dstV[((size_t)(b*64 + crel + cc0  ))*512 + (col>>1)] = pack2h(acc[oct][0]+bv0, acc[oct][1]+bv0);
      dstV[((size_t)(b*64 + crel + cc0+8))*512 + (col>>1)] = pack2h(acc[oct][2]+bv1, acc[oct][3]+bv1);
    }
  } else {
    // transposed: D[px][o]
    int wpx = warp&3, wo = warp>>2;
    float acc[2][4];
    acc[0][0]=acc[0][1]=acc[0][2]=acc[0][3]=0.f;
    acc[1][0]=acc[1][1]=acc[1][2]=acc[1][3]=0.f;
    #pragma unroll
    for (int kk=0; kk<4; kk++){
      unsigned a[4]; ldsmA(a, uX, wpx*16, kk);
      unsigned bb[4]; ldsmB2(bb, uW, wo*16, kk);
      mma16(acc[0], a, bb[0], bb[1]);
      mma16(acc[1], a, bb[2], bb[3]);
    }
    int row0 = wpx*16 + g;
    #pragma unroll
    for (int oct=0; oct<2; oct++){
      int col = wo*16 + oct*8 + 2*tq;          // o rel
      float b0 = bias[o0+col], b1 = bias[o0+col+1];
      int wj = (crel + col) >> 1;
      dstT[((size_t)(b*1024 + p0 + row0  ))*32 + wj] = pack2h(acc[oct][0]+b0, acc[oct][1]+b1);
      dstT[((size_t)(b*1024 + p0 + row0+8))*32 + wj] = pack2h(acc[oct][2]+b0, acc[oct][3]+b1);
    }
  }
}

// ------------------- pass 1 (pipelined K): row softmax stats ----------
__global__ __launch_bounds__(256) void qk_stats(){
  __shared__ unsigned uQ[2048];
  __shared__ unsigned uK[2][2][2048];
  __shared__ float sM[2][64], sL[2][64];
  int b = blockIdx.x, n0 = blockIdx.y*64, which = blockIdx.z;
  const unsigned* qsrc = g_qT + (size_t)(b*1024 + n0)*32;
  const unsigned* ksrc = g_kT[which] + (size_t)b*1024*32;
  int tid=threadIdx.x, warp=tid>>5, tq=(tid&31)&3;
  int g = (tid&31)>>2;
  int wn = warp&3, wm = warp>>2;
  loadTile(uQ, qsrc, 32, tid);
  loadTileAsync(uK[0][0], ksrc, 32, tid);
  loadTileAsync(uK[0][1], ksrc + 64*32, 32, tid);
  CP_COMMIT;
  CP_WAIT0;
  __syncthreads();
  float M0=-1e30f, M1=-1e30f, L0=0.f, L1=0.f;
  for (int it=0; it<8; it++){
    int cur = it&1;
    if (it < 7){
      const unsigned* kn = ksrc + (size_t)(it+1)*128*32;
      loadTileAsync(uK[cur^1][0], kn, 32, tid);
      loadTileAsync(uK[cur^1][1], kn + 64*32, 32, tid);
      CP_COMMIT;
    }
    const unsigned* kt = uK[cur][wm];
    float cfr[8][4];
    #pragma unroll
    for(int mf=0;mf<8;mf++){cfr[mf][0]=0.f;cfr[mf][1]=0.f;cfr[mf][2]=0.f;cfr[mf][3]=0.f;}
    #pragma unroll
    for (int kk=0; kk<4; kk++){
      unsigned a[4]; ldsmA(a, uQ, wn*16, kk);
      #pragma unroll
      for (int mp=0; mp<4; mp++){
        unsigned bb[4]; ldsmB2(bb, kt, mp*16, kk);
        mma16(cfr[2*mp  ], a, bb[0], bb[1]);
        mma16(cfr[2*mp+1], a, bb[2], bb[3]);
      }
    }
    float tm0=-1e30f, tm1=-1e30f;
    #pragma unroll
    for(int mf=0;mf<8;mf++){
      tm0 = fmaxf(tm0, fmaxf(cfr[mf][0], cfr[mf][1]));
      tm1 = fmaxf(tm1, fmaxf(cfr[mf][2], cfr[mf][3]));
    }
    tm0 = fmaxf(tm0, __shfl_xor_sync(0xffffffffu, tm0, 1));
    tm0 = fmaxf(tm0, __shfl_xor_sync(0xffffffffu, tm0, 2));
    tm1 = fmaxf(tm1, __shfl_xor_sync(0xffffffffu, tm1, 1));
    tm1 = fmaxf(tm1, __shfl_xor_sync(0xffffffffu, tm1, 2));
    float nM0 = fmaxf(M0, tm0), nM1 = fmaxf(M1, tm1);
    float c0 = nM0*LOG2E, c1 = nM1*LOG2E;
    float s0=0.f, s1=0.f;
    #pragma unroll
    for(int mf=0;mf<8;mf++){
      float2 e0 = exp2_pair_f(__fmaf_rn(cfr[mf][0], LOG2E, -c0),
                              __fmaf_rn(cfr[mf][1], LOG2E, -c0));
      float2 e1 = exp2_pair_f(__fmaf_rn(cfr[mf][2], LOG2E, -c1),
                              __fmaf_rn(cfr[mf][3], LOG2E, -c1));
      s0 += e0.x + e0.y;
      s1 += e1.x + e1.y;
    }
    s0 += __shfl_xor_sync(0xffffffffu, s0, 1);
    s0 += __shfl_xor_sync(0xffffffffu, s0, 2);
    s1 += __shfl_xor_sync(0xffffffffu, s1, 1);
    s1 += __shfl_xor_sync(0xffffffffu, s1, 2);
    L0 = L0*__expf(M0-nM0) + s0; M0 = nM0;
    L1 = L1*__expf(M1-nM1) + s1; M1 = nM1;
    if (it < 7){ CP_WAIT0; }
    __syncthreads();
  }
  if (tq==0){
    sM[wm][wn*16+g  ] = M0; sL[wm][wn*16+g  ] = L0;
    sM[wm][wn*16+8+g] = M1; sL[wm][wn*16+8+g] = L1;
  }
  __syncthreads();
  if (tid<64){
    float Ma = sM[0][tid], Mb = sM[1][tid];
    float M  = fmaxf(Ma, Mb);
    float L  = sL[0][tid]*__expf(Ma-M) + sL[1][tid]*__expf(Mb-M);
    g_roff[which][b*HW + n0 + tid] = __fmaf_rn(M, LOG2E, __log2f(L));
  }
}

// ------------------- merged pass 2 + tail (128-n iterations) --------------------
#define WB 22784   // per-which arena stride (words)
__global__ __launch_bounds__(512,1) void av_tail(const float* __restrict__ z1_w,
                                                 const float* __restrict__ z1_b,
                                                 const float* __restrict__ z2_b,
                                                 float* __restrict__ out, int t, int ws)
{
  extern __shared__ unsigned arena[];
  int b = blockIdx.x, m0 = blockIdx.y*64;
  int p0 = m0;
  int tid = threadIdx.x;
  int lane = tid & 31, g = lane>>2, tq = lane&3;

  // ================= AV phase =================
  {
    int which = tid >> 8;
    int ltid  = tid & 255;
    int warp8 = ltid >> 5;
    int wr = warp8 & 3, wm = warp8 >> 2;
    unsigned* base = arena + which*WB;
    unsigned* uK  = base;                 // 2048
    unsigned* uQb = base + 2048;          // [2][2][2048]
    unsigned* uVb = base + 10240;         // [2][2][2048]
    unsigned* uP  = base + 18432;         // [2][2048]
    float*   sro  = (float*)(base + 22528); // [2][128]
    const unsigned* qsrc = g_qT + (size_t)b*1024*32;
    const unsigned* ksrc = g_kT[which] + (size_t)(b*1024 + m0)*32;
    const unsigned* vsrc = g_vv[which] + (size_t)b*64*512;
    const float*    roff = g_roff[which] + b*HW;

    loadTile(uK, ksrc, 32, ltid);
    loadTileAsync(uQb,        qsrc,          32, ltid);
    loadTileAsync(uQb + 2048, qsrc + 64*32,  32, ltid);
    loadTileAsync(uVb,        vsrc,          512, ltid);
    loadTileAsync(uVb + 2048, vsrc + 32,     512, ltid);
    CP_COMMIT;
    if (ltid < 128) sro[ltid] = roff[ltid];
    float accZ[4][4];
    #pragma unroll
    for(int mf=0;mf<4;mf++){accZ[mf][0]=0.f;accZ[mf][1]=0.f;accZ[mf][2]=0.f;accZ[mf][3]=0.f;}
    CP_WAIT0;
    __syncthreads();

    for (int itn=0; itn<8; itn++){
      int nb = itn*128;
      int cur = itn&1;
      if (itn < 7){
        int buf = cur^1;
        loadTileAsync(uQb + buf*4096,        qsrc + (size_t)(nb+128)*32, 32, ltid);
        loadTileAsync(uQb + buf*4096 + 2048, qsrc + (size_t)(nb+192)*32, 32, ltid);
        loadTileAsync(uVb + buf*4096,        vsrc + ((nb+128)>>1), 512, ltid);
        loadTileAsync(uVb + buf*4096 + 2048, vsrc + ((nb+192)>>1), 512, ltid);
        CP_COMMIT;
        if (ltid < 128) sro[buf*128 + ltid] = roff[nb+128+ltid];
      }
      #pragma unroll
      for (int s=0; s<2; s++){
        unsigned* uQ = uQb + cur*4096 + s*2048;
        float*    sr = sro + cur*128 + s*64;
        unsigned* uPs = uP + s*2048;
        float accS[4][4];
        #pragma unroll
        for(int mf=0;mf<4;mf++){accS[mf][0]=0.f;accS[mf][1]=0.f;accS[mf][2]=0.f;accS[mf][3]=0.f;}
        #pragma unroll
        for (int kk=0; kk<4; kk++){
          unsigned a[4]; ldsmA(a, uK, wr*16, kk);
          #pragma unroll
          for (int mp=0; mp<2; mp++){
            unsigned bb[4]; ldsmB2(bb, uQ, wm*32 + mp*16, kk);
            mma16(accS[2*mp  ], a, bb[0], bb[1]);
            mma16(accS[2*mp+1], a, bb[2], bb[3]);
          }
        }
        #pragma unroll
        for (int mf=0; mf<4; mf++){
          int n = wm*32 + mf*8 + 2*tq;
          float ro0 = sr[n], ro1 = sr[n+1];
          int jn = n >> 1;
          int r0 = wr*16 + g;
          uPs[tw(r0,   jn)] = exp2_pair_h(__fmaf_rn(accS[mf][0], LOG2E, -ro0),
                                          __fmaf_rn(accS[mf][1], LOG2E, -ro1));
          uPs[tw(r0+8, jn)] = exp2_pair_h(__fmaf_rn(accS[mf][2], LOG2E, -ro0),
                                          __fmaf_rn(accS[mf][3], LOG2E, -ro1));
        }
      }
      __syncthreads();
      #pragma unroll
      for (int s=0; s<2; s++){
        unsigned* uV = uVb + cur*4096 + s*2048;
        unsigned* uPs = uP + s*2048;
        #pragma unroll
        for (int kk=0; kk<4; kk++){
          unsigned a[4]; ldsmA(a, uV, wr*16, kk);
          #pragma unroll
          for (int mp=0; mp<2; mp++){
            unsigned bb[4]; ldsmB2(bb, uPs, wm*32 + mp*16, kk);
            mma16(accZ[2*mp  ], a, bb[0], bb[1]);
            mma16(accZ[2*mp+1], a, bb[2], bb[3]);
          }
        }
      }
      if (itn < 7){ CP_WAIT0; }
      __syncthreads();
    }
    // write Zcat tile to smem (tf32)
    unsigned* sZc = arena;
    int zoff = which*64;
    #pragma unroll
    for (int mf=0; mf<4; mf++){
      int r0 = zoff + wr*16 + g, r1 = r0 + 8;
      int col = wm*32 + mf*8 + 2*tq;
      *(uint2*)&sZc[r0*72 + col] = make_uint2(f2t(accZ[mf][0]), f2t(accZ[mf][1]));
      *(uint2*)&sZc[r1*72 + col] = make_uint2(f2t(accZ[mf][2]), f2t(accZ[mf][3]));
    }
  }
  // ================= tail phase =================
  unsigned* sZc = arena;                 // [128][72] tf32
  unsigned* uz1 = arena + 9216;          // [64][132]
  unsigned* sOh = arena + 17664;         // [64][72]
  unsigned* sZ  = arena + 22272;         // [64][72]
  unsigned* wch = arena + 26880;         // [8][200]
  float*  gates = (float*)arena;         // [192][66]

  for (int idx=tid; idx<8192; idx+=512){
    int o = idx>>7, c = idx&127;
    uz1[o*132+c] = f2t(z1_w[o*128+c]);
  }
  for (int idx=tid; idx<2048; idx+=512){
    int c = idx>>5, p2 = idx&31;
    float2 v = *(const float2*)&g_oh[((size_t)b*64+c)*HW + p0 + 2*p2];
    *(uint2*)&sOh[c*72 + 2*p2] = make_uint2(f2t(v.x), f2t(v.y));
  }
  __syncthreads();

  int warp16 = tid>>5;
  int wc = warp16 & 1, wm8 = warp16 >> 1;

  // ---- z1 ----
  float a1[2][4];
  #pragma unroll
  for(int ot=0;ot<2;ot++){a1[ot][0]=0.f;a1[ot][1]=0.f;a1[ot][2]=0.f;a1[ot][3]=0.f;}
  for (int cc=0; cc<128; cc+=8){
    unsigned b0 = sZc[(cc+tq  )*72 + wm8*8 + g];
    unsigned b1 = sZc[(cc+tq+4)*72 + wm8*8 + g];
    #pragma unroll
    for (int ot=0; ot<2; ot++){
      unsigned a[4];
      int r = ot*32 + wc*16 + g;
      a[0]=uz1[(r  )*132 + cc+tq];   a[1]=uz1[(r+8)*132 + cc+tq];
      a[2]=uz1[(r  )*132 + cc+tq+4]; a[3]=uz1[(r+8)*132 + cc+tq+4];
      mma8(a1[ot], a, b0, b1);
    }
  }
  __syncthreads();
  #pragma unroll
  for (int ot=0; ot<2; ot++){
    int r0 = ot*32 + wc*16 + g, r1 = r0 + 8;
    int col = wm8*8 + 2*tq;
    float bv0 = z1_b[r0], bv1 = z1_b[r1];
    *(uint2*)&sZ[r0*72 + col] = make_uint2(f2t(a1[ot][0]+bv0), f2t(a1[ot][1]+bv0));
    *(uint2*)&sZ[r1*72 + col] = make_uint2(f2t(a1[ot][2]+bv1), f2t(a1[ot][3]+bv1));
  }
  // ---- z2 ----
  float a2[6][4];
  #pragma unroll
  for(int ot=0;ot<6;ot++){a2[ot][0]=0.f;a2[ot][1]=0.f;a2[ot][2]=0.f;a2[ot][3]=0.f;}
  for (int cc=0; cc<128; cc+=8){
    __syncthreads();
    for (int idx=tid; idx<1536; idx+=512){
      int r = idx/192, o = idx - r*192;
      wch[r*200 + o] = g_z2T[(cc+r)*192 + o];
    }
    __syncthreads();
    const unsigned* src = (cc<64) ? (sZ + cc*72) : (sOh + (cc-64)*72);
    unsigned b0 = src[ tq   *72 + wm8*8 + g];
    unsigned b1 = src[(tq+4)*72 + wm8*8 + g];
    #pragma unroll
    for (int ot=0; ot<6; ot++){
      unsigned a[4];
      int o = ot*32 + wc*16 + g;
      a[0]=wch[ tq   *200 + o];   a[1]=wch[ tq   *200 + o+8];
      a[2]=wch[(tq+4)*200 + o];   a[3]=wch[(tq+4)*200 + o+8];
      mma8(a2[ot], a, b0, b1);
    }
  }
  __syncthreads();
  #pragma unroll
  for (int ot=0; ot<6; ot++){
    int r0 = ot*32 + wc*16 + g, r1 = r0 + 8;
    int col = wm8*8 + 2*tq;
    float bv0 = z2_b[r0], bv1 = z2_b[r1];
    *(float2*)&gates[r0*66 + col] = make_float2(a2[ot][0]+bv0, a2[ot][1]+bv0);
    *(float2*)&gates[r1*66 + col] = make_float2(a2[ot][2]+bv1, a2[ot][3]+bv1);
  }
  __syncthreads();
  // ---- gating epilogue ----
  for (int i=tid; i<4096; i+=512){
    int c = i>>6, p = i&63;
    float vo = gates[(c     )*66 + p];
    float vg = gates[(64 +c )*66 + p];
    float vi = gates[(128+c )*66 + p];
    int idx = (b*64 + c)*1024 + p0 + p;
    float si = sigm(vi);
    float om  = tfast(vg)*si + (1.f-si)*g_im[idx];
    float oh2 = sigm(vo)*om;
    g_im[idx] = om;
    g_ih[idx] = oh2;
    out[(((size_t)b*TT + t)*64 + c)*HW + p0 + p] = oh2;
    if (ws){
      float* st = out + (size_t)BB*TT*64*HW;
      st[idx]            = oh2;
      st[NSTATE + idx]   = g_ic[idx];
      st[2*NSTATE + idx] = om;
    }
  }
}

extern "C" void kernel_launch(void* const* d_in, const int* in_sizes, int n_in,
                              void* d_out, int out_size)
{
  const float* inputs = (const float*)d_in[0];
  const float* conv_w = (const float*)d_in[1];
  const float* conv_b = (const float*)d_in[2];
  const float* gn_g   = (const float*)d_in[3];
  const float* gn_b   = (const float*)d_in[4];
  const float* h_w    = (const float*)d_in[5];
  const float* h_b    = (const float*)d_in[6];
  const float* m_w    = (const float*)d_in[7];
  const float* m_b    = (const float*)d_in[8];
  const float* z1_w   = (const float*)d_in[9];
  const float* z1_b   = (const float*)d_in[10];
  const float* z2_w   = (const float*)d_in[11];
  const float* z2_b   = (const float*)d_in[12];
  float* out = (float*)d_out;

  const int AT_SMEM = 2*WB*4;   // 182272
  cudaFuncSetAttribute(av_tail, cudaFuncAttributeMaxDynamicSharedMemorySize, AT_SMEM);

  zero_states<<<2048,256>>>();
  wtrans<<<256,256>>>(conv_w, z2_w, h_w, m_w);
  int write_states = (out_size >= (int)(BB*TT*64*HW + 3*NSTATE)) ? 1 : 0;

  for (int t=0; t<TT; t++){
    conv_tc<<<dim3(8,4,8),256>>>(inputs, conv_b, t);
    gn_lstm8<<<256,256>>>(gn_g, gn_b, t);
    lin_hm<<<dim3(8,10,16),256>>>(h_b, m_b);
    qk_stats<<<dim3(8,16,2),256>>>();
    av_tail<<<dim3(8,16),512,AT_SMEM>>>(z1_w, z1_b, z2_b, out, t, (t==TT-1) ? write_states : 0);
  }
}

// round 14
// speedup vs baseline: 3.5697x; 1.0280x over previous
#include <cuda_runtime.h>
#include <cuda_fp16.h>
#include <math.h>

#define BB 8
#define TT 8
#define HW 1024
#define CG 256
#define NSTATE (BB*64*HW)   // 524288
#define LOG2E 1.4426950408889634f

// ---- persistent state ----
__device__ float g_ih[NSTATE];
__device__ float g_ic[NSTATE];
__device__ float g_im[NSTATE];
// ---- scratch ----
__device__ float g_gates[BB*CG*HW];
__device__ float g_gsum [2][64];
__device__ float g_gsum2[2][64];
__device__ float g_oh[NSTATE];
__device__ float g_roff[2][BB*HW];
__device__ unsigned g_wTh[8*9*256*8];
__device__ unsigned g_z2T[128*192];
__device__ unsigned g_hmw[10*1024];
__device__ unsigned g_qT[8*1024*32];
__device__ unsigned g_kT[2][8*1024*32];
__device__ unsigned g_vv[2][8*64*512];

__device__ __forceinline__ float sigm(float x){
  float e = __expf(-x);
  float r; asm("rcp.approx.f32 %0,%1;" : "=f"(r) : "f"(1.f+e));
  return r;
}
__device__ __forceinline__ float tfast(float x){
  return __fmaf_rn(2.f, sigm(2.f*x), -1.f);
}
__device__ __forceinline__ unsigned f2t(float x){
  unsigned r; asm("cvt.rna.tf32.f32 %0,%1;" : "=r"(r) : "f"(x)); return r;
}
__device__ __forceinline__ void mma8(float* d, const unsigned* a, unsigned b0, unsigned b1){
  asm volatile("mma.sync.aligned.m16n8k8.row.col.f32.tf32.tf32.f32 "
    "{%0,%1,%2,%3},{%4,%5,%6,%7},{%8,%9},{%0,%1,%2,%3};"
    : "+f"(d[0]),"+f"(d[1]),"+f"(d[2]),"+f"(d[3])
    : "r"(a[0]),"r"(a[1]),"r"(a[2]),"r"(a[3]),"r"(b0),"r"(b1));
}
__device__ __forceinline__ void mma16(float* d, const unsigned* a, unsigned b0, unsigned b1){
  asm volatile("mma.sync.aligned.m16n8k16.row.col.f32.f16.f16.f32 "
    "{%0,%1,%2,%3},{%4,%5,%6,%7},{%8,%9},{%0,%1,%2,%3};"
    : "+f"(d[0]),"+f"(d[1]),"+f"(d[2]),"+f"(d[3])
    : "r"(a[0]),"r"(a[1]),"r"(a[2]),"r"(a[3]),"r"(b0),"r"(b1));
}
__device__ __forceinline__ unsigned pack2h(float x, float y){
  __half2 h = __floats2half2_rn(x, y);
  return *(unsigned*)&h;
}
__device__ __forceinline__ unsigned exp2_pair_h(float x0, float x1){
  __half2 h = h2exp2(__floats2half2_rn(x0, x1));
  return *(unsigned*)&h;
}
__device__ __forceinline__ float2 exp2_pair_f(float x0, float x1){
  __half2 h = h2exp2(__floats2half2_rn(x0, x1));
  return __half22float2(h);
}

__device__ __forceinline__ int tw(int row, int j){ return row*32 + (j ^ ((row&7)<<2)); }

__device__ __forceinline__ unsigned saddr(const unsigned* p){
  return (unsigned)__cvta_generic_to_shared((const void*)p);
}
__device__ __forceinline__ void cpa16(unsigned* sdst, const void* gsrc){
  unsigned ad = saddr(sdst);
  asm volatile("cp.async.cg.shared.global [%0], [%1], 16;" :: "r"(ad), "l"(gsrc));
}
#define CP_COMMIT asm volatile("cp.async.commit_group;")
#define CP_WAIT0  asm volatile("cp.async.wait_group 0;")

__device__ __forceinline__ void loadTile(unsigned* dst, const unsigned* __restrict__ src,
                                         int rowstride, int ltid){
  #pragma unroll
  for (int it=0; it<2; it++){
    int idx = it*256 + ltid;
    int row = idx>>3, j4 = (idx&7)*4;
    uint4 v = *(const uint4*)(src + (size_t)row*rowstride + j4);
    *(uint4*)&dst[tw(row, j4)] = v;
  }
}
__device__ __forceinline__ void loadTileAsync(unsigned* dst, const unsigned* __restrict__ src,
                                              int rowstride, int ltid){
  #pragma unroll
  for (int it=0; it<2; it++){
    int idx = it*256 + ltid;
    int row = idx>>3, j4 = (idx&7)*4;
    cpa16(dst + tw(row, j4), src + (size_t)row*rowstride + j4);
  }
}
__device__ __forceinline__ void ldsmA(unsigned* a, const unsigned* t, int r, int kk){
  int lane = threadIdx.x & 31;
  int row = r + (lane&7) + (lane&8);
  int j   = kk*8 + ((lane>>4)<<2);
  unsigned ad = saddr(t + tw(row, j));
  asm volatile("ldmatrix.sync.aligned.m8n8.x4.shared.b16 {%0,%1,%2,%3}, [%4];"
    : "=r"(a[0]),"=r"(a[1]),"=r"(a[2]),"=r"(a[3]) : "r"(ad));
}
__device__ __forceinline__ void ldsmB2(unsigned* b, const unsigned* t, int nb, int kk){
  int lane = threadIdx.x & 31;
  int row = nb + (lane&7) + ((lane>>4)<<3);
  int j   = kk*8 + (((lane>>3)&1)<<2);
  unsigned ad = saddr(t + tw(row, j));
  asm volatile("ldmatrix.sync.aligned.m8n8.x4.shared.b16 {%0,%1,%2,%3}, [%4];"
    : "=r"(b[0]),"=r"(b[1]),"=r"(b[2]),"=r"(b[3]) : "r"(ad));
}

__global__ void zero_states(){
  int i = blockIdx.x*256 + threadIdx.x;
  if (i < NSTATE){ g_ih[i]=0.f; g_ic[i]=0.f; g_im[i]=0.f; }
  if (blockIdx.x==0 && threadIdx.x<64){
    g_gsum[0][threadIdx.x]=0.f; g_gsum2[0][threadIdx.x]=0.f;
    g_gsum[1][threadIdx.x]=0.f; g_gsum2[1][threadIdx.x]=0.f;
  }
}

__global__ void wtrans(const float* __restrict__ w, const float* __restrict__ z2w,
                       const float* __restrict__ hw, const float* __restrict__ mw){
  int co = blockIdx.x;
  for (int idx = threadIdx.x; idx < 576; idx += 256){
    int chunk = idx/72, r = idx - chunk*72, pos = r>>3, j = r&7;
    int ci = chunk*16 + 2*j;
    float v0 = w[((size_t)co*128 + ci  )*9 + pos];
    float v1 = w[((size_t)co*128 + ci+1)*9 + pos];
    g_wTh[((size_t)(chunk*9+pos)*256 + co)*8 + j] = pack2h(v0, v1);
  }
  if (co < 192){
    for (int c = threadIdx.x; c < 128; c += 256)
      g_z2T[c*192 + co] = f2t(z2w[co*128 + c]);
    if (threadIdx.x < 32){
      int j = threadIdx.x;
      int y = co>>5, row = co&31;
      g_hmw[y*1024 + tw(row, j)] = pack2h(hw[co*64 + 2*j], hw[co*64 + 2*j + 1]);
    }
  }
  if (co < 128 && threadIdx.x >= 32 && threadIdx.x < 64){
    int j = threadIdx.x - 32;
    int y = 6 + (co>>5), row = co&31;
    g_hmw[y*1024 + tw(row, j)] = pack2h(mw[co*64 + 2*j], mw[co*64 + 2*j + 1]);
  }
}

// ------------- 3x3 conv (fp16 TC, pipelined staging) + fused GN stats -------
__global__ __launch_bounds__(256) void conv_tc(const float* __restrict__ xin,
                                               const float* __restrict__ bias, int t)
{
  int pt = blockIdx.x, cot = blockIdx.y, b = blockIdx.z;
  int y0 = pt*4, co0 = cot*64, par = t & 1;
  __shared__ unsigned sIn[8*232];
  __shared__ unsigned sW[2][4608];
  __shared__ float ws[8], ws2[8];
  int tid=threadIdx.x, warp=tid>>5, lane=tid&31, g=lane>>2, tq=lane&3;
  int wc = warp&3, wm = warp>>2;
  float acc[8][4];
  #pragma unroll
  for(int j=0;j<8;j++){acc[j][0]=0.f;acc[j][1]=0.f;acc[j][2]=0.f;acc[j][3]=0.f;}

  int pix = tid;
  int yy = pix/34, xx = pix - yy*34;
  int gy = y0-1+yy, gx = xx-1;
  bool pv = (pix<204) && ((unsigned)gy<32u) && ((unsigned)gx<32u);
  int gidx = gy*32 + gx;

  const float* xbase = xin + (size_t)(b*TT+t)*64*HW;
  const float* hbase = g_ih + (size_t)b*64*HW;

  float rin[16];
  {
    const float* src = xbase;
    #pragma unroll
    for (int j=0;j<8;j++){
      rin[2*j]=0.f; rin[2*j+1]=0.f;
      if (pv){ rin[2*j] = src[(size_t)(2*j)*HW + gidx]; rin[2*j+1] = src[(size_t)(2*j+1)*HW + gidx]; }
    }
  }
  for (int i4=tid; i4<1152; i4+=256)
    cpa16(&sW[0][i4*4], g_wTh + (size_t)0*9*2048 + co0*8 + (i4>>7)*2048 + (i4&127)*4);
  CP_COMMIT;

  for (int chunk=0; chunk<8; chunk++){
    int cb = chunk&1;
    __syncthreads();
    if (pix < 204){
      #pragma unroll
      for (int j=0;j<8;j++) sIn[j*232 + pix] = pack2h(rin[2*j], rin[2*j+1]);
    }
    CP_WAIT0;
    __syncthreads();
    if (chunk < 7){
      const float* src = (chunk+1<4) ? (xbase + (size_t)(chunk+1)*16*HW)
                                     : (hbase + (size_t)(chunk+1-4)*16*HW);
      #pragma unroll
      for (int j=0;j<8;j++){
        rin[2*j]=0.f; rin[2*j+1]=0.f;
        if (pv){ rin[2*j] = src[(size_t)(2*j)*HW + gidx]; rin[2*j+1] = src[(size_t)(2*j+1)*HW + gidx]; }
      }
      for (int i4=tid; i4<1152; i4+=256)
        cpa16(&sW[cb^1][i4*4], g_wTh + (size_t)(chunk+1)*9*2048 + co0*8 + (i4>>7)*2048 + (i4&127)*4);
      CP_COMMIT;
    }
    #pragma unroll
    for (int pos=0; pos<9; pos++){
      int ky = pos/3, kx = pos - 3*ky;
      unsigned a[4];
      int rb = pos*512 + (wc*16+g)*8;
      a[0] = sW[cb][rb + tq];       a[1] = sW[cb][rb + 64 + tq];
      a[2] = sW[cb][rb + tq + 4];   a[3] = sW[cb][rb + 64 + tq + 4];
      #pragma unroll
      for (int mf=0; mf<8; mf++){
        int p = wm*64 + mf*8 + g;
        int pixb = ((p>>5)+ky)*34 + (p&31) + kx;
        mma16(acc[mf], a, sIn[tq*232 + pixb], sIn[(tq+4)*232 + pixb]);
      }
    }
  }
  int r0 = co0 + wc*16 + g, r1 = r0 + 8;
  float bv0 = bias[r0], bv1 = bias[r1];
  float s=0.f, s2=0.f;
  #pragma unroll
  for (int mf=0; mf<8; mf++){
    int col = y0*32 + wm*64 + mf*8 + 2*tq;
    float v0=acc[mf][0]+bv0, v1=acc[mf][1]+bv0;
    float v2=acc[mf][2]+bv1, v3=acc[mf][3]+bv1;
    *(float2*)&g_gates[((size_t)b*CG + r0)*HW + col] = make_float2(v0,v1);
    *(float2*)&g_gates[((size_t)b*CG + r1)*HW + col] = make_float2(v2,v3);
    s  += v0+v1+v2+v3;
    s2 += v0*v0+v1*v1+v2*v2+v3*v3;
  }
  #pragma unroll
  for (int off=16; off; off>>=1){
    s  += __shfl_xor_sync(0xffffffffu, s , off);
    s2 += __shfl_xor_sync(0xffffffffu, s2, off);
  }
  if (lane==0){ ws[warp]=s; ws2[warp]=s2; }
  __syncthreads();
  if (tid<2){
    float S  = ws [tid*2]+ws [tid*2+1]+ws [tid*2+4]+ws [tid*2+5];
    float S2 = ws2[tid*2]+ws2[tid*2+1]+ws2[tid*2+4]+ws2[tid*2+5];
    int gidx2 = b*8 + (co0>>5) + tid;
    atomicAdd(&g_gsum [par][gidx2], S );
    atomicAdd(&g_gsum2[par][gidx2], S2);
  }
}

// ---------- fused GN+LSTM gating + QKV projections (fp16 TC) ----------
// grid (b=8, pt=16 of 64px), block 512 (16 warps = 2 yb-groups of 8)
__global__ __launch_bounds__(512) void gn_qkv(const float* __restrict__ gg,
                                              const float* __restrict__ gb,
                                              const float* __restrict__ h_b,
                                              const float* __restrict__ m_b, int t)
{
  __shared__ unsigned sOh[2048];     // oh tw tile [px][c-pair]
  __shared__ unsigned sIm[2048];     // im tw tile
  __shared__ unsigned uW[2][2048];   // weight pair double buffer
  __shared__ float smu[8], srs[8];
  int b = blockIdx.x, p0 = blockIdx.y*64;
  int tid = threadIdx.x;
  int par = t & 1;
  if (tid < 8){
    float s  = g_gsum [par][b*8+tid];
    float s2 = g_gsum2[par][b*8+tid];
    float m   = s*(1.f/32768.f);
    float var = s2*(1.f/32768.f) - m*m;
    smu[tid] = m;
    srs[tid] = rsqrtf(var + 1e-5f);
  }
  if (b==0 && blockIdx.y==0 && tid>=64 && tid<128){
    g_gsum[par^1][tid-64]=0.f; g_gsum2[par^1][tid-64]=0.f;
  }
  // stage im tile (previous-step im)
  {
    const float* imb = g_im + (size_t)b*64*HW + p0;
    #pragma unroll
    for (int it=0; it<4; it++){
      int idx = it*512 + tid;
      int px = idx & 63, j = idx >> 6;
      float v0 = imb[(size_t)(2*j  )*HW + px];
      float v1 = imb[(size_t)(2*j+1)*HW + px];
      sIm[tw(px, j)] = pack2h(v0, v1);
    }
  }
  __syncthreads();   // stats ready
  // ---- gating: produce oh tile (smem + global), update ic ----
  {
    const float* gt  = g_gates + (size_t)b*CG*HW + p0;
    float* icp = g_ic + (size_t)b*64*HW + p0;
    float* ohp = g_oh + (size_t)b*64*HW + p0;
    #pragma unroll
    for (int it=0; it<4; it++){
      int idx = it*512 + tid;
      int px = idx & 63, j = idx >> 6;
      float ohpair[2];
      #pragma unroll
      for (int e=0; e<2; e++){
        int cc = 2*j + e;
        float vi = gt[(size_t)(cc     )*HW + px];
        float vf = gt[(size_t)(cc+ 64 )*HW + px];
        float vc = gt[(size_t)(cc+128 )*HW + px];
        float vo = gt[(size_t)(cc+192 )*HW + px];
        int g0 = cc >> 5;
        float a  = (vi-smu[g0  ])*srs[g0  ]*gg[cc    ] + gb[cc    ];
        float f2 = (vf-smu[g0+2])*srs[g0+2]*gg[cc+64 ] + gb[cc+64 ];
        float cg = (vc-smu[g0+4])*srs[g0+4]*gg[cc+128] + gb[cc+128];
        float o  = (vo-smu[g0+6])*srs[g0+6]*gg[cc+192] + gb[cc+192];
        float icv = icp[(size_t)cc*HW + px];
        float oc = icv*sigm(f2) + sigm(a)*tfast(cg);
        float oh = sigm(o)*tfast(oc);
        icp[(size_t)cc*HW + px] = oc;
        ohp[(size_t)cc*HW + px] = oh;
        ohpair[e] = oh;
      }
      sOh[tw(px, j)] = pack2h(ohpair[0], ohpair[1]);
    }
  }
  // prefetch weights pair 0 (yb 0,1)
  cpa16(&uW[0][tid*4], g_hmw + tid*4);
  CP_COMMIT;
  __syncthreads();   // sOh visible

  int warp = tid>>5, lane = tid&31, g = lane>>2, tq = lane&3;
  int wgrp  = warp >> 3;      // 0/1 -> yb within pair
  int warp8 = warp & 7;

  for (int pr=0; pr<5; pr++){
    int buf = pr & 1;
    CP_WAIT0;
    __syncthreads();
    if (pr < 4){
      cpa16(&uW[buf^1][tid*4], g_hmw + (pr+1)*2048 + tid*4);
      CP_COMMIT;
    }
    int yb = 2*pr + wgrp;
    const unsigned* w  = uW[buf] + wgrp*1024;
    const unsigned* xT = (yb < 6) ? sOh : sIm;
    const float* bias  = (yb < 6) ? h_b : m_b;
    int o0 = (yb < 6) ? yb*32 : (yb-6)*32;
    unsigned* dstT = 0; unsigned* dstV = 0; int crel = 0;
    if (yb < 6){
      if      (o0 <  64){ dstT = g_qT;    crel = o0;       }
      else if (o0 < 128){ dstT = g_kT[0]; crel = o0 - 64;  }
      else              { dstV = g_vv[0]; crel = o0 - 128; }
    } else {
      if (o0 < 64){ dstT = g_kT[1]; crel = o0; }
      else        { dstV = g_vv[1]; crel = o0 - 64; }
    }
    if (dstV){
      int wc = warp8&1, wm = warp8>>1;
      float acc[2][4];
      acc[0][0]=acc[0][1]=acc[0][2]=acc[0][3]=0.f;
      acc[1][0]=acc[1][1]=acc[1][2]=acc[1][3]=0.f;
      #pragma unroll
      for (int kk=0; kk<4; kk++){
        unsigned a[4]; ldsmA(a, w, wc*16, kk);
        unsigned bb[4]; ldsmB2(bb, xT, wm*16, kk);
        mma16(acc[0], a, bb[0], bb[1]);
        mma16(acc[1], a, bb[2], bb[3]);
      }
      int cc0 = wc*16 + g;
      float bv0 = bias[o0+cc0], bv1 = bias[o0+cc0+8];
      #pragma unroll
      for (int oct=0; oct<2; oct++){
        int col = p0 + wm*16 + oct*8 + 2*tq;
        dstV[((size_t)(b*64 + crel + cc0  ))*512 + (col>>1)] = pack2h(acc[oct][0]+bv0, acc[oct][1]+bv0);
        dstV[((size_t)(b*64 + crel + cc0+8))*512 + (col>>1)] = pack2h(acc[oct][2]+bv1, acc[oct][3]+bv1);
      }
    } else {
      int wpx = warp8&3, wo = warp8>>2;
      float acc[2][4];
      acc[0][0]=acc[0][1]=acc[0][2]=acc[0][3]=0.f;
      acc[1][0]=acc[1][1]=acc[1][2]=acc[1][3]=0.f;
      #pragma unroll
      for (int kk=0; kk<4; kk++){
        unsigned a[4]; ldsmA(a, xT, wpx*16, kk);
        unsigned bb[4]; ldsmB2(bb, w, wo*16, kk);
        mma16(acc[0], a, bb[0], bb[1]);
        mma16(acc[1], a, bb[2], bb[3]);
      }
      int row0 = wpx*16 + g;
      #pragma unroll
      for (int oct=0; oct<2; oct++){
        int col = wo*16 + oct*8 + 2*tq;
        float b0 = bias[o0+col], b1 = bias[o0+col+1];
        int wj = (crel + col) >> 1;
        dstT[((size_t)(b*1024 + p0 + row0  ))*32 + wj] = pack2h(acc[oct][0]+b0, acc[oct][1]+b1);
        dstT[((size_t)(b*1024 + p0 + row0+8))*32 + wj] = pack2h(acc[oct][2]+b0, acc[oct][3]+b1);
      }
    }
  }
}

// ------------------- pass 1 (pipelined K): row softmax stats ----------
__global__ __launch_bounds__(256) void qk_stats(){
  __shared__ unsigned uQ[2048];
  __shared__ unsigned uK[2][2][2048];
  __shared__ float sM[2][64], sL[2][64];
  int b = blockIdx.x, n0 = blockIdx.y*64, which = blockIdx.z;
  const unsigned* qsrc = g_qT + (size_t)(b*1024 + n0)*32;
  const unsigned* ksrc = g_kT[which] + (size_t)b*1024*32;
  int tid=threadIdx.x, warp=tid>>5, tq=(tid&31)&3;
  int g = (tid&31)>>2;
  int wn = warp&3, wm = warp>>2;
  loadTile(uQ, qsrc, 32, tid);
  loadTileAsync(uK[0][0], ksrc, 32, tid);
  loadTileAsync(uK[0][1], ksrc + 64*32, 32, tid);
  CP_COMMIT;
  CP_WAIT0;
  __syncthreads();
  float M0=-1e30f, M1=-1e30f, L0=0.f, L1=0.f;
  for (int it=0; it<8; it++){
    int cur = it&1;
    if (it < 7){
      const unsigned* kn = ksrc + (size_t)(it+1)*128*32;
      loadTileAsync(uK[cur^1][0], kn, 32, tid);
      loadTileAsync(uK[cur^1][1], kn + 64*32, 32, tid);
      CP_COMMIT;
    }
    const unsigned* kt = uK[cur][wm];
    float cfr[8][4];
    #pragma unroll
    for(int mf=0;mf<8;mf++){cfr[mf][0]=0.f;cfr[mf][1]=0.f;cfr[mf][2]=0.f;cfr[mf][3]=0.f;}
    #pragma unroll
    for (int kk=0; kk<4; kk++){
      unsigned a[4]; ldsmA(a, uQ, wn*16, kk);
      #pragma unroll
      for (int mp=0; mp<4; mp++){
        unsigned bb[4]; ldsmB2(bb, kt, mp*16, kk);
        mma16(cfr[2*mp  ], a, bb[0], bb[1]);
        mma16(cfr[2*mp+1], a, bb[2], bb[3]);
      }
    }
    float tm0=-1e30f, tm1=-1e30f;
    #pragma unroll
    for(int mf=0;mf<8;mf++){
      tm0 = fmaxf(tm0, fmaxf(cfr[mf][0], cfr[mf][1]));
      tm1 = fmaxf(tm1, fmaxf(cfr[mf][2], cfr[mf][3]));
    }
    tm0 = fmaxf(tm0, __shfl_xor_sync(0xffffffffu, tm0, 1));
    tm0 = fmaxf(tm0, __shfl_xor_sync(0xffffffffu, tm0, 2));
    tm1 = fmaxf(tm1, __shfl_xor_sync(0xffffffffu, tm1, 1));
    tm1 = fmaxf(tm1, __shfl_xor_sync(0xffffffffu, tm1, 2));
    float nM0 = fmaxf(M0, tm0), nM1 = fmaxf(M1, tm1);
    float c0 = nM0*LOG2E, c1 = nM1*LOG2E;
    float s0=0.f, s1=0.f;
    #pragma unroll
    for(int mf=0;mf<8;mf++){
      float2 e0 = exp2_pair_f(__fmaf_rn(cfr[mf][0], LOG2E, -c0),
                              __fmaf_rn(cfr[mf][1], LOG2E, -c0));
      float2 e1 = exp2_pair_f(__fmaf_rn(cfr[mf][2], LOG2E, -c1),
                              __fmaf_rn(cfr[mf][3], LOG2E, -c1));
      s0 += e0.x + e0.y;
      s1 += e1.x + e1.y;
    }
    s0 += __shfl_xor_sync(0xffffffffu, s0, 1);
    s0 += __shfl_xor_sync(0xffffffffu, s0, 2);
    s1 += __shfl_xor_sync(0xffffffffu, s1, 1);
    s1 += __shfl_xor_sync(0xffffffffu, s1, 2);
    L0 = L0*__expf(M0-nM0) + s0; M0 = nM0;
    L1 = L1*__expf(M1-nM1) + s1; M1 = nM1;
    if (it < 7){ CP_WAIT0; }
    __syncthreads();
  }
  if (tq==0){
    sM[wm][wn*16+g  ] = M0; sL[wm][wn*16+g  ] = L0;
    sM[wm][wn*16+8+g] = M1; sL[wm][wn*16+8+g] = L1;
  }
  __syncthreads();
  if (tid<64){
    float Ma = sM[0][tid], Mb = sM[1][tid];
    float M  = fmaxf(Ma, Mb);
    float L  = sL[0][tid]*__expf(Ma-M) + sL[1][tid]*__expf(Mb-M);
    g_roff[which][b*HW + n0 + tid] = __fmaf_rn(M, LOG2E, __log2f(L));
  }
}

// ------------------- merged pass 2 + tail (128-n iterations) --------------------
#define WB 22784
__global__ __launch_bounds__(512,1) void av_tail(const float* __restrict__ z1_w,
                                                 const float* __restrict__ z1_b,
                                                 const float* __restrict__ z2_b,
                                                 float* __restrict__ out, int t, int ws)
{
  extern __shared__ unsigned arena[];
  int b = blockIdx.x, m0 = blockIdx.y*64;
  int p0 = m0;
  int tid = threadIdx.x;
  int lane = tid & 31, g = lane>>2, tq = lane&3;

  // ================= AV phase =================
  {
    int which = tid >> 8;
    int ltid  = tid & 255;
    int warp8 = ltid >> 5;
    int wr = warp8 & 3, wm = warp8 >> 2;
    unsigned* base = arena + which*WB;
    unsigned* uK  = base;
    unsigned* uQb = base + 2048;
    unsigned* uVb = base + 10240;
    unsigned* uP  = base + 18432;
    float*   sro  = (float*)(base + 22528);
    const unsigned* qsrc = g_qT + (size_t)b*1024*32;
    const unsigned* ksrc = g_kT[which] + (size_t)(b*1024 + m0)*32;
    const unsigned* vsrc = g_vv[which] + (size_t)b*64*512;
    const float*    roff = g_roff[which] + b*HW;

    loadTile(uK, ksrc, 32, ltid);
    loadTileAsync(uQb,        qsrc,          32, ltid);
    loadTileAsync(uQb + 2048, qsrc + 64*32,  32, ltid);
    loadTileAsync(uVb,        vsrc,          512, ltid);
    loadTileAsync(uVb + 2048, vsrc + 32,     512, ltid);
    CP_COMMIT;
    if (ltid < 128) sro[ltid] = roff[ltid];
    float accZ[4][4];
    #pragma unroll
    for(int mf=0;mf<4;mf++){accZ[mf][0]=0.f;accZ[mf][1]=0.f;accZ[mf][2]=0.f;accZ[mf][3]=0.f;}
    CP_WAIT0;
    __syncthreads();

    for (int itn=0; itn<8; itn++){
      int nb = itn*128;
      int cur = itn&1;
      if (itn < 7){
        int buf = cur^1;
        loadTileAsync(uQb + buf*4096,        qsrc + (size_t)(nb+128)*32, 32, ltid);
        loadTileAsync(uQb + buf*4096 + 2048, qsrc + (size_t)(nb+192)*32, 32, ltid);
        loadTileAsync(uVb + buf*4096,        vsrc + ((nb+128)>>1), 512, ltid);
        loadTileAsync(uVb + buf*4096 + 2048, vsrc + ((nb+192)>>1), 512, ltid);
        CP_COMMIT;
        if (ltid < 128) sro[buf*128 + ltid] = roff[nb+128+ltid];
      }
      #pragma unroll
      for (int s=0; s<2; s++){
        unsigned* uQ = uQb + cur*4096 + s*2048;
        float*    sr = sro + cur*128 + s*64;
        unsigned* uPs = uP + s*2048;
        float accS[4][4];
        #pragma unroll
        for(int mf=0;mf<4;mf++){accS[mf][0]=0.f;accS[mf][1]=0.f;accS[mf][2]=0.f;accS[mf][3]=0.f;}
        #pragma unroll
        for (int kk=0; kk<4; kk++){
          unsigned a[4]; ldsmA(a, uK, wr*16, kk);
          #pragma unroll
          for (int mp=0; mp<2; mp++){
            unsigned bb[4]; ldsmB2(bb, uQ, wm*32 + mp*16, kk);
            mma16(accS[2*mp  ], a, bb[0], bb[1]);
            mma16(accS[2*mp+1], a, bb[2], bb[3]);
          }
        }
        #pragma unroll
        for (int mf=0; mf<4; mf++){
          int n = wm*32 + mf*8 + 2*tq;
          float ro0 = sr[n], ro1 = sr[n+1];
          int jn = n >> 1;
          int r0 = wr*16 + g;
          uPs[tw(r0,   jn)] = exp2_pair_h(__fmaf_rn(accS[mf][0], LOG2E, -ro0),
                                          __fmaf_rn(accS[mf][1], LOG2E, -ro1));
          uPs[tw(r0+8, jn)] = exp2_pair_h(__fmaf_rn(accS[mf][2], LOG2E, -ro0),
                                          __fmaf_rn(accS[mf][3], LOG2E, -ro1));
        }
      }
      __syncthreads();
      #pragma unroll
      for (int s=0; s<2; s++){
        unsigned* uV = uVb + cur*4096 + s*2048;
        unsigned* uPs = uP + s*2048;
        #pragma unroll
        for (int kk=0; kk<4; kk++){
          unsigned a[4]; ldsmA(a, uV, wr*16, kk);
          #pragma unroll
          for (int mp=0; mp<2; mp++){
            unsigned bb[4]; ldsmB2(bb, uPs, wm*32 + mp*16, kk);
            mma16(accZ[2*mp  ], a, bb[0], bb[1]);
            mma16(accZ[2*mp+1], a, bb[2], bb[3]);
          }
        }
      }
      if (itn < 7){ CP_WAIT0; }
      __syncthreads();
    }
    unsigned* sZc = arena;
    int zoff = which*64;
    #pragma unroll
    for (int mf=0; mf<4; mf++){
      int r0 = zoff + wr*16 + g, r1 = r0 + 8;
      int col = wm*32 + mf*8 + 2*tq;
      *(uint2*)&sZc[r0*72 + col] = make_uint2(f2t(accZ[mf][0]), f2t(accZ[mf][1]));
      *(uint2*)&sZc[r1*72 + col] = make_uint2(f2t(accZ[mf][2]), f2t(accZ[mf][3]));
    }
  }
  // ================= tail phase =================
  unsigned* sZc = arena;
  unsigned* uz1 = arena + 9216;
  unsigned* sOh = arena + 17664;
  unsigned* sZ  = arena + 22272;
  unsigned* wch = arena + 26880;
  float*  gates = (float*)arena;

  for (int idx=tid; idx<8192; idx+=512){
    int o = idx>>7, c = idx&127;
    uz1[o*132+c] = f2t(z1_w[o*128+c]);
  }
  for (int idx=tid; idx<2048; idx+=512){
    int c = idx>>5, p2 = idx&31;
    float2 v = *(const float2*)&g_oh[((size_t)b*64+c)*HW + p0 + 2*p2];
    *(uint2*)&sOh[c*72 + 2*p2] = make_uint2(f2t(v.x), f2t(v.y));
  }
  __syncthreads();

  int warp16 = tid>>5;
  int wc = warp16 & 1, wm8 = warp16 >> 1;

  float a1[2][4];
  #pragma unroll
  for(int ot=0;ot<2;ot++){a1[ot][0]=0.f;a1[ot][1]=0.f;a1[ot][2]=0.f;a1[ot][3]=0.f;}
  for (int cc=0; cc<128; cc+=8){
    unsigned b0 = sZc[(cc+tq  )*72 + wm8*8 + g];
    unsigned b1 = sZc[(cc+tq+4)*72 + wm8*8 + g];
    #pragma unroll
    for (int ot=0; ot<2; ot++){
      unsigned a[4];
      int r = ot*32 + wc*16 + g;
      a[0]=uz1[(r  )*132 + cc+tq];   a[1]=uz1[(r+8)*132 + cc+tq];
      a[2]=uz1[(r  )*132 + cc+tq+4]; a[3]=uz1[(r+8)*132 + cc+tq+4];
      mma8(a1[ot], a, b0, b1);
    }
  }
  __syncthreads();
  #pragma unroll
  for (int ot=0; ot<2; ot++){
    int r0 = ot*32 + wc*16 + g, r1 = r0 + 8;
    int col = wm8*8 + 2*tq;
    float bv0 = z1_b[r0], bv1 = z1_b[r1];
    *(uint2*)&sZ[r0*72 + col] = make_uint2(f2t(a1[ot][0]+bv0), f2t(a1[ot][1]+bv0));
    *(uint2*)&sZ[r1*72 + col] = make_uint2(f2t(a1[ot][2]+bv1), f2t(a1[ot][3]+bv1));
  }
  float a2[6][4];
  #pragma unroll
  for(int ot=0;ot<6;ot++){a2[ot][0]=0.f;a2[ot][1]=0.f;a2[ot][2]=0.f;a2[ot][3]=0.f;}
  for (int cc=0; cc<128; cc+=8){
    __syncthreads();
    for (int idx=tid; idx<1536; idx+=512){
      int r = idx/192, o = idx - r*192;
      wch[r*200 + o] = g_z2T[(cc+r)*192 + o];
    }
    __syncthreads();
    const unsigned* src = (cc<64) ? (sZ + cc*72) : (sOh + (cc-64)*72);
    unsigned b0 = src[ tq   *72 + wm8*8 + g];
    unsigned b1 = src[(tq+4)*72 + wm8*8 + g];
    #pragma unroll
    for (int ot=0; ot<6; ot++){
      unsigned a[4];
      int o = ot*32 + wc*16 + g;
      a[0]=wch[ tq   *200 + o];   a[1]=wch[ tq   *200 + o+8];
      a[2]=wch[(tq+4)*200 + o];   a[3]=wch[(tq+4)*200 + o+8];
      mma8(a2[ot], a, b0, b1);
    }
  }
  __syncthreads();
  #pragma unroll
  for (int ot=0; ot<6; ot++){
    int r0 = ot*32 + wc*16 + g, r1 = r0 + 8;
    int col = wm8*8 + 2*tq;
    float bv0 = z2_b[r0], bv1 = z2_b[r1];
    *(float2*)&gates[r0*66 + col] = make_float2(a2[ot][0]+bv0, a2[ot][1]+bv0);
    *(float2*)&gates[r1*66 + col] = make_float2(a2[ot][2]+bv1, a2[ot][3]+bv1);
  }
  __syncthreads();
  for (int i=tid; i<4096; i+=512){
    int c = i>>6, p = i&63;
    float vo = gates[(c     )*66 + p];
    float vg = gates[(64 +c )*66 + p];
    float vi = gates[(128+c )*66 + p];
    int idx = (b*64 + c)*1024 + p0 + p;
    float si = sigm(vi);
    float om  = tfast(vg)*si + (1.f-si)*g_im[idx];
    float oh2 = sigm(vo)*om;
    g_im[idx] = om;
    g_ih[idx] = oh2;
    out[(((size_t)b*TT + t)*64 + c)*HW + p0 + p] = oh2;
    if (ws){
      float* st = out + (size_t)BB*TT*64*HW;
      st[idx]            = oh2;
      st[NSTATE + idx]   = g_ic[idx];
      st[2*NSTATE + idx] = om;
    }
  }
}

extern "C" void kernel_launch(void* const* d_in, const int* in_sizes, int n_in,
                              void* d_out, int out_size)
{
  const float* inputs = (const float*)d_in[0];
  const float* conv_w = (const float*)d_in[1];
  const float* conv_b = (const float*)d_in[2];
  const float* gn_g   = (const float*)d_in[3];
  const float* gn_b   = (const float*)d_in[4];
  const float* h_w    = (const float*)d_in[5];
  const float* h_b    = (const float*)d_in[6];
  const float* m_w    = (const float*)d_in[7];
  const float* m_b    = (const float*)d_in[8];
  const float* z1_w   = (const float*)d_in[9];
  const float* z1_b   = (const float*)d_in[10];
  const float* z2_w   = (const float*)d_in[11];
  const float* z2_b   = (const float*)d_in[12];
  float* out = (float*)d_out;

  const int AT_SMEM = 2*WB*4;   // 182272
  cudaFuncSetAttribute(av_tail, cudaFuncAttributeMaxDynamicSharedMemorySize, AT_SMEM);

  zero_states<<<2048,256>>>();
  wtrans<<<256,256>>>(conv_w, z2_w, h_w, m_w);
  int write_states = (out_size >= (int)(BB*TT*64*HW + 3*NSTATE)) ? 1 : 0;

  for (int t=0; t<TT; t++){
    conv_tc<<<dim3(8,4,8),256>>>(inputs, conv_b, t);
    gn_qkv<<<dim3(8,16),512>>>(gn_g, gn_b, h_b, m_b, t);
    qk_stats<<<dim3(8,16,2),256>>>();
    av_tail<<<dim3(8,16),512,AT_SMEM>>>(z1_w, z1_b, z2_b, out, t, (t==TT-1) ? write_states : 0);
  }
}

// round 15
// speedup vs baseline: 4.0514x; 1.1349x over previous
#include <cuda_runtime.h>
#include <cuda_fp16.h>
#include <math.h>

#define BB 8
#define TT 8
#define HW 1024
#define CG 256
#define NSTATE (BB*64*HW)   // 524288
#define LOG2E 1.4426950408889634f

// ---- persistent state ----
__device__ float g_ih[NSTATE];
__device__ float g_ic[NSTATE];
__device__ float g_im[NSTATE];
// ---- scratch ----
__device__ float g_gates[BB*CG*HW];
__device__ float g_gsum [2][64];
__device__ float g_gsum2[2][64];
__device__ float g_oh[NSTATE];
__device__ float g_roff[2][BB*HW];
__device__ unsigned g_wTh[8*9*256*8];
__device__ unsigned g_z2T[128*192];
__device__ unsigned g_z1u[64*128];      // z1 weights tf32 pre-converted
__device__ unsigned g_hmw[10*1024];
__device__ unsigned g_qT[8*1024*32];
__device__ unsigned g_kT[2][8*1024*32];
__device__ unsigned g_vv[2][8*64*512];

__device__ __forceinline__ float sigm(float x){
  float e = __expf(-x);
  float r; asm("rcp.approx.f32 %0,%1;" : "=f"(r) : "f"(1.f+e));
  return r;
}
__device__ __forceinline__ float tfast(float x){
  return __fmaf_rn(2.f, sigm(2.f*x), -1.f);
}
__device__ __forceinline__ unsigned f2t(float x){
  unsigned r; asm("cvt.rna.tf32.f32 %0,%1;" : "=r"(r) : "f"(x)); return r;
}
__device__ __forceinline__ void mma8(float* d, const unsigned* a, unsigned b0, unsigned b1){
  asm volatile("mma.sync.aligned.m16n8k8.row.col.f32.tf32.tf32.f32 "
    "{%0,%1,%2,%3},{%4,%5,%6,%7},{%8,%9},{%0,%1,%2,%3};"
    : "+f"(d[0]),"+f"(d[1]),"+f"(d[2]),"+f"(d[3])
    : "r"(a[0]),"r"(a[1]),"r"(a[2]),"r"(a[3]),"r"(b0),"r"(b1));
}
__device__ __forceinline__ void mma16(float* d, const unsigned* a, unsigned b0, unsigned b1){
  asm volatile("mma.sync.aligned.m16n8k16.row.col.f32.f16.f16.f32 "
    "{%0,%1,%2,%3},{%4,%5,%6,%7},{%8,%9},{%0,%1,%2,%3};"
    : "+f"(d[0]),"+f"(d[1]),"+f"(d[2]),"+f"(d[3])
    : "r"(a[0]),"r"(a[1]),"r"(a[2]),"r"(a[3]),"r"(b0),"r"(b1));
}
__device__ __forceinline__ unsigned pack2h(float x, float y){
  __half2 h = __floats2half2_rn(x, y);
  return *(unsigned*)&h;
}
__device__ __forceinline__ unsigned exp2_pair_h(float x0, float x1){
  __half2 h = h2exp2(__floats2half2_rn(x0, x1));
  return *(unsigned*)&h;
}
__device__ __forceinline__ float2 exp2_pair_f(float x0, float x1){
  __half2 h = h2exp2(__floats2half2_rn(x0, x1));
  return __half22float2(h);
}

__device__ __forceinline__ int tw(int row, int j){ return row*32 + (j ^ ((row&7)<<2)); }

__device__ __forceinline__ unsigned saddr(const unsigned* p){
  return (unsigned)__cvta_generic_to_shared((const void*)p);
}
__device__ __forceinline__ void cpa16(unsigned* sdst, const void* gsrc){
  unsigned ad = saddr(sdst);
  asm volatile("cp.async.cg.shared.global [%0], [%1], 16;" :: "r"(ad), "l"(gsrc));
}
#define CP_COMMIT asm volatile("cp.async.commit_group;")
#define CP_WAIT0  asm volatile("cp.async.wait_group 0;")

__device__ __forceinline__ void loadTile(unsigned* dst, const unsigned* __restrict__ src,
                                         int rowstride, int ltid){
  #pragma unroll
  for (int it=0; it<2; it++){
    int idx = it*256 + ltid;
    int row = idx>>3, j4 = (idx&7)*4;
    uint4 v = *(const uint4*)(src + (size_t)row*rowstride + j4);
    *(uint4*)&dst[tw(row, j4)] = v;
  }
}
__device__ __forceinline__ void loadTileAsync(unsigned* dst, const unsigned* __restrict__ src,
                                              int rowstride, int ltid){
  #pragma unroll
  for (int it=0; it<2; it++){
    int idx = it*256 + ltid;
    int row = idx>>3, j4 = (idx&7)*4;
    cpa16(dst + tw(row, j4), src + (size_t)row*rowstride + j4);
  }
}
__device__ __forceinline__ void ldsmA(unsigned* a, const unsigned* t, int r, int kk){
  int lane = threadIdx.x & 31;
  int row = r + (lane&7) + (lane&8);
  int j   = kk*8 + ((lane>>4)<<2);
  unsigned ad = saddr(t + tw(row, j));
  asm volatile("ldmatrix.sync.aligned.m8n8.x4.shared.b16 {%0,%1,%2,%3}, [%4];"
    : "=r"(a[0]),"=r"(a[1]),"=r"(a[2]),"=r"(a[3]) : "r"(ad));
}
__device__ __forceinline__ void ldsmB2(unsigned* b, const unsigned* t, int nb, int kk){
  int lane = threadIdx.x & 31;
  int row = nb + (lane&7) + ((lane>>4)<<3);
  int j   = kk*8 + (((lane>>3)&1)<<2);
  unsigned ad = saddr(t + tw(row, j));
  asm volatile("ldmatrix.sync.aligned.m8n8.x4.shared.b16 {%0,%1,%2,%3}, [%4];"
    : "=r"(b[0]),"=r"(b[1]),"=r"(b[2]),"=r"(b[3]) : "r"(ad));
}

__global__ void zero_states(){
  int i = blockIdx.x*256 + threadIdx.x;
  if (i < NSTATE){ g_ih[i]=0.f; g_ic[i]=0.f; g_im[i]=0.f; }
  if (blockIdx.x==0 && threadIdx.x<64){
    g_gsum[0][threadIdx.x]=0.f; g_gsum2[0][threadIdx.x]=0.f;
    g_gsum[1][threadIdx.x]=0.f; g_gsum2[1][threadIdx.x]=0.f;
  }
}

__global__ void wtrans(const float* __restrict__ w, const float* __restrict__ z2w,
                       const float* __restrict__ hw, const float* __restrict__ mw,
                       const float* __restrict__ z1w){
  int co = blockIdx.x;
  for (int idx = threadIdx.x; idx < 576; idx += 256){
    int chunk = idx/72, r = idx - chunk*72, pos = r>>3, j = r&7;
    int ci = chunk*16 + 2*j;
    float v0 = w[((size_t)co*128 + ci  )*9 + pos];
    float v1 = w[((size_t)co*128 + ci+1)*9 + pos];
    g_wTh[((size_t)(chunk*9+pos)*256 + co)*8 + j] = pack2h(v0, v1);
  }
  if (co < 192){
    for (int c = threadIdx.x; c < 128; c += 256)
      g_z2T[c*192 + co] = f2t(z2w[co*128 + c]);
    if (threadIdx.x < 32){
      int j = threadIdx.x;
      int y = co>>5, row = co&31;
      g_hmw[y*1024 + tw(row, j)] = pack2h(hw[co*64 + 2*j], hw[co*64 + 2*j + 1]);
    }
  }
  if (co < 128 && threadIdx.x >= 32 && threadIdx.x < 64){
    int j = threadIdx.x - 32;
    int y = 6 + (co>>5), row = co&31;
    g_hmw[y*1024 + tw(row, j)] = pack2h(mw[co*64 + 2*j], mw[co*64 + 2*j + 1]);
  }
  if (co < 64){
    for (int c = threadIdx.x; c < 128; c += 256)
      g_z1u[co*128 + c] = f2t(z1w[co*128 + c]);
  }
}

// ------------- 3x3 conv (fp16 TC, pipelined staging) + fused GN stats -------
__global__ __launch_bounds__(256) void conv_tc(const float* __restrict__ xin,
                                               const float* __restrict__ bias, int t)
{
  int pt = blockIdx.x, cot = blockIdx.y, b = blockIdx.z;
  int y0 = pt*4, co0 = cot*64, par = t & 1;
  __shared__ unsigned sIn[8*232];
  __shared__ unsigned sW[2][4608];
  __shared__ float ws[8], ws2[8];
  int tid=threadIdx.x, warp=tid>>5, lane=tid&31, g=lane>>2, tq=lane&3;
  int wc = warp&3, wm = warp>>2;
  float acc[8][4];
  #pragma unroll
  for(int j=0;j<8;j++){acc[j][0]=0.f;acc[j][1]=0.f;acc[j][2]=0.f;acc[j][3]=0.f;}

  int pix = tid;
  int yy = pix/34, xx = pix - yy*34;
  int gy = y0-1+yy, gx = xx-1;
  bool pv = (pix<204) && ((unsigned)gy<32u) && ((unsigned)gx<32u);
  int gidx = gy*32 + gx;

  const float* xbase = xin + (size_t)(b*TT+t)*64*HW;
  const float* hbase = g_ih + (size_t)b*64*HW;

  float rin[16];
  {
    const float* src = xbase;
    #pragma unroll
    for (int j=0;j<8;j++){
      rin[2*j]=0.f; rin[2*j+1]=0.f;
      if (pv){ rin[2*j] = src[(size_t)(2*j)*HW + gidx]; rin[2*j+1] = src[(size_t)(2*j+1)*HW + gidx]; }
    }
  }
  for (int i4=tid; i4<1152; i4+=256)
    cpa16(&sW[0][i4*4], g_wTh + (size_t)0*9*2048 + co0*8 + (i4>>7)*2048 + (i4&127)*4);
  CP_COMMIT;

  for (int chunk=0; chunk<8; chunk++){
    int cb = chunk&1;
    __syncthreads();
    if (pix < 204){
      #pragma unroll
      for (int j=0;j<8;j++) sIn[j*232 + pix] = pack2h(rin[2*j], rin[2*j+1]);
    }
    CP_WAIT0;
    __syncthreads();
    if (chunk < 7){
      const float* src = (chunk+1<4) ? (xbase + (size_t)(chunk+1)*16*HW)
                                     : (hbase + (size_t)(chunk+1-4)*16*HW);
      #pragma unroll
      for (int j=0;j<8;j++){
        rin[2*j]=0.f; rin[2*j+1]=0.f;
        if (pv){ rin[2*j] = src[(size_t)(2*j)*HW + gidx]; rin[2*j+1] = src[(size_t)(2*j+1)*HW + gidx]; }
      }
      for (int i4=tid; i4<1152; i4+=256)
        cpa16(&sW[cb^1][i4*4], g_wTh + (size_t)(chunk+1)*9*2048 + co0*8 + (i4>>7)*2048 + (i4&127)*4);
      CP_COMMIT;
    }
    #pragma unroll
    for (int pos=0; pos<9; pos++){
      int ky = pos/3, kx = pos - 3*ky;
      unsigned a[4];
      int rb = pos*512 + (wc*16+g)*8;
      a[0] = sW[cb][rb + tq];       a[1] = sW[cb][rb + 64 + tq];
      a[2] = sW[cb][rb + tq + 4];   a[3] = sW[cb][rb + 64 + tq + 4];
      #pragma unroll
      for (int mf=0; mf<8; mf++){
        int p = wm*64 + mf*8 + g;
        int pixb = ((p>>5)+ky)*34 + (p&31) + kx;
        mma16(acc[mf], a, sIn[tq*232 + pixb], sIn[(tq+4)*232 + pixb]);
      }
    }
  }
  int r0 = co0 + wc*16 + g, r1 = r0 + 8;
  float bv0 = bias[r0], bv1 = bias[r1];
  float s=0.f, s2=0.f;
  #pragma unroll
  for (int mf=0; mf<8; mf++){
    int col = y0*32 + wm*64 + mf*8 + 2*tq;
    float v0=acc[mf][0]+bv0, v1=acc[mf][1]+bv0;
    float v2=acc[mf][2]+bv1, v3=acc[mf][3]+bv1;
    *(float2*)&g_gates[((size_t)b*CG + r0)*HW + col] = make_float2(v0,v1);
    *(float2*)&g_gates[((size_t)b*CG + r1)*HW + col] = make_float2(v2,v3);
    s  += v0+v1+v2+v3;
    s2 += v0*v0+v1*v1+v2*v2+v3*v3;
  }
  #pragma unroll
  for (int off=16; off; off>>=1){
    s  += __shfl_xor_sync(0xffffffffu, s , off);
    s2 += __shfl_xor_sync(0xffffffffu, s2, off);
  }
  if (lane==0){ ws[warp]=s; ws2[warp]=s2; }
  __syncthreads();
  if (tid<2){
    float S  = ws [tid*2]+ws [tid*2+1]+ws [tid*2+4]+ws [tid*2+5];
    float S2 = ws2[tid*2]+ws2[tid*2+1]+ws2[tid*2+4]+ws2[tid*2+5];
    int gidx2 = b*8 + (co0>>5) + tid;
    atomicAdd(&g_gsum [par][gidx2], S );
    atomicAdd(&g_gsum2[par][gidx2], S2);
  }
}

// ---------- fused GN+LSTM gating + QKV projections (fp16 TC, 32px tiles) ------
// grid (b=8, pt=32 of 32px), block 256 (8 warps = 2 yb-groups of 4)
__global__ __launch_bounds__(256) void gn_qkv(const float* __restrict__ gg,
                                              const float* __restrict__ gb,
                                              const float* __restrict__ h_b,
                                              const float* __restrict__ m_b, int t)
{
  __shared__ unsigned sOh[1024];     // oh tw tile [32px][32 c-pair]
  __shared__ unsigned sIm[1024];     // im tw tile
  __shared__ unsigned uW[2][2048];   // weight pair double buffer
  __shared__ float smu[8], srs[8];
  int b = blockIdx.x, p0 = blockIdx.y*32;
  int tid = threadIdx.x;
  int par = t & 1;
  if (tid < 8){
    float s  = g_gsum [par][b*8+tid];
    float s2 = g_gsum2[par][b*8+tid];
    float m   = s*(1.f/32768.f);
    float var = s2*(1.f/32768.f) - m*m;
    smu[tid] = m;
    srs[tid] = rsqrtf(var + 1e-5f);
  }
  if (b==0 && blockIdx.y==0 && tid>=64 && tid<128){
    g_gsum[par^1][tid-64]=0.f; g_gsum2[par^1][tid-64]=0.f;
  }
  // prefetch weights pair 0 (yb 0,1)
  cpa16(&uW[0][tid*4], g_hmw + tid*4);
  cpa16(&uW[0][(tid+256)*4], g_hmw + (tid+256)*4);
  CP_COMMIT;
  // stage im tile
  {
    const float* imb = g_im + (size_t)b*64*HW + p0;
    #pragma unroll
    for (int it=0; it<4; it++){
      int idx = it*256 + tid;
      int px = idx & 31, j = idx >> 5;
      float v0 = imb[(size_t)(2*j  )*HW + px];
      float v1 = imb[(size_t)(2*j+1)*HW + px];
      sIm[tw(px, j)] = pack2h(v0, v1);
    }
  }
  __syncthreads();   // stats ready
  // ---- gating: produce oh tile (smem + global), update ic ----
  {
    const float* gt  = g_gates + (size_t)b*CG*HW + p0;
    float* icp = g_ic + (size_t)b*64*HW + p0;
    float* ohp = g_oh + (size_t)b*64*HW + p0;
    #pragma unroll
    for (int it=0; it<4; it++){
      int idx = it*256 + tid;
      int px = idx & 31, j = idx >> 5;
      float ohpair[2];
      #pragma unroll
      for (int e=0; e<2; e++){
        int cc = 2*j + e;
        float vi = gt[(size_t)(cc     )*HW + px];
        float vf = gt[(size_t)(cc+ 64 )*HW + px];
        float vc = gt[(size_t)(cc+128 )*HW + px];
        float vo = gt[(size_t)(cc+192 )*HW + px];
        int g0 = cc >> 5;
        float a  = (vi-smu[g0  ])*srs[g0  ]*gg[cc    ] + gb[cc    ];
        float f2 = (vf-smu[g0+2])*srs[g0+2]*gg[cc+64 ] + gb[cc+64 ];
        float cg = (vc-smu[g0+4])*srs[g0+4]*gg[cc+128] + gb[cc+128];
        float o  = (vo-smu[g0+6])*srs[g0+6]*gg[cc+192] + gb[cc+192];
        float icv = icp[(size_t)cc*HW + px];
        float oc = icv*sigm(f2) + sigm(a)*tfast(cg);
        float oh = sigm(o)*tfast(oc);
        icp[(size_t)cc*HW + px] = oc;
        ohp[(size_t)cc*HW + px] = oh;
        ohpair[e] = oh;
      }
      sOh[tw(px, j)] = pack2h(ohpair[0], ohpair[1]);
    }
  }
  __syncthreads();   // sOh visible

  int warp = tid>>5, lane = tid&31, g = lane>>2, tq = lane&3;
  int wgrp  = warp >> 2;      // 0/1 -> yb within pair
  int warp4 = warp & 3;

  for (int pr=0; pr<5; pr++){
    int buf = pr & 1;
    CP_WAIT0;
    __syncthreads();
    if (pr < 4){
      cpa16(&uW[buf^1][tid*4], g_hmw + (pr+1)*2048 + tid*4);
      cpa16(&uW[buf^1][(tid+256)*4], g_hmw + (pr+1)*2048 + (tid+256)*4);
      CP_COMMIT;
    }
    int yb = 2*pr + wgrp;
    const unsigned* w  = uW[buf] + wgrp*1024;
    const unsigned* xT = (yb < 6) ? sOh : sIm;
    const float* bias  = (yb < 6) ? h_b : m_b;
    int o0 = (yb < 6) ? yb*32 : (yb-6)*32;
    unsigned* dstT = 0; unsigned* dstV = 0; int crel = 0;
    if (yb < 6){
      if      (o0 <  64){ dstT = g_qT;    crel = o0;       }
      else if (o0 < 128){ dstT = g_kT[0]; crel = o0 - 64;  }
      else              { dstV = g_vv[0]; crel = o0 - 128; }
    } else {
      if (o0 < 64){ dstT = g_kT[1]; crel = o0; }
      else        { dstV = g_vv[1]; crel = o0 - 64; }
    }
    if (dstV){
      int wc = warp4&1, wm = warp4>>1;
      float acc[2][4];
      acc[0][0]=acc[0][1]=acc[0][2]=acc[0][3]=0.f;
      acc[1][0]=acc[1][1]=acc[1][2]=acc[1][3]=0.f;
      #pragma unroll
      for (int kk=0; kk<4; kk++){
        unsigned a[4]; ldsmA(a, w, wc*16, kk);
        unsigned bb[4]; ldsmB2(bb, xT, wm*16, kk);
        mma16(acc[0], a, bb[0], bb[1]);
        mma16(acc[1], a, bb[2], bb[3]);
      }
      int cc0 = wc*16 + g;
      float bv0 = bias[o0+cc0], bv1 = bias[o0+cc0+8];
      #pragma unroll
      for (int oct=0; oct<2; oct++){
        int col = p0 + wm*16 + oct*8 + 2*tq;
        dstV[((size_t)(b*64 + crel + cc0  ))*512 + (col>>1)] = pack2h(acc[oct][0]+bv0, acc[oct][1]+bv0);
        dstV[((size_t)(b*64 + crel + cc0+8))*512 + (col>>1)] = pack2h(acc[oct][2]+bv1, acc[oct][3]+bv1);
      }
    } else {
      int wpx = warp4&1, wo = warp4>>1;
      float acc[2][4];
      acc[0][0]=acc[0][1]=acc[0][2]=acc[0][3]=0.f;
      acc[1][0]=acc[1][1]=acc[1][2]=acc[1][3]=0.f;
      #pragma unroll
      for (int kk=0; kk<4; kk++){
        unsigned a[4]; ldsmA(a, xT, wpx*16, kk);
        unsigned bb[4]; ldsmB2(bb, w, wo*16, kk);
        mma16(acc[0], a, bb[0], bb[1]);
        mma16(acc[1], a, bb[2], bb[3]);
      }
      int row0 = wpx*16 + g;
      #pragma unroll
      for (int oct=0; oct<2; oct++){
        int col = wo*16 + oct*8 + 2*tq;
        float b0 = bias[o0+col], b1 = bias[o0+col+1];
        int wj = (crel + col) >> 1;
        dstT[((size_t)(b*1024 + p0 + row0  ))*32 + wj] = pack2h(acc[oct][0]+b0, acc[oct][1]+b1);
        dstT[((size_t)(b*1024 + p0 + row0+8))*32 + wj] = pack2h(acc[oct][2]+b0, acc[oct][3]+b1);
      }
    }
  }
}

// ------------------- pass 1 (pipelined K): row softmax stats ----------
__global__ __launch_bounds__(256) void qk_stats(){
  __shared__ unsigned uQ[2048];
  __shared__ unsigned uK[2][2][2048];
  __shared__ float sM[2][64], sL[2][64];
  int b = blockIdx.x, n0 = blockIdx.y*64, which = blockIdx.z;
  const unsigned* qsrc = g_qT + (size_t)(b*1024 + n0)*32;
  const unsigned* ksrc = g_kT[which] + (size_t)b*1024*32;
  int tid=threadIdx.x, warp=tid>>5, tq=(tid&31)&3;
  int g = (tid&31)>>2;
  int wn = warp&3, wm = warp>>2;
  loadTile(uQ, qsrc, 32, tid);
  loadTileAsync(uK[0][0], ksrc, 32, tid);
  loadTileAsync(uK[0][1], ksrc + 64*32, 32, tid);
  CP_COMMIT;
  CP_WAIT0;
  __syncthreads();
  float M0=-1e30f, M1=-1e30f, L0=0.f, L1=0.f;
  for (int it=0; it<8; it++){
    int cur = it&1;
    if (it < 7){
      const unsigned* kn = ksrc + (size_t)(it+1)*128*32;
      loadTileAsync(uK[cur^1][0], kn, 32, tid);
      loadTileAsync(uK[cur^1][1], kn + 64*32, 32, tid);
      CP_COMMIT;
    }
    const unsigned* kt = uK[cur][wm];
    float cfr[8][4];
    #pragma unroll
    for(int mf=0;mf<8;mf++){cfr[mf][0]=0.f;cfr[mf][1]=0.f;cfr[mf][2]=0.f;cfr[mf][3]=0.f;}
    #pragma unroll
    for (int kk=0; kk<4; kk++){
      unsigned a[4]; ldsmA(a, uQ, wn*16, kk);
      #pragma unroll
      for (int mp=0; mp<4; mp++){
        unsigned bb[4]; ldsmB2(bb, kt, mp*16, kk);
        mma16(cfr[2*mp  ], a, bb[0], bb[1]);
        mma16(cfr[2*mp+1], a, bb[2], bb[3]);
      }
    }
    float tm0=-1e30f, tm1=-1e30f;
    #pragma unroll
    for(int mf=0;mf<8;mf++){
      tm0 = fmaxf(tm0, fmaxf(cfr[mf][0], cfr[mf][1]));
      tm1 = fmaxf(tm1, fmaxf(cfr[mf][2], cfr[mf][3]));
    }
    tm0 = fmaxf(tm0, __shfl_xor_sync(0xffffffffu, tm0, 1));
    tm0 = fmaxf(tm0, __shfl_xor_sync(0xffffffffu, tm0, 2));
    tm1 = fmaxf(tm1, __shfl_xor_sync(0xffffffffu, tm1, 1));
    tm1 = fmaxf(tm1, __shfl_xor_sync(0xffffffffu, tm1, 2));
    float nM0 = fmaxf(M0, tm0), nM1 = fmaxf(M1, tm1);
    float c0 = nM0*LOG2E, c1 = nM1*LOG2E;
    float s0=0.f, s1=0.f;
    #pragma unroll
    for(int mf=0;mf<8;mf++){
      float2 e0 = exp2_pair_f(__fmaf_rn(cfr[mf][0], LOG2E, -c0),
                              __fmaf_rn(cfr[mf][1], LOG2E, -c0));
      float2 e1 = exp2_pair_f(__fmaf_rn(cfr[mf][2], LOG2E, -c1),
                              __fmaf_rn(cfr[mf][3], LOG2E, -c1));
      s0 += e0.x + e0.y;
      s1 += e1.x + e1.y;
    }
    s0 += __shfl_xor_sync(0xffffffffu, s0, 1);
    s0 += __shfl_xor_sync(0xffffffffu, s0, 2);
    s1 += __shfl_xor_sync(0xffffffffu, s1, 1);
    s1 += __shfl_xor_sync(0xffffffffu, s1, 2);
    L0 = L0*__expf(M0-nM0) + s0; M0 = nM0;
    L1 = L1*__expf(M1-nM1) + s1; M1 = nM1;
    if (it < 7){ CP_WAIT0; }
    __syncthreads();
  }
  if (tq==0){
    sM[wm][wn*16+g  ] = M0; sL[wm][wn*16+g  ] = L0;
    sM[wm][wn*16+8+g] = M1; sL[wm][wn*16+8+g] = L1;
  }
  __syncthreads();
  if (tid<64){
    float Ma = sM[0][tid], Mb = sM[1][tid];
    float M  = fmaxf(Ma, Mb);
    float L  = sL[0][tid]*__expf(Ma-M) + sL[1][tid]*__expf(Mb-M);
    g_roff[which][b*HW + n0 + tid] = __fmaf_rn(M, LOG2E, __log2f(L));
  }
}

// ------------------- merged pass 2 + tail (128-n iterations) --------------------
#define WB 22784
__global__ __launch_bounds__(512,1) void av_tail(const float* __restrict__ z1_b,
                                                 const float* __restrict__ z2_b,
                                                 float* __restrict__ out, int t, int ws)
{
  extern __shared__ unsigned arena[];
  int b = blockIdx.x, m0 = blockIdx.y*64;
  int p0 = m0;
  int tid = threadIdx.x;
  int lane = tid & 31, g = lane>>2, tq = lane&3;

  // ================= AV phase =================
  {
    int which = tid >> 8;
    int ltid  = tid & 255;
    int warp8 = ltid >> 5;
    int wr = warp8 & 3, wm = warp8 >> 2;
    unsigned* base = arena + which*WB;
    unsigned* uK  = base;
    unsigned* uQb = base + 2048;
    unsigned* uVb = base + 10240;
    unsigned* uP  = base + 18432;
    float*   sro  = (float*)(base + 22528);
    const unsigned* qsrc = g_qT + (size_t)b*1024*32;
    const unsigned* ksrc = g_kT[which] + (size_t)(b*1024 + m0)*32;
    const unsigned* vsrc = g_vv[which] + (size_t)b*64*512;
    const float*    roff = g_roff[which] + b*HW;

    loadTile(uK, ksrc, 32, ltid);
    loadTileAsync(uQb,        qsrc,          32, ltid);
    loadTileAsync(uQb + 2048, qsrc + 64*32,  32, ltid);
    loadTileAsync(uVb,        vsrc,          512, ltid);
    loadTileAsync(uVb + 2048, vsrc + 32,     512, ltid);
    CP_COMMIT;
    if (ltid < 128) sro[ltid] = roff[ltid];
    float accZ[4][4];
    #pragma unroll
    for(int mf=0;mf<4;mf++){accZ[mf][0]=0.f;accZ[mf][1]=0.f;accZ[mf][2]=0.f;accZ[mf][3]=0.f;}
    CP_WAIT0;
    __syncthreads();

    for (int itn=0; itn<8; itn++){
      int nb = itn*128;
      int cur = itn&1;
      if (itn < 7){
        int buf = cur^1;
        loadTileAsync(uQb + buf*4096,        qsrc + (size_t)(nb+128)*32, 32, ltid);
        loadTileAsync(uQb + buf*4096 + 2048, qsrc + (size_t)(nb+192)*32, 32, ltid);
        loadTileAsync(uVb + buf*4096,        vsrc + ((nb+128)>>1), 512, ltid);
        loadTileAsync(uVb + buf*4096 + 2048, vsrc + ((nb+192)>>1), 512, ltid);
        CP_COMMIT;
        if (ltid < 128) sro[buf*128 + ltid] = roff[nb+128+ltid];
      }
      #pragma unroll
      for (int s=0; s<2; s++){
        unsigned* uQ = uQb + cur*4096 + s*2048;
        float*    sr = sro + cur*128 + s*64;
        unsigned* uPs = uP + s*2048;
        float accS[4][4];
        #pragma unroll
        for(int mf=0;mf<4;mf++){accS[mf][0]=0.f;accS[mf][1]=0.f;accS[mf][2]=0.f;accS[mf][3]=0.f;}
        #pragma unroll
        for (int kk=0; kk<4; kk++){
          unsigned a[4]; ldsmA(a, uK, wr*16, kk);
          #pragma unroll
          for (int mp=0; mp<2; mp++){
            unsigned bb[4]; ldsmB2(bb, uQ, wm*32 + mp*16, kk);
            mma16(accS[2*mp  ], a, bb[0], bb[1]);
            mma16(accS[2*mp+1], a, bb[2], bb[3]);
          }
        }
        #pragma unroll
        for (int mf=0; mf<4; mf++){
          int n = wm*32 + mf*8 + 2*tq;
          float ro0 = sr[n], ro1 = sr[n+1];
          int jn = n >> 1;
          int r0 = wr*16 + g;
          uPs[tw(r0,   jn)] = exp2_pair_h(__fmaf_rn(accS[mf][0], LOG2E, -ro0),
                                          __fmaf_rn(accS[mf][1], LOG2E, -ro1));
          uPs[tw(r0+8, jn)] = exp2_pair_h(__fmaf_rn(accS[mf][2], LOG2E, -ro0),
                                          __fmaf_rn(accS[mf][3], LOG2E, -ro1));
        }
      }
      __syncthreads();
      #pragma unroll
      for (int s=0; s<2; s++){
        unsigned* uV = uVb + cur*4096 + s*2048;
        unsigned* uPs = uP + s*2048;
        #pragma unroll
        for (int kk=0; kk<4; kk++){
          unsigned a[4]; ldsmA(a, uV, wr*16, kk);
          #pragma unroll
          for (int mp=0; mp<2; mp++){
            unsigned bb[4]; ldsmB2(bb, uPs, wm*32 + mp*16, kk);
            mma16(accZ[2*mp  ], a, bb[0], bb[1]);
            mma16(accZ[2*mp+1], a, bb[2], bb[3]);
          }
        }
      }
      if (itn < 7){ CP_WAIT0; }
      __syncthreads();
    }
    unsigned* sZc = arena;
    int zoff = which*64;
    #pragma unroll
    for (int mf=0; mf<4; mf++){
      int r0 = zoff + wr*16 + g, r1 = r0 + 8;
      int col = wm*32 + mf*8 + 2*tq;
      *(uint2*)&sZc[r0*72 + col] = make_uint2(f2t(accZ[mf][0]), f2t(accZ[mf][1]));
      *(uint2*)&sZc[r1*72 + col] = make_uint2(f2t(accZ[mf][2]), f2t(accZ[mf][3]));
    }
  }
  // ================= tail phase =================
  unsigned* sZc  = arena;                // [128][72] tf32
  unsigned* uz1  = arena + 9216;         // [64][132]
  unsigned* sOh  = arena + 17664;        // [64][72]
  unsigned* sZ   = arena + 22272;        // [64][72]
  unsigned* wch0 = arena + 26880;        // [8][200]
  unsigned* wch1 = arena + 28480;        // [8][200]
  float*  gates  = (float*)arena;        // [192][66]

  // stage z1 weights via cp.async (pre-converted tf32)
  for (int i4=tid; i4<2048; i4+=512)
    cpa16(&uz1[(i4>>5)*132 + (i4&31)*4], g_z1u + i4*4);
  // prefetch z2T chunk 0
  if (tid < 384)
    cpa16(&wch0[(tid/48)*200 + (tid%48)*4], g_z2T + (tid/48)*192 + (tid%48)*4);
  CP_COMMIT;
  for (int idx=tid; idx<2048; idx+=512){
    int c = idx>>5, p2 = idx&31;
    float2 v = *(const float2*)&g_oh[((size_t)b*64+c)*HW + p0 + 2*p2];
    *(uint2*)&sOh[c*72 + 2*p2] = make_uint2(f2t(v.x), f2t(v.y));
  }
  CP_WAIT0;
  __syncthreads();

  int warp16 = tid>>5;
  int wc = warp16 & 1, wm8 = warp16 >> 1;

  // ---- z1 ----
  float a1[2][4];
  #pragma unroll
  for(int ot=0;ot<2;ot++){a1[ot][0]=0.f;a1[ot][1]=0.f;a1[ot][2]=0.f;a1[ot][3]=0.f;}
  for (int cc=0; cc<128; cc+=8){
    unsigned b0 = sZc[(cc+tq  )*72 + wm8*8 + g];
    unsigned b1 = sZc[(cc+tq+4)*72 + wm8*8 + g];
    #pragma unroll
    for (int ot=0; ot<2; ot++){
      unsigned a[4];
      int r = ot*32 + wc*16 + g;
      a[0]=uz1[(r  )*132 + cc+tq];   a[1]=uz1[(r+8)*132 + cc+tq];
      a[2]=uz1[(r  )*132 + cc+tq+4]; a[3]=uz1[(r+8)*132 + cc+tq+4];
      mma8(a1[ot], a, b0, b1);
    }
  }
  __syncthreads();
  #pragma unroll
  for (int ot=0; ot<2; ot++){
    int r0 = ot*32 + wc*16 + g, r1 = r0 + 8;
    int col = wm8*8 + 2*tq;
    float bv0 = z1_b[r0], bv1 = z1_b[r1];
    *(uint2*)&sZ[r0*72 + col] = make_uint2(f2t(a1[ot][0]+bv0), f2t(a1[ot][1]+bv0));
    *(uint2*)&sZ[r1*72 + col] = make_uint2(f2t(a1[ot][2]+bv1), f2t(a1[ot][3]+bv1));
  }
  // ---- z2 (cp.async double-buffered weight chunks) ----
  float a2[6][4];
  #pragma unroll
  for(int ot=0;ot<6;ot++){a2[ot][0]=0.f;a2[ot][1]=0.f;a2[ot][2]=0.f;a2[ot][3]=0.f;}
  for (int ch=0; ch<16; ch++){
    unsigned* wch = (ch&1) ? wch1 : wch0;
    if (ch > 0){ CP_WAIT0; }
    __syncthreads();
    if (ch < 15){
      unsigned* wn = ((ch+1)&1) ? wch1 : wch0;
      if (tid < 384)
        cpa16(&wn[(tid/48)*200 + (tid%48)*4], g_z2T + ((size_t)(ch+1)*8 + tid/48)*192 + (tid%48)*4);
      CP_COMMIT;
    }
    int cc = ch*8;
    const unsigned* src = (cc<64) ? (sZ + cc*72) : (sOh + (cc-64)*72);
    unsigned b0 = src[ tq   *72 + wm8*8 + g];
    unsigned b1 = src[(tq+4)*72 + wm8*8 + g];
    #pragma unroll
    for (int ot=0; ot<6; ot++){
      unsigned a[4];
      int o = ot*32 + wc*16 + g;
      a[0]=wch[ tq   *200 + o];   a[1]=wch[ tq   *200 + o+8];
      a[2]=wch[(tq+4)*200 + o];   a[3]=wch[(tq+4)*200 + o+8];
      mma8(a2[ot], a, b0, b1);
    }
  }
  __syncthreads();
  #pragma unroll
  for (int ot=0; ot<6; ot++){
    int r0 = ot*32 + wc*16 + g, r1 = r0 + 8;
    int col = wm8*8 + 2*tq;
    float bv0 = z2_b[r0], bv1 = z2_b[r1];
    *(float2*)&gates[r0*66 + col] = make_float2(a2[ot][0]+bv0, a2[ot][1]+bv0);
    *(float2*)&gates[r1*66 + col] = make_float2(a2[ot][2]+bv1, a2[ot][3]+bv1);
  }
  __syncthreads();
  for (int i=tid; i<4096; i+=512){
    int c = i>>6, p = i&63;
    float vo = gates[(c     )*66 + p];
    float vg = gates[(64 +c )*66 + p];
    float vi = gates[(128+c )*66 + p];
    int idx = (b*64 + c)*1024 + p0 + p;
    float si = sigm(vi);
    float om  = tfast(vg)*si + (1.f-si)*g_im[idx];
    float oh2 = sigm(vo)*om;
    g_im[idx] = om;
    g_ih[idx] = oh2;
    out[(((size_t)b*TT + t)*64 + c)*HW + p0 + p] = oh2;
    if (ws){
      float* st = out + (size_t)BB*TT*64*HW;
      st[idx]            = oh2;
      st[NSTATE + idx]   = g_ic[idx];
      st[2*NSTATE + idx] = om;
    }
  }
}

extern "C" void kernel_launch(void* const* d_in, const int* in_sizes, int n_in,
                              void* d_out, int out_size)
{
  const float* inputs = (const float*)d_in[0];
  const float* conv_w = (const float*)d_in[1];
  const float* conv_b = (const float*)d_in[2];
  const float* gn_g   = (const float*)d_in[3];
  const float* gn_b   = (const float*)d_in[4];
  const float* h_w    = (const float*)d_in[5];
  const float* h_b    = (const float*)d_in[6];
  const float* m_w    = (const float*)d_in[7];
  const float* m_b    = (const float*)d_in[8];
  const float* z1_w   = (const float*)d_in[9];
  const float* z1_b   = (const float*)d_in[10];
  const float* z2_w   = (const float*)d_in[11];
  const float* z2_b   = (const float*)d_in[12];
  float* out = (float*)d_out;

  const int AT_SMEM = 2*WB*4;   // 182272
  cudaFuncSetAttribute(av_tail, cudaFuncAttributeMaxDynamicSharedMemorySize, AT_SMEM);

  zero_states<<<2048,256>>>();
  wtrans<<<256,256>>>(conv_w, z2_w, h_w, m_w, z1_w);
  int write_states = (out_size >= (int)(BB*TT*64*HW + 3*NSTATE)) ? 1 : 0;

  for (int t=0; t<TT; t++){
    conv_tc<<<dim3(8,4,8),256>>>(inputs, conv_b, t);
    gn_qkv<<<dim3(8,32),256>>>(gn_g, gn_b, h_b, m_b, t);
    qk_stats<<<dim3(8,16,2),256>>>();
    av_tail<<<dim3(8,16),512,AT_SMEM>>>(z1_b, z2_b, out, t, (t==TT-1) ? write_states : 0);
  }
}

// round 16
// speedup vs baseline: 4.0843x; 1.0081x over previous
#include <cuda_runtime.h>
#include <cuda_fp16.h>
#include <math.h>

#define BB 8
#define TT 8
#define HW 1024
#define CG 256
#define NSTATE (BB*64*HW)   // 524288
#define LOG2E 1.4426950408889634f

// ---- persistent state ----
__device__ float g_ih[NSTATE];
__device__ float g_ic[NSTATE];
__device__ float g_im[NSTATE];
// ---- scratch ----
__device__ float g_gates[BB*CG*HW];
__device__ float g_gsum [2][64];
__device__ float g_gsum2[2][64];
__device__ float g_oh[NSTATE];
__device__ float g_roff[2][BB*HW];
__device__ unsigned g_wTh[8*9*256*8];
__device__ unsigned g_z2T[128*192];
__device__ unsigned g_z1u[64*128];
__device__ unsigned g_hmw[10*1024];
__device__ unsigned g_qT[8*1024*32];
__device__ unsigned g_kT[2][8*1024*32];
__device__ unsigned g_vv[2][8*64*512];

__device__ __forceinline__ float sigm(float x){
  float e = __expf(-x);
  float r; asm("rcp.approx.f32 %0,%1;" : "=f"(r) : "f"(1.f+e));
  return r;
}
__device__ __forceinline__ float tfast(float x){
  return __fmaf_rn(2.f, sigm(2.f*x), -1.f);
}
__device__ __forceinline__ unsigned f2t(float x){
  unsigned r; asm("cvt.rna.tf32.f32 %0,%1;" : "=r"(r) : "f"(x)); return r;
}
__device__ __forceinline__ void mma8(float* d, const unsigned* a, unsigned b0, unsigned b1){
  asm volatile("mma.sync.aligned.m16n8k8.row.col.f32.tf32.tf32.f32 "
    "{%0,%1,%2,%3},{%4,%5,%6,%7},{%8,%9},{%0,%1,%2,%3};"
    : "+f"(d[0]),"+f"(d[1]),"+f"(d[2]),"+f"(d[3])
    : "r"(a[0]),"r"(a[1]),"r"(a[2]),"r"(a[3]),"r"(b0),"r"(b1));
}
__device__ __forceinline__ void mma16(float* d, const unsigned* a, unsigned b0, unsigned b1){
  asm volatile("mma.sync.aligned.m16n8k16.row.col.f32.f16.f16.f32 "
    "{%0,%1,%2,%3},{%4,%5,%6,%7},{%8,%9},{%0,%1,%2,%3};"
    : "+f"(d[0]),"+f"(d[1]),"+f"(d[2]),"+f"(d[3])
    : "r"(a[0]),"r"(a[1]),"r"(a[2]),"r"(a[3]),"r"(b0),"r"(b1));
}
__device__ __forceinline__ unsigned pack2h(float x, float y){
  __half2 h = __floats2half2_rn(x, y);
  return *(unsigned*)&h;
}
__device__ __forceinline__ unsigned exp2_pair_h(float x0, float x1){
  __half2 h = h2exp2(__floats2half2_rn(x0, x1));
  return *(unsigned*)&h;
}
__device__ __forceinline__ float2 exp2_pair_f(float x0, float x1){
  __half2 h = h2exp2(__floats2half2_rn(x0, x1));
  return __half22float2(h);
}

__device__ __forceinline__ int tw(int row, int j){ return row*32 + (j ^ ((row&7)<<2)); }

__device__ __forceinline__ unsigned saddr(const unsigned* p){
  return (unsigned)__cvta_generic_to_shared((const void*)p);
}
__device__ __forceinline__ void cpa16(unsigned* sdst, const void* gsrc){
  unsigned ad = saddr(sdst);
  asm volatile("cp.async.cg.shared.global [%0], [%1], 16;" :: "r"(ad), "l"(gsrc));
}
#define CP_COMMIT asm volatile("cp.async.commit_group;")
#define CP_WAIT0  asm volatile("cp.async.wait_group 0;")

__device__ __forceinline__ void loadTile(unsigned* dst, const unsigned* __restrict__ src,
                                         int rowstride, int ltid){
  #pragma unroll
  for (int it=0; it<2; it++){
    int idx = it*256 + ltid;
    int row = idx>>3, j4 = (idx&7)*4;
    uint4 v = *(const uint4*)(src + (size_t)row*rowstride + j4);
    *(uint4*)&dst[tw(row, j4)] = v;
  }
}
__device__ __forceinline__ void loadTileAsync(unsigned* dst, const unsigned* __restrict__ src,
                                              int rowstride, int ltid){
  #pragma unroll
  for (int it=0; it<2; it++){
    int idx = it*256 + ltid;
    int row = idx>>3, j4 = (idx&7)*4;
    cpa16(dst + tw(row, j4), src + (size_t)row*rowstride + j4);
  }
}
__device__ __forceinline__ void ldsmA(unsigned* a, const unsigned* t, int r, int kk){
  int lane = threadIdx.x & 31;
  int row = r + (lane&7) + (lane&8);
  int j   = kk*8 + ((lane>>4)<<2);
  unsigned ad = saddr(t + tw(row, j));
  asm volatile("ldmatrix.sync.aligned.m8n8.x4.shared.b16 {%0,%1,%2,%3}, [%4];"
    : "=r"(a[0]),"=r"(a[1]),"=r"(a[2]),"=r"(a[3]) : "r"(ad));
}
__device__ __forceinline__ void ldsmB2(unsigned* b, const unsigned* t, int nb, int kk){
  int lane = threadIdx.x & 31;
  int row = nb + (lane&7) + ((lane>>4)<<3);
  int j   = kk*8 + (((lane>>3)&1)<<2);
  unsigned ad = saddr(t + tw(row, j));
  asm volatile("ldmatrix.sync.aligned.m8n8.x4.shared.b16 {%0,%1,%2,%3}, [%4];"
    : "=r"(b[0]),"=r"(b[1]),"=r"(b[2]),"=r"(b[3]) : "r"(ad));
}

__global__ void zero_states(){
  int i = blockIdx.x*256 + threadIdx.x;
  if (i < NSTATE){ g_ih[i]=0.f; g_ic[i]=0.f; g_im[i]=0.f; }
  if (blockIdx.x==0 && threadIdx.x<64){
    g_gsum[0][threadIdx.x]=0.f; g_gsum2[0][threadIdx.x]=0.f;
    g_gsum[1][threadIdx.x]=0.f; g_gsum2[1][threadIdx.x]=0.f;
  }
}

__global__ void wtrans(const float* __restrict__ w, const float* __restrict__ z2w,
                       const float* __restrict__ hw, const float* __restrict__ mw,
                       const float* __restrict__ z1w){
  int co = blockIdx.x;
  for (int idx = threadIdx.x; idx < 576; idx += 256){
    int chunk = idx/72, r = idx - chunk*72, pos = r>>3, j = r&7;
    int ci = chunk*16 + 2*j;
    float v0 = w[((size_t)co*128 + ci  )*9 + pos];
    float v1 = w[((size_t)co*128 + ci+1)*9 + pos];
    g_wTh[((size_t)(chunk*9+pos)*256 + co)*8 + j] = pack2h(v0, v1);
  }
  if (co < 192){
    for (int c = threadIdx.x; c < 128; c += 256)
      g_z2T[c*192 + co] = f2t(z2w[co*128 + c]);
    if (threadIdx.x < 32){
      int j = threadIdx.x;
      int y = co>>5, row = co&31;
      g_hmw[y*1024 + tw(row, j)] = pack2h(hw[co*64 + 2*j], hw[co*64 + 2*j + 1]);
    }
  }
  if (co < 128 && threadIdx.x >= 32 && threadIdx.x < 64){
    int j = threadIdx.x - 32;
    int y = 6 + (co>>5), row = co&31;
    g_hmw[y*1024 + tw(row, j)] = pack2h(mw[co*64 + 2*j], mw[co*64 + 2*j + 1]);
  }
  if (co < 64){
    for (int c = threadIdx.x; c < 128; c += 256)
      g_z1u[co*128 + c] = f2t(z1w[co*128 + c]);
  }
}

// ------------- 3x3 conv (fp16 TC, pipelined staging) + fused GN stats -------
__global__ __launch_bounds__(256) void conv_tc(const float* __restrict__ xin,
                                               const float* __restrict__ bias, int t)
{
  int pt = blockIdx.x, cot = blockIdx.y, b = blockIdx.z;
  int y0 = pt*4, co0 = cot*64, par = t & 1;
  __shared__ unsigned sIn[8*232];
  __shared__ unsigned sW[2][4608];
  __shared__ float ws[8], ws2[8];
  int tid=threadIdx.x, warp=tid>>5, lane=tid&31, g=lane>>2, tq=lane&3;
  int wc = warp&3, wm = warp>>2;
  float acc[8][4];
  #pragma unroll
  for(int j=0;j<8;j++){acc[j][0]=0.f;acc[j][1]=0.f;acc[j][2]=0.f;acc[j][3]=0.f;}

  int pix = tid;
  int yy = pix/34, xx = pix - yy*34;
  int gy = y0-1+yy, gx = xx-1;
  bool pv = (pix<204) && ((unsigned)gy<32u) && ((unsigned)gx<32u);
  int gidx = gy*32 + gx;

  const float* xbase = xin + (size_t)(b*TT+t)*64*HW;
  const float* hbase = g_ih + (size_t)b*64*HW;

  float rin[16];
  {
    const float* src = xbase;
    #pragma unroll
    for (int j=0;j<8;j++){
      rin[2*j]=0.f; rin[2*j+1]=0.f;
      if (pv){ rin[2*j] = src[(size_t)(2*j)*HW + gidx]; rin[2*j+1] = src[(size_t)(2*j+1)*HW + gidx]; }
    }
  }
  for (int i4=tid; i4<1152; i4+=256)
    cpa16(&sW[0][i4*4], g_wTh + (size_t)0*9*2048 + co0*8 + (i4>>7)*2048 + (i4&127)*4);
  CP_COMMIT;

  for (int chunk=0; chunk<8; chunk++){
    int cb = chunk&1;
    __syncthreads();
    if (pix < 204){
      #pragma unroll
      for (int j=0;j<8;j++) sIn[j*232 + pix] = pack2h(rin[2*j], rin[2*j+1]);
    }
    CP_WAIT0;
    __syncthreads();
    if (chunk < 7){
      const float* src = (chunk+1<4) ? (xbase + (size_t)(chunk+1)*16*HW)
                                     : (hbase + (size_t)(chunk+1-4)*16*HW);
      #pragma unroll
      for (int j=0;j<8;j++){
        rin[2*j]=0.f; rin[2*j+1]=0.f;
        if (pv){ rin[2*j] = src[(size_t)(2*j)*HW + gidx]; rin[2*j+1] = src[(size_t)(2*j+1)*HW + gidx]; }
      }
      for (int i4=tid; i4<1152; i4+=256)
        cpa16(&sW[cb^1][i4*4], g_wTh + (size_t)(chunk+1)*9*2048 + co0*8 + (i4>>7)*2048 + (i4&127)*4);
      CP_COMMIT;
    }
    #pragma unroll
    for (int pos=0; pos<9; pos++){
      int ky = pos/3, kx = pos - 3*ky;
      unsigned a[4];
      int rb = pos*512 + (wc*16+g)*8;
      a[0] = sW[cb][rb + tq];       a[1] = sW[cb][rb + 64 + tq];
      a[2] = sW[cb][rb + tq + 4];   a[3] = sW[cb][rb + 64 + tq + 4];
      #pragma unroll
      for (int mf=0; mf<8; mf++){
        int p = wm*64 + mf*8 + g;
        int pixb = ((p>>5)+ky)*34 + (p&31) + kx;
        mma16(acc[mf], a, sIn[tq*232 + pixb], sIn[(tq+4)*232 + pixb]);
      }
    }
  }
  int r0 = co0 + wc*16 + g, r1 = r0 + 8;
  float bv0 = bias[r0], bv1 = bias[r1];
  float s=0.f, s2=0.f;
  #pragma unroll
  for (int mf=0; mf<8; mf++){
    int col = y0*32 + wm*64 + mf*8 + 2*tq;
    float v0=acc[mf][0]+bv0, v1=acc[mf][1]+bv0;
    float v2=acc[mf][2]+bv1, v3=acc[mf][3]+bv1;
    *(float2*)&g_gates[((size_t)b*CG + r0)*HW + col] = make_float2(v0,v1);
    *(float2*)&g_gates[((size_t)b*CG + r1)*HW + col] = make_float2(v2,v3);
    s  += v0+v1+v2+v3;
    s2 += v0*v0+v1*v1+v2*v2+v3*v3;
  }
  #pragma unroll
  for (int off=16; off; off>>=1){
    s  += __shfl_xor_sync(0xffffffffu, s , off);
    s2 += __shfl_xor_sync(0xffffffffu, s2, off);
  }
  if (lane==0){ ws[warp]=s; ws2[warp]=s2; }
  __syncthreads();
  if (tid<2){
    float S  = ws [tid*2]+ws [tid*2+1]+ws [tid*2+4]+ws [tid*2+5];
    float S2 = ws2[tid*2]+ws2[tid*2+1]+ws2[tid*2+4]+ws2[tid*2+5];
    int gidx2 = b*8 + (co0>>5) + tid;
    atomicAdd(&g_gsum [par][gidx2], S );
    atomicAdd(&g_gsum2[par][gidx2], S2);
  }
}

// ---------- fused GN+LSTM gating + QKV projections (all weights resident) -----
// grid (b=8, pt=32 of 32px), block 256 (8 warps = 2 yb-groups of 4)
__global__ __launch_bounds__(256) void gn_qkv(const float* __restrict__ gg,
                                              const float* __restrict__ gb,
                                              const float* __restrict__ h_b,
                                              const float* __restrict__ m_b, int t)
{
  extern __shared__ unsigned dyn[];
  unsigned* sOh   = dyn;            // 1024
  unsigned* sIm   = dyn + 1024;     // 1024
  unsigned* uWall = dyn + 2048;     // 10240 (all 10 weight tiles)
  float*    smu   = (float*)(dyn + 12288);  // 8
  float*    srs   = smu + 8;
  int b = blockIdx.x, p0 = blockIdx.y*32;
  int tid = threadIdx.x;
  int par = t & 1;
  // async ALL projection weights (hidden under the gating phase)
  #pragma unroll
  for (int it=0; it<10; it++)
    cpa16(&uWall[(it*256 + tid)*4], g_hmw + (it*256 + tid)*4);
  CP_COMMIT;
  if (tid < 8){
    float s  = g_gsum [par][b*8+tid];
    float s2 = g_gsum2[par][b*8+tid];
    float m   = s*(1.f/32768.f);
    float var = s2*(1.f/32768.f) - m*m;
    smu[tid] = m;
    srs[tid] = rsqrtf(var + 1e-5f);
  }
  if (b==0 && blockIdx.y==0 && tid>=64 && tid<128){
    g_gsum[par^1][tid-64]=0.f; g_gsum2[par^1][tid-64]=0.f;
  }
  // stage im tile
  {
    const float* imb = g_im + (size_t)b*64*HW + p0;
    #pragma unroll
    for (int it=0; it<4; it++){
      int idx = it*256 + tid;
      int px = idx & 31, j = idx >> 5;
      float v0 = imb[(size_t)(2*j  )*HW + px];
      float v1 = imb[(size_t)(2*j+1)*HW + px];
      sIm[tw(px, j)] = pack2h(v0, v1);
    }
  }
  __syncthreads();   // stats ready
  // ---- gating: produce oh tile (smem + global), update ic ----
  {
    const float* gt  = g_gates + (size_t)b*CG*HW + p0;
    float* icp = g_ic + (size_t)b*64*HW + p0;
    float* ohp = g_oh + (size_t)b*64*HW + p0;
    #pragma unroll
    for (int it=0; it<4; it++){
      int idx = it*256 + tid;
      int px = idx & 31, j = idx >> 5;
      float ohpair[2];
      #pragma unroll
      for (int e=0; e<2; e++){
        int cc = 2*j + e;
        float vi = gt[(size_t)(cc     )*HW + px];
        float vf = gt[(size_t)(cc+ 64 )*HW + px];
        float vc = gt[(size_t)(cc+128 )*HW + px];
        float vo = gt[(size_t)(cc+192 )*HW + px];
        int g0 = cc >> 5;
        float a  = (vi-smu[g0  ])*srs[g0  ]*gg[cc    ] + gb[cc    ];
        float f2 = (vf-smu[g0+2])*srs[g0+2]*gg[cc+64 ] + gb[cc+64 ];
        float cg = (vc-smu[g0+4])*srs[g0+4]*gg[cc+128] + gb[cc+128];
        float o  = (vo-smu[g0+6])*srs[g0+6]*gg[cc+192] + gb[cc+192];
        float icv = icp[(size_t)cc*HW + px];
        float oc = icv*sigm(f2) + sigm(a)*tfast(cg);
        float oh = sigm(o)*tfast(oc);
        icp[(size_t)cc*HW + px] = oc;
        ohp[(size_t)cc*HW + px] = oh;
        ohpair[e] = oh;
      }
      sOh[tw(px, j)] = pack2h(ohpair[0], ohpair[1]);
    }
  }
  CP_WAIT0;          // weights landed
  __syncthreads();   // sOh + weights visible

  int warp = tid>>5, lane = tid&31, g = lane>>2, tq = lane&3;
  int wgrp  = warp >> 2;
  int warp4 = warp & 3;

  #pragma unroll
  for (int pr=0; pr<5; pr++){
    int yb = 2*pr + wgrp;
    const unsigned* w  = uWall + yb*1024;
    const unsigned* xT = (yb < 6) ? sOh : sIm;
    const float* bias  = (yb < 6) ? h_b : m_b;
    int o0 = (yb < 6) ? yb*32 : (yb-6)*32;
    unsigned* dstT = 0; unsigned* dstV = 0; int crel = 0;
    if (yb < 6){
      if      (o0 <  64){ dstT = g_qT;    crel = o0;       }
      else if (o0 < 128){ dstT = g_kT[0]; crel = o0 - 64;  }
      else              { dstV = g_vv[0]; crel = o0 - 128; }
    } else {
      if (o0 < 64){ dstT = g_kT[1]; crel = o0; }
      else        { dstV = g_vv[1]; crel = o0 - 64; }
    }
    if (dstV){
      int wc = warp4&1, wm = warp4>>1;
      float acc[2][4];
      acc[0][0]=acc[0][1]=acc[0][2]=acc[0][3]=0.f;
      acc[1][0]=acc[1][1]=acc[1][2]=acc[1][3]=0.f;
      #pragma unroll
      for (int kk=0; kk<4; kk++){
        unsigned a[4]; ldsmA(a, w, wc*16, kk);
        unsigned bb[4]; ldsmB2(bb, xT, wm*16, kk);
        mma16(acc[0], a, bb[0], bb[1]);
        mma16(acc[1], a, bb[2], bb[3]);
      }
      int cc0 = wc*16 + g;
      float bv0 = bias[o0+cc0], bv1 = bias[o0+cc0+8];
      #pragma unroll
      for (int oct=0; oct<2; oct++){
        int col = p0 + wm*16 + oct*8 + 2*tq;
        dstV[((size_t)(b*64 + crel + cc0  ))*512 + (col>>1)] = pack2h(acc[oct][0]+bv0, acc[oct][1]+bv0);
        dstV[((size_t)(b*64 + crel + cc0+8))*512 + (col>>1)] = pack2h(acc[oct][2]+bv1, acc[oct][3]+bv1);
      }
    } else {
      int wpx = warp4&1, wo = warp4>>1;
      float acc[2][4];
      acc[0][0]=acc[0][1]=acc[0][2]=acc[0][3]=0.f;
      acc[1][0]=acc[1][1]=acc[1][2]=acc[1][3]=0.f;
      #pragma unroll
      for (int kk=0; kk<4; kk++){
        unsigned a[4]; ldsmA(a, xT, wpx*16, kk);
        unsigned bb[4]; ldsmB2(bb, w, wo*16, kk);
        mma16(acc[0], a, bb[0], bb[1]);
        mma16(acc[1], a, bb[2], bb[3]);
      }
      int row0 = wpx*16 + g;
      #pragma unroll
      for (int oct=0; oct<2; oct++){
        int col = wo*16 + oct*8 + 2*tq;
        float b0 = bias[o0+col], b1 = bias[o0+col+1];
        int wj = (crel + col) >> 1;
        dstT[((size_t)(b*1024 + p0 + row0  ))*32 + wj] = pack2h(acc[oct][0]+b0, acc[oct][1]+b1);
        dstT[((size_t)(b*1024 + p0 + row0+8))*32 + wj] = pack2h(acc[oct][2]+b0, acc[oct][3]+b1);
      }
    }
  }
}

// ------------------- pass 1 (pipelined K): row softmax stats ----------
__global__ __launch_bounds__(256) void qk_stats(){
  __shared__ unsigned uQ[2048];
  __shared__ unsigned uK[2][2][2048];
  __shared__ float sM[2][64], sL[2][64];
  int b = blockIdx.x, n0 = blockIdx.y*64, which = blockIdx.z;
  const unsigned* qsrc = g_qT + (size_t)(b*1024 + n0)*32;
  const unsigned* ksrc = g_kT[which] + (size_t)b*1024*32;
  int tid=threadIdx.x, warp=tid>>5, tq=(tid&31)&3;
  int g = (tid&31)>>2;
  int wn = warp&3, wm = warp>>2;
  loadTile(uQ, qsrc, 32, tid);
  loadTileAsync(uK[0][0], ksrc, 32, tid);
  loadTileAsync(uK[0][1], ksrc + 64*32, 32, tid);
  CP_COMMIT;
  CP_WAIT0;
  __syncthreads();
  float M0=-1e30f, M1=-1e30f, L0=0.f, L1=0.f;
  for (int it=0; it<8; it++){
    int cur = it&1;
    if (it < 7){
      const unsigned* kn = ksrc + (size_t)(it+1)*128*32;
      loadTileAsync(uK[cur^1][0], kn, 32, tid);
      loadTileAsync(uK[cur^1][1], kn + 64*32, 32, tid);
      CP_COMMIT;
    }
    const unsigned* kt = uK[cur][wm];
    float cfr[8][4];
    #pragma unroll
    for(int mf=0;mf<8;mf++){cfr[mf][0]=0.f;cfr[mf][1]=0.f;cfr[mf][2]=0.f;cfr[mf][3]=0.f;}
    #pragma unroll
    for (int kk=0; kk<4; kk++){
      unsigned a[4]; ldsmA(a, uQ, wn*16, kk);
      #pragma unroll
      for (int mp=0; mp<4; mp++){
        unsigned bb[4]; ldsmB2(bb, kt, mp*16, kk);
        mma16(cfr[2*mp  ], a, bb[0], bb[1]);
        mma16(cfr[2*mp+1], a, bb[2], bb[3]);
      }
    }
    float tm0=-1e30f, tm1=-1e30f;
    #pragma unroll
    for(int mf=0;mf<8;mf++){
      tm0 = fmaxf(tm0, fmaxf(cfr[mf][0], cfr[mf][1]));
      tm1 = fmaxf(tm1, fmaxf(cfr[mf][2], cfr[mf][3]));
    }
    tm0 = fmaxf(tm0, __shfl_xor_sync(0xffffffffu, tm0, 1));
    tm0 = fmaxf(tm0, __shfl_xor_sync(0xffffffffu, tm0, 2));
    tm1 = fmaxf(tm1, __shfl_xor_sync(0xffffffffu, tm1, 1));
    tm1 = fmaxf(tm1, __shfl_xor_sync(0xffffffffu, tm1, 2));
    float nM0 = fmaxf(M0, tm0), nM1 = fmaxf(M1, tm1);
    float c0 = nM0*LOG2E, c1 = nM1*LOG2E;
    float s0=0.f, s1=0.f;
    #pragma unroll
    for(int mf=0;mf<8;mf++){
      float2 e0 = exp2_pair_f(__fmaf_rn(cfr[mf][0], LOG2E, -c0),
                              __fmaf_rn(cfr[mf][1], LOG2E, -c0));
      float2 e1 = exp2_pair_f(__fmaf_rn(cfr[mf][2], LOG2E, -c1),
                              __fmaf_rn(cfr[mf][3], LOG2E, -c1));
      s0 += e0.x + e0.y;
      s1 += e1.x + e1.y;
    }
    s0 += __shfl_xor_sync(0xffffffffu, s0, 1);
    s0 += __shfl_xor_sync(0xffffffffu, s0, 2);
    s1 += __shfl_xor_sync(0xffffffffu, s1, 1);
    s1 += __shfl_xor_sync(0xffffffffu, s1, 2);
    L0 = L0*__expf(M0-nM0) + s0; M0 = nM0;
    L1 = L1*__expf(M1-nM1) + s1; M1 = nM1;
    if (it < 7){ CP_WAIT0; }
    __syncthreads();
  }
  if (tq==0){
    sM[wm][wn*16+g  ] = M0; sL[wm][wn*16+g  ] = L0;
    sM[wm][wn*16+8+g] = M1; sL[wm][wn*16+8+g] = L1;
  }
  __syncthreads();
  if (tid<64){
    float Ma = sM[0][tid], Mb = sM[1][tid];
    float M  = fmaxf(Ma, Mb);
    float L  = sL[0][tid]*__expf(Ma-M) + sL[1][tid]*__expf(Mb-M);
    g_roff[which][b*HW + n0 + tid] = __fmaf_rn(M, LOG2E, __log2f(L));
  }
}

// ------------------- merged pass 2 + tail (128-n iterations) --------------------
#define WB 22784
__global__ __launch_bounds__(512,1) void av_tail(const float* __restrict__ z1_b,
                                                 const float* __restrict__ z2_b,
                                                 float* __restrict__ out, int t, int ws)
{
  extern __shared__ unsigned arena[];
  int b = blockIdx.x, m0 = blockIdx.y*64;
  int p0 = m0;
  int tid = threadIdx.x;
  int lane = tid & 31, g = lane>>2, tq = lane&3;

  // ================= AV phase =================
  {
    int which = tid >> 8;
    int ltid  = tid & 255;
    int warp8 = ltid >> 5;
    int wr = warp8 & 3, wm = warp8 >> 2;
    unsigned* base = arena + which*WB;
    unsigned* uK  = base;
    unsigned* uQb = base + 2048;
    unsigned* uVb = base + 10240;
    unsigned* uP  = base + 18432;
    float*   sro  = (float*)(base + 22528);
    const unsigned* qsrc = g_qT + (size_t)b*1024*32;
    const unsigned* ksrc = g_kT[which] + (size_t)(b*1024 + m0)*32;
    const unsigned* vsrc = g_vv[which] + (size_t)b*64*512;
    const float*    roff = g_roff[which] + b*HW;

    loadTile(uK, ksrc, 32, ltid);
    loadTileAsync(uQb,        qsrc,          32, ltid);
    loadTileAsync(uQb + 2048, qsrc + 64*32,  32, ltid);
    loadTileAsync(uVb,        vsrc,          512, ltid);
    loadTileAsync(uVb + 2048, vsrc + 32,     512, ltid);
    CP_COMMIT;
    if (ltid < 128) sro[ltid] = roff[ltid];
    float accZ[4][4];
    #pragma unroll
    for(int mf=0;mf<4;mf++){accZ[mf][0]=0.f;accZ[mf][1]=0.f;accZ[mf][2]=0.f;accZ[mf][3]=0.f;}
    CP_WAIT0;
    __syncthreads();

    for (int itn=0; itn<8; itn++){
      int nb = itn*128;
      int cur = itn&1;
      if (itn < 7){
        int buf = cur^1;
        loadTileAsync(uQb + buf*4096,        qsrc + (size_t)(nb+128)*32, 32, ltid);
        loadTileAsync(uQb + buf*4096 + 2048, qsrc + (size_t)(nb+192)*32, 32, ltid);
        loadTileAsync(uVb + buf*4096,        vsrc + ((nb+128)>>1), 512, ltid);
        loadTileAsync(uVb + buf*4096 + 2048, vsrc + ((nb+192)>>1), 512, ltid);
        CP_COMMIT;
        if (ltid < 128) sro[buf*128 + ltid] = roff[nb+128+ltid];
      }
      #pragma unroll
      for (int s=0; s<2; s++){
        unsigned* uQ = uQb + cur*4096 + s*2048;
        float*    sr = sro + cur*128 + s*64;
        unsigned* uPs = uP + s*2048;
        float accS[4][4];
        #pragma unroll
        for(int mf=0;mf<4;mf++){accS[mf][0]=0.f;accS[mf][1]=0.f;accS[mf][2]=0.f;accS[mf][3]=0.f;}
        #pragma unroll
        for (int kk=0; kk<4; kk++){
          unsigned a[4]; ldsmA(a, uK, wr*16, kk);
          #pragma unroll
          for (int mp=0; mp<2; mp++){
            unsigned bb[4]; ldsmB2(bb, uQ, wm*32 + mp*16, kk);
            mma16(accS[2*mp  ], a, bb[0], bb[1]);
            mma16(accS[2*mp+1], a, bb[2], bb[3]);
          }
        }
        #pragma unroll
        for (int mf=0; mf<4; mf++){
          int n = wm*32 + mf*8 + 2*tq;
          float ro0 = sr[n], ro1 = sr[n+1];
          int jn = n >> 1;
          int r0 = wr*16 + g;
          uPs[tw(r0,   jn)] = exp2_pair_h(__fmaf_rn(accS[mf][0], LOG2E, -ro0),
                                          __fmaf_rn(accS[mf][1], LOG2E, -ro1));
          uPs[tw(r0+8, jn)] = exp2_pair_h(__fmaf_rn(accS[mf][2], LOG2E, -ro0),
                                          __fmaf_rn(accS[mf][3], LOG2E, -ro1));
        }
      }
      __syncthreads();
      #pragma unroll
      for (int s=0; s<2; s++){
        unsigned* uV = uVb + cur*4096 + s*2048;
        unsigned* uPs = uP + s*2048;
        #pragma unroll
        for (int kk=0; kk<4; kk++){
          unsigned a[4]; ldsmA(a, uV, wr*16, kk);
          #pragma unroll
          for (int mp=0; mp<2; mp++){
            unsigned bb[4]; ldsmB2(bb, uPs, wm*32 + mp*16, kk);
            mma16(accZ[2*mp  ], a, bb[0], bb[1]);
            mma16(accZ[2*mp+1], a, bb[2], bb[3]);
          }
        }
      }
      if (itn < 7){ CP_WAIT0; }
      __syncthreads();
    }
    unsigned* sZc = arena;
    int zoff = which*64;
    #pragma unroll
    for (int mf=0; mf<4; mf++){
      int r0 = zoff + wr*16 + g, r1 = r0 + 8;
      int col = wm*32 + mf*8 + 2*tq;
      *(uint2*)&sZc[r0*72 + col] = make_uint2(f2t(accZ[mf][0]), f2t(accZ[mf][1]));
      *(uint2*)&sZc[r1*72 + col] = make_uint2(f2t(accZ[mf][2]), f2t(accZ[mf][3]));
    }
  }
  // ================= tail phase =================
  unsigned* sZc  = arena;
  unsigned* uz1  = arena + 9216;
  unsigned* sOh  = arena + 17664;
  unsigned* sZ   = arena + 22272;
  unsigned* wch0 = arena + 26880;
  unsigned* wch1 = arena + 28480;
  float*  gates  = (float*)arena;

  for (int i4=tid; i4<2048; i4+=512)
    cpa16(&uz1[(i4>>5)*132 + (i4&31)*4], g_z1u + i4*4);
  if (tid < 384)
    cpa16(&wch0[(tid/48)*200 + (tid%48)*4], g_z2T + (tid/48)*192 + (tid%48)*4);
  CP_COMMIT;
  for (int idx=tid; idx<2048; idx+=512){
    int c = idx>>5, p2 = idx&31;
    float2 v = *(const float2*)&g_oh[((size_t)b*64+c)*HW + p0 + 2*p2];
    *(uint2*)&sOh[c*72 + 2*p2] = make_uint2(f2t(v.x), f2t(v.y));
  }
  CP_WAIT0;
  __syncthreads();

  int warp16 = tid>>5;
  int wc = warp16 & 1, wm8 = warp16 >> 1;

  float a1[2][4];
  #pragma unroll
  for(int ot=0;ot<2;ot++){a1[ot][0]=0.f;a1[ot][1]=0.f;a1[ot][2]=0.f;a1[ot][3]=0.f;}
  for (int cc=0; cc<128; cc+=8){
    unsigned b0 = sZc[(cc+tq  )*72 + wm8*8 + g];
    unsigned b1 = sZc[(cc+tq+4)*72 + wm8*8 + g];
    #pragma unroll
    for (int ot=0; ot<2; ot++){
      unsigned a[4];
      int r = ot*32 + wc*16 + g;
      a[0]=uz1[(r  )*132 + cc+tq];   a[1]=uz1[(r+8)*132 + cc+tq];
      a[2]=uz1[(r  )*132 + cc+tq+4]; a[3]=uz1[(r+8)*132 + cc+tq+4];
      mma8(a1[ot], a, b0, b1);
    }
  }
  __syncthreads();
  #pragma unroll
  for (int ot=0; ot<2; ot++){
    int r0 = ot*32 + wc*16 + g, r1 = r0 + 8;
    int col = wm8*8 + 2*tq;
    float bv0 = z1_b[r0], bv1 = z1_b[r1];
    *(uint2*)&sZ[r0*72 + col] = make_uint2(f2t(a1[ot][0]+bv0), f2t(a1[ot][1]+bv0));
    *(uint2*)&sZ[r1*72 + col] = make_uint2(f2t(a1[ot][2]+bv1), f2t(a1[ot][3]+bv1));
  }
  float a2[6][4];
  #pragma unroll
  for(int ot=0;ot<6;ot++){a2[ot][0]=0.f;a2[ot][1]=0.f;a2[ot][2]=0.f;a2[ot][3]=0.f;}
  for (int ch=0; ch<16; ch++){
    unsigned* wch = (ch&1) ? wch1 : wch0;
    if (ch > 0){ CP_WAIT0; }
    __syncthreads();
    if (ch < 15){
      unsigned* wn = ((ch+1)&1) ? wch1 : wch0;
      if (tid < 384)
        cpa16(&wn[(tid/48)*200 + (tid%48)*4], g_z2T + ((size_t)(ch+1)*8 + tid/48)*192 + (tid%48)*4);
      CP_COMMIT;
    }
    int cc = ch*8;
    const unsigned* src = (cc<64) ? (sZ + cc*72) : (sOh + (cc-64)*72);
    unsigned b0 = src[ tq   *72 + wm8*8 + g];
    unsigned b1 = src[(tq+4)*72 + wm8*8 + g];
    #pragma unroll
    for (int ot=0; ot<6; ot++){
      unsigned a[4];
      int o = ot*32 + wc*16 + g;
      a[0]=wch[ tq   *200 + o];   a[1]=wch[ tq   *200 + o+8];
      a[2]=wch[(tq+4)*200 + o];   a[3]=wch[(tq+4)*200 + o+8];
      mma8(a2[ot], a, b0, b1);
    }
  }
  __syncthreads();
  #pragma unroll
  for (int ot=0; ot<6; ot++){
    int r0 = ot*32 + wc*16 + g, r1 = r0 + 8;
    int col = wm8*8 + 2*tq;
    float bv0 = z2_b[r0], bv1 = z2_b[r1];
    *(float2*)&gates[r0*66 + col] = make_float2(a2[ot][0]+bv0, a2[ot][1]+bv0);
    *(float2*)&gates[r1*66 + col] = make_float2(a2[ot][2]+bv1, a2[ot][3]+bv1);
  }
  __syncthreads();
  for (int i=tid; i<4096; i+=512){
    int c = i>>6, p = i&63;
    float vo = gates[(c     )*66 + p];
    float vg = gates[(64 +c )*66 + p];
    float vi = gates[(128+c )*66 + p];
    int idx = (b*64 + c)*1024 + p0 + p;
    float si = sigm(vi);
    float om  = tfast(vg)*si + (1.f-si)*g_im[idx];
    float oh2 = sigm(vo)*om;
    g_im[idx] = om;
    g_ih[idx] = oh2;
    out[(((size_t)b*TT + t)*64 + c)*HW + p0 + p] = oh2;
    if (ws){
      float* st = out + (size_t)BB*TT*64*HW;
      st[idx]            = oh2;
      st[NSTATE + idx]   = g_ic[idx];
      st[2*NSTATE + idx] = om;
    }
  }
}

extern "C" void kernel_launch(void* const* d_in, const int* in_sizes, int n_in,
                              void* d_out, int out_size)
{
  const float* inputs = (const float*)d_in[0];
  const float* conv_w = (const float*)d_in[1];
  const float* conv_b = (const float*)d_in[2];
  const float* gn_g   = (const float*)d_in[3];
  const float* gn_b   = (const float*)d_in[4];
  const float* h_w    = (const float*)d_in[5];
  const float* h_b    = (const float*)d_in[6];
  const float* m_w    = (const float*)d_in[7];
  const float* m_b    = (const float*)d_in[8];
  const float* z1_w   = (const float*)d_in[9];
  const float* z1_b   = (const float*)d_in[10];
  const float* z2_w   = (const float*)d_in[11];
  const float* z2_b   = (const float*)d_in[12];
  float* out = (float*)d_out;

  const int AT_SMEM = 2*WB*4;      // 182272
  const int GQ_SMEM = 12288*4 + 64; // 49216
  cudaFuncSetAttribute(av_tail, cudaFuncAttributeMaxDynamicSharedMemorySize, AT_SMEM);
  cudaFuncSetAttribute(gn_qkv,  cudaFuncAttributeMaxDynamicSharedMemorySize, GQ_SMEM);

  zero_states<<<2048,256>>>();
  wtrans<<<256,256>>>(conv_w, z2_w, h_w, m_w, z1_w);
  int write_states = (out_size >= (int)(BB*TT*64*HW + 3*NSTATE)) ? 1 : 0;

  for (int t=0; t<TT; t++){
    conv_tc<<<dim3(8,4,8),256>>>(inputs, conv_b, t);
    gn_qkv<<<dim3(8,32),256,GQ_SMEM>>>(gn_g, gn_b, h_b, m_b, t);
    qk_stats<<<dim3(8,16,2),256>>>();
    av_tail<<<dim3(8,16),512,AT_SMEM>>>(z1_b, z2_b, out, t, (t==TT-1) ? write_states : 0);
  }
}

// round 17
// speedup vs baseline: 4.1512x; 1.0164x over previous
#include <cuda_runtime.h>
#include <cuda_fp16.h>
#include <math.h>

#define BB 8
#define TT 8
#define HW 1024
#define CG 256
#define NSTATE (BB*64*HW)   // 524288
#define LOG2E 1.4426950408889634f

// ---- persistent state ----
__device__ float g_ih[NSTATE];
__device__ float g_ic[NSTATE];
__device__ float g_im[NSTATE];
// ---- scratch ----
__device__ float g_gates[BB*CG*HW];
__device__ float g_gsum [2][64];
__device__ float g_gsum2[2][64];
__device__ float g_oh[NSTATE];
__device__ float g_roff[2][BB*HW];
__device__ unsigned g_wTh[8*9*256*8];
__device__ unsigned g_z2T[128*192];
__device__ unsigned g_z1u[64*128];
__device__ unsigned g_hmw[10*1024];
__device__ unsigned g_qT[8*1024*32];
__device__ unsigned g_kT[2][8*1024*32];
__device__ unsigned g_vv[2][8*64*512];

__device__ __forceinline__ float sigm(float x){
  float e = __expf(-x);
  float r; asm("rcp.approx.f32 %0,%1;" : "=f"(r) : "f"(1.f+e));
  return r;
}
__device__ __forceinline__ float tfast(float x){
  return __fmaf_rn(2.f, sigm(2.f*x), -1.f);
}
__device__ __forceinline__ unsigned f2t(float x){
  unsigned r; asm("cvt.rna.tf32.f32 %0,%1;" : "=r"(r) : "f"(x)); return r;
}
__device__ __forceinline__ void mma8(float* d, const unsigned* a, unsigned b0, unsigned b1){
  asm volatile("mma.sync.aligned.m16n8k8.row.col.f32.tf32.tf32.f32 "
    "{%0,%1,%2,%3},{%4,%5,%6,%7},{%8,%9},{%0,%1,%2,%3};"
    : "+f"(d[0]),"+f"(d[1]),"+f"(d[2]),"+f"(d[3])
    : "r"(a[0]),"r"(a[1]),"r"(a[2]),"r"(a[3]),"r"(b0),"r"(b1));
}
__device__ __forceinline__ void mma16(float* d, const unsigned* a, unsigned b0, unsigned b1){
  asm volatile("mma.sync.aligned.m16n8k16.row.col.f32.f16.f16.f32 "
    "{%0,%1,%2,%3},{%4,%5,%6,%7},{%8,%9},{%0,%1,%2,%3};"
    : "+f"(d[0]),"+f"(d[1]),"+f"(d[2]),"+f"(d[3])
    : "r"(a[0]),"r"(a[1]),"r"(a[2]),"r"(a[3]),"r"(b0),"r"(b1));
}
__device__ __forceinline__ unsigned pack2h(float x, float y){
  __half2 h = __floats2half2_rn(x, y);
  return *(unsigned*)&h;
}
__device__ __forceinline__ unsigned exp2_pair_h(float x0, float x1){
  __half2 h = h2exp2(__floats2half2_rn(x0, x1));
  return *(unsigned*)&h;
}
__device__ __forceinline__ float2 exp2_pair_f(float x0, float x1){
  __half2 h = h2exp2(__floats2half2_rn(x0, x1));
  return __half22float2(h);
}

__device__ __forceinline__ int tw(int row, int j){ return row*32 + (j ^ ((row&7)<<2)); }

__device__ __forceinline__ unsigned saddr(const unsigned* p){
  return (unsigned)__cvta_generic_to_shared((const void*)p);
}
__device__ __forceinline__ void cpa16(unsigned* sdst, const void* gsrc){
  unsigned ad = saddr(sdst);
  asm volatile("cp.async.cg.shared.global [%0], [%1], 16;" :: "r"(ad), "l"(gsrc));
}
#define CP_COMMIT asm volatile("cp.async.commit_group;")
#define CP_WAIT0  asm volatile("cp.async.wait_group 0;")

__device__ __forceinline__ void loadTile(unsigned* dst, const unsigned* __restrict__ src,
                                         int rowstride, int ltid){
  #pragma unroll
  for (int it=0; it<2; it++){
    int idx = it*256 + ltid;
    int row = idx>>3, j4 = (idx&7)*4;
    uint4 v = *(const uint4*)(src + (size_t)row*rowstride + j4);
    *(uint4*)&dst[tw(row, j4)] = v;
  }
}
__device__ __forceinline__ void loadTileAsync(unsigned* dst, const unsigned* __restrict__ src,
                                              int rowstride, int ltid){
  #pragma unroll
  for (int it=0; it<2; it++){
    int idx = it*256 + ltid;
    int row = idx>>3, j4 = (idx&7)*4;
    cpa16(dst + tw(row, j4), src + (size_t)row*rowstride + j4);
  }
}
__device__ __forceinline__ void ldsmA(unsigned* a, const unsigned* t, int r, int kk){
  int lane = threadIdx.x & 31;
  int row = r + (lane&7) + (lane&8);
  int j   = kk*8 + ((lane>>4)<<2);
  unsigned ad = saddr(t + tw(row, j));
  asm volatile("ldmatrix.sync.aligned.m8n8.x4.shared.b16 {%0,%1,%2,%3}, [%4];"
    : "=r"(a[0]),"=r"(a[1]),"=r"(a[2]),"=r"(a[3]) : "r"(ad));
}
__device__ __forceinline__ void ldsmB2(unsigned* b, const unsigned* t, int nb, int kk){
  int lane = threadIdx.x & 31;
  int row = nb + (lane&7) + ((lane>>4)<<3);
  int j   = kk*8 + (((lane>>3)&1)<<2);
  unsigned ad = saddr(t + tw(row, j));
  asm volatile("ldmatrix.sync.aligned.m8n8.x4.shared.b16 {%0,%1,%2,%3}, [%4];"
    : "=r"(b[0]),"=r"(b[1]),"=r"(b[2]),"=r"(b[3]) : "r"(ad));
}

__global__ void zero_states(){
  int i = blockIdx.x*256 + threadIdx.x;
  if (i < NSTATE){ g_ih[i]=0.f; g_ic[i]=0.f; g_im[i]=0.f; }
  if (blockIdx.x==0 && threadIdx.x<64){
    g_gsum[0][threadIdx.x]=0.f; g_gsum2[0][threadIdx.x]=0.f;
    g_gsum[1][threadIdx.x]=0.f; g_gsum2[1][threadIdx.x]=0.f;
  }
}

__global__ void wtrans(const float* __restrict__ w, const float* __restrict__ z2w,
                       const float* __restrict__ hw, const float* __restrict__ mw,
                       const float* __restrict__ z1w){
  int co = blockIdx.x;
  for (int idx = threadIdx.x; idx < 576; idx += 256){
    int chunk = idx/72, r = idx - chunk*72, pos = r>>3, j = r&7;
    int ci = chunk*16 + 2*j;
    float v0 = w[((size_t)co*128 + ci  )*9 + pos];
    float v1 = w[((size_t)co*128 + ci+1)*9 + pos];
    g_wTh[((size_t)(chunk*9+pos)*256 + co)*8 + j] = pack2h(v0, v1);
  }
  if (co < 192){
    for (int c = threadIdx.x; c < 128; c += 256)
      g_z2T[c*192 + co] = f2t(z2w[co*128 + c]);
    if (threadIdx.x < 32){
      int j = threadIdx.x;
      int y = co>>5, row = co&31;
      g_hmw[y*1024 + tw(row, j)] = pack2h(hw[co*64 + 2*j], hw[co*64 + 2*j + 1]);
    }
  }
  if (co < 128 && threadIdx.x >= 32 && threadIdx.x < 64){
    int j = threadIdx.x - 32;
    int y = 6 + (co>>5), row = co&31;
    g_hmw[y*1024 + tw(row, j)] = pack2h(mw[co*64 + 2*j], mw[co*64 + 2*j + 1]);
  }
  if (co < 64){
    for (int c = threadIdx.x; c < 128; c += 256)
      g_z1u[co*128 + c] = f2t(z1w[co*128 + c]);
  }
}

// ------------- 3x3 conv (fp16 TC, pipelined staging) + fused GN stats -------
__global__ __launch_bounds__(256) void conv_tc(const float* __restrict__ xin,
                                               const float* __restrict__ bias, int t)
{
  int pt = blockIdx.x, cot = blockIdx.y, b = blockIdx.z;
  int y0 = pt*4, co0 = cot*64, par = t & 1;
  __shared__ unsigned sIn[8*232];
  __shared__ unsigned sW[2][4608];
  __shared__ float ws[8], ws2[8];
  int tid=threadIdx.x, warp=tid>>5, lane=tid&31, g=lane>>2, tq=lane&3;
  int wc = warp&3, wm = warp>>2;
  float acc[8][4];
  #pragma unroll
  for(int j=0;j<8;j++){acc[j][0]=0.f;acc[j][1]=0.f;acc[j][2]=0.f;acc[j][3]=0.f;}

  int pix = tid;
  int yy = pix/34, xx = pix - yy*34;
  int gy = y0-1+yy, gx = xx-1;
  bool pv = (pix<204) && ((unsigned)gy<32u) && ((unsigned)gx<32u);
  int gidx = gy*32 + gx;

  const float* xbase = xin + (size_t)(b*TT+t)*64*HW;
  const float* hbase = g_ih + (size_t)b*64*HW;

  float rin[16];
  {
    const float* src = xbase;
    #pragma unroll
    for (int j=0;j<8;j++){
      rin[2*j]=0.f; rin[2*j+1]=0.f;
      if (pv){ rin[2*j] = src[(size_t)(2*j)*HW + gidx]; rin[2*j+1] = src[(size_t)(2*j+1)*HW + gidx]; }
    }
  }
  for (int i4=tid; i4<1152; i4+=256)
    cpa16(&sW[0][i4*4], g_wTh + (size_t)0*9*2048 + co0*8 + (i4>>7)*2048 + (i4&127)*4);
  CP_COMMIT;

  for (int chunk=0; chunk<8; chunk++){
    int cb = chunk&1;
    __syncthreads();
    if (pix < 204){
      #pragma unroll
      for (int j=0;j<8;j++) sIn[j*232 + pix] = pack2h(rin[2*j], rin[2*j+1]);
    }
    CP_WAIT0;
    __syncthreads();
    if (chunk < 7){
      const float* src = (chunk+1<4) ? (xbase + (size_t)(chunk+1)*16*HW)
                                     : (hbase + (size_t)(chunk+1-4)*16*HW);
      #pragma unroll
      for (int j=0;j<8;j++){
        rin[2*j]=0.f; rin[2*j+1]=0.f;
        if (pv){ rin[2*j] = src[(size_t)(2*j)*HW + gidx]; rin[2*j+1] = src[(size_t)(2*j+1)*HW + gidx]; }
      }
      for (int i4=tid; i4<1152; i4+=256)
        cpa16(&sW[cb^1][i4*4], g_wTh + (size_t)(chunk+1)*9*2048 + co0*8 + (i4>>7)*2048 + (i4&127)*4);
      CP_COMMIT;
    }
    #pragma unroll
    for (int pos=0; pos<9; pos++){
      int ky = pos/3, kx = pos - 3*ky;
      unsigned a[4];
      int rb = pos*512 + (wc*16+g)*8;
      a[0] = sW[cb][rb + tq];       a[1] = sW[cb][rb + 64 + tq];
      a[2] = sW[cb][rb + tq + 4];   a[3] = sW[cb][rb + 64 + tq + 4];
      #pragma unroll
      for (int mf=0; mf<8; mf++){
        int p = wm*64 + mf*8 + g;
        int pixb = ((p>>5)+ky)*34 + (p&31) + kx;
        mma16(acc[mf], a, sIn[tq*232 + pixb], sIn[(tq+4)*232 + pixb]);
      }
    }
  }
  int r0 = co0 + wc*16 + g, r1 = r0 + 8;
  float bv0 = bias[r0], bv1 = bias[r1];
  float s=0.f, s2=0.f;
  #pragma unroll
  for (int mf=0; mf<8; mf++){
    int col = y0*32 + wm*64 + mf*8 + 2*tq;
    float v0=acc[mf][0]+bv0, v1=acc[mf][1]+bv0;
    float v2=acc[mf][2]+bv1, v3=acc[mf][3]+bv1;
    *(float2*)&g_gates[((size_t)b*CG + r0)*HW + col] = make_float2(v0,v1);
    *(float2*)&g_gates[((size_t)b*CG + r1)*HW + col] = make_float2(v2,v3);
    s  += v0+v1+v2+v3;
    s2 += v0*v0+v1*v1+v2*v2+v3*v3;
  }
  #pragma unroll
  for (int off=16; off; off>>=1){
    s  += __shfl_xor_sync(0xffffffffu, s , off);
    s2 += __shfl_xor_sync(0xffffffffu, s2, off);
  }
  if (lane==0){ ws[warp]=s; ws2[warp]=s2; }
  __syncthreads();
  if (tid<2){
    float S  = ws [tid*2]+ws [tid*2+1]+ws [tid*2+4]+ws [tid*2+5];
    float S2 = ws2[tid*2]+ws2[tid*2+1]+ws2[tid*2+4]+ws2[tid*2+5];
    int gidx2 = b*8 + (co0>>5) + tid;
    atomicAdd(&g_gsum [par][gidx2], S );
    atomicAdd(&g_gsum2[par][gidx2], S2);
  }
}

// ---------- fused GN+LSTM gating + QKV projections (512 threads) --------------
// grid (b=8, pt=32 of 32px), block 512 (16 warps = 4 yb-groups of 4)
__global__ __launch_bounds__(512) void gn_qkv(const float* __restrict__ gg,
                                              const float* __restrict__ gb,
                                              const float* __restrict__ h_b,
                                              const float* __restrict__ m_b, int t)
{
  extern __shared__ unsigned dyn[];
  unsigned* sOh   = dyn;            // 1024
  unsigned* sIm   = dyn + 1024;     // 1024
  unsigned* uWall = dyn + 2048;     // 10240 (all 10 weight tiles)
  float*    smu   = (float*)(dyn + 12288);  // 8
  float*    srs   = smu + 8;
  int b = blockIdx.x, p0 = blockIdx.y*32;
  int tid = threadIdx.x;
  int par = t & 1;
  // async ALL projection weights (hidden under the gating phase)
  #pragma unroll
  for (int it=0; it<5; it++)
    cpa16(&uWall[(it*512 + tid)*4], g_hmw + (it*512 + tid)*4);
  CP_COMMIT;
  if (tid < 8){
    float s  = g_gsum [par][b*8+tid];
    float s2 = g_gsum2[par][b*8+tid];
    float m   = s*(1.f/32768.f);
    float var = s2*(1.f/32768.f) - m*m;
    smu[tid] = m;
    srs[tid] = rsqrtf(var + 1e-5f);
  }
  if (b==0 && blockIdx.y==0 && tid>=64 && tid<128){
    g_gsum[par^1][tid-64]=0.f; g_gsum2[par^1][tid-64]=0.f;
  }
  // stage im tile
  {
    const float* imb = g_im + (size_t)b*64*HW + p0;
    #pragma unroll
    for (int it=0; it<2; it++){
      int idx = it*512 + tid;
      int px = idx & 31, j = idx >> 5;
      float v0 = imb[(size_t)(2*j  )*HW + px];
      float v1 = imb[(size_t)(2*j+1)*HW + px];
      sIm[tw(px, j)] = pack2h(v0, v1);
    }
  }
  __syncthreads();   // stats ready
  // ---- gating: produce oh tile (smem + global), update ic ----
  {
    const float* gt  = g_gates + (size_t)b*CG*HW + p0;
    float* icp = g_ic + (size_t)b*64*HW + p0;
    float* ohp = g_oh + (size_t)b*64*HW + p0;
    #pragma unroll
    for (int it=0; it<2; it++){
      int idx = it*512 + tid;
      int px = idx & 31, j = idx >> 5;
      float ohpair[2];
      #pragma unroll
      for (int e=0; e<2; e++){
        int cc = 2*j + e;
        float vi = gt[(size_t)(cc     )*HW + px];
        float vf = gt[(size_t)(cc+ 64 )*HW + px];
        float vc = gt[(size_t)(cc+128 )*HW + px];
        float vo = gt[(size_t)(cc+192 )*HW + px];
        int g0 = cc >> 5;
        float a  = (vi-smu[g0  ])*srs[g0  ]*gg[cc    ] + gb[cc    ];
        float f2 = (vf-smu[g0+2])*srs[g0+2]*gg[cc+64 ] + gb[cc+64 ];
        float cg = (vc-smu[g0+4])*srs[g0+4]*gg[cc+128] + gb[cc+128];
        float o  = (vo-smu[g0+6])*srs[g0+6]*gg[cc+192] + gb[cc+192];
        float icv = icp[(size_t)cc*HW + px];
        float oc = icv*sigm(f2) + sigm(a)*tfast(cg);
        float oh = sigm(o)*tfast(oc);
        icp[(size_t)cc*HW + px] = oc;
        ohp[(size_t)cc*HW + px] = oh;
        ohpair[e] = oh;
      }
      sOh[tw(px, j)] = pack2h(ohpair[0], ohpair[1]);
    }
  }
  CP_WAIT0;          // weights landed
  __syncthreads();   // sOh + weights visible

  int warp = tid>>5, lane = tid&31, g = lane>>2, tq = lane&3;
  int wgrp  = warp >> 2;     // 0..3 -> yb within round
  int warp4 = warp & 3;

  #pragma unroll
  for (int pr=0; pr<3; pr++){
    int yb = 4*pr + wgrp;
    if (yb < 10){
      const unsigned* w  = uWall + yb*1024;
      const unsigned* xT = (yb < 6) ? sOh : sIm;
      const float* bias  = (yb < 6) ? h_b : m_b;
      int o0 = (yb < 6) ? yb*32 : (yb-6)*32;
      unsigned* dstT = 0; unsigned* dstV = 0; int crel = 0;
      if (yb < 6){
        if      (o0 <  64){ dstT = g_qT;    crel = o0;       }
        else if (o0 < 128){ dstT = g_kT[0]; crel = o0 - 64;  }
        else              { dstV = g_vv[0]; crel = o0 - 128; }
      } else {
        if (o0 < 64){ dstT = g_kT[1]; crel = o0; }
        else        { dstV = g_vv[1]; crel = o0 - 64; }
      }
      if (dstV){
        int wc = warp4&1, wm = warp4>>1;
        float acc[2][4];
        acc[0][0]=acc[0][1]=acc[0][2]=acc[0][3]=0.f;
        acc[1][0]=acc[1][1]=acc[1][2]=acc[1][3]=0.f;
        #pragma unroll
        for (int kk=0; kk<4; kk++){
          unsigned a[4]; ldsmA(a, w, wc*16, kk);
          unsigned bb[4]; ldsmB2(bb, xT, wm*16, kk);
          mma16(acc[0], a, bb[0], bb[1]);
          mma16(acc[1], a, bb[2], bb[3]);
        }
        int cc0 = wc*16 + g;
        float bv0 = bias[o0+cc0], bv1 = bias[o0+cc0+8];
        #pragma unroll
        for (int oct=0; oct<2; oct++){
          int col = p0 + wm*16 + oct*8 + 2*tq;
          dstV[((size_t)(b*64 + crel + cc0  ))*512 + (col>>1)] = pack2h(acc[oct][0]+bv0, acc[oct][1]+bv0);
          dstV[((size_t)(b*64 + crel + cc0+8))*512 + (col>>1)] = pack2h(acc[oct][2]+bv1, acc[oct][3]+bv1);
        }
      } else {
        int wpx = warp4&1, wo = warp4>>1;
        float acc[2][4];
        acc[0][0]=acc[0][1]=acc[0][2]=acc[0][3]=0.f;
        acc[1][0]=acc[1][1]=acc[1][2]=acc[1][3]=0.f;
        #pragma unroll
        for (int kk=0; kk<4; kk++){
          unsigned a[4]; ldsmA(a, xT, wpx*16, kk);
          unsigned bb[4]; ldsmB2(bb, w, wo*16, kk);
          mma16(acc[0], a, bb[0], bb[1]);
          mma16(acc[1], a, bb[2], bb[3]);
        }
        int row0 = wpx*16 + g;
        #pragma unroll
        for (int oct=0; oct<2; oct++){
          int col = wo*16 + oct*8 + 2*tq;
          float b0 = bias[o0+col], b1 = bias[o0+col+1];
          int wj = (crel + col) >> 1;
          dstT[((size_t)(b*1024 + p0 + row0  ))*32 + wj] = pack2h(acc[oct][0]+b0, acc[oct][1]+b1);
          dstT[((size_t)(b*1024 + p0 + row0+8))*32 + wj] = pack2h(acc[oct][2]+b0, acc[oct][3]+b1);
        }
      }
    }
  }
}

// ------------------- pass 1 (pipelined K): row softmax stats ----------
__global__ __launch_bounds__(256) void qk_stats(){
  __shared__ unsigned uQ[2048];
  __shared__ unsigned uK[2][2][2048];
  __shared__ float sM[2][64], sL[2][64];
  int b = blockIdx.x, n0 = blockIdx.y*64, which = blockIdx.z;
  const unsigned* qsrc = g_qT + (size_t)(b*1024 + n0)*32;
  const unsigned* ksrc = g_kT[which] + (size_t)b*1024*32;
  int tid=threadIdx.x, warp=tid>>5, tq=(tid&31)&3;
  int g = (tid&31)>>2;
  int wn = warp&3, wm = warp>>2;
  loadTile(uQ, qsrc, 32, tid);
  loadTileAsync(uK[0][0], ksrc, 32, tid);
  loadTileAsync(uK[0][1], ksrc + 64*32, 32, tid);
  CP_COMMIT;
  CP_WAIT0;
  __syncthreads();
  float M0=-1e30f, M1=-1e30f, L0=0.f, L1=0.f;
  for (int it=0; it<8; it++){
    int cur = it&1;
    if (it < 7){
      const unsigned* kn = ksrc + (size_t)(it+1)*128*32;
      loadTileAsync(uK[cur^1][0], kn, 32, tid);
      loadTileAsync(uK[cur^1][1], kn + 64*32, 32, tid);
      CP_COMMIT;
    }
    const unsigned* kt = uK[cur][wm];
    float cfr[8][4];
    #pragma unroll
    for(int mf=0;mf<8;mf++){cfr[mf][0]=0.f;cfr[mf][1]=0.f;cfr[mf][2]=0.f;cfr[mf][3]=0.f;}
    #pragma unroll
    for (int kk=0; kk<4; kk++){
      unsigned a[4]; ldsmA(a, uQ, wn*16, kk);
      #pragma unroll
      for (int mp=0; mp<4; mp++){
        unsigned bb[4]; ldsmB2(bb, kt, mp*16, kk);
        mma16(cfr[2*mp  ], a, bb[0], bb[1]);
        mma16(cfr[2*mp+1], a, bb[2], bb[3]);
      }
    }
    float tm0=-1e30f, tm1=-1e30f;
    #pragma unroll
    for(int mf=0;mf<8;mf++){
      tm0 = fmaxf(tm0, fmaxf(cfr[mf][0], cfr[mf][1]));
      tm1 = fmaxf(tm1, fmaxf(cfr[mf][2], cfr[mf][3]));
    }
    tm0 = fmaxf(tm0, __shfl_xor_sync(0xffffffffu, tm0, 1));
    tm0 = fmaxf(tm0, __shfl_xor_sync(0xffffffffu, tm0, 2));
    tm1 = fmaxf(tm1, __shfl_xor_sync(0xffffffffu, tm1, 1));
    tm1 = fmaxf(tm1, __shfl_xor_sync(0xffffffffu, tm1, 2));
    float nM0 = fmaxf(M0, tm0), nM1 = fmaxf(M1, tm1);
    float c0 = nM0*LOG2E, c1 = nM1*LOG2E;
    float s0=0.f, s1=0.f;
    #pragma unroll
    for(int mf=0;mf<8;mf++){
      float2 e0 = exp2_pair_f(__fmaf_rn(cfr[mf][0], LOG2E, -c0),
                              __fmaf_rn(cfr[mf][1], LOG2E, -c0));
      float2 e1 = exp2_pair_f(__fmaf_rn(cfr[mf][2], LOG2E, -c1),
                              __fmaf_rn(cfr[mf][3], LOG2E, -c1));
      s0 += e0.x + e0.y;
      s1 += e1.x + e1.y;
    }
    s0 += __shfl_xor_sync(0xffffffffu, s0, 1);
    s0 += __shfl_xor_sync(0xffffffffu, s0, 2);
    s1 += __shfl_xor_sync(0xffffffffu, s1, 1);
    s1 += __shfl_xor_sync(0xffffffffu, s1, 2);
    L0 = L0*__expf(M0-nM0) + s0; M0 = nM0;
    L1 = L1*__expf(M1-nM1) + s1; M1 = nM1;
    if (it < 7){ CP_WAIT0; }
    __syncthreads();
  }
  if (tq==0){
    sM[wm][wn*16+g  ] = M0; sL[wm][wn*16+g  ] = L0;
    sM[wm][wn*16+8+g] = M1; sL[wm][wn*16+8+g] = L1;
  }
  __syncthreads();
  if (tid<64){
    float Ma = sM[0][tid], Mb = sM[1][tid];
    float M  = fmaxf(Ma, Mb);
    float L  = sL[0][tid]*__expf(Ma-M) + sL[1][tid]*__expf(Mb-M);
    g_roff[which][b*HW + n0 + tid] = __fmaf_rn(M, LOG2E, __log2f(L));
  }
}

// ------------------- merged pass 2 + tail (128-n iterations) --------------------
#define WB 22784
__global__ __launch_bounds__(512,1) void av_tail(const float* __restrict__ z1_b,
                                                 const float* __restrict__ z2_b,
                                                 float* __restrict__ out, int t, int ws)
{
  extern __shared__ unsigned arena[];
  int b = blockIdx.x, m0 = blockIdx.y*64;
  int p0 = m0;
  int tid = threadIdx.x;
  int lane = tid & 31, g = lane>>2, tq = lane&3;

  // ================= AV phase =================
  {
    int which = tid >> 8;
    int ltid  = tid & 255;
    int warp8 = ltid >> 5;
    int wr = warp8 & 3, wm = warp8 >> 2;
    unsigned* base = arena + which*WB;
    unsigned* uK  = base;
    unsigned* uQb = base + 2048;
    unsigned* uVb = base + 10240;
    unsigned* uP  = base + 18432;
    float*   sro  = (float*)(base + 22528);
    const unsigned* qsrc = g_qT + (size_t)b*1024*32;
    const unsigned* ksrc = g_kT[which] + (size_t)(b*1024 + m0)*32;
    const unsigned* vsrc = g_vv[which] + (size_t)b*64*512;
    const float*    roff = g_roff[which] + b*HW;

    loadTile(uK, ksrc, 32, ltid);
    loadTileAsync(uQb,        qsrc,          32, ltid);
    loadTileAsync(uQb + 2048, qsrc + 64*32,  32, ltid);
    loadTileAsync(uVb,        vsrc,          512, ltid);
    loadTileAsync(uVb + 2048, vsrc + 32,     512, ltid);
    CP_COMMIT;
    if (ltid < 128) sro[ltid] = roff[ltid];
    float accZ[4][4];
    #pragma unroll
    for(int mf=0;mf<4;mf++){accZ[mf][0]=0.f;accZ[mf][1]=0.f;accZ[mf][2]=0.f;accZ[mf][3]=0.f;}
    CP_WAIT0;
    __syncthreads();

    for (int itn=0; itn<8; itn++){
      int nb = itn*128;
      int cur = itn&1;
      if (itn < 7){
        int buf = cur^1;
        loadTileAsync(uQb + buf*4096,        qsrc + (size_t)(nb+128)*32, 32, ltid);
        loadTileAsync(uQb + buf*4096 + 2048, qsrc + (size_t)(nb+192)*32, 32, ltid);
        loadTileAsync(uVb + buf*4096,        vsrc + ((nb+128)>>1), 512, ltid);
        loadTileAsync(uVb + buf*4096 + 2048, vsrc + ((nb+192)>>1), 512, ltid);
        CP_COMMIT;
        if (ltid < 128) sro[buf*128 + ltid] = roff[nb+128+ltid];
      }
      #pragma unroll
      for (int s=0; s<2; s++){
        unsigned* uQ = uQb + cur*4096 + s*2048;
        float*    sr = sro + cur*128 + s*64;
        unsigned* uPs = uP + s*2048;
        float accS[4][4];
        #pragma unroll
        for(int mf=0;mf<4;mf++){accS[mf][0]=0.f;accS[mf][1]=0.f;accS[mf][2]=0.f;accS[mf][3]=0.f;}
        #pragma unroll
        for (int kk=0; kk<4; kk++){
          unsigned a[4]; ldsmA(a, uK, wr*16, kk);
          #pragma unroll
          for (int mp=0; mp<2; mp++){
            unsigned bb[4]; ldsmB2(bb, uQ, wm*32 + mp*16, kk);
            mma16(accS[2*mp  ], a, bb[0], bb[1]);
            mma16(accS[2*mp+1], a, bb[2], bb[3]);
          }
        }
        #pragma unroll
        for (int mf=0; mf<4; mf++){
          int n = wm*32 + mf*8 + 2*tq;
          float ro0 = sr[n], ro1 = sr[n+1];
          int jn = n >> 1;
          int r0 = wr*16 + g;
          uPs[tw(r0,   jn)] = exp2_pair_h(__fmaf_rn(accS[mf][0], LOG2E, -ro0),
                                          __fmaf_rn(accS[mf][1], LOG2E, -ro1));
          uPs[tw(r0+8, jn)] = exp2_pair_h(__fmaf_rn(accS[mf][2], LOG2E, -ro0),
                                          __fmaf_rn(accS[mf][3], LOG2E, -ro1));
        }
      }
      __syncthreads();
      #pragma unroll
      for (int s=0; s<2; s++){
        unsigned* uV = uVb + cur*4096 + s*2048;
        unsigned* uPs = uP + s*2048;
        #pragma unroll
        for (int kk=0; kk<4; kk++){
          unsigned a[4]; ldsmA(a, uV, wr*16, kk);
          #pragma unroll
          for (int mp=0; mp<2; mp++){
            unsigned bb[4]; ldsmB2(bb, uPs, wm*32 + mp*16, kk);
            mma16(accZ[2*mp  ], a, bb[0], bb[1]);
            mma16(accZ[2*mp+1], a, bb[2], bb[3]);
          }
        }
      }
      if (itn < 7){ CP_WAIT0; }
      __syncthreads();
    }
    unsigned* sZc = arena;
    int zoff = which*64;
    #pragma unroll
    for (int mf=0; mf<4; mf++){
      int r0 = zoff + wr*16 + g, r1 = r0 + 8;
      int col = wm*32 + mf*8 + 2*tq;
      *(uint2*)&sZc[r0*72 + col] = make_uint2(f2t(accZ[mf][0]), f2t(accZ[mf][1]));
      *(uint2*)&sZc[r1*72 + col] = make_uint2(f2t(accZ[mf][2]), f2t(accZ[mf][3]));
    }
  }
  // ================= tail phase =================
  unsigned* sZc  = arena;
  unsigned* uz1  = arena + 9216;
  unsigned* sOh  = arena + 17664;
  unsigned* sZ   = arena + 22272;
  unsigned* wch0 = arena + 26880;
  unsigned* wch1 = arena + 28480;
  float*  gates  = (float*)arena;

  for (int i4=tid; i4<2048; i4+=512)
    cpa16(&uz1[(i4>>5)*132 + (i4&31)*4], g_z1u + i4*4);
  if (tid < 384)
    cpa16(&wch0[(tid/48)*200 + (tid%48)*4], g_z2T + (tid/48)*192 + (tid%48)*4);
  CP_COMMIT;
  for (int idx=tid; idx<2048; idx+=512){
    int c = idx>>5, p2 = idx&31;
    float2 v = *(const float2*)&g_oh[((size_t)b*64+c)*HW + p0 + 2*p2];
    *(uint2*)&sOh[c*72 + 2*p2] = make_uint2(f2t(v.x), f2t(v.y));
  }
  CP_WAIT0;
  __syncthreads();

  int warp16 = tid>>5;
  int wc = warp16 & 1, wm8 = warp16 >> 1;

  float a1[2][4];
  #pragma unroll
  for(int ot=0;ot<2;ot++){a1[ot][0]=0.f;a1[ot][1]=0.f;a1[ot][2]=0.f;a1[ot][3]=0.f;}
  for (int cc=0; cc<128; cc+=8){
    unsigned b0 = sZc[(cc+tq  )*72 + wm8*8 + g];
    unsigned b1 = sZc[(cc+tq+4)*72 + wm8*8 + g];
    #pragma unroll
    for (int ot=0; ot<2; ot++){
      unsigned a[4];
      int r = ot*32 + wc*16 + g;
      a[0]=uz1[(r  )*132 + cc+tq];   a[1]=uz1[(r+8)*132 + cc+tq];
      a[2]=uz1[(r  )*132 + cc+tq+4]; a[3]=uz1[(r+8)*132 + cc+tq+4];
      mma8(a1[ot], a, b0, b1);
    }
  }
  __syncthreads();
  #pragma unroll
  for (int ot=0; ot<2; ot++){
    int r0 = ot*32 + wc*16 + g, r1 = r0 + 8;
    int col = wm8*8 + 2*tq;
    float bv0 = z1_b[r0], bv1 = z1_b[r1];
    *(uint2*)&sZ[r0*72 + col] = make_uint2(f2t(a1[ot][0]+bv0), f2t(a1[ot][1]+bv0));
    *(uint2*)&sZ[r1*72 + col] = make_uint2(f2t(a1[ot][2]+bv1), f2t(a1[ot][3]+bv1));
  }
  float a2[6][4];
  #pragma unroll
  for(int ot=0;ot<6;ot++){a2[ot][0]=0.f;a2[ot][1]=0.f;a2[ot][2]=0.f;a2[ot][3]=0.f;}
  for (int ch=0; ch<16; ch++){
    unsigned* wch = (ch&1) ? wch1 : wch0;
    if (ch > 0){ CP_WAIT0; }
    __syncthreads();
    if (ch < 15){
      unsigned* wn = ((ch+1)&1) ? wch1 : wch0;
      if (tid < 384)
        cpa16(&wn[(tid/48)*200 + (tid%48)*4], g_z2T + ((size_t)(ch+1)*8 + tid/48)*192 + (tid%48)*4);
      CP_COMMIT;
    }
    int cc = ch*8;
    const unsigned* src = (cc<64) ? (sZ + cc*72) : (sOh + (cc-64)*72);
    unsigned b0 = src[ tq   *72 + wm8*8 + g];
    unsigned b1 = src[(tq+4)*72 + wm8*8 + g];
    #pragma unroll
    for (int ot=0; ot<6; ot++){
      unsigned a[4];
      int o = ot*32 + wc*16 + g;
      a[0]=wch[ tq   *200 + o];   a[1]=wch[ tq   *200 + o+8];
      a[2]=wch[(tq+4)*200 + o];   a[3]=wch[(tq+4)*200 + o+8];
      mma8(a2[ot], a, b0, b1);
    }
  }
  __syncthreads();
  #pragma unroll
  for (int ot=0; ot<6; ot++){
    int r0 = ot*32 + wc*16 + g, r1 = r0 + 8;
    int col = wm8*8 + 2*tq;
    float bv0 = z2_b[r0], bv1 = z2_b[r1];
    *(float2*)&gates[r0*66 + col] = make_float2(a2[ot][0]+bv0, a2[ot][1]+bv0);
    *(float2*)&gates[r1*66 + col] = make_float2(a2[ot][2]+bv1, a2[ot][3]+bv1);
  }
  __syncthreads();
  for (int i=tid; i<4096; i+=512){
    int c = i>>6, p = i&63;
    float vo = gates[(c     )*66 + p];
    float vg = gates[(64 +c )*66 + p];
    float vi = gates[(128+c )*66 + p];
    int idx = (b*64 + c)*1024 + p0 + p;
    float si = sigm(vi);
    float om  = tfast(vg)*si + (1.f-si)*g_im[idx];
    float oh2 = sigm(vo)*om;
    g_im[idx] = om;
    g_ih[idx] = oh2;
    out[(((size_t)b*TT + t)*64 + c)*HW + p0 + p] = oh2;
    if (ws){
      float* st = out + (size_t)BB*TT*64*HW;
      st[idx]            = oh2;
      st[NSTATE + idx]   = g_ic[idx];
      st[2*NSTATE + idx] = om;
    }
  }
}

extern "C" void kernel_launch(void* const* d_in, const int* in_sizes, int n_in,
                              void* d_out, int out_size)
{
  const float* inputs = (const float*)d_in[0];
  const float* conv_w = (const float*)d_in[1];
  const float* conv_b = (const float*)d_in[2];
  const float* gn_g   = (const float*)d_in[3];
  const float* gn_b   = (const float*)d_in[4];
  const float* h_w    = (const float*)d_in[5];
  const float* h_b    = (const float*)d_in[6];
  const float* m_w    = (const float*)d_in[7];
  const float* m_b    = (const float*)d_in[8];
  const float* z1_w   = (const float*)d_in[9];
  const float* z1_b   = (const float*)d_in[10];
  const float* z2_w   = (const float*)d_in[11];
  const float* z2_b   = (const float*)d_in[12];
  float* out = (float*)d_out;

  const int AT_SMEM = 2*WB*4;      // 182272
  const int GQ_SMEM = 12288*4 + 64; // 49216
  cudaFuncSetAttribute(av_tail, cudaFuncAttributeMaxDynamicSharedMemorySize, AT_SMEM);
  cudaFuncSetAttribute(gn_qkv,  cudaFuncAttributeMaxDynamicSharedMemorySize, GQ_SMEM);

  zero_states<<<2048,256>>>();
  wtrans<<<256,256>>>(conv_w, z2_w, h_w, m_w, z1_w);
  int write_states = (out_size >= (int)(BB*TT*64*HW + 3*NSTATE)) ? 1 : 0;

  for (int t=0; t<TT; t++){
    conv_tc<<<dim3(8,4,8),256>>>(inputs, conv_b, t);
    gn_qkv<<<dim3(8,32),512,GQ_SMEM>>>(gn_g, gn_b, h_b, m_b, t);
    qk_stats<<<dim3(8,16,2),256>>>();
    av_tail<<<dim3(8,16),512,AT_SMEM>>>(z1_b, z2_b, out, t, (t==TT-1) ? write_states : 0);
  }
}